// round 1
// baseline (speedup 1.0000x reference)
#include <cuda_runtime.h>
#include <cuda_bf16.h>
#include <math.h>

// ---------------- problem constants ----------------
#define BATCH 32
#define ZL 64
#define SL 256
#define TT 320           // ZL+SL
#define NN 384           // ZL + TT (xc length)
#define DIM 768
#define HEADS 12
#define HD 64
#define HID 3072
#define QKV3 2304

// output offsets (float elements)
#define O_XOUT   0LL
#define O_GIT    7864320LL
#define O_GIS    7866368LL
#define O_ATTN   7874560LL
#define O_XIOUT  64497664LL
#define O_GITI   72361984LL
#define O_GISI   72364032LL
#define O_IATTN  72372224LL
#define O_ALPHA  128995328LL
#define O_UM     129003520LL
#define O_U      129011712LL
#define O_UI     129019904LL

// ---------------- scratch (device globals; allocation-free) ----------------
__device__ float g_cat   [BATCH*ZL*2*DIM];      // concat(z,zi) features
__device__ float g_zf    [BATCH*ZL*DIM];
__device__ float g_ns    [BATCH*SL*DIM];
__device__ float g_nsi   [BATCH*SL*DIM];
__device__ float g_attnx [BATCH*ZL*SL];
__device__ float g_attnxi[BATCH*ZL*SL];
__device__ float g_xc    [BATCH*NN*DIM];
__device__ float g_ln    [BATCH*NN*DIM];
__device__ float g_qkv   [BATCH*NN*QKV3];
__device__ float g_ao    [BATCH*NN*DIM];
__device__ float g_xattn [BATCH*NN*DIM];
__device__ float g_xiattn[BATCH*NN*DIM];
__device__ float g_v     [BATCH*SL*DIM];
__device__ float g_vf    [BATCH*SL*DIM];
__device__ float g_vfc   [BATCH*TT*DIM];
__device__ float g_xnew  [BATCH*TT*DIM];
__device__ float g_xinew [BATCH*TT*DIM];
__device__ float g_adap2 [BATCH*TT*DIM];
__device__ float g_h     [BATCH*TT*HID];

// ---------------- GEMM: C = alpha*A*B(^T) + bias + res1 + res2, opt GELU ----
// A: (M,K) row-major, lda. BT=true: B is (N,K) row-major (weight layout).
// BT=false: B is (K,N) row-major. Batched over (b,h) via blockIdx.z.
// Requires M%64==0, N%64==0, K%16==0.
#define BM 64
#define BN 64
#define BK 16

template<bool BT>
__global__ __launch_bounds__(256)
void gemm64(const float* __restrict__ A, const float* __restrict__ B,
            const float* __restrict__ bias,
            const float* __restrict__ res1, const float* __restrict__ res2,
            float* __restrict__ C,
            int K, int lda, int ldb, int ldc,
            long long sAb, long long sBb, long long sCb,
            int batchH,
            long long sAh, long long sBh, long long sCh,
            float alpha, int act)
{
    __shared__ float As[BK][BM+4];
    __shared__ float Bs[BK][BN+4];

    int bz = blockIdx.z;
    int b  = bz / batchH;
    int h  = bz - b*batchH;
    A += (long long)b*sAb + (long long)h*sAh;
    B += (long long)b*sBb + (long long)h*sBh;
    long long coff = (long long)b*sCb + (long long)h*sCh;
    C += coff;
    if (res1) res1 += coff;
    if (res2) res2 += coff;

    const int m0 = blockIdx.y * BM;
    const int n0 = blockIdx.x * BN;

    const int tid = threadIdx.x;
    const int tx = tid & 15;    // micro col group
    const int ty = tid >> 4;    // micro row group

    // loader maps
    const int lk = tid & 15;    // k within tile
    const int lr = tid >> 4;    // base row 0..15 (strided by 16)
    const int lnn = tid & 63;   // n (BN mode)
    const int lkk = tid >> 6;   // k base (BN mode)

    const float* Ab = A + (long long)m0*lda;
    const float* Bb = BT ? (B + (long long)n0*ldb) : (B + n0);

    float acc[4][4] = {{0.f}};

    for (int k0 = 0; k0 < K; k0 += BK) {
        #pragma unroll
        for (int i = 0; i < 4; i++)
            As[lk][lr + 16*i] = Ab[(long long)(lr + 16*i)*lda + (k0 + lk)];
        if (BT) {
            #pragma unroll
            for (int i = 0; i < 4; i++)
                Bs[lk][lr + 16*i] = Bb[(long long)(lr + 16*i)*ldb + (k0 + lk)];
        } else {
            #pragma unroll
            for (int i = 0; i < 4; i++)
                Bs[lkk + 4*i][lnn] = Bb[(long long)(k0 + lkk + 4*i)*ldb + lnn];
        }
        __syncthreads();
        #pragma unroll
        for (int kk = 0; kk < BK; kk++) {
            float4 a4 = *(const float4*)(&As[kk][ty*4]);
            float4 b4 = *(const float4*)(&Bs[kk][tx*4]);
            float ar[4] = {a4.x, a4.y, a4.z, a4.w};
            float br[4] = {b4.x, b4.y, b4.z, b4.w};
            #pragma unroll
            for (int i = 0; i < 4; i++)
                #pragma unroll
                for (int j = 0; j < 4; j++)
                    acc[i][j] = fmaf(ar[i], br[j], acc[i][j]);
        }
        __syncthreads();
    }

    #pragma unroll
    for (int i = 0; i < 4; i++) {
        int row = m0 + ty*4 + i;
        #pragma unroll
        for (int j = 0; j < 4; j++) {
            int col = n0 + tx*4 + j;
            float v = acc[i][j] * alpha;
            if (bias) v += bias[col];
            long long idx = (long long)row*ldc + col;
            if (res1) v += res1[idx];
            if (res2) v += res2[idx];
            if (act == 1) v = 0.5f * v * (1.f + erff(v * 0.70710678118654752f));
            C[idx] = v;
        }
    }
}

// ---------------- LayerNorm over 768 features -------------------------------
// grid: (rows_per_batch, nbatch), block 256 (3 elems/thread)
__global__ void ln_kernel(const float* __restrict__ in, float* __restrict__ out,
                          const float* __restrict__ g, const float* __restrict__ b,
                          long long in_bstride, long long out_bstride)
{
    const float* x = in  + (long long)blockIdx.y*in_bstride  + (long long)blockIdx.x*DIM;
    float*       y = out + (long long)blockIdx.y*out_bstride + (long long)blockIdx.x*DIM;
    int tid = threadIdx.x;
    float v0 = x[tid], v1 = x[tid+256], v2 = x[tid+512];

    __shared__ float sh[256];
    sh[tid] = v0 + v1 + v2;
    __syncthreads();
    for (int o = 128; o > 0; o >>= 1) { if (tid < o) sh[tid] += sh[tid+o]; __syncthreads(); }
    float mean = sh[0] * (1.f/768.f);
    __syncthreads();
    float d0 = v0-mean, d1 = v1-mean, d2 = v2-mean;
    sh[tid] = d0*d0 + d1*d1 + d2*d2;
    __syncthreads();
    for (int o = 128; o > 0; o >>= 1) { if (tid < o) sh[tid] += sh[tid+o]; __syncthreads(); }
    float inv = rsqrtf(sh[0] * (1.f/768.f) + 1e-5f);
    y[tid]     = d0*inv*g[tid]     + b[tid];
    y[tid+256] = d1*inv*g[tid+256] + b[tid+256];
    y[tid+512] = d2*inv*g[tid+512] + b[tid+512];
}

// ---------------- softmax over rows of length 384 ---------------------------
__global__ void softmax384(float* __restrict__ data)
{
    float* x = data + (long long)blockIdx.x * 384;
    int tid = threadIdx.x;  // 128
    float a = x[tid], b = x[tid+128], c = x[tid+256];
    __shared__ float sh[128];
    float m = fmaxf(a, fmaxf(b, c));
    sh[tid] = m; __syncthreads();
    for (int o = 64; o > 0; o >>= 1) { if (tid < o) sh[tid] = fmaxf(sh[tid], sh[tid+o]); __syncthreads(); }
    m = sh[0]; __syncthreads();
    float e0 = expf(a-m), e1 = expf(b-m), e2 = expf(c-m);
    sh[tid] = e0+e1+e2; __syncthreads();
    for (int o = 64; o > 0; o >>= 1) { if (tid < o) sh[tid] += sh[tid+o]; __syncthreads(); }
    float inv = 1.f / sh[0];
    x[tid] = e0*inv; x[tid+128] = e1*inv; x[tid+256] = e2*inv;
}

// ---------------- fusion: entropies over ZL axis ----------------------------
// grid B, block 256 (one thread per s)
__global__ void fusion_kernel(const float* __restrict__ ax, const float* __restrict__ axi,
                              float* __restrict__ alpha_o, float* __restrict__ um_o,
                              float* __restrict__ u_o, float* __restrict__ ui_o)
{
    int b = blockIdx.x, s = threadIdx.x;
    const float* X  = ax  + (long long)b*ZL*SL + s;
    const float* Xi = axi + (long long)b*ZL*SL + s;
    float u, ui;
    {
        float mx = -1e30f;
        for (int t = 0; t < ZL; t++) mx = fmaxf(mx, X[t*SL]);
        float sum = 0.f;
        for (int t = 0; t < ZL; t++) sum += expf(X[t*SL] - mx);
        float inv = 1.f/sum, acc = 0.f;
        for (int t = 0; t < ZL; t++) { float p = expf(X[t*SL]-mx)*inv; acc -= p*logf(p + 1e-8f); }
        u = acc;
    }
    {
        float mx = -1e30f;
        for (int t = 0; t < ZL; t++) mx = fmaxf(mx, Xi[t*SL]);
        float sum = 0.f;
        for (int t = 0; t < ZL; t++) sum += expf(Xi[t*SL] - mx);
        float inv = 1.f/sum, acc = 0.f;
        for (int t = 0; t < ZL; t++) { float p = expf(Xi[t*SL]-mx)*inv; acc -= p*logf(p + 1e-8f); }
        ui = acc;
    }
    int idx = b*SL + s;
    float alpha = 1.f / (1.f + expf(-(ui - u)));
    alpha_o[idx] = alpha;
    um_o[idx] = 0.5f*(u + ui);
    u_o[idx] = u;
    ui_o[idx] = ui;
}

// ---------------- elementwise helpers ----------------------------------------
__global__ void cat_feat_k(const float* __restrict__ x, const float* __restrict__ xi,
                           float* __restrict__ o)
{
    long long i = (long long)blockIdx.x*blockDim.x + threadIdx.x;
    const long long n = (long long)BATCH*ZL*2*DIM;
    if (i >= n) return;
    int c = (int)(i % (2*DIM));
    long long bt = i / (2*DIM);
    long long b = bt / ZL, t = bt % ZL;
    long long src = (b*TT + t)*DIM;
    o[i] = (c < DIM) ? x[src + c] : xi[src + c - DIM];
}

__global__ void cat_seq_k(const float* __restrict__ zf, const float* __restrict__ x,
                          float* __restrict__ o)
{
    long long i = (long long)blockIdx.x*blockDim.x + threadIdx.x;
    const long long n = (long long)BATCH*NN*DIM;
    if (i >= n) return;
    int c = (int)(i % DIM);
    long long bt = i / DIM;
    long long b = bt / NN, t = bt % NN;
    o[i] = (t < ZL) ? zf[(b*ZL + t)*DIM + c]
                    : x[(b*TT + (t-ZL))*DIM + c];
}

__global__ void make_v_k(const float* __restrict__ ns, const float* __restrict__ nsi,
                         const float* __restrict__ alpha, float* __restrict__ v)
{
    long long i = (long long)blockIdx.x*blockDim.x + threadIdx.x;
    const long long n = (long long)BATCH*SL*DIM;
    if (i >= n) return;
    long long bs = i / DIM;
    float a = alpha[bs];
    v[i] = a*ns[i] + (1.f - a)*nsi[i];
}

__global__ void make_vfc_k(const float* __restrict__ xiattn, const float* __restrict__ vf,
                           float* __restrict__ o)
{
    long long i = (long long)blockIdx.x*blockDim.x + threadIdx.x;
    const long long n = (long long)BATCH*TT*DIM;
    if (i >= n) return;
    int c = (int)(i % DIM);
    long long bt = i / DIM;
    long long b = bt / TT, t = bt % TT;
    o[i] = (t < ZL) ? xiattn[(b*NN + t)*DIM + c]
                    : vf[(b*SL + (t-ZL))*DIM + c];
}

__global__ void make_xnew_k(const float* __restrict__ x, const float* __restrict__ xi,
                            const float* __restrict__ xattn, const float* __restrict__ xiattn,
                            const float* __restrict__ vfc,
                            float* __restrict__ xo, float* __restrict__ xio)
{
    long long i = (long long)blockIdx.x*blockDim.x + threadIdx.x;
    const long long n = (long long)BATCH*TT*DIM;
    if (i >= n) return;
    int c = (int)(i % DIM);
    long long bt = i / DIM;
    long long b = bt / TT, t = bt % TT;
    long long aidx = (b*NN + ZL + t)*DIM + c;   // rows 64..383 of attn outputs
    float vf = vfc[i];
    xo[i]  = x[i]  + xattn[aidx]  + vf;
    xio[i] = xi[i] + xiattn[aidx] + vf;
}

__global__ void i2f_k(const int* __restrict__ in, float* __restrict__ out, int n)
{
    int i = blockIdx.x*blockDim.x + threadIdx.x;
    if (i < n) out[i] = (float)in[i];
}

// ---------------- host-side launch helpers ----------------------------------
static inline void gemm(const float* A, const float* B, const float* bias,
                        const float* r1, const float* r2, float* C,
                        int M, int N, int K, int lda, int ldb, int ldc,
                        long long sAb, long long sBb, long long sCb,
                        int nb, int nh,
                        long long sAh, long long sBh, long long sCh,
                        float alpha, int act, bool bt)
{
    dim3 g(N/BN, M/BM, nb*nh);
    if (bt) gemm64<true ><<<g, 256>>>(A,B,bias,r1,r2,C,K,lda,ldb,ldc,sAb,sBb,sCb,nh,sAh,sBh,sCh,alpha,act);
    else    gemm64<false><<<g, 256>>>(A,B,bias,r1,r2,C,K,lda,ldb,ldc,sAb,sBb,sCb,nh,sAh,sBh,sCh,alpha,act);
}

static inline int cdiv(long long a, int b) { return (int)((a + b - 1) / b); }

extern "C" void kernel_launch(void* const* d_in, const int* in_sizes, int n_in,
                              void* d_out, int out_size)
{
    const float* x      = (const float*)d_in[0];
    const float* xi     = (const float*)d_in[1];
    const int*   git    = (const int*)  d_in[2];
    const int*   giti   = (const int*)  d_in[3];
    const int*   gis    = (const int*)  d_in[4];
    const int*   gisi   = (const int*)  d_in[5];
    const float* w_qkv  = (const float*)d_in[6];
    const float* b_qkv  = (const float*)d_in[7];
    const float* w_proj = (const float*)d_in[8];
    const float* b_proj = (const float*)d_in[9];
    const float* g1     = (const float*)d_in[10];
    const float* bt1    = (const float*)d_in[11];
    const float* g2     = (const float*)d_in[12];
    const float* bt2    = (const float*)d_in[13];
    const float* w_fc1  = (const float*)d_in[14];
    const float* b_fc1  = (const float*)d_in[15];
    const float* w_fc2  = (const float*)d_in[16];
    const float* b_fc2  = (const float*)d_in[17];
    const float* w_al   = (const float*)d_in[18];
    const float* b_al   = (const float*)d_in[19];
    const float* w_al2  = (const float*)d_in[20];
    const float* b_al2  = (const float*)d_in[21];
    const float* w_fus  = (const float*)d_in[22];
    const float* b_fus  = (const float*)d_in[23];
    float* out = (float*)d_out;

    float *p_cat, *p_zf, *p_ns, *p_nsi, *p_attnx, *p_attnxi, *p_xc, *p_ln, *p_qkv,
          *p_ao, *p_xattn, *p_xiattn, *p_v, *p_vf, *p_vfc, *p_xnew, *p_xinew,
          *p_adap2, *p_h;
    cudaGetSymbolAddress((void**)&p_cat,    g_cat);
    cudaGetSymbolAddress((void**)&p_zf,     g_zf);
    cudaGetSymbolAddress((void**)&p_ns,     g_ns);
    cudaGetSymbolAddress((void**)&p_nsi,    g_nsi);
    cudaGetSymbolAddress((void**)&p_attnx,  g_attnx);
    cudaGetSymbolAddress((void**)&p_attnxi, g_attnxi);
    cudaGetSymbolAddress((void**)&p_xc,     g_xc);
    cudaGetSymbolAddress((void**)&p_ln,     g_ln);
    cudaGetSymbolAddress((void**)&p_qkv,    g_qkv);
    cudaGetSymbolAddress((void**)&p_ao,     g_ao);
    cudaGetSymbolAddress((void**)&p_xattn,  g_xattn);
    cudaGetSymbolAddress((void**)&p_xiattn, g_xiattn);
    cudaGetSymbolAddress((void**)&p_v,      g_v);
    cudaGetSymbolAddress((void**)&p_vf,     g_vf);
    cudaGetSymbolAddress((void**)&p_vfc,    g_vfc);
    cudaGetSymbolAddress((void**)&p_xnew,   g_xnew);
    cudaGetSymbolAddress((void**)&p_xinew,  g_xinew);
    cudaGetSymbolAddress((void**)&p_adap2,  g_adap2);
    cudaGetSymbolAddress((void**)&p_h,      g_h);

    const float scale_dim = 1.f / sqrtf((float)DIM);  // 768^-0.5
    const float scale_hd  = 0.125f;                   // 64^-0.5

    // ---- index passthroughs (int -> float) ----
    i2f_k<<<cdiv(BATCH*ZL, 256), 256>>>(git,  out + O_GIT,  BATCH*ZL);
    i2f_k<<<cdiv(BATCH*SL, 256), 256>>>(gis,  out + O_GIS,  BATCH*SL);
    i2f_k<<<cdiv(BATCH*ZL, 256), 256>>>(giti, out + O_GITI, BATCH*ZL);
    i2f_k<<<cdiv(BATCH*SL, 256), 256>>>(gisi, out + O_GISI, BATCH*SL);

    // ---- z_f = concat(z, zi) @ w_al^T + b_al ----
    cat_feat_k<<<cdiv((long long)BATCH*ZL*2*DIM, 256), 256>>>(x, xi, p_cat);
    gemm(p_cat, w_al, b_al, nullptr, nullptr, p_zf,
         BATCH*ZL, DIM, 2*DIM, 2*DIM, 2*DIM, DIM,
         0,0,0, 1,1, 0,0,0, 1.f, 0, true);

    // ---- ns/nsi = LN(s)/LN(si) ----
    ln_kernel<<<dim3(SL, BATCH), 256>>>(x  + (long long)ZL*DIM, p_ns,  g1, bt1,
                                        (long long)TT*DIM, (long long)SL*DIM);
    ln_kernel<<<dim3(SL, BATCH), 256>>>(xi + (long long)ZL*DIM, p_nsi, g1, bt1,
                                        (long long)TT*DIM, (long long)SL*DIM);

    // ---- attn_x / attn_xi = z_f @ ns^T * scale (batched per b) ----
    gemm(p_zf, p_ns, nullptr, nullptr, nullptr, p_attnx,
         ZL, SL, DIM, DIM, DIM, SL,
         (long long)ZL*DIM, (long long)SL*DIM, (long long)ZL*SL,
         BATCH, 1, 0,0,0, scale_dim, 0, true);
    gemm(p_zf, p_nsi, nullptr, nullptr, nullptr, p_attnxi,
         ZL, SL, DIM, DIM, DIM, SL,
         (long long)ZL*DIM, (long long)SL*DIM, (long long)ZL*SL,
         BATCH, 1, 0,0,0, scale_dim, 0, true);

    // ---- MHA for both streams ----
    const float* src[2]   = {x, xi};
    float*       attn_o[2]= {out + O_ATTN, out + O_IATTN};
    float*       proj_o[2]= {p_xattn, p_xiattn};
    for (int side = 0; side < 2; side++) {
        cat_seq_k<<<cdiv((long long)BATCH*NN*DIM, 256), 256>>>(p_zf, src[side], p_xc);
        ln_kernel<<<dim3(NN, BATCH), 256>>>(p_xc, p_ln, g1, bt1,
                                            (long long)NN*DIM, (long long)NN*DIM);
        // qkv
        gemm(p_ln, w_qkv, b_qkv, nullptr, nullptr, p_qkv,
             BATCH*NN, QKV3, DIM, DIM, DIM, QKV3,
             0,0,0, 1,1, 0,0,0, 1.f, 0, true);
        // scores = q @ k^T * hd^-0.5 -> directly into d_out attn region
        gemm(p_qkv, p_qkv + DIM, nullptr, nullptr, nullptr, attn_o[side],
             NN, NN, HD, QKV3, QKV3, NN,
             (long long)NN*QKV3, (long long)NN*QKV3, (long long)HEADS*NN*NN,
             BATCH, HEADS, HD, HD, (long long)NN*NN, scale_hd, 0, true);
        // softmax in place (this IS the attn output)
        softmax384<<<BATCH*HEADS*NN, 128>>>(attn_o[side]);
        // out = attn @ v  (B not transposed), write as (B, NN, H*HD)
        gemm(attn_o[side], p_qkv + 2*DIM, nullptr, nullptr, nullptr, p_ao,
             NN, HD, NN, NN, QKV3, DIM,
             (long long)HEADS*NN*NN, (long long)NN*QKV3, (long long)NN*DIM,
             BATCH, HEADS, (long long)NN*NN, HD, HD, 1.f, 0, false);
        // proj
        gemm(p_ao, w_proj, b_proj, nullptr, nullptr, proj_o[side],
             BATCH*NN, DIM, DIM, DIM, DIM, DIM,
             0,0,0, 1,1, 0,0,0, 1.f, 0, true);
    }

    // ---- fusion ----
    fusion_kernel<<<BATCH, SL>>>(p_attnx, p_attnxi,
                                 out + O_ALPHA, out + O_UM, out + O_U, out + O_UI);
    make_v_k<<<cdiv((long long)BATCH*SL*DIM, 256), 256>>>(p_ns, p_nsi, out + O_ALPHA, p_v);
    gemm(p_v, w_fus, b_fus, nullptr, nullptr, p_vf,
         BATCH*SL, DIM, DIM, DIM, DIM, DIM,
         0,0,0, 1,1, 0,0,0, 1.f, 0, true);
    make_vfc_k<<<cdiv((long long)BATCH*TT*DIM, 256), 256>>>(p_xiattn, p_vf, p_vfc);

    // ---- residual adds ----
    make_xnew_k<<<cdiv((long long)BATCH*TT*DIM, 256), 256>>>(
        x, xi, p_xattn, p_xiattn, p_vfc, p_xnew, p_xinew);

    // ---- adap2 = LN(v_fc, g2, bt2) @ w_al2^T + b_al2 ----
    ln_kernel<<<dim3(TT, BATCH), 256>>>(p_vfc, p_ln, g2, bt2,
                                        (long long)TT*DIM, (long long)TT*DIM);
    gemm(p_ln, w_al2, b_al2, nullptr, nullptr, p_adap2,
         BATCH*TT, DIM, DIM, DIM, DIM, DIM,
         0,0,0, 1,1, 0,0,0, 1.f, 0, true);

    // ---- MLP for both streams; fc2 epilogue fuses residual + adap2 ----
    float* xn[2]  = {p_xnew, p_xinew};
    float* xo[2]  = {out + O_XOUT, out + O_XIOUT};
    for (int side = 0; side < 2; side++) {
        ln_kernel<<<dim3(TT, BATCH), 256>>>(xn[side], p_ln, g2, bt2,
                                            (long long)TT*DIM, (long long)TT*DIM);
        gemm(p_ln, w_fc1, b_fc1, nullptr, nullptr, p_h,
             BATCH*TT, HID, DIM, DIM, DIM, HID,
             0,0,0, 1,1, 0,0,0, 1.f, 1, true);          // GELU (exact)
        gemm(p_h, w_fc2, b_fc2, xn[side], p_adap2, xo[side],
             BATCH*TT, DIM, HID, HID, HID, DIM,
             0,0,0, 1,1, 0,0,0, 1.f, 0, true);
    }
}

// round 3
// speedup vs baseline: 2.2207x; 2.2207x over previous
#include <cuda_runtime.h>
#include <cuda_bf16.h>
#include <math.h>
#include <cstdint>

// ---------------- problem constants ----------------
#define BATCH 32
#define ZL 64
#define SL 256
#define TT 320           // ZL+SL
#define NN 384           // ZL + TT (xc length)
#define DIM 768
#define HEADS 12
#define HD 64
#define HID 3072
#define QKV3 2304

// output offsets (float elements)
#define O_XOUT   0LL
#define O_GIT    7864320LL
#define O_GIS    7866368LL
#define O_ATTN   7874560LL
#define O_XIOUT  64497664LL
#define O_GITI   72361984LL
#define O_GISI   72364032LL
#define O_IATTN  72372224LL
#define O_ALPHA  128995328LL
#define O_UM     129003520LL
#define O_U      129011712LL
#define O_UI     129019904LL

// ---------------- scratch (device globals; allocation-free) ----------------
__device__ float g_cat   [BATCH*ZL*2*DIM];
__device__ float g_zf    [BATCH*ZL*DIM];
__device__ float g_ns    [BATCH*SL*DIM];
__device__ float g_nsi   [BATCH*SL*DIM];
__device__ float g_attnx [BATCH*ZL*SL];
__device__ float g_attnxi[BATCH*ZL*SL];
__device__ float g_xc    [BATCH*NN*DIM];
__device__ float g_ln    [BATCH*NN*DIM];
__device__ float g_qkv   [BATCH*NN*QKV3];
__device__ float g_vt    [BATCH*HEADS*HD*NN];
__device__ float g_ao    [BATCH*NN*DIM];
__device__ float g_xattn [BATCH*NN*DIM];
__device__ float g_xiattn[BATCH*NN*DIM];
__device__ float g_v     [BATCH*SL*DIM];
__device__ float g_vf    [BATCH*SL*DIM];
__device__ float g_vfc   [BATCH*TT*DIM];
__device__ float g_xnew  [BATCH*TT*DIM];
__device__ float g_xinew [BATCH*TT*DIM];
__device__ float g_adap2 [BATCH*TT*DIM];
__device__ float g_h     [BATCH*TT*HID];

// =============== mma.sync bf16 helpers (baseline ISA, works on sm_103) ======
__device__ __forceinline__ void mma16816(float* d, const uint32_t* a, const uint32_t* b) {
    asm volatile("mma.sync.aligned.m16n8k16.row.col.f32.bf16.bf16.f32 "
        "{%0,%1,%2,%3}, {%4,%5,%6,%7}, {%8,%9}, {%0,%1,%2,%3};"
        : "+f"(d[0]), "+f"(d[1]), "+f"(d[2]), "+f"(d[3])
        : "r"(a[0]), "r"(a[1]), "r"(a[2]), "r"(a[3]), "r"(b[0]), "r"(b[1]));
}

// split fp32 pair -> (hi bf16x2, lo bf16x2)
__device__ __forceinline__ void split2(float x, float y, uint32_t& h, uint32_t& l) {
    __nv_bfloat16 hx = __float2bfloat16_rn(x);
    __nv_bfloat16 hy = __float2bfloat16_rn(y);
    float lx = x - __bfloat162float(hx);
    float ly = y - __bfloat162float(hy);
    __nv_bfloat162 hp; hp.x = hx; hp.y = hy;
    __nv_bfloat162 lp; lp.x = __float2bfloat16_rn(lx); lp.y = __float2bfloat16_rn(ly);
    h = *(uint32_t*)&hp;
    l = *(uint32_t*)&lp;
}

// =============== 3xBF16 mma.sync GEMM ===============
// C = alpha * A @ B^T (+bias +res1 +res2, opt GELU)
// A: (M,K) row-major fp32, B: (N,K) row-major fp32.
// CTA tile 128x64, K chunk 32, 8 warps (4m x 2n), warp tile 32x32.
// M%128==0, N%64==0, K%32==0.
#define RW 40              // SMEM row width in halves (32 data + 8 pad)
#define STAGE_B 30720      // (128+128+64+64)*RW*2 bytes
#define MM_SMEM (2*STAGE_B)

__global__ __launch_bounds__(256, 2)
void mm_gemm(const float* __restrict__ A, const float* __restrict__ B,
             const float* __restrict__ bias,
             const float* __restrict__ res1, const float* __restrict__ res2,
             float* __restrict__ C,
             int K, int lda, int ldb, int ldc,
             long long sAb, long long sBb, long long sCb, int batchH,
             long long sAh, long long sBh, long long sCh,
             float alpha, int act)
{
    extern __shared__ char dsm[];

    const int tid  = threadIdx.x;
    const int lane = tid & 31;
    const int w    = tid >> 5;
    const int wm   = w >> 1;          // 0..3
    const int wn   = w & 1;           // 0..1
    const int g    = lane >> 2;       // 0..7
    const int t    = lane & 3;        // 0..3

    const int bz = blockIdx.z;
    const int b  = bz / batchH;
    const int h  = bz - b*batchH;
    const int m0 = blockIdx.y * 128;
    const int n0 = blockIdx.x * 64;
    const float* Ab = A + (long long)b*sAb + (long long)h*sAh + (long long)m0*lda;
    const float* Bb = B + (long long)b*sBb + (long long)h*sBh + (long long)n0*ldb;
    const long long coff = (long long)b*sCb + (long long)h*sCh;

    // loader mapping: thread handles col-group q (4 floats), rows r0+32p
    const int lq = tid & 7;           // 0..7 -> cols 4q..4q+3
    const int lr = tid >> 3;          // 0..31

    float Cf[2][4][4];
    #pragma unroll
    for (int mi = 0; mi < 2; mi++)
        #pragma unroll
        for (int ni = 0; ni < 4; ni++)
            #pragma unroll
            for (int j = 0; j < 4; j++) Cf[mi][ni][j] = 0.f;

    const int NC = K >> 5;
    float4 pA[4], pB[2];

    // prefetch chunk 0
    #pragma unroll
    for (int p = 0; p < 4; p++)
        pA[p] = *(const float4*)(Ab + (long long)(lr + 32*p)*lda + 4*lq);
    #pragma unroll
    for (int p = 0; p < 2; p++)
        pB[p] = *(const float4*)(Bb + (long long)(lr + 32*p)*ldb + 4*lq);

    for (int c = 0; c < NC; c++) {
        char* sb = dsm + (c & 1) * STAGE_B;
        __nv_bfloat16* Ah = (__nv_bfloat16*)sb;
        __nv_bfloat16* Al = Ah + 128*RW;
        __nv_bfloat16* Bh = Al + 128*RW;
        __nv_bfloat16* Bl = Bh + 64*RW;

        // ---- store prefetched chunk with hi/lo split ----
        #pragma unroll
        for (int p = 0; p < 4; p++) {
            uint32_t h0, l0, h1, l1;
            split2(pA[p].x, pA[p].y, h0, l0);
            split2(pA[p].z, pA[p].w, h1, l1);
            int off = (lr + 32*p)*RW + 4*lq;
            *(uint32_t*)(Ah + off)     = h0;
            *(uint32_t*)(Ah + off + 2) = h1;
            *(uint32_t*)(Al + off)     = l0;
            *(uint32_t*)(Al + off + 2) = l1;
        }
        #pragma unroll
        for (int p = 0; p < 2; p++) {
            uint32_t h0, l0, h1, l1;
            split2(pB[p].x, pB[p].y, h0, l0);
            split2(pB[p].z, pB[p].w, h1, l1);
            int off = (lr + 32*p)*RW + 4*lq;
            *(uint32_t*)(Bh + off)     = h0;
            *(uint32_t*)(Bh + off + 2) = h1;
            *(uint32_t*)(Bl + off)     = l0;
            *(uint32_t*)(Bl + off + 2) = l1;
        }
        __syncthreads();

        // ---- prefetch next chunk ----
        if (c + 1 < NC) {
            const int k0 = (c + 1) << 5;
            #pragma unroll
            for (int p = 0; p < 4; p++)
                pA[p] = *(const float4*)(Ab + (long long)(lr + 32*p)*lda + k0 + 4*lq);
            #pragma unroll
            for (int p = 0; p < 2; p++)
                pB[p] = *(const float4*)(Bb + (long long)(lr + 32*p)*ldb + k0 + 4*lq);
        }

        // ---- compute: 2 k16 steps ----
        #pragma unroll
        for (int ks = 0; ks < 2; ks++) {
            const int c0 = ks*16 + 2*t;
            uint32_t ah[2][4], al[2][4], bh[4][2], bl[4][2];
            #pragma unroll
            for (int mi = 0; mi < 2; mi++) {
                int r0 = wm*32 + mi*16 + g;
                #pragma unroll
                for (int j = 0; j < 4; j++) {
                    int off = (r0 + 8*(j & 1))*RW + c0 + 8*(j >> 1);
                    ah[mi][j] = *(uint32_t*)(Ah + off);
                    al[mi][j] = *(uint32_t*)(Al + off);
                }
            }
            #pragma unroll
            for (int ni = 0; ni < 4; ni++) {
                int r0 = wn*32 + ni*8 + g;
                #pragma unroll
                for (int j = 0; j < 2; j++) {
                    int off = r0*RW + c0 + 8*j;
                    bh[ni][j] = *(uint32_t*)(Bh + off);
                    bl[ni][j] = *(uint32_t*)(Bl + off);
                }
            }
            #pragma unroll
            for (int mi = 0; mi < 2; mi++)
                #pragma unroll
                for (int ni = 0; ni < 4; ni++) {
                    mma16816(Cf[mi][ni], ah[mi], bh[ni]);
                    mma16816(Cf[mi][ni], ah[mi], bl[ni]);
                    mma16816(Cf[mi][ni], al[mi], bh[ni]);
                }
        }
        __syncthreads();
    }

    // ---- epilogue: frags -> SMEM -> coalesced fused write ----
    const int ROWW = 68;
    float* sbuf = (float*)dsm;
    #pragma unroll
    for (int mi = 0; mi < 2; mi++)
        #pragma unroll
        for (int ni = 0; ni < 4; ni++)
            #pragma unroll
            for (int j = 0; j < 4; j++) {
                int row = wm*32 + mi*16 + g + 8*(j >> 1);
                int col = wn*32 + ni*8 + 2*t + (j & 1);
                sbuf[row*ROWW + col] = Cf[mi][ni][j];
            }
    __syncthreads();

    #pragma unroll
    for (int p = 0; p < 8; p++) {
        int i4 = tid + (p << 8);
        int elem = i4 << 2;
        int rr = elem >> 6;
        int cc = elem & 63;
        float4 v = *(float4*)(sbuf + rr*ROWW + cc);
        v.x *= alpha; v.y *= alpha; v.z *= alpha; v.w *= alpha;
        if (bias) {
            float4 bb = *(const float4*)(bias + n0 + cc);
            v.x += bb.x; v.y += bb.y; v.z += bb.z; v.w += bb.w;
        }
        long long off = coff + (long long)(m0 + rr)*ldc + (n0 + cc);
        if (res1) {
            float4 a = *(const float4*)(res1 + off);
            v.x += a.x; v.y += a.y; v.z += a.z; v.w += a.w;
        }
        if (res2) {
            float4 a = *(const float4*)(res2 + off);
            v.x += a.x; v.y += a.y; v.z += a.z; v.w += a.w;
        }
        if (act == 1) {
            v.x = 0.5f*v.x*(1.f + erff(v.x*0.70710678118654752f));
            v.y = 0.5f*v.y*(1.f + erff(v.y*0.70710678118654752f));
            v.z = 0.5f*v.z*(1.f + erff(v.z*0.70710678118654752f));
            v.w = 0.5f*v.w*(1.f + erff(v.w*0.70710678118654752f));
        }
        *(float4*)(C + off) = v;
    }
}

// =============== FFMA GEMM (kept for M=64 attn_x) ===============
#define BM 64
#define BN 64
#define BK 16
template<bool BT>
__global__ __launch_bounds__(256)
void gemm64(const float* __restrict__ A, const float* __restrict__ B,
            const float* __restrict__ bias,
            const float* __restrict__ res1, const float* __restrict__ res2,
            float* __restrict__ C,
            int K, int lda, int ldb, int ldc,
            long long sAb, long long sBb, long long sCb,
            int batchH,
            long long sAh, long long sBh, long long sCh,
            float alpha, int act)
{
    __shared__ float As[BK][BM+4];
    __shared__ float Bs[BK][BN+4];

    int bz = blockIdx.z;
    int b  = bz / batchH;
    int h  = bz - b*batchH;
    A += (long long)b*sAb + (long long)h*sAh;
    B += (long long)b*sBb + (long long)h*sBh;
    long long coff = (long long)b*sCb + (long long)h*sCh;
    C += coff;
    if (res1) res1 += coff;
    if (res2) res2 += coff;

    const int m0 = blockIdx.y * BM;
    const int n0 = blockIdx.x * BN;
    const int tid = threadIdx.x;
    const int tx = tid & 15;
    const int ty = tid >> 4;
    const int lk = tid & 15;
    const int lr = tid >> 4;
    const int lnn = tid & 63;
    const int lkk = tid >> 6;

    const float* Abp = A + (long long)m0*lda;
    const float* Bbp = BT ? (B + (long long)n0*ldb) : (B + n0);

    float acc[4][4] = {{0.f}};
    for (int k0 = 0; k0 < K; k0 += BK) {
        #pragma unroll
        for (int i = 0; i < 4; i++)
            As[lk][lr + 16*i] = Abp[(long long)(lr + 16*i)*lda + (k0 + lk)];
        if (BT) {
            #pragma unroll
            for (int i = 0; i < 4; i++)
                Bs[lk][lr + 16*i] = Bbp[(long long)(lr + 16*i)*ldb + (k0 + lk)];
        } else {
            #pragma unroll
            for (int i = 0; i < 4; i++)
                Bs[lkk + 4*i][lnn] = Bbp[(long long)(k0 + lkk + 4*i)*ldb + lnn];
        }
        __syncthreads();
        #pragma unroll
        for (int kk = 0; kk < BK; kk++) {
            float4 a4 = *(const float4*)(&As[kk][ty*4]);
            float4 b4 = *(const float4*)(&Bs[kk][tx*4]);
            float ar[4] = {a4.x, a4.y, a4.z, a4.w};
            float br[4] = {b4.x, b4.y, b4.z, b4.w};
            #pragma unroll
            for (int i = 0; i < 4; i++)
                #pragma unroll
                for (int j = 0; j < 4; j++)
                    acc[i][j] = fmaf(ar[i], br[j], acc[i][j]);
        }
        __syncthreads();
    }
    #pragma unroll
    for (int i = 0; i < 4; i++) {
        int row = m0 + ty*4 + i;
        #pragma unroll
        for (int j = 0; j < 4; j++) {
            int col = n0 + tx*4 + j;
            float v = acc[i][j] * alpha;
            if (bias) v += bias[col];
            long long idx = (long long)row*ldc + col;
            if (res1) v += res1[idx];
            if (res2) v += res2[idx];
            if (act == 1) v = 0.5f * v * (1.f + erff(v * 0.70710678118654752f));
            C[idx] = v;
        }
    }
}

// ---------------- LayerNorm over 768 features -------------------------------
__global__ void ln_kernel(const float* __restrict__ in, float* __restrict__ out,
                          const float* __restrict__ g, const float* __restrict__ b,
                          long long in_bstride, long long out_bstride)
{
    const float* x = in  + (long long)blockIdx.y*in_bstride  + (long long)blockIdx.x*DIM;
    float*       y = out + (long long)blockIdx.y*out_bstride + (long long)blockIdx.x*DIM;
    int tid = threadIdx.x;
    float v0 = x[tid], v1 = x[tid+256], v2 = x[tid+512];
    __shared__ float sh[256];
    sh[tid] = v0 + v1 + v2;
    __syncthreads();
    for (int o = 128; o > 0; o >>= 1) { if (tid < o) sh[tid] += sh[tid+o]; __syncthreads(); }
    float mean = sh[0] * (1.f/768.f);
    __syncthreads();
    float d0 = v0-mean, d1 = v1-mean, d2 = v2-mean;
    sh[tid] = d0*d0 + d1*d1 + d2*d2;
    __syncthreads();
    for (int o = 128; o > 0; o >>= 1) { if (tid < o) sh[tid] += sh[tid+o]; __syncthreads(); }
    float inv = rsqrtf(sh[0] * (1.f/768.f) + 1e-5f);
    y[tid]     = d0*inv*g[tid]     + b[tid];
    y[tid+256] = d1*inv*g[tid+256] + b[tid+256];
    y[tid+512] = d2*inv*g[tid+512] + b[tid+512];
}

// ---------------- softmax over rows of length 384 ---------------------------
__global__ void softmax384(float* __restrict__ data)
{
    float* x = data + (long long)blockIdx.x * 384;
    int tid = threadIdx.x;  // 128
    float a = x[tid], b = x[tid+128], c = x[tid+256];
    __shared__ float sh[128];
    float m = fmaxf(a, fmaxf(b, c));
    sh[tid] = m; __syncthreads();
    for (int o = 64; o > 0; o >>= 1) { if (tid < o) sh[tid] = fmaxf(sh[tid], sh[tid+o]); __syncthreads(); }
    m = sh[0]; __syncthreads();
    float e0 = expf(a-m), e1 = expf(b-m), e2 = expf(c-m);
    sh[tid] = e0+e1+e2; __syncthreads();
    for (int o = 64; o > 0; o >>= 1) { if (tid < o) sh[tid] += sh[tid+o]; __syncthreads(); }
    float inv = 1.f / sh[0];
    x[tid] = e0*inv; x[tid+128] = e1*inv; x[tid+256] = e2*inv;
}

// ---------------- fusion: entropies over ZL axis ----------------------------
__global__ void fusion_kernel(const float* __restrict__ ax, const float* __restrict__ axi,
                              float* __restrict__ alpha_o, float* __restrict__ um_o,
                              float* __restrict__ u_o, float* __restrict__ ui_o)
{
    int b = blockIdx.x, s = threadIdx.x;
    const float* X  = ax  + (long long)b*ZL*SL + s;
    const float* Xi = axi + (long long)b*ZL*SL + s;
    float u, ui;
    {
        float mx = -1e30f;
        for (int t = 0; t < ZL; t++) mx = fmaxf(mx, X[t*SL]);
        float sum = 0.f;
        for (int t = 0; t < ZL; t++) sum += expf(X[t*SL] - mx);
        float inv = 1.f/sum, acc = 0.f;
        for (int t = 0; t < ZL; t++) { float p = expf(X[t*SL]-mx)*inv; acc -= p*logf(p + 1e-8f); }
        u = acc;
    }
    {
        float mx = -1e30f;
        for (int t = 0; t < ZL; t++) mx = fmaxf(mx, Xi[t*SL]);
        float sum = 0.f;
        for (int t = 0; t < ZL; t++) sum += expf(Xi[t*SL] - mx);
        float inv = 1.f/sum, acc = 0.f;
        for (int t = 0; t < ZL; t++) { float p = expf(Xi[t*SL]-mx)*inv; acc -= p*logf(p + 1e-8f); }
        ui = acc;
    }
    int idx = b*SL + s;
    float alpha = 1.f / (1.f + expf(-(ui - u)));
    alpha_o[idx] = alpha;
    um_o[idx] = 0.5f*(u + ui);
    u_o[idx] = u;
    ui_o[idx] = ui;
}

// ---------------- elementwise helpers ----------------------------------------
__global__ void cat_feat_k(const float* __restrict__ x, const float* __restrict__ xi,
                           float* __restrict__ o)
{
    long long i = (long long)blockIdx.x*blockDim.x + threadIdx.x;
    const long long n = (long long)BATCH*ZL*2*DIM;
    if (i >= n) return;
    int c = (int)(i % (2*DIM));
    long long bt = i / (2*DIM);
    long long b = bt / ZL, t = bt % ZL;
    long long src = (b*TT + t)*DIM;
    o[i] = (c < DIM) ? x[src + c] : xi[src + c - DIM];
}

__global__ void cat_seq_k(const float* __restrict__ zf, const float* __restrict__ x,
                          float* __restrict__ o)
{
    long long i = (long long)blockIdx.x*blockDim.x + threadIdx.x;
    const long long n = (long long)BATCH*NN*DIM;
    if (i >= n) return;
    int c = (int)(i % DIM);
    long long bt = i / DIM;
    long long b = bt / NN, t = bt % NN;
    o[i] = (t < ZL) ? zf[(b*ZL + t)*DIM + c]
                    : x[(b*TT + (t-ZL))*DIM + c];
}

__global__ void vtrans_k(const float* __restrict__ qkv, float* __restrict__ vt)
{
    __shared__ float t[32][33];
    int bh = blockIdx.z;
    long long b = bh / HEADS, h = bh % HEADS;
    const float* src = qkv + b*NN*QKV3 + 2*DIM + h*HD;
    int tt0 = blockIdx.x*32;
    int cc0 = blockIdx.y*32;
    int tx = threadIdx.x, ty = threadIdx.y;  // 32 x 8
    #pragma unroll
    for (int i = 0; i < 32; i += 8)
        t[ty+i][tx] = src[(long long)(tt0+ty+i)*QKV3 + cc0 + tx];
    __syncthreads();
    float* dst = vt + ((long long)bh*HD)*NN;
    #pragma unroll
    for (int i = 0; i < 32; i += 8)
        dst[(long long)(cc0+ty+i)*NN + tt0 + tx] = t[tx][ty+i];
}

__global__ void make_v_k(const float* __restrict__ ns, const float* __restrict__ nsi,
                         const float* __restrict__ alpha, float* __restrict__ v)
{
    long long i = (long long)blockIdx.x*blockDim.x + threadIdx.x;
    const long long n = (long long)BATCH*SL*DIM;
    if (i >= n) return;
    long long bs = i / DIM;
    float a = alpha[bs];
    v[i] = a*ns[i] + (1.f - a)*nsi[i];
}

__global__ void make_vfc_k(const float* __restrict__ xiattn, const float* __restrict__ vf,
                           float* __restrict__ o)
{
    long long i = (long long)blockIdx.x*blockDim.x + threadIdx.x;
    const long long n = (long long)BATCH*TT*DIM;
    if (i >= n) return;
    int c = (int)(i % DIM);
    long long bt = i / DIM;
    long long b = bt / TT, t = bt % TT;
    o[i] = (t < ZL) ? xiattn[(b*NN + t)*DIM + c]
                    : vf[(b*SL + (t-ZL))*DIM + c];
}

__global__ void make_xnew_k(const float* __restrict__ x, const float* __restrict__ xi,
                            const float* __restrict__ xattn, const float* __restrict__ xiattn,
                            const float* __restrict__ vfc,
                            float* __restrict__ xo, float* __restrict__ xio)
{
    long long i = (long long)blockIdx.x*blockDim.x + threadIdx.x;
    const long long n = (long long)BATCH*TT*DIM;
    if (i >= n) return;
    int c = (int)(i % DIM);
    long long bt = i / DIM;
    long long b = bt / TT, t = bt % TT;
    long long aidx = (b*NN + ZL + t)*DIM + c;
    float vf = vfc[i];
    xo[i]  = x[i]  + xattn[aidx]  + vf;
    xio[i] = xi[i] + xiattn[aidx] + vf;
}

__global__ void i2f_k(const int* __restrict__ in, float* __restrict__ out, int n)
{
    int i = blockIdx.x*blockDim.x + threadIdx.x;
    if (i < n) out[i] = (float)in[i];
}

// ---------------- host-side helpers ----------------
static inline void mm(const float* A, const float* B, const float* bias,
                      const float* r1, const float* r2, float* C,
                      int M, int N, int K, int lda, int ldb, int ldc,
                      long long sAb, long long sBb, long long sCb,
                      int nb, int nh,
                      long long sAh, long long sBh, long long sCh,
                      float alpha, int act)
{
    static bool attr_set = false;
    if (!attr_set) {
        cudaFuncSetAttribute(mm_gemm, cudaFuncAttributeMaxDynamicSharedMemorySize, MM_SMEM);
        attr_set = true;
    }
    dim3 g(N/64, M/128, nb*nh);
    mm_gemm<<<g, 256, MM_SMEM>>>(A,B,bias,r1,r2,C,K,lda,ldb,ldc,sAb,sBb,sCb,nh,sAh,sBh,sCh,alpha,act);
}

static inline void gemmf(const float* A, const float* B, const float* bias,
                         const float* r1, const float* r2, float* C,
                         int M, int N, int K, int lda, int ldb, int ldc,
                         long long sAb, long long sBb, long long sCb,
                         int nb, int nh,
                         long long sAh, long long sBh, long long sCh,
                         float alpha, int act, bool bt)
{
    dim3 g(N/BN, M/BM, nb*nh);
    if (bt) gemm64<true ><<<g, 256>>>(A,B,bias,r1,r2,C,K,lda,ldb,ldc,sAb,sBb,sCb,nh,sAh,sBh,sCh,alpha,act);
    else    gemm64<false><<<g, 256>>>(A,B,bias,r1,r2,C,K,lda,ldb,ldc,sAb,sBb,sCb,nh,sAh,sBh,sCh,alpha,act);
}

static inline int cdiv(long long a, int b) { return (int)((a + b - 1) / b); }

extern "C" void kernel_launch(void* const* d_in, const int* in_sizes, int n_in,
                              void* d_out, int out_size)
{
    const float* x      = (const float*)d_in[0];
    const float* xi     = (const float*)d_in[1];
    const int*   git    = (const int*)  d_in[2];
    const int*   giti   = (const int*)  d_in[3];
    const int*   gis    = (const int*)  d_in[4];
    const int*   gisi   = (const int*)  d_in[5];
    const float* w_qkv  = (const float*)d_in[6];
    const float* b_qkv  = (const float*)d_in[7];
    const float* w_proj = (const float*)d_in[8];
    const float* b_proj = (const float*)d_in[9];
    const float* g1     = (const float*)d_in[10];
    const float* bt1    = (const float*)d_in[11];
    const float* g2     = (const float*)d_in[12];
    const float* bt2    = (const float*)d_in[13];
    const float* w_fc1  = (const float*)d_in[14];
    const float* b_fc1  = (const float*)d_in[15];
    const float* w_fc2  = (const float*)d_in[16];
    const float* b_fc2  = (const float*)d_in[17];
    const float* w_al   = (const float*)d_in[18];
    const float* b_al   = (const float*)d_in[19];
    const float* w_al2  = (const float*)d_in[20];
    const float* b_al2  = (const float*)d_in[21];
    const float* w_fus  = (const float*)d_in[22];
    const float* b_fus  = (const float*)d_in[23];
    float* out = (float*)d_out;

    float *p_cat, *p_zf, *p_ns, *p_nsi, *p_attnx, *p_attnxi, *p_xc, *p_ln, *p_qkv,
          *p_vt, *p_ao, *p_xattn, *p_xiattn, *p_v, *p_vf, *p_vfc, *p_xnew, *p_xinew,
          *p_adap2, *p_h;
    cudaGetSymbolAddress((void**)&p_cat,    g_cat);
    cudaGetSymbolAddress((void**)&p_zf,     g_zf);
    cudaGetSymbolAddress((void**)&p_ns,     g_ns);
    cudaGetSymbolAddress((void**)&p_nsi,    g_nsi);
    cudaGetSymbolAddress((void**)&p_attnx,  g_attnx);
    cudaGetSymbolAddress((void**)&p_attnxi, g_attnxi);
    cudaGetSymbolAddress((void**)&p_xc,     g_xc);
    cudaGetSymbolAddress((void**)&p_ln,     g_ln);
    cudaGetSymbolAddress((void**)&p_qkv,    g_qkv);
    cudaGetSymbolAddress((void**)&p_vt,     g_vt);
    cudaGetSymbolAddress((void**)&p_ao,     g_ao);
    cudaGetSymbolAddress((void**)&p_xattn,  g_xattn);
    cudaGetSymbolAddress((void**)&p_xiattn, g_xiattn);
    cudaGetSymbolAddress((void**)&p_v,      g_v);
    cudaGetSymbolAddress((void**)&p_vf,     g_vf);
    cudaGetSymbolAddress((void**)&p_vfc,    g_vfc);
    cudaGetSymbolAddress((void**)&p_xnew,   g_xnew);
    cudaGetSymbolAddress((void**)&p_xinew,  g_xinew);
    cudaGetSymbolAddress((void**)&p_adap2,  g_adap2);
    cudaGetSymbolAddress((void**)&p_h,      g_h);

    const float scale_dim = 1.f / sqrtf((float)DIM);
    const float scale_hd  = 0.125f;

    // ---- index passthroughs ----
    i2f_k<<<cdiv(BATCH*ZL, 256), 256>>>(git,  out + O_GIT,  BATCH*ZL);
    i2f_k<<<cdiv(BATCH*SL, 256), 256>>>(gis,  out + O_GIS,  BATCH*SL);
    i2f_k<<<cdiv(BATCH*ZL, 256), 256>>>(giti, out + O_GITI, BATCH*ZL);
    i2f_k<<<cdiv(BATCH*SL, 256), 256>>>(gisi, out + O_GISI, BATCH*SL);

    // ---- z_f = concat(z,zi) @ w_al^T + b_al ----
    cat_feat_k<<<cdiv((long long)BATCH*ZL*2*DIM, 256), 256>>>(x, xi, p_cat);
    mm(p_cat, w_al, b_al, nullptr, nullptr, p_zf,
       BATCH*ZL, DIM, 2*DIM, 2*DIM, 2*DIM, DIM,
       0,0,0, 1,1, 0,0,0, 1.f, 0);

    // ---- ns/nsi ----
    ln_kernel<<<dim3(SL, BATCH), 256>>>(x  + (long long)ZL*DIM, p_ns,  g1, bt1,
                                        (long long)TT*DIM, (long long)SL*DIM);
    ln_kernel<<<dim3(SL, BATCH), 256>>>(xi + (long long)ZL*DIM, p_nsi, g1, bt1,
                                        (long long)TT*DIM, (long long)SL*DIM);

    // ---- attn_x / attn_xi (M=64 per batch -> FFMA gemm) ----
    gemmf(p_zf, p_ns, nullptr, nullptr, nullptr, p_attnx,
          ZL, SL, DIM, DIM, DIM, SL,
          (long long)ZL*DIM, (long long)SL*DIM, (long long)ZL*SL,
          BATCH, 1, 0,0,0, scale_dim, 0, true);
    gemmf(p_zf, p_nsi, nullptr, nullptr, nullptr, p_attnxi,
          ZL, SL, DIM, DIM, DIM, SL,
          (long long)ZL*DIM, (long long)SL*DIM, (long long)ZL*SL,
          BATCH, 1, 0,0,0, scale_dim, 0, true);

    // ---- MHA both streams ----
    const float* src[2]    = {x, xi};
    float*       attn_o[2] = {out + O_ATTN, out + O_IATTN};
    float*       proj_o[2] = {p_xattn, p_xiattn};
    for (int side = 0; side < 2; side++) {
        cat_seq_k<<<cdiv((long long)BATCH*NN*DIM, 256), 256>>>(p_zf, src[side], p_xc);
        ln_kernel<<<dim3(NN, BATCH), 256>>>(p_xc, p_ln, g1, bt1,
                                            (long long)NN*DIM, (long long)NN*DIM);
        // qkv
        mm(p_ln, w_qkv, b_qkv, nullptr, nullptr, p_qkv,
           BATCH*NN, QKV3, DIM, DIM, DIM, QKV3,
           0,0,0, 1,1, 0,0,0, 1.f, 0);
        // V transpose for attn@V
        vtrans_k<<<dim3(NN/32, HD/32, BATCH*HEADS), dim3(32,8)>>>(p_qkv, p_vt);
        // scores = q @ k^T * hd^-0.5 -> d_out attn region
        mm(p_qkv, p_qkv + DIM, nullptr, nullptr, nullptr, attn_o[side],
           NN, NN, HD, QKV3, QKV3, NN,
           (long long)NN*QKV3, (long long)NN*QKV3, (long long)HEADS*NN*NN,
           BATCH, HEADS, HD, HD, (long long)NN*NN, scale_hd, 0);
        // softmax in place
        softmax384<<<BATCH*HEADS*NN, 128>>>(attn_o[side]);
        // out = P @ V  (B = V^T, K-major)
        mm(attn_o[side], p_vt, nullptr, nullptr, nullptr, p_ao,
           NN, HD, NN, NN, NN, DIM,
           (long long)HEADS*NN*NN, (long long)HEADS*HD*NN, (long long)NN*DIM,
           BATCH, HEADS, (long long)NN*NN, (long long)HD*NN, HD, 1.f, 0);
        // proj
        mm(p_ao, w_proj, b_proj, nullptr, nullptr, proj_o[side],
           BATCH*NN, DIM, DIM, DIM, DIM, DIM,
           0,0,0, 1,1, 0,0,0, 1.f, 0);
    }

    // ---- fusion ----
    fusion_kernel<<<BATCH, SL>>>(p_attnx, p_attnxi,
                                 out + O_ALPHA, out + O_UM, out + O_U, out + O_UI);
    make_v_k<<<cdiv((long long)BATCH*SL*DIM, 256), 256>>>(p_ns, p_nsi, out + O_ALPHA, p_v);
    mm(p_v, w_fus, b_fus, nullptr, nullptr, p_vf,
       BATCH*SL, DIM, DIM, DIM, DIM, DIM,
       0,0,0, 1,1, 0,0,0, 1.f, 0);
    make_vfc_k<<<cdiv((long long)BATCH*TT*DIM, 256), 256>>>(p_xiattn, p_vf, p_vfc);

    // ---- residual adds ----
    make_xnew_k<<<cdiv((long long)BATCH*TT*DIM, 256), 256>>>(
        x, xi, p_xattn, p_xiattn, p_vfc, p_xnew, p_xinew);

    // ---- adap2 ----
    ln_kernel<<<dim3(TT, BATCH), 256>>>(p_vfc, p_ln, g2, bt2,
                                        (long long)TT*DIM, (long long)TT*DIM);
    mm(p_ln, w_al2, b_al2, nullptr, nullptr, p_adap2,
       BATCH*TT, DIM, DIM, DIM, DIM, DIM,
       0,0,0, 1,1, 0,0,0, 1.f, 0);

    // ---- MLP both streams ----
    float* xn[2] = {p_xnew, p_xinew};
    float* xo[2] = {out + O_XOUT, out + O_XIOUT};
    for (int side = 0; side < 2; side++) {
        ln_kernel<<<dim3(TT, BATCH), 256>>>(xn[side], p_ln, g2, bt2,
                                            (long long)TT*DIM, (long long)TT*DIM);
        mm(p_ln, w_fc1, b_fc1, nullptr, nullptr, p_h,
           BATCH*TT, HID, DIM, DIM, DIM, HID,
           0,0,0, 1,1, 0,0,0, 1.f, 1);
        mm(p_h, w_fc2, b_fc2, xn[side], p_adap2, xo[side],
           BATCH*TT, DIM, HID, HID, HID, DIM,
           0,0,0, 1,1, 0,0,0, 1.f, 0);
    }
}

// round 4
// speedup vs baseline: 2.3267x; 1.0477x over previous
#include <cuda_runtime.h>
#include <cuda_bf16.h>
#include <math.h>
#include <cstdint>

// ---------------- problem constants ----------------
#define BATCH 32
#define ZL 64
#define SL 256
#define TT 320           // ZL+SL
#define NN 384           // ZL + TT (xc length)
#define DIM 768
#define HEADS 12
#define HD 64
#define HID 3072
#define QKV3 2304

// output offsets (float elements)
#define O_XOUT   0LL
#define O_GIT    7864320LL
#define O_GIS    7866368LL
#define O_ATTN   7874560LL
#define O_XIOUT  64497664LL
#define O_GITI   72361984LL
#define O_GISI   72364032LL
#define O_IATTN  72372224LL
#define O_ALPHA  128995328LL
#define O_UM     129003520LL
#define O_U      129011712LL
#define O_UI     129019904LL

// ---------------- scratch (device globals; allocation-free) ----------------
__device__ float g_cat   [BATCH*ZL*2*DIM];
__device__ float g_zf    [BATCH*ZL*DIM];
__device__ float g_ns    [BATCH*SL*DIM];
__device__ float g_nsi   [BATCH*SL*DIM];
__device__ float g_attnx [BATCH*ZL*SL];
__device__ float g_attnxi[BATCH*ZL*SL];
__device__ float g_ln    [BATCH*NN*DIM];
__device__ float g_qkv   [BATCH*NN*QKV3];
__device__ float g_vt    [BATCH*HEADS*HD*NN];
__device__ float g_ao    [BATCH*NN*DIM];
__device__ float g_xattn [BATCH*NN*DIM];
__device__ float g_xiattn[BATCH*NN*DIM];
__device__ float g_v     [BATCH*SL*DIM];
__device__ float g_vf    [BATCH*SL*DIM];
__device__ float g_vfc   [BATCH*TT*DIM];
__device__ float g_xnew  [BATCH*TT*DIM];
__device__ float g_xinew [BATCH*TT*DIM];
__device__ float g_adap2 [BATCH*TT*DIM];
__device__ float g_h     [BATCH*TT*HID];

// =============== helpers =====================================================
__device__ __forceinline__ uint32_t smem_u32(const void* p) {
    uint32_t a;
    asm("{ .reg .u64 t; cvta.to.shared.u64 t, %1; cvt.u32.u64 %0, t; }" : "=r"(a) : "l"(p));
    return a;
}
__device__ __forceinline__ void mma16816(float* d, const uint32_t* a, const uint32_t* b) {
    asm volatile("mma.sync.aligned.m16n8k16.row.col.f32.bf16.bf16.f32 "
        "{%0,%1,%2,%3}, {%4,%5,%6,%7}, {%8,%9}, {%0,%1,%2,%3};"
        : "+f"(d[0]), "+f"(d[1]), "+f"(d[2]), "+f"(d[3])
        : "r"(a[0]), "r"(a[1]), "r"(a[2]), "r"(a[3]), "r"(b[0]), "r"(b[1]));
}
__device__ __forceinline__ void ldsm4(uint32_t& r0, uint32_t& r1, uint32_t& r2, uint32_t& r3,
                                      uint32_t addr) {
    asm volatile("ldmatrix.sync.aligned.m8n8.x4.shared.b16 {%0,%1,%2,%3}, [%4];"
        : "=r"(r0), "=r"(r1), "=r"(r2), "=r"(r3) : "r"(addr));
}
// split fp32 pair -> (hi bf16x2, lo bf16x2)
__device__ __forceinline__ void split2(float x, float y, uint32_t& h, uint32_t& l) {
    __nv_bfloat16 hx = __float2bfloat16_rn(x);
    __nv_bfloat16 hy = __float2bfloat16_rn(y);
    float lx = x - __bfloat162float(hx);
    float ly = y - __bfloat162float(hy);
    __nv_bfloat162 hp; hp.x = hx; hp.y = hy;
    __nv_bfloat162 lp; lp.x = __float2bfloat16_rn(lx); lp.y = __float2bfloat16_rn(ly);
    h = *(uint32_t*)&hp;
    l = *(uint32_t*)&lp;
}

// =============== 3xBF16 mma.sync GEMM, ldmatrix fragments ====================
// C = alpha * A @ B^T (+bias +res1 +res2, opt GELU)
// A: (M,K) row-major fp32, B: (N,K) row-major fp32. 512 threads, warps 4x4.
// M%TM==0, N%TN==0, K%32==0.
#define RWH 40             // SMEM row width in halves (32 data + 8 pad)

template<int TM, int TN>
__global__ __launch_bounds__(512, 1)
void mm2(const float* __restrict__ A, const float* __restrict__ B,
         const float* __restrict__ bias,
         const float* __restrict__ res1, const float* __restrict__ res2,
         float* __restrict__ C,
         int K, int lda, int ldb, int ldc,
         long long sAb, long long sBb, long long sCb, int batchH,
         long long sAh, long long sBh, long long sCh,
         float alpha, int act)
{
    extern __shared__ char dsm[];
    constexpr int WTM = TM/4, WTN = TN/4;
    constexpr int MI = WTM/16, NI = WTN/8;
    constexpr int AHL = TM*RWH;            // halves per A matrix (hi or lo)
    constexpr int BHL = TN*RWH;
    constexpr int STAGE_BYTES = (2*AHL + 2*BHL)*2;
    constexpr int PA = TM/64, PB = TN/64;  // float4s per thread per chunk

    const int tid  = threadIdx.x;
    const int lane = tid & 31;
    const int w    = tid >> 5;
    const int wm   = w >> 2;
    const int wn   = w & 3;

    const int bz = blockIdx.z;
    const int b  = bz / batchH;
    const int h  = bz - b*batchH;
    const int m0 = blockIdx.y * TM;
    const int n0 = blockIdx.x * TN;
    const float* Ab = A + (long long)b*sAb + (long long)h*sAh + (long long)m0*lda;
    const float* Bb = B + (long long)b*sBb + (long long)h*sBh + (long long)n0*ldb;
    const long long coff = (long long)b*sCb + (long long)h*sCh;

    const int lq = tid & 7;     // col group of 4 floats
    const int lr = tid >> 3;    // 0..63

    const uint32_t sb0 = smem_u32(dsm);
    // lane-dependent ldmatrix base offsets (bytes, within stage)
    const uint32_t a_l = (uint32_t)(((wm*WTM + (lane & 15))*RWH + ((lane >> 4) << 3)) * 2);
    const uint32_t b_l = (uint32_t)(2*AHL*2 + ((wn*WTN + (lane & 15))*RWH + ((lane >> 4) << 3)) * 2);

    float acc[MI][NI][4];
    #pragma unroll
    for (int mi = 0; mi < MI; mi++)
        #pragma unroll
        for (int ni = 0; ni < NI; ni++)
            #pragma unroll
            for (int j = 0; j < 4; j++) acc[mi][ni][j] = 0.f;

    const int NC = K >> 5;
    float4 pA[PA], pB[PB];

    #pragma unroll
    for (int p = 0; p < PA; p++)
        pA[p] = *(const float4*)(Ab + (long long)(lr + 64*p)*lda + 4*lq);
    #pragma unroll
    for (int p = 0; p < PB; p++)
        pB[p] = *(const float4*)(Bb + (long long)(lr + 64*p)*ldb + 4*lq);

    for (int c = 0; c < NC; c++) {
        const int st = c & 1;
        char* sb = dsm + st * STAGE_BYTES;
        __nv_bfloat16* Ah = (__nv_bfloat16*)sb;
        __nv_bfloat16* Al = Ah + AHL;
        __nv_bfloat16* Bh = Al + AHL;
        __nv_bfloat16* Bl = Bh + BHL;

        #pragma unroll
        for (int p = 0; p < PA; p++) {
            uint32_t h0, l0, h1, l1;
            split2(pA[p].x, pA[p].y, h0, l0);
            split2(pA[p].z, pA[p].w, h1, l1);
            int off = (lr + 64*p)*RWH + 4*lq;
            *(uint32_t*)(Ah + off)     = h0;
            *(uint32_t*)(Ah + off + 2) = h1;
            *(uint32_t*)(Al + off)     = l0;
            *(uint32_t*)(Al + off + 2) = l1;
        }
        #pragma unroll
        for (int p = 0; p < PB; p++) {
            uint32_t h0, l0, h1, l1;
            split2(pB[p].x, pB[p].y, h0, l0);
            split2(pB[p].z, pB[p].w, h1, l1);
            int off = (lr + 64*p)*RWH + 4*lq;
            *(uint32_t*)(Bh + off)     = h0;
            *(uint32_t*)(Bh + off + 2) = h1;
            *(uint32_t*)(Bl + off)     = l0;
            *(uint32_t*)(Bl + off + 2) = l1;
        }
        __syncthreads();

        if (c + 1 < NC) {
            const int k0 = (c + 1) << 5;
            #pragma unroll
            for (int p = 0; p < PA; p++)
                pA[p] = *(const float4*)(Ab + (long long)(lr + 64*p)*lda + k0 + 4*lq);
            #pragma unroll
            for (int p = 0; p < PB; p++)
                pB[p] = *(const float4*)(Bb + (long long)(lr + 64*p)*ldb + k0 + 4*lq);
        }

        const uint32_t stageu = sb0 + st * STAGE_BYTES;
        #pragma unroll
        for (int ks = 0; ks < 2; ks++) {
            const uint32_t kb = ks * 32;   // 16 halves = 32 bytes
            uint32_t ah[MI][4], alr[MI][4];
            #pragma unroll
            for (int mi = 0; mi < MI; mi++) {
                uint32_t ad = stageu + a_l + mi*(16*RWH*2) + kb;
                ldsm4(ah[mi][0], ah[mi][1], ah[mi][2], ah[mi][3], ad);
                ldsm4(alr[mi][0], alr[mi][1], alr[mi][2], alr[mi][3], ad + AHL*2);
            }
            uint32_t bh[NI][2], bl[NI][2];
            #pragma unroll
            for (int nj = 0; nj < NI/2; nj++) {
                uint32_t bd = stageu + b_l + nj*(16*RWH*2) + kb;
                uint32_t q0, q1, q2, q3;
                ldsm4(q0, q1, q2, q3, bd);
                bh[2*nj][0] = q0; bh[2*nj][1] = q2;
                bh[2*nj+1][0] = q1; bh[2*nj+1][1] = q3;
                ldsm4(q0, q1, q2, q3, bd + BHL*2);
                bl[2*nj][0] = q0; bl[2*nj][1] = q2;
                bl[2*nj+1][0] = q1; bl[2*nj+1][1] = q3;
            }
            #pragma unroll
            for (int mi = 0; mi < MI; mi++)
                #pragma unroll
                for (int ni = 0; ni < NI; ni++) {
                    mma16816(acc[mi][ni], ah[mi], bh[ni]);
                    mma16816(acc[mi][ni], ah[mi], bl[ni]);
                    mma16816(acc[mi][ni], alr[mi], bh[ni]);
                }
        }
        __syncthreads();
    }

    // ---- epilogue: frags -> SMEM -> coalesced fused write ----
    constexpr int ROWW = TN + 4;
    float* sbuf = (float*)dsm;
    const int g = lane >> 2, t4 = lane & 3;
    #pragma unroll
    for (int mi = 0; mi < MI; mi++)
        #pragma unroll
        for (int ni = 0; ni < NI; ni++)
            #pragma unroll
            for (int j = 0; j < 4; j++) {
                int row = wm*WTM + mi*16 + g + 8*(j >> 1);
                int col = wn*WTN + ni*8 + 2*t4 + (j & 1);
                sbuf[row*ROWW + col] = acc[mi][ni][j];
            }
    __syncthreads();

    #pragma unroll
    for (int p = 0; p < TM*TN/2048; p++) {
        int i4 = tid + (p << 9);
        int elem = i4 << 2;
        int rr = elem / TN;
        int cc = elem - rr*TN;
        float4 v = *(float4*)(sbuf + rr*ROWW + cc);
        v.x *= alpha; v.y *= alpha; v.z *= alpha; v.w *= alpha;
        if (bias) {
            float4 bb = *(const float4*)(bias + n0 + cc);
            v.x += bb.x; v.y += bb.y; v.z += bb.z; v.w += bb.w;
        }
        long long off = coff + (long long)(m0 + rr)*ldc + (n0 + cc);
        if (res1) {
            float4 a = *(const float4*)(res1 + off);
            v.x += a.x; v.y += a.y; v.z += a.z; v.w += a.w;
        }
        if (res2) {
            float4 a = *(const float4*)(res2 + off);
            v.x += a.x; v.y += a.y; v.z += a.z; v.w += a.w;
        }
        if (act == 1) {
            v.x = 0.5f*v.x*(1.f + erff(v.x*0.70710678118654752f));
            v.y = 0.5f*v.y*(1.f + erff(v.y*0.70710678118654752f));
            v.z = 0.5f*v.z*(1.f + erff(v.z*0.70710678118654752f));
            v.w = 0.5f*v.w*(1.f + erff(v.w*0.70710678118654752f));
        }
        *(float4*)(C + off) = v;
    }
}

// ---------------- LayerNorm over 768 features -------------------------------
__global__ void ln_kernel(const float* __restrict__ in, float* __restrict__ out,
                          const float* __restrict__ g, const float* __restrict__ b,
                          long long in_bstride, long long out_bstride)
{
    const float* x = in  + (long long)blockIdx.y*in_bstride  + (long long)blockIdx.x*DIM;
    float*       y = out + (long long)blockIdx.y*out_bstride + (long long)blockIdx.x*DIM;
    int tid = threadIdx.x;
    float v0 = x[tid], v1 = x[tid+256], v2 = x[tid+512];
    __shared__ float sh[256];
    sh[tid] = v0 + v1 + v2;
    __syncthreads();
    for (int o = 128; o > 0; o >>= 1) { if (tid < o) sh[tid] += sh[tid+o]; __syncthreads(); }
    float mean = sh[0] * (1.f/768.f);
    __syncthreads();
    float d0 = v0-mean, d1 = v1-mean, d2 = v2-mean;
    sh[tid] = d0*d0 + d1*d1 + d2*d2;
    __syncthreads();
    for (int o = 128; o > 0; o >>= 1) { if (tid < o) sh[tid] += sh[tid+o]; __syncthreads(); }
    float inv = rsqrtf(sh[0] * (1.f/768.f) + 1e-5f);
    y[tid]     = d0*inv*g[tid]     + b[tid];
    y[tid+256] = d1*inv*g[tid+256] + b[tid+256];
    y[tid+512] = d2*inv*g[tid+512] + b[tid+512];
}

// LN over the concat [z_f, x] without materializing the concat
__global__ void ln_cat_kernel(const float* __restrict__ zf, const float* __restrict__ x,
                              float* __restrict__ out,
                              const float* __restrict__ g, const float* __restrict__ b)
{
    int t = blockIdx.x, bb = blockIdx.y;
    const float* src = (t < ZL) ? zf + ((long long)bb*ZL + t)*DIM
                                : x  + ((long long)bb*TT + (t - ZL))*DIM;
    float* y = out + ((long long)bb*NN + t)*DIM;
    int tid = threadIdx.x;
    float v0 = src[tid], v1 = src[tid+256], v2 = src[tid+512];
    __shared__ float sh[256];
    sh[tid] = v0 + v1 + v2;
    __syncthreads();
    for (int o = 128; o > 0; o >>= 1) { if (tid < o) sh[tid] += sh[tid+o]; __syncthreads(); }
    float mean = sh[0] * (1.f/768.f);
    __syncthreads();
    float d0 = v0-mean, d1 = v1-mean, d2 = v2-mean;
    sh[tid] = d0*d0 + d1*d1 + d2*d2;
    __syncthreads();
    for (int o = 128; o > 0; o >>= 1) { if (tid < o) sh[tid] += sh[tid+o]; __syncthreads(); }
    float inv = rsqrtf(sh[0] * (1.f/768.f) + 1e-5f);
    y[tid]     = d0*inv*g[tid]     + b[tid];
    y[tid+256] = d1*inv*g[tid+256] + b[tid+256];
    y[tid+512] = d2*inv*g[tid+512] + b[tid+512];
}

// ---------------- softmax over rows of length 384 ---------------------------
__global__ void softmax384(float* __restrict__ data)
{
    float* x = data + (long long)blockIdx.x * 384;
    int tid = threadIdx.x;  // 128
    float a = x[tid], b = x[tid+128], c = x[tid+256];
    __shared__ float sh[128];
    float m = fmaxf(a, fmaxf(b, c));
    sh[tid] = m; __syncthreads();
    for (int o = 64; o > 0; o >>= 1) { if (tid < o) sh[tid] = fmaxf(sh[tid], sh[tid+o]); __syncthreads(); }
    m = sh[0]; __syncthreads();
    float e0 = expf(a-m), e1 = expf(b-m), e2 = expf(c-m);
    sh[tid] = e0+e1+e2; __syncthreads();
    for (int o = 64; o > 0; o >>= 1) { if (tid < o) sh[tid] += sh[tid+o]; __syncthreads(); }
    float inv = 1.f / sh[0];
    x[tid] = e0*inv; x[tid+128] = e1*inv; x[tid+256] = e2*inv;
}

// ---------------- fusion: entropies over ZL axis ----------------------------
__global__ void fusion_kernel(const float* __restrict__ ax, const float* __restrict__ axi,
                              float* __restrict__ alpha_o, float* __restrict__ um_o,
                              float* __restrict__ u_o, float* __restrict__ ui_o)
{
    int b = blockIdx.x, s = threadIdx.x;
    const float* X  = ax  + (long long)b*ZL*SL + s;
    const float* Xi = axi + (long long)b*ZL*SL + s;
    float u, ui;
    {
        float mx = -1e30f;
        for (int t = 0; t < ZL; t++) mx = fmaxf(mx, X[t*SL]);
        float sum = 0.f;
        for (int t = 0; t < ZL; t++) sum += expf(X[t*SL] - mx);
        float inv = 1.f/sum, acc = 0.f;
        for (int t = 0; t < ZL; t++) { float p = expf(X[t*SL]-mx)*inv; acc -= p*logf(p + 1e-8f); }
        u = acc;
    }
    {
        float mx = -1e30f;
        for (int t = 0; t < ZL; t++) mx = fmaxf(mx, Xi[t*SL]);
        float sum = 0.f;
        for (int t = 0; t < ZL; t++) sum += expf(Xi[t*SL] - mx);
        float inv = 1.f/sum, acc = 0.f;
        for (int t = 0; t < ZL; t++) { float p = expf(Xi[t*SL]-mx)*inv; acc -= p*logf(p + 1e-8f); }
        ui = acc;
    }
    int idx = b*SL + s;
    float alpha = 1.f / (1.f + expf(-(ui - u)));
    alpha_o[idx] = alpha;
    um_o[idx] = 0.5f*(u + ui);
    u_o[idx] = u;
    ui_o[idx] = ui;
}

// ---------------- elementwise helpers ----------------------------------------
__global__ void cat_feat_k(const float* __restrict__ x, const float* __restrict__ xi,
                           float* __restrict__ o)
{
    long long i = (long long)blockIdx.x*blockDim.x + threadIdx.x;
    const long long n = (long long)BATCH*ZL*2*DIM;
    if (i >= n) return;
    int c = (int)(i % (2*DIM));
    long long bt = i / (2*DIM);
    long long b = bt / ZL, t = bt % ZL;
    long long src = (b*TT + t)*DIM;
    o[i] = (c < DIM) ? x[src + c] : xi[src + c - DIM];
}

__global__ void vtrans_k(const float* __restrict__ qkv, float* __restrict__ vt)
{
    __shared__ float t[32][33];
    int bh = blockIdx.z;
    long long b = bh / HEADS, h = bh % HEADS;
    const float* src = qkv + b*NN*QKV3 + 2*DIM + h*HD;
    int tt0 = blockIdx.x*32;
    int cc0 = blockIdx.y*32;
    int tx = threadIdx.x, ty = threadIdx.y;  // 32 x 8
    #pragma unroll
    for (int i = 0; i < 32; i += 8)
        t[ty+i][tx] = src[(long long)(tt0+ty+i)*QKV3 + cc0 + tx];
    __syncthreads();
    float* dst = vt + ((long long)bh*HD)*NN;
    #pragma unroll
    for (int i = 0; i < 32; i += 8)
        dst[(long long)(cc0+ty+i)*NN + tt0 + tx] = t[tx][ty+i];
}

__global__ void make_v_k(const float* __restrict__ ns, const float* __restrict__ nsi,
                         const float* __restrict__ alpha, float* __restrict__ v)
{
    long long i = (long long)blockIdx.x*blockDim.x + threadIdx.x;
    const long long n = (long long)BATCH*SL*DIM;
    if (i >= n) return;
    long long bs = i / DIM;
    float a = alpha[bs];
    v[i] = a*ns[i] + (1.f - a)*nsi[i];
}

__global__ void make_vfc_k(const float* __restrict__ xiattn, const float* __restrict__ vf,
                           float* __restrict__ o)
{
    long long i = (long long)blockIdx.x*blockDim.x + threadIdx.x;
    const long long n = (long long)BATCH*TT*DIM;
    if (i >= n) return;
    int c = (int)(i % DIM);
    long long bt = i / DIM;
    long long b = bt / TT, t = bt % TT;
    o[i] = (t < ZL) ? xiattn[(b*NN + t)*DIM + c]
                    : vf[(b*SL + (t-ZL))*DIM + c];
}

__global__ void make_xnew_k(const float* __restrict__ x, const float* __restrict__ xi,
                            const float* __restrict__ xattn, const float* __restrict__ xiattn,
                            const float* __restrict__ vfc,
                            float* __restrict__ xo, float* __restrict__ xio)
{
    long long i = (long long)blockIdx.x*blockDim.x + threadIdx.x;
    const long long n = (long long)BATCH*TT*DIM;
    if (i >= n) return;
    int c = (int)(i % DIM);
    long long bt = i / DIM;
    long long b = bt / TT, t = bt % TT;
    long long aidx = (b*NN + ZL + t)*DIM + c;
    float vf = vfc[i];
    xo[i]  = x[i]  + xattn[aidx]  + vf;
    xio[i] = xi[i] + xiattn[aidx] + vf;
}

__global__ void i2f_k(const int* __restrict__ in, float* __restrict__ out, int n)
{
    int i = blockIdx.x*blockDim.x + threadIdx.x;
    if (i < n) out[i] = (float)in[i];
}

// ---------------- host-side helpers ----------------
template<int TM, int TN>
static inline void mm(const float* A, const float* B, const float* bias,
                      const float* r1, const float* r2, float* C,
                      int M, int N, int K, int lda, int ldb, int ldc,
                      long long sAb, long long sBb, long long sCb,
                      int nb, int nh,
                      long long sAh, long long sBh, long long sCh,
                      float alpha, int act)
{
    constexpr int STAGE_BYTES = (2*TM*RWH + 2*TN*RWH)*2;
    constexpr int EPI = TM*(TN+4)*4;
    constexpr int DS = (2*STAGE_BYTES > EPI) ? 2*STAGE_BYTES : EPI;
    static bool init = false;
    if (!init) {
        cudaFuncSetAttribute(mm2<TM,TN>, cudaFuncAttributeMaxDynamicSharedMemorySize, DS);
        init = true;
    }
    dim3 g(N/TN, M/TM, nb*nh);
    mm2<TM,TN><<<g, 512, DS>>>(A,B,bias,r1,r2,C,K,lda,ldb,ldc,sAb,sBb,sCb,nh,sAh,sBh,sCh,alpha,act);
}

static inline int cdiv(long long a, int b) { return (int)((a + b - 1) / b); }

extern "C" void kernel_launch(void* const* d_in, const int* in_sizes, int n_in,
                              void* d_out, int out_size)
{
    const float* x      = (const float*)d_in[0];
    const float* xi     = (const float*)d_in[1];
    const int*   git    = (const int*)  d_in[2];
    const int*   giti   = (const int*)  d_in[3];
    const int*   gis    = (const int*)  d_in[4];
    const int*   gisi   = (const int*)  d_in[5];
    const float* w_qkv  = (const float*)d_in[6];
    const float* b_qkv  = (const float*)d_in[7];
    const float* w_proj = (const float*)d_in[8];
    const float* b_proj = (const float*)d_in[9];
    const float* g1     = (const float*)d_in[10];
    const float* bt1    = (const float*)d_in[11];
    const float* g2     = (const float*)d_in[12];
    const float* bt2    = (const float*)d_in[13];
    const float* w_fc1  = (const float*)d_in[14];
    const float* b_fc1  = (const float*)d_in[15];
    const float* w_fc2  = (const float*)d_in[16];
    const float* b_fc2  = (const float*)d_in[17];
    const float* w_al   = (const float*)d_in[18];
    const float* b_al   = (const float*)d_in[19];
    const float* w_al2  = (const float*)d_in[20];
    const float* b_al2  = (const float*)d_in[21];
    const float* w_fus  = (const float*)d_in[22];
    const float* b_fus  = (const float*)d_in[23];
    float* out = (float*)d_out;

    float *p_cat, *p_zf, *p_ns, *p_nsi, *p_attnx, *p_attnxi, *p_ln, *p_qkv,
          *p_vt, *p_ao, *p_xattn, *p_xiattn, *p_v, *p_vf, *p_vfc, *p_xnew, *p_xinew,
          *p_adap2, *p_h;
    cudaGetSymbolAddress((void**)&p_cat,    g_cat);
    cudaGetSymbolAddress((void**)&p_zf,     g_zf);
    cudaGetSymbolAddress((void**)&p_ns,     g_ns);
    cudaGetSymbolAddress((void**)&p_nsi,    g_nsi);
    cudaGetSymbolAddress((void**)&p_attnx,  g_attnx);
    cudaGetSymbolAddress((void**)&p_attnxi, g_attnxi);
    cudaGetSymbolAddress((void**)&p_ln,     g_ln);
    cudaGetSymbolAddress((void**)&p_qkv,    g_qkv);
    cudaGetSymbolAddress((void**)&p_vt,     g_vt);
    cudaGetSymbolAddress((void**)&p_ao,     g_ao);
    cudaGetSymbolAddress((void**)&p_xattn,  g_xattn);
    cudaGetSymbolAddress((void**)&p_xiattn, g_xiattn);
    cudaGetSymbolAddress((void**)&p_v,      g_v);
    cudaGetSymbolAddress((void**)&p_vf,     g_vf);
    cudaGetSymbolAddress((void**)&p_vfc,    g_vfc);
    cudaGetSymbolAddress((void**)&p_xnew,   g_xnew);
    cudaGetSymbolAddress((void**)&p_xinew,  g_xinew);
    cudaGetSymbolAddress((void**)&p_adap2,  g_adap2);
    cudaGetSymbolAddress((void**)&p_h,      g_h);

    const float scale_dim = 1.f / sqrtf((float)DIM);
    const float scale_hd  = 0.125f;

    // ---- index passthroughs ----
    i2f_k<<<cdiv(BATCH*ZL, 256), 256>>>(git,  out + O_GIT,  BATCH*ZL);
    i2f_k<<<cdiv(BATCH*SL, 256), 256>>>(gis,  out + O_GIS,  BATCH*SL);
    i2f_k<<<cdiv(BATCH*ZL, 256), 256>>>(giti, out + O_GITI, BATCH*ZL);
    i2f_k<<<cdiv(BATCH*SL, 256), 256>>>(gisi, out + O_GISI, BATCH*SL);

    // ---- z_f = concat(z,zi) @ w_al^T + b_al ----
    cat_feat_k<<<cdiv((long long)BATCH*ZL*2*DIM, 256), 256>>>(x, xi, p_cat);
    mm<128,128>(p_cat, w_al, b_al, nullptr, nullptr, p_zf,
                BATCH*ZL, DIM, 2*DIM, 2*DIM, 2*DIM, DIM,
                0,0,0, 1,1, 0,0,0, 1.f, 0);

    // ---- ns/nsi ----
    ln_kernel<<<dim3(SL, BATCH), 256>>>(x  + (long long)ZL*DIM, p_ns,  g1, bt1,
                                        (long long)TT*DIM, (long long)SL*DIM);
    ln_kernel<<<dim3(SL, BATCH), 256>>>(xi + (long long)ZL*DIM, p_nsi, g1, bt1,
                                        (long long)TT*DIM, (long long)SL*DIM);

    // ---- attn_x / attn_xi : per-batch 64 x 256 x 768 ----
    mm<64,128>(p_zf, p_ns, nullptr, nullptr, nullptr, p_attnx,
               ZL, SL, DIM, DIM, DIM, SL,
               (long long)ZL*DIM, (long long)SL*DIM, (long long)ZL*SL,
               BATCH, 1, 0,0,0, scale_dim, 0);
    mm<64,128>(p_zf, p_nsi, nullptr, nullptr, nullptr, p_attnxi,
               ZL, SL, DIM, DIM, DIM, SL,
               (long long)ZL*DIM, (long long)SL*DIM, (long long)ZL*SL,
               BATCH, 1, 0,0,0, scale_dim, 0);

    // ---- MHA both streams ----
    const float* src[2]    = {x, xi};
    float*       attn_o[2] = {out + O_ATTN, out + O_IATTN};
    float*       proj_o[2] = {p_xattn, p_xiattn};
    for (int side = 0; side < 2; side++) {
        ln_cat_kernel<<<dim3(NN, BATCH), 256>>>(p_zf, src[side], p_ln, g1, bt1);
        // qkv
        mm<128,128>(p_ln, w_qkv, b_qkv, nullptr, nullptr, p_qkv,
                    BATCH*NN, QKV3, DIM, DIM, DIM, QKV3,
                    0,0,0, 1,1, 0,0,0, 1.f, 0);
        // V transpose for attn@V
        vtrans_k<<<dim3(NN/32, HD/32, BATCH*HEADS), dim3(32,8)>>>(p_qkv, p_vt);
        // scores = q @ k^T * hd^-0.5 -> d_out attn region
        mm<128,128>(p_qkv, p_qkv + DIM, nullptr, nullptr, nullptr, attn_o[side],
                    NN, NN, HD, QKV3, QKV3, NN,
                    (long long)NN*QKV3, (long long)NN*QKV3, (long long)HEADS*NN*NN,
                    BATCH, HEADS, HD, HD, (long long)NN*NN, scale_hd, 0);
        // softmax in place
        softmax384<<<BATCH*HEADS*NN, 128>>>(attn_o[side]);
        // out = P @ V  (B = V^T, K-major)
        mm<128,64>(attn_o[side], p_vt, nullptr, nullptr, nullptr, p_ao,
                   NN, HD, NN, NN, NN, DIM,
                   (long long)HEADS*NN*NN, (long long)HEADS*HD*NN, (long long)NN*DIM,
                   BATCH, HEADS, (long long)NN*NN, (long long)HD*NN, HD, 1.f, 0);
        // proj
        mm<128,128>(p_ao, w_proj, b_proj, nullptr, nullptr, proj_o[side],
                    BATCH*NN, DIM, DIM, DIM, DIM, DIM,
                    0,0,0, 1,1, 0,0,0, 1.f, 0);
    }

    // ---- fusion ----
    fusion_kernel<<<BATCH, SL>>>(p_attnx, p_attnxi,
                                 out + O_ALPHA, out + O_UM, out + O_U, out + O_UI);
    make_v_k<<<cdiv((long long)BATCH*SL*DIM, 256), 256>>>(p_ns, p_nsi, out + O_ALPHA, p_v);
    mm<128,128>(p_v, w_fus, b_fus, nullptr, nullptr, p_vf,
                BATCH*SL, DIM, DIM, DIM, DIM, DIM,
                0,0,0, 1,1, 0,0,0, 1.f, 0);
    make_vfc_k<<<cdiv((long long)BATCH*TT*DIM, 256), 256>>>(p_xiattn, p_vf, p_vfc);

    // ---- residual adds ----
    make_xnew_k<<<cdiv((long long)BATCH*TT*DIM, 256), 256>>>(
        x, xi, p_xattn, p_xiattn, p_vfc, p_xnew, p_xinew);

    // ---- adap2 ----
    ln_kernel<<<dim3(TT, BATCH), 256>>>(p_vfc, p_ln, g2, bt2,
                                        (long long)TT*DIM, (long long)TT*DIM);
    mm<128,128>(p_ln, w_al2, b_al2, nullptr, nullptr, p_adap2,
                BATCH*TT, DIM, DIM, DIM, DIM, DIM,
                0,0,0, 1,1, 0,0,0, 1.f, 0);

    // ---- MLP both streams ----
    float* xn[2] = {p_xnew, p_xinew};
    float* xo[2] = {out + O_XOUT, out + O_XIOUT};
    for (int side = 0; side < 2; side++) {
        ln_kernel<<<dim3(TT, BATCH), 256>>>(xn[side], p_ln, g2, bt2,
                                            (long long)TT*DIM, (long long)TT*DIM);
        mm<128,128>(p_ln, w_fc1, b_fc1, nullptr, nullptr, p_h,
                    BATCH*TT, HID, DIM, DIM, DIM, HID,
                    0,0,0, 1,1, 0,0,0, 1.f, 1);
        mm<128,128>(p_h, w_fc2, b_fc2, xn[side], p_adap2, xo[side],
                    BATCH*TT, DIM, HID, HID, HID, DIM,
                    0,0,0, 1,1, 0,0,0, 1.f, 0);
    }
}

// round 5
// speedup vs baseline: 3.7158x; 1.5971x over previous
#include <cuda_runtime.h>
#include <cuda_fp16.h>
#include <math.h>
#include <cstdint>

// ---------------- problem constants ----------------
#define BATCH 32
#define ZL 64
#define SL 256
#define TT 320           // ZL+SL
#define NN 384           // ZL + TT (xc length)
#define DIM 768
#define HEADS 12
#define HD 64
#define HID 3072
#define QKV3 2304

// output offsets (float elements)
#define O_XOUT   0LL
#define O_GIT    7864320LL
#define O_GIS    7866368LL
#define O_ATTN   7874560LL
#define O_XIOUT  64497664LL
#define O_GITI   72361984LL
#define O_GISI   72364032LL
#define O_IATTN  72372224LL
#define O_ALPHA  128995328LL
#define O_UM     129003520LL
#define O_U      129011712LL
#define O_UI     129019904LL

// ---------------- scratch (device globals; allocation-free) ----------------
__device__ float g_cat   [BATCH*ZL*2*DIM];
__device__ float g_zf    [BATCH*ZL*DIM];
__device__ float g_ns    [BATCH*SL*DIM];
__device__ float g_nsi   [BATCH*SL*DIM];
__device__ float g_attnx [BATCH*ZL*SL];
__device__ float g_attnxi[BATCH*ZL*SL];
__device__ float g_ln    [BATCH*NN*DIM];
__device__ float g_qkv   [BATCH*NN*QKV3];
__device__ float g_vt    [BATCH*HEADS*HD*NN];
__device__ float g_ao    [BATCH*NN*DIM];
__device__ float g_xattn [BATCH*NN*DIM];
__device__ float g_xiattn[BATCH*NN*DIM];
__device__ float g_v     [BATCH*SL*DIM];
__device__ float g_vf    [BATCH*SL*DIM];
__device__ float g_vfc   [BATCH*TT*DIM];
__device__ float g_xnew  [BATCH*TT*DIM];
__device__ float g_xinew [BATCH*TT*DIM];
__device__ float g_adap2 [BATCH*TT*DIM];
__device__ float g_h     [BATCH*TT*HID];

// =============== helpers =====================================================
__device__ __forceinline__ uint32_t smem_u32(const void* p) {
    uint32_t a;
    asm("{ .reg .u64 t; cvta.to.shared.u64 t, %1; cvt.u32.u64 %0, t; }" : "=r"(a) : "l"(p));
    return a;
}
__device__ __forceinline__ void mma16816h(float* d, const uint32_t* a, const uint32_t* b) {
    asm volatile("mma.sync.aligned.m16n8k16.row.col.f32.f16.f16.f32 "
        "{%0,%1,%2,%3}, {%4,%5,%6,%7}, {%8,%9}, {%0,%1,%2,%3};"
        : "+f"(d[0]), "+f"(d[1]), "+f"(d[2]), "+f"(d[3])
        : "r"(a[0]), "r"(a[1]), "r"(a[2]), "r"(a[3]), "r"(b[0]), "r"(b[1]));
}
__device__ __forceinline__ void ldsm4(uint32_t& r0, uint32_t& r1, uint32_t& r2, uint32_t& r3,
                                      uint32_t addr) {
    asm volatile("ldmatrix.sync.aligned.m8n8.x4.shared.b16 {%0,%1,%2,%3}, [%4];"
        : "=r"(r0), "=r"(r1), "=r"(r2), "=r"(r3) : "r"(addr));
}
__device__ __forceinline__ uint32_t pack_h2(float x, float y) {
    __half2 p = __float22half2_rn(make_float2(x, y));
    return *(uint32_t*)&p;
}

// =============== fp16 mma.sync GEMM, ldmatrix fragments ======================
// C = alpha * A @ B^T (+bias +res1 +res2, opt GELU)
// A: (M,K) row-major fp32, B: (N,K) row-major fp32. 512 threads, warps 4x4.
// M%TM==0, N%TN==0, K%32==0.
#define RWH 40             // SMEM row width in halves (32 data + 8 pad)

template<int TM, int TN>
__global__ __launch_bounds__(512, 1)
void mm2(const float* __restrict__ A, const float* __restrict__ B,
         const float* __restrict__ bias,
         const float* __restrict__ res1, const float* __restrict__ res2,
         float* __restrict__ C,
         int K, int lda, int ldb, int ldc,
         long long sAb, long long sBb, long long sCb, int batchH,
         long long sAh, long long sBh, long long sCh,
         float alpha, int act)
{
    extern __shared__ char dsm[];
    constexpr int WTM = TM/4, WTN = TN/4;
    constexpr int MI = WTM/16, NI = WTN/8;
    constexpr int AHL = TM*RWH;            // halves in A tile
    constexpr int BHL = TN*RWH;
    constexpr int STAGE_BYTES = (AHL + BHL)*2;
    constexpr int PA = TM/64, PB = TN/64;  // float4s per thread per chunk

    const int tid  = threadIdx.x;
    const int lane = tid & 31;
    const int w    = tid >> 5;
    const int wm   = w >> 2;
    const int wn   = w & 3;

    const int bz = blockIdx.z;
    const int b  = bz / batchH;
    const int h  = bz - b*batchH;
    const int m0 = blockIdx.y * TM;
    const int n0 = blockIdx.x * TN;
    const float* Ab = A + (long long)b*sAb + (long long)h*sAh + (long long)m0*lda;
    const float* Bb = B + (long long)b*sBb + (long long)h*sBh + (long long)n0*ldb;
    const long long coff = (long long)b*sCb + (long long)h*sCh;

    const int lq = tid & 7;     // col group of 4 floats
    const int lr = tid >> 3;    // 0..63

    const uint32_t sb0 = smem_u32(dsm);
    // lane-dependent ldmatrix base offsets (bytes, within stage)
    const uint32_t a_l = (uint32_t)(((wm*WTM + (lane & 15))*RWH + ((lane >> 4) << 3)) * 2);
    const uint32_t b_l = (uint32_t)(AHL*2 + ((wn*WTN + (lane & 15))*RWH + ((lane >> 4) << 3)) * 2);

    float acc[MI][NI][4];
    #pragma unroll
    for (int mi = 0; mi < MI; mi++)
        #pragma unroll
        for (int ni = 0; ni < NI; ni++)
            #pragma unroll
            for (int j = 0; j < 4; j++) acc[mi][ni][j] = 0.f;

    const int NC = K >> 5;
    float4 pA[PA], pB[PB];

    #pragma unroll
    for (int p = 0; p < PA; p++)
        pA[p] = *(const float4*)(Ab + (long long)(lr + 64*p)*lda + 4*lq);
    #pragma unroll
    for (int p = 0; p < PB; p++)
        pB[p] = *(const float4*)(Bb + (long long)(lr + 64*p)*ldb + 4*lq);

    for (int c = 0; c < NC; c++) {
        const int st = c & 1;
        char* sb = dsm + st * STAGE_BYTES;
        __half* Ah = (__half*)sb;
        __half* Bh = Ah + AHL;

        #pragma unroll
        for (int p = 0; p < PA; p++) {
            int off = (lr + 64*p)*RWH + 4*lq;
            *(uint32_t*)(Ah + off)     = pack_h2(pA[p].x, pA[p].y);
            *(uint32_t*)(Ah + off + 2) = pack_h2(pA[p].z, pA[p].w);
        }
        #pragma unroll
        for (int p = 0; p < PB; p++) {
            int off = (lr + 64*p)*RWH + 4*lq;
            *(uint32_t*)(Bh + off)     = pack_h2(pB[p].x, pB[p].y);
            *(uint32_t*)(Bh + off + 2) = pack_h2(pB[p].z, pB[p].w);
        }
        __syncthreads();

        if (c + 1 < NC) {
            const int k0 = (c + 1) << 5;
            #pragma unroll
            for (int p = 0; p < PA; p++)
                pA[p] = *(const float4*)(Ab + (long long)(lr + 64*p)*lda + k0 + 4*lq);
            #pragma unroll
            for (int p = 0; p < PB; p++)
                pB[p] = *(const float4*)(Bb + (long long)(lr + 64*p)*ldb + k0 + 4*lq);
        }

        const uint32_t stageu = sb0 + st * STAGE_BYTES;
        #pragma unroll
        for (int ks = 0; ks < 2; ks++) {
            const uint32_t kb = ks * 32;   // 16 halves = 32 bytes
            uint32_t ah[MI][4];
            #pragma unroll
            for (int mi = 0; mi < MI; mi++) {
                uint32_t ad = stageu + a_l + mi*(16*RWH*2) + kb;
                ldsm4(ah[mi][0], ah[mi][1], ah[mi][2], ah[mi][3], ad);
            }
            uint32_t bh[NI][2];
            #pragma unroll
            for (int nj = 0; nj < NI/2; nj++) {
                uint32_t bd = stageu + b_l + nj*(16*RWH*2) + kb;
                uint32_t q0, q1, q2, q3;
                ldsm4(q0, q1, q2, q3, bd);
                bh[2*nj][0] = q0; bh[2*nj][1] = q2;
                bh[2*nj+1][0] = q1; bh[2*nj+1][1] = q3;
            }
            #pragma unroll
            for (int mi = 0; mi < MI; mi++)
                #pragma unroll
                for (int ni = 0; ni < NI; ni++)
                    mma16816h(acc[mi][ni], ah[mi], bh[ni]);
        }
        __syncthreads();
    }

    // ---- epilogue: frags -> SMEM -> coalesced fused write ----
    constexpr int ROWW = TN + 4;
    float* sbuf = (float*)dsm;
    const int g = lane >> 2, t4 = lane & 3;
    #pragma unroll
    for (int mi = 0; mi < MI; mi++)
        #pragma unroll
        for (int ni = 0; ni < NI; ni++)
            #pragma unroll
            for (int j = 0; j < 4; j++) {
                int row = wm*WTM + mi*16 + g + 8*(j >> 1);
                int col = wn*WTN + ni*8 + 2*t4 + (j & 1);
                sbuf[row*ROWW + col] = acc[mi][ni][j];
            }
    __syncthreads();

    #pragma unroll
    for (int p = 0; p < TM*TN/2048; p++) {
        int i4 = tid + (p << 9);
        int elem = i4 << 2;
        int rr = elem / TN;
        int cc = elem - rr*TN;
        float4 v = *(float4*)(sbuf + rr*ROWW + cc);
        v.x *= alpha; v.y *= alpha; v.z *= alpha; v.w *= alpha;
        if (bias) {
            float4 bb = *(const float4*)(bias + n0 + cc);
            v.x += bb.x; v.y += bb.y; v.z += bb.z; v.w += bb.w;
        }
        long long off = coff + (long long)(m0 + rr)*ldc + (n0 + cc);
        if (res1) {
            float4 a = *(const float4*)(res1 + off);
            v.x += a.x; v.y += a.y; v.z += a.z; v.w += a.w;
        }
        if (res2) {
            float4 a = *(const float4*)(res2 + off);
            v.x += a.x; v.y += a.y; v.z += a.z; v.w += a.w;
        }
        if (act == 1) {
            v.x = 0.5f*v.x*(1.f + erff(v.x*0.70710678118654752f));
            v.y = 0.5f*v.y*(1.f + erff(v.y*0.70710678118654752f));
            v.z = 0.5f*v.z*(1.f + erff(v.z*0.70710678118654752f));
            v.w = 0.5f*v.w*(1.f + erff(v.w*0.70710678118654752f));
        }
        *(float4*)(C + off) = v;
    }
}

// ---------------- LayerNorm over 768 features -------------------------------
__global__ void ln_kernel(const float* __restrict__ in, float* __restrict__ out,
                          const float* __restrict__ g, const float* __restrict__ b,
                          long long in_bstride, long long out_bstride)
{
    const float* x = in  + (long long)blockIdx.y*in_bstride  + (long long)blockIdx.x*DIM;
    float*       y = out + (long long)blockIdx.y*out_bstride + (long long)blockIdx.x*DIM;
    int tid = threadIdx.x;
    float v0 = x[tid], v1 = x[tid+256], v2 = x[tid+512];
    __shared__ float sh[256];
    sh[tid] = v0 + v1 + v2;
    __syncthreads();
    for (int o = 128; o > 0; o >>= 1) { if (tid < o) sh[tid] += sh[tid+o]; __syncthreads(); }
    float mean = sh[0] * (1.f/768.f);
    __syncthreads();
    float d0 = v0-mean, d1 = v1-mean, d2 = v2-mean;
    sh[tid] = d0*d0 + d1*d1 + d2*d2;
    __syncthreads();
    for (int o = 128; o > 0; o >>= 1) { if (tid < o) sh[tid] += sh[tid+o]; __syncthreads(); }
    float inv = rsqrtf(sh[0] * (1.f/768.f) + 1e-5f);
    y[tid]     = d0*inv*g[tid]     + b[tid];
    y[tid+256] = d1*inv*g[tid+256] + b[tid+256];
    y[tid+512] = d2*inv*g[tid+512] + b[tid+512];
}

// LN over the concat [z_f, x] without materializing the concat
__global__ void ln_cat_kernel(const float* __restrict__ zf, const float* __restrict__ x,
                              float* __restrict__ out,
                              const float* __restrict__ g, const float* __restrict__ b)
{
    int t = blockIdx.x, bb = blockIdx.y;
    const float* src = (t < ZL) ? zf + ((long long)bb*ZL + t)*DIM
                                : x  + ((long long)bb*TT + (t - ZL))*DIM;
    float* y = out + ((long long)bb*NN + t)*DIM;
    int tid = threadIdx.x;
    float v0 = src[tid], v1 = src[tid+256], v2 = src[tid+512];
    __shared__ float sh[256];
    sh[tid] = v0 + v1 + v2;
    __syncthreads();
    for (int o = 128; o > 0; o >>= 1) { if (tid < o) sh[tid] += sh[tid+o]; __syncthreads(); }
    float mean = sh[0] * (1.f/768.f);
    __syncthreads();
    float d0 = v0-mean, d1 = v1-mean, d2 = v2-mean;
    sh[tid] = d0*d0 + d1*d1 + d2*d2;
    __syncthreads();
    for (int o = 128; o > 0; o >>= 1) { if (tid < o) sh[tid] += sh[tid+o]; __syncthreads(); }
    float inv = rsqrtf(sh[0] * (1.f/768.f) + 1e-5f);
    y[tid]     = d0*inv*g[tid]     + b[tid];
    y[tid+256] = d1*inv*g[tid+256] + b[tid+256];
    y[tid+512] = d2*inv*g[tid+512] + b[tid+512];
}

// ---------------- softmax over rows of length 384 ---------------------------
__global__ void softmax384(float* __restrict__ data)
{
    float* x = data + (long long)blockIdx.x * 384;
    int tid = threadIdx.x;  // 128
    float a = x[tid], b = x[tid+128], c = x[tid+256];
    __shared__ float sh[128];
    float m = fmaxf(a, fmaxf(b, c));
    sh[tid] = m; __syncthreads();
    for (int o = 64; o > 0; o >>= 1) { if (tid < o) sh[tid] = fmaxf(sh[tid], sh[tid+o]); __syncthreads(); }
    m = sh[0]; __syncthreads();
    float e0 = expf(a-m), e1 = expf(b-m), e2 = expf(c-m);
    sh[tid] = e0+e1+e2; __syncthreads();
    for (int o = 64; o > 0; o >>= 1) { if (tid < o) sh[tid] += sh[tid+o]; __syncthreads(); }
    float inv = 1.f / sh[0];
    x[tid] = e0*inv; x[tid+128] = e1*inv; x[tid+256] = e2*inv;
}

// ---------------- fusion: entropies over ZL axis ----------------------------
__global__ void fusion_kernel(const float* __restrict__ ax, const float* __restrict__ axi,
                              float* __restrict__ alpha_o, float* __restrict__ um_o,
                              float* __restrict__ u_o, float* __restrict__ ui_o)
{
    int b = blockIdx.x, s = threadIdx.x;
    const float* X  = ax  + (long long)b*ZL*SL + s;
    const float* Xi = axi + (long long)b*ZL*SL + s;
    float u, ui;
    {
        float mx = -1e30f;
        for (int t = 0; t < ZL; t++) mx = fmaxf(mx, X[t*SL]);
        float sum = 0.f;
        for (int t = 0; t < ZL; t++) sum += expf(X[t*SL] - mx);
        float inv = 1.f/sum, acc = 0.f;
        for (int t = 0; t < ZL; t++) { float p = expf(X[t*SL]-mx)*inv; acc -= p*logf(p + 1e-8f); }
        u = acc;
    }
    {
        float mx = -1e30f;
        for (int t = 0; t < ZL; t++) mx = fmaxf(mx, Xi[t*SL]);
        float sum = 0.f;
        for (int t = 0; t < ZL; t++) sum += expf(Xi[t*SL] - mx);
        float inv = 1.f/sum, acc = 0.f;
        for (int t = 0; t < ZL; t++) { float p = expf(Xi[t*SL]-mx)*inv; acc -= p*logf(p + 1e-8f); }
        ui = acc;
    }
    int idx = b*SL + s;
    float alpha = 1.f / (1.f + expf(-(ui - u)));
    alpha_o[idx] = alpha;
    um_o[idx] = 0.5f*(u + ui);
    u_o[idx] = u;
    ui_o[idx] = ui;
}

// ---------------- elementwise helpers ----------------------------------------
__global__ void cat_feat_k(const float* __restrict__ x, const float* __restrict__ xi,
                           float* __restrict__ o)
{
    long long i = (long long)blockIdx.x*blockDim.x + threadIdx.x;
    const long long n = (long long)BATCH*ZL*2*DIM;
    if (i >= n) return;
    int c = (int)(i % (2*DIM));
    long long bt = i / (2*DIM);
    long long b = bt / ZL, t = bt % ZL;
    long long src = (b*TT + t)*DIM;
    o[i] = (c < DIM) ? x[src + c] : xi[src + c - DIM];
}

__global__ void vtrans_k(const float* __restrict__ qkv, float* __restrict__ vt)
{
    __shared__ float t[32][33];
    int bh = blockIdx.z;
    long long b = bh / HEADS, h = bh % HEADS;
    const float* src = qkv + b*NN*QKV3 + 2*DIM + h*HD;
    int tt0 = blockIdx.x*32;
    int cc0 = blockIdx.y*32;
    int tx = threadIdx.x, ty = threadIdx.y;  // 32 x 8
    #pragma unroll
    for (int i = 0; i < 32; i += 8)
        t[ty+i][tx] = src[(long long)(tt0+ty+i)*QKV3 + cc0 + tx];
    __syncthreads();
    float* dst = vt + ((long long)bh*HD)*NN;
    #pragma unroll
    for (int i = 0; i < 32; i += 8)
        dst[(long long)(cc0+ty+i)*NN + tt0 + tx] = t[tx][ty+i];
}

__global__ void make_v_k(const float* __restrict__ ns, const float* __restrict__ nsi,
                         const float* __restrict__ alpha, float* __restrict__ v)
{
    long long i = (long long)blockIdx.x*blockDim.x + threadIdx.x;
    const long long n = (long long)BATCH*SL*DIM;
    if (i >= n) return;
    long long bs = i / DIM;
    float a = alpha[bs];
    v[i] = a*ns[i] + (1.f - a)*nsi[i];
}

__global__ void make_vfc_k(const float* __restrict__ xiattn, const float* __restrict__ vf,
                           float* __restrict__ o)
{
    long long i = (long long)blockIdx.x*blockDim.x + threadIdx.x;
    const long long n = (long long)BATCH*TT*DIM;
    if (i >= n) return;
    int c = (int)(i % DIM);
    long long bt = i / DIM;
    long long b = bt / TT, t = bt % TT;
    o[i] = (t < ZL) ? xiattn[(b*NN + t)*DIM + c]
                    : vf[(b*SL + (t-ZL))*DIM + c];
}

__global__ void make_xnew_k(const float* __restrict__ x, const float* __restrict__ xi,
                            const float* __restrict__ xattn, const float* __restrict__ xiattn,
                            const float* __restrict__ vfc,
                            float* __restrict__ xo, float* __restrict__ xio)
{
    long long i = (long long)blockIdx.x*blockDim.x + threadIdx.x;
    const long long n = (long long)BATCH*TT*DIM;
    if (i >= n) return;
    int c = (int)(i % DIM);
    long long bt = i / DIM;
    long long b = bt / TT, t = bt % TT;
    long long aidx = (b*NN + ZL + t)*DIM + c;
    float vf = vfc[i];
    xo[i]  = x[i]  + xattn[aidx]  + vf;
    xio[i] = xi[i] + xiattn[aidx] + vf;
}

__global__ void i2f_k(const int* __restrict__ in, float* __restrict__ out, int n)
{
    int i = blockIdx.x*blockDim.x + threadIdx.x;
    if (i < n) out[i] = (float)in[i];
}

// ---------------- host-side helpers ----------------
template<int TM, int TN>
static inline void mm(const float* A, const float* B, const float* bias,
                      const float* r1, const float* r2, float* C,
                      int M, int N, int K, int lda, int ldb, int ldc,
                      long long sAb, long long sBb, long long sCb,
                      int nb, int nh,
                      long long sAh, long long sBh, long long sCh,
                      float alpha, int act)
{
    constexpr int STAGE_BYTES = (TM*RWH + TN*RWH)*2;
    constexpr int EPI = TM*(TN+4)*4;
    constexpr int DS = (2*STAGE_BYTES > EPI) ? 2*STAGE_BYTES : EPI;
    static bool init = false;
    if (!init) {
        cudaFuncSetAttribute(mm2<TM,TN>, cudaFuncAttributeMaxDynamicSharedMemorySize, DS);
        init = true;
    }
    dim3 g(N/TN, M/TM, nb*nh);
    mm2<TM,TN><<<g, 512, DS>>>(A,B,bias,r1,r2,C,K,lda,ldb,ldc,sAb,sBb,sCb,nh,sAh,sBh,sCh,alpha,act);
}

static inline int cdiv(long long a, int b) { return (int)((a + b - 1) / b); }

extern "C" void kernel_launch(void* const* d_in, const int* in_sizes, int n_in,
                              void* d_out, int out_size)
{
    const float* x      = (const float*)d_in[0];
    const float* xi     = (const float*)d_in[1];
    const int*   git    = (const int*)  d_in[2];
    const int*   giti   = (const int*)  d_in[3];
    const int*   gis    = (const int*)  d_in[4];
    const int*   gisi   = (const int*)  d_in[5];
    const float* w_qkv  = (const float*)d_in[6];
    const float* b_qkv  = (const float*)d_in[7];
    const float* w_proj = (const float*)d_in[8];
    const float* b_proj = (const float*)d_in[9];
    const float* g1     = (const float*)d_in[10];
    const float* bt1    = (const float*)d_in[11];
    const float* g2     = (const float*)d_in[12];
    const float* bt2    = (const float*)d_in[13];
    const float* w_fc1  = (const float*)d_in[14];
    const float* b_fc1  = (const float*)d_in[15];
    const float* w_fc2  = (const float*)d_in[16];
    const float* b_fc2  = (const float*)d_in[17];
    const float* w_al   = (const float*)d_in[18];
    const float* b_al   = (const float*)d_in[19];
    const float* w_al2  = (const float*)d_in[20];
    const float* b_al2  = (const float*)d_in[21];
    const float* w_fus  = (const float*)d_in[22];
    const float* b_fus  = (const float*)d_in[23];
    float* out = (float*)d_out;

    float *p_cat, *p_zf, *p_ns, *p_nsi, *p_attnx, *p_attnxi, *p_ln, *p_qkv,
          *p_vt, *p_ao, *p_xattn, *p_xiattn, *p_v, *p_vf, *p_vfc, *p_xnew, *p_xinew,
          *p_adap2, *p_h;
    cudaGetSymbolAddress((void**)&p_cat,    g_cat);
    cudaGetSymbolAddress((void**)&p_zf,     g_zf);
    cudaGetSymbolAddress((void**)&p_ns,     g_ns);
    cudaGetSymbolAddress((void**)&p_nsi,    g_nsi);
    cudaGetSymbolAddress((void**)&p_attnx,  g_attnx);
    cudaGetSymbolAddress((void**)&p_attnxi, g_attnxi);
    cudaGetSymbolAddress((void**)&p_ln,     g_ln);
    cudaGetSymbolAddress((void**)&p_qkv,    g_qkv);
    cudaGetSymbolAddress((void**)&p_vt,     g_vt);
    cudaGetSymbolAddress((void**)&p_ao,     g_ao);
    cudaGetSymbolAddress((void**)&p_xattn,  g_xattn);
    cudaGetSymbolAddress((void**)&p_xiattn, g_xiattn);
    cudaGetSymbolAddress((void**)&p_v,      g_v);
    cudaGetSymbolAddress((void**)&p_vf,     g_vf);
    cudaGetSymbolAddress((void**)&p_vfc,    g_vfc);
    cudaGetSymbolAddress((void**)&p_xnew,   g_xnew);
    cudaGetSymbolAddress((void**)&p_xinew,  g_xinew);
    cudaGetSymbolAddress((void**)&p_adap2,  g_adap2);
    cudaGetSymbolAddress((void**)&p_h,      g_h);

    const float scale_dim = 1.f / sqrtf((float)DIM);
    const float scale_hd  = 0.125f;

    // ---- z_f = concat(z,zi) @ w_al^T + b_al ----
    cat_feat_k<<<cdiv((long long)BATCH*ZL*2*DIM, 256), 256>>>(x, xi, p_cat);     // launch 0
    mm<128,128>(p_cat, w_al, b_al, nullptr, nullptr, p_zf,                        // 1
                BATCH*ZL, DIM, 2*DIM, 2*DIM, 2*DIM, DIM,
                0,0,0, 1,1, 0,0,0, 1.f, 0);

    // ---- ns/nsi ----
    ln_kernel<<<dim3(SL, BATCH), 256>>>(x  + (long long)ZL*DIM, p_ns,  g1, bt1,   // 2
                                        (long long)TT*DIM, (long long)SL*DIM);
    ln_kernel<<<dim3(SL, BATCH), 256>>>(xi + (long long)ZL*DIM, p_nsi, g1, bt1,   // 3
                                        (long long)TT*DIM, (long long)SL*DIM);

    // ---- MHA both streams (launch 5 = qkv mm2 -> ncu profile target) ----
    const float* src[2]    = {x, xi};
    float*       attn_o[2] = {out + O_ATTN, out + O_IATTN};
    float*       proj_o[2] = {p_xattn, p_xiattn};
    for (int side = 0; side < 2; side++) {
        ln_cat_kernel<<<dim3(NN, BATCH), 256>>>(p_zf, src[side], p_ln, g1, bt1);  // 4
        mm<128,128>(p_ln, w_qkv, b_qkv, nullptr, nullptr, p_qkv,                  // 5
                    BATCH*NN, QKV3, DIM, DIM, DIM, QKV3,
                    0,0,0, 1,1, 0,0,0, 1.f, 0);
        vtrans_k<<<dim3(NN/32, HD/32, BATCH*HEADS), dim3(32,8)>>>(p_qkv, p_vt);
        // scores = q @ k^T * hd^-0.5 -> d_out attn region
        mm<128,128>(p_qkv, p_qkv + DIM, nullptr, nullptr, nullptr, attn_o[side],
                    NN, NN, HD, QKV3, QKV3, NN,
                    (long long)NN*QKV3, (long long)NN*QKV3, (long long)HEADS*NN*NN,
                    BATCH, HEADS, HD, HD, (long long)NN*NN, scale_hd, 0);
        softmax384<<<BATCH*HEADS*NN, 128>>>(attn_o[side]);
        // out = P @ V  (B = V^T, K-major)
        mm<128,64>(attn_o[side], p_vt, nullptr, nullptr, nullptr, p_ao,
                   NN, HD, NN, NN, NN, DIM,
                   (long long)HEADS*NN*NN, (long long)HEADS*HD*NN, (long long)NN*DIM,
                   BATCH, HEADS, (long long)NN*NN, (long long)HD*NN, HD, 1.f, 0);
        mm<128,128>(p_ao, w_proj, b_proj, nullptr, nullptr, proj_o[side],
                    BATCH*NN, DIM, DIM, DIM, DIM, DIM,
                    0,0,0, 1,1, 0,0,0, 1.f, 0);
    }

    // ---- attn_x / attn_xi : per-batch 64 x 256 x 768 ----
    mm<64,128>(p_zf, p_ns, nullptr, nullptr, nullptr, p_attnx,
               ZL, SL, DIM, DIM, DIM, SL,
               (long long)ZL*DIM, (long long)SL*DIM, (long long)ZL*SL,
               BATCH, 1, 0,0,0, scale_dim, 0);
    mm<64,128>(p_zf, p_nsi, nullptr, nullptr, nullptr, p_attnxi,
               ZL, SL, DIM, DIM, DIM, SL,
               (long long)ZL*DIM, (long long)SL*DIM, (long long)ZL*SL,
               BATCH, 1, 0,0,0, scale_dim, 0);

    // ---- fusion ----
    fusion_kernel<<<BATCH, SL>>>(p_attnx, p_attnxi,
                                 out + O_ALPHA, out + O_UM, out + O_U, out + O_UI);
    make_v_k<<<cdiv((long long)BATCH*SL*DIM, 256), 256>>>(p_ns, p_nsi, out + O_ALPHA, p_v);
    mm<128,128>(p_v, w_fus, b_fus, nullptr, nullptr, p_vf,
                BATCH*SL, DIM, DIM, DIM, DIM, DIM,
                0,0,0, 1,1, 0,0,0, 1.f, 0);
    make_vfc_k<<<cdiv((long long)BATCH*TT*DIM, 256), 256>>>(p_xiattn, p_vf, p_vfc);

    // ---- residual adds ----
    make_xnew_k<<<cdiv((long long)BATCH*TT*DIM, 256), 256>>>(
        x, xi, p_xattn, p_xiattn, p_vfc, p_xnew, p_xinew);

    // ---- adap2 ----
    ln_kernel<<<dim3(TT, BATCH), 256>>>(p_vfc, p_ln, g2, bt2,
                                        (long long)TT*DIM, (long long)TT*DIM);
    mm<128,128>(p_ln, w_al2, b_al2, nullptr, nullptr, p_adap2,
                BATCH*TT, DIM, DIM, DIM, DIM, DIM,
                0,0,0, 1,1, 0,0,0, 1.f, 0);

    // ---- MLP both streams ----
    float* xn[2] = {p_xnew, p_xinew};
    float* xo[2] = {out + O_XOUT, out + O_XIOUT};
    for (int side = 0; side < 2; side++) {
        ln_kernel<<<dim3(TT, BATCH), 256>>>(xn[side], p_ln, g2, bt2,
                                            (long long)TT*DIM, (long long)TT*DIM);
        mm<128,128>(p_ln, w_fc1, b_fc1, nullptr, nullptr, p_h,
                    BATCH*TT, HID, DIM, DIM, DIM, HID,
                    0,0,0, 1,1, 0,0,0, 1.f, 1);
        mm<128,128>(p_h, w_fc2, b_fc2, xn[side], p_adap2, xo[side],
                    BATCH*TT, DIM, HID, HID, HID, DIM,
                    0,0,0, 1,1, 0,0,0, 1.f, 0);
    }

    // ---- index passthroughs (moved to end so launch #5 is a GEMM) ----
    i2f_k<<<cdiv(BATCH*ZL, 256), 256>>>(git,  out + O_GIT,  BATCH*ZL);
    i2f_k<<<cdiv(BATCH*SL, 256), 256>>>(gis,  out + O_GIS,  BATCH*SL);
    i2f_k<<<cdiv(BATCH*ZL, 256), 256>>>(giti, out + O_GITI, BATCH*ZL);
    i2f_k<<<cdiv(BATCH*SL, 256), 256>>>(gisi, out + O_GISI, BATCH*SL);
}

// round 6
// speedup vs baseline: 4.3170x; 1.1618x over previous
#include <cuda_runtime.h>
#include <cuda_fp16.h>
#include <math.h>
#include <cstdint>

// ---------------- problem constants ----------------
#define BATCH 32
#define ZL 64
#define SL 256
#define TT 320
#define NN 384
#define DIM 768
#define HEADS 12
#define HD 64
#define HID 3072
#define QKV3 2304

#define O_XOUT   0LL
#define O_GIT    7864320LL
#define O_GIS    7866368LL
#define O_ATTN   7874560LL
#define O_XIOUT  64497664LL
#define O_GITI   72361984LL
#define O_GISI   72364032LL
#define O_IATTN  72372224LL
#define O_ALPHA  128995328LL
#define O_UM     129003520LL
#define O_U      129011712LL
#define O_UI     129019904LL

// ---------------- scratch ----------------
__device__ __half g_cath [BATCH*ZL*2*DIM];
__device__ float  g_zf   [BATCH*ZL*DIM];
__device__ float  g_ns   [BATCH*SL*DIM];
__device__ float  g_nsi  [BATCH*SL*DIM];
__device__ float  g_attnx [BATCH*ZL*SL];
__device__ float  g_attnxi[BATCH*ZL*SL];
__device__ __half g_lnh  [BATCH*NN*DIM];
__device__ float  g_qkv  [BATCH*NN*QKV3];
__device__ __half g_vth  [BATCH*HEADS*HD*NN];
__device__ __half g_aoh  [BATCH*NN*DIM];
__device__ float  g_xattn [BATCH*NN*DIM];
__device__ float  g_xiattn[BATCH*NN*DIM];
__device__ float  g_v    [BATCH*SL*DIM];
__device__ float  g_vf   [BATCH*SL*DIM];
__device__ float  g_vfc  [BATCH*TT*DIM];
__device__ float  g_xnew [BATCH*TT*DIM];
__device__ float  g_xinew[BATCH*TT*DIM];
__device__ float  g_adap2[BATCH*TT*DIM];
__device__ __half g_hh   [BATCH*TT*HID];
// fp16 weight copies
__device__ __half g_wqkvh[QKV3*DIM];
__device__ __half g_wprojh[DIM*DIM];
__device__ __half g_wfc1h[HID*DIM];
__device__ __half g_wfc2h[DIM*HID];
__device__ __half g_walh [DIM*2*DIM];
__device__ __half g_wal2h[DIM*DIM];
__device__ __half g_wfush[DIM*DIM];

// =============== helpers =====================================================
__device__ __forceinline__ uint32_t smem_u32(const void* p) {
    uint32_t a;
    asm("{ .reg .u64 t; cvta.to.shared.u64 t, %1; cvt.u32.u64 %0, t; }" : "=r"(a) : "l"(p));
    return a;
}
__device__ __forceinline__ void mma16816h(float* d, const uint32_t* a, const uint32_t* b) {
    asm volatile("mma.sync.aligned.m16n8k16.row.col.f32.f16.f16.f32 "
        "{%0,%1,%2,%3}, {%4,%5,%6,%7}, {%8,%9}, {%0,%1,%2,%3};"
        : "+f"(d[0]), "+f"(d[1]), "+f"(d[2]), "+f"(d[3])
        : "r"(a[0]), "r"(a[1]), "r"(a[2]), "r"(a[3]), "r"(b[0]), "r"(b[1]));
}
__device__ __forceinline__ void ldsm4(uint32_t& r0, uint32_t& r1, uint32_t& r2, uint32_t& r3,
                                      uint32_t addr) {
    asm volatile("ldmatrix.sync.aligned.m8n8.x4.shared.b16 {%0,%1,%2,%3}, [%4];"
        : "=r"(r0), "=r"(r1), "=r"(r2), "=r"(r3) : "r"(addr));
}
__device__ __forceinline__ uint32_t pack_h2(float x, float y) {
    __half2 p = __float22half2_rn(make_float2(x, y));
    return *(uint32_t*)&p;
}
// raw prefetch type per element type
template<typename T> struct RawVec;
template<> struct RawVec<float>  { using type = float4; };
template<> struct RawVec<__half> { using type = uint2;  };
__device__ __forceinline__ uint2 to_h2(const float4& v) {
    return make_uint2(pack_h2(v.x, v.y), pack_h2(v.z, v.w));
}
__device__ __forceinline__ uint2 to_h2(const uint2& v) { return v; }
__device__ __forceinline__ void st_out4(float* p, float4 v) { *(float4*)p = v; }
__device__ __forceinline__ void st_out4(__half* p, float4 v) {
    *(uint2*)p = make_uint2(pack_h2(v.x, v.y), pack_h2(v.z, v.w));
}
__device__ __forceinline__ void st_s(float* p, float v)  { *p = v; }
__device__ __forceinline__ void st_s(__half* p, float v) { *p = __float2half_rn(v); }

// =============== fp16 mma.sync GEMM, typed A/B/C =============================
#define RWH 40

template<int TM, int TN, typename TA, typename TB, typename TC>
__global__ __launch_bounds__(512, 1)
void mm2(const TA* __restrict__ A, const TB* __restrict__ B,
         const float* __restrict__ bias,
         const float* __restrict__ res1, const float* __restrict__ res2,
         TC* __restrict__ C,
         int K, int lda, int ldb, int ldc,
         long long sAb, long long sBb, long long sCb, int batchH,
         long long sAh, long long sBh, long long sCh,
         float alpha, int act)
{
    extern __shared__ char dsm[];
    constexpr int WTM = TM/4, WTN = TN/4;
    constexpr int MI = WTM/16, NI = WTN/8;
    constexpr int AHL = TM*RWH;
    constexpr int BHL = TN*RWH;
    constexpr int STAGE_BYTES = (AHL + BHL)*2;
    constexpr int PA = TM/64, PB = TN/64;

    const int tid  = threadIdx.x;
    const int lane = tid & 31;
    const int w    = tid >> 5;
    const int wm   = w >> 2;
    const int wn   = w & 3;

    const int bz = blockIdx.z;
    const int b  = bz / batchH;
    const int h  = bz - b*batchH;
    const int m0 = blockIdx.y * TM;
    const int n0 = blockIdx.x * TN;
    const TA* Ab = A + (long long)b*sAb + (long long)h*sAh + (long long)m0*lda;
    const TB* Bb = B + (long long)b*sBb + (long long)h*sBh + (long long)n0*ldb;
    const long long coff = (long long)b*sCb + (long long)h*sCh;

    const int lq = tid & 7;
    const int lr = tid >> 3;

    const uint32_t sb0 = smem_u32(dsm);
    const uint32_t a_l = (uint32_t)(((wm*WTM + (lane & 15))*RWH + ((lane >> 4) << 3)) * 2);
    const uint32_t b_l = (uint32_t)(AHL*2 + ((wn*WTN + (lane & 15))*RWH + ((lane >> 4) << 3)) * 2);

    float acc[MI][NI][4];
    #pragma unroll
    for (int mi = 0; mi < MI; mi++)
        #pragma unroll
        for (int ni = 0; ni < NI; ni++)
            #pragma unroll
            for (int j = 0; j < 4; j++) acc[mi][ni][j] = 0.f;

    const int NC = K >> 5;
    typename RawVec<TA>::type pA[PA];
    typename RawVec<TB>::type pB[PB];

    #pragma unroll
    for (int p = 0; p < PA; p++)
        pA[p] = *(const typename RawVec<TA>::type*)(Ab + (long long)(lr + 64*p)*lda + 4*lq);
    #pragma unroll
    for (int p = 0; p < PB; p++)
        pB[p] = *(const typename RawVec<TB>::type*)(Bb + (long long)(lr + 64*p)*ldb + 4*lq);

    for (int c = 0; c < NC; c++) {
        const int st = c & 1;
        char* sb = dsm + st * STAGE_BYTES;
        __half* Ah = (__half*)sb;
        __half* Bh = Ah + AHL;

        #pragma unroll
        for (int p = 0; p < PA; p++)
            *(uint2*)(Ah + (lr + 64*p)*RWH + 4*lq) = to_h2(pA[p]);
        #pragma unroll
        for (int p = 0; p < PB; p++)
            *(uint2*)(Bh + (lr + 64*p)*RWH + 4*lq) = to_h2(pB[p]);
        __syncthreads();

        if (c + 1 < NC) {
            const int k0 = (c + 1) << 5;
            #pragma unroll
            for (int p = 0; p < PA; p++)
                pA[p] = *(const typename RawVec<TA>::type*)(Ab + (long long)(lr + 64*p)*lda + k0 + 4*lq);
            #pragma unroll
            for (int p = 0; p < PB; p++)
                pB[p] = *(const typename RawVec<TB>::type*)(Bb + (long long)(lr + 64*p)*ldb + k0 + 4*lq);
        }

        const uint32_t stageu = sb0 + st * STAGE_BYTES;
        #pragma unroll
        for (int ks = 0; ks < 2; ks++) {
            const uint32_t kb = ks * 32;
            uint32_t ah[MI][4];
            #pragma unroll
            for (int mi = 0; mi < MI; mi++) {
                uint32_t ad = stageu + a_l + mi*(16*RWH*2) + kb;
                ldsm4(ah[mi][0], ah[mi][1], ah[mi][2], ah[mi][3], ad);
            }
            uint32_t bh[NI][2];
            #pragma unroll
            for (int nj = 0; nj < NI/2; nj++) {
                uint32_t bd = stageu + b_l + nj*(16*RWH*2) + kb;
                uint32_t q0, q1, q2, q3;
                ldsm4(q0, q1, q2, q3, bd);
                bh[2*nj][0] = q0; bh[2*nj][1] = q2;
                bh[2*nj+1][0] = q1; bh[2*nj+1][1] = q3;
            }
            #pragma unroll
            for (int mi = 0; mi < MI; mi++)
                #pragma unroll
                for (int ni = 0; ni < NI; ni++)
                    mma16816h(acc[mi][ni], ah[mi], bh[ni]);
        }
        __syncthreads();
    }

    // ---- epilogue ----
    constexpr int ROWW = TN + 4;
    float* sbuf = (float*)dsm;
    const int g = lane >> 2, t4 = lane & 3;
    #pragma unroll
    for (int mi = 0; mi < MI; mi++)
        #pragma unroll
        for (int ni = 0; ni < NI; ni++)
            #pragma unroll
            for (int j = 0; j < 4; j++) {
                int row = wm*WTM + mi*16 + g + 8*(j >> 1);
                int col = wn*WTN + ni*8 + 2*t4 + (j & 1);
                sbuf[row*ROWW + col] = acc[mi][ni][j];
            }
    __syncthreads();

    #pragma unroll
    for (int p = 0; p < TM*TN/2048; p++) {
        int i4 = tid + (p << 9);
        int elem = i4 << 2;
        int rr = elem / TN;
        int cc = elem - rr*TN;
        float4 v = *(float4*)(sbuf + rr*ROWW + cc);
        v.x *= alpha; v.y *= alpha; v.z *= alpha; v.w *= alpha;
        if (bias) {
            float4 bb = *(const float4*)(bias + n0 + cc);
            v.x += bb.x; v.y += bb.y; v.z += bb.z; v.w += bb.w;
        }
        long long off = coff + (long long)(m0 + rr)*ldc + (n0 + cc);
        if (res1) {
            float4 a = *(const float4*)(res1 + off);
            v.x += a.x; v.y += a.y; v.z += a.z; v.w += a.w;
        }
        if (res2) {
            float4 a = *(const float4*)(res2 + off);
            v.x += a.x; v.y += a.y; v.z += a.z; v.w += a.w;
        }
        if (act == 1) {
            v.x = 0.5f*v.x*(1.f + erff(v.x*0.70710678118654752f));
            v.y = 0.5f*v.y*(1.f + erff(v.y*0.70710678118654752f));
            v.z = 0.5f*v.z*(1.f + erff(v.z*0.70710678118654752f));
            v.w = 0.5f*v.w*(1.f + erff(v.w*0.70710678118654752f));
        }
        st_out4(C + off, v);
    }
}

// =============== fused QK^T + softmax kernel ================================
// grid (3, BATCH*HEADS); CTA computes 128 q-rows x 384 kv-cols, K=64, then
// row-softmax on fragments and writes P (f32) to the attn output region.
#define RW2 72
__global__ __launch_bounds__(512, 1)
void attn_score(const float* __restrict__ qkv, float* __restrict__ attn)
{
    extern __shared__ char dsm[];
    __half* Qs = (__half*)dsm;                 // 128*RW2
    __half* Ks = Qs + 128*RW2;                 // 384*RW2
    float*  red = (float*)(Ks + 384*RW2);      // 128*4

    const int tid = threadIdx.x;
    const int lane = tid & 31;
    const int w = tid >> 5;
    const int wm = w >> 2, wn = w & 3;
    const int g = lane >> 2, t4 = lane & 3;

    const int m0 = blockIdx.x * 128;
    const int bh = blockIdx.y;
    const int b  = bh / HEADS;
    const int hh = bh - b*HEADS;

    const float* qbase = qkv + (long long)b*NN*QKV3 + hh*HD;

    // load Q (128 x 64) and K (384 x 64) as fp16 into SMEM
    #pragma unroll
    for (int p = 0; p < 4; p++) {
        int u = tid + (p << 9);
        int r = u >> 4, q4 = u & 15;
        float4 v = *(const float4*)(qbase + (long long)(m0 + r)*QKV3 + 4*q4);
        *(uint2*)(Qs + r*RW2 + 4*q4) = to_h2(v);
    }
    #pragma unroll
    for (int p = 0; p < 12; p++) {
        int u = tid + (p << 9);
        int r = u >> 4, q4 = u & 15;
        float4 v = *(const float4*)(qbase + DIM + (long long)r*QKV3 + 4*q4);
        *(uint2*)(Ks + r*RW2 + 4*q4) = to_h2(v);
    }
    __syncthreads();

    const uint32_t sq = smem_u32(Qs);
    const uint32_t sk = smem_u32(Ks);
    const uint32_t a_l = sq + ((wm*32 + (lane & 15))*RW2 + ((lane >> 4) << 3)) * 2;
    const uint32_t b_l = sk + ((wn*96 + (lane & 15))*RW2 + ((lane >> 4) << 3)) * 2;

    float acc[2][12][4];
    #pragma unroll
    for (int mi = 0; mi < 2; mi++)
        #pragma unroll
        for (int ni = 0; ni < 12; ni++)
            #pragma unroll
            for (int j = 0; j < 4; j++) acc[mi][ni][j] = 0.f;

    #pragma unroll
    for (int ks = 0; ks < 4; ks++) {
        const uint32_t kb = ks * 32;
        uint32_t ah[2][4];
        #pragma unroll
        for (int mi = 0; mi < 2; mi++)
            ldsm4(ah[mi][0], ah[mi][1], ah[mi][2], ah[mi][3],
                  a_l + mi*(16*RW2*2) + kb);
        #pragma unroll
        for (int nj = 0; nj < 6; nj++) {
            uint32_t q0, q1, q2, q3;
            ldsm4(q0, q1, q2, q3, b_l + nj*(16*RW2*2) + kb);
            uint32_t b0[2] = {q0, q2}, b1[2] = {q1, q3};
            #pragma unroll
            for (int mi = 0; mi < 2; mi++) {
                mma16816h(acc[mi][2*nj],   ah[mi], b0);
                mma16816h(acc[mi][2*nj+1], ah[mi], b1);
            }
        }
    }

    // scale
    #pragma unroll
    for (int mi = 0; mi < 2; mi++)
        #pragma unroll
        for (int ni = 0; ni < 12; ni++)
            #pragma unroll
            for (int j = 0; j < 4; j++) acc[mi][ni][j] *= 0.125f;

    // row max (4 rows per thread: mi x h2)
    float M[2][2];
    #pragma unroll
    for (int mi = 0; mi < 2; mi++)
        #pragma unroll
        for (int h2 = 0; h2 < 2; h2++) {
            float m = -1e30f;
            #pragma unroll
            for (int ni = 0; ni < 12; ni++)
                m = fmaxf(m, fmaxf(acc[mi][ni][2*h2], acc[mi][ni][2*h2+1]));
            m = fmaxf(m, __shfl_xor_sync(0xFFFFFFFFu, m, 1));
            m = fmaxf(m, __shfl_xor_sync(0xFFFFFFFFu, m, 2));
            if (t4 == 0) red[(wm*32 + mi*16 + g + 8*h2)*4 + wn] = m;
        }
    __syncthreads();
    #pragma unroll
    for (int mi = 0; mi < 2; mi++)
        #pragma unroll
        for (int h2 = 0; h2 < 2; h2++) {
            int row = wm*32 + mi*16 + g + 8*h2;
            M[mi][h2] = fmaxf(fmaxf(red[row*4], red[row*4+1]),
                              fmaxf(red[row*4+2], red[row*4+3]));
        }
    __syncthreads();

    // exp + row sum
    float S[2][2];
    #pragma unroll
    for (int mi = 0; mi < 2; mi++)
        #pragma unroll
        for (int h2 = 0; h2 < 2; h2++) {
            float s = 0.f;
            #pragma unroll
            for (int ni = 0; ni < 12; ni++) {
                float e0 = __expf(acc[mi][ni][2*h2]   - M[mi][h2]);
                float e1 = __expf(acc[mi][ni][2*h2+1] - M[mi][h2]);
                acc[mi][ni][2*h2] = e0; acc[mi][ni][2*h2+1] = e1;
                s += e0 + e1;
            }
            s += __shfl_xor_sync(0xFFFFFFFFu, s, 1);
            s += __shfl_xor_sync(0xFFFFFFFFu, s, 2);
            if (t4 == 0) red[(wm*32 + mi*16 + g + 8*h2)*4 + wn] = s;
        }
    __syncthreads();
    #pragma unroll
    for (int mi = 0; mi < 2; mi++)
        #pragma unroll
        for (int h2 = 0; h2 < 2; h2++) {
            int row = wm*32 + mi*16 + g + 8*h2;
            S[mi][h2] = 1.f / (red[row*4] + red[row*4+1] + red[row*4+2] + red[row*4+3]);
        }

    // write P
    float* abase = attn + (long long)bh*NN*NN;
    #pragma unroll
    for (int mi = 0; mi < 2; mi++)
        #pragma unroll
        for (int h2 = 0; h2 < 2; h2++) {
            int row = m0 + wm*32 + mi*16 + g + 8*h2;
            float inv = S[mi][h2];
            float* rp = abase + (long long)row*NN + wn*96 + 2*t4;
            #pragma unroll
            for (int ni = 0; ni < 12; ni++) {
                float2 o;
                o.x = acc[mi][ni][2*h2]   * inv;
                o.y = acc[mi][ni][2*h2+1] * inv;
                *(float2*)(rp + ni*8) = o;
            }
        }
}

// ---------------- LayerNorm over 768 features -------------------------------
template<typename TO>
__global__ void ln_kernel(const float* __restrict__ in, TO* __restrict__ out,
                          const float* __restrict__ g, const float* __restrict__ b,
                          long long in_bstride, long long out_bstride)
{
    const float* x = in  + (long long)blockIdx.y*in_bstride  + (long long)blockIdx.x*DIM;
    TO*          y = out + (long long)blockIdx.y*out_bstride + (long long)blockIdx.x*DIM;
    int tid = threadIdx.x;
    float v0 = x[tid], v1 = x[tid+256], v2 = x[tid+512];
    __shared__ float sh[256];
    sh[tid] = v0 + v1 + v2;
    __syncthreads();
    for (int o = 128; o > 0; o >>= 1) { if (tid < o) sh[tid] += sh[tid+o]; __syncthreads(); }
    float mean = sh[0] * (1.f/768.f);
    __syncthreads();
    float d0 = v0-mean, d1 = v1-mean, d2 = v2-mean;
    sh[tid] = d0*d0 + d1*d1 + d2*d2;
    __syncthreads();
    for (int o = 128; o > 0; o >>= 1) { if (tid < o) sh[tid] += sh[tid+o]; __syncthreads(); }
    float inv = rsqrtf(sh[0] * (1.f/768.f) + 1e-5f);
    st_s(y + tid,     d0*inv*g[tid]     + b[tid]);
    st_s(y + tid+256, d1*inv*g[tid+256] + b[tid+256]);
    st_s(y + tid+512, d2*inv*g[tid+512] + b[tid+512]);
}

__global__ void ln_cat_kernel(const float* __restrict__ zf, const float* __restrict__ x,
                              __half* __restrict__ out,
                              const float* __restrict__ g, const float* __restrict__ b)
{
    int t = blockIdx.x, bb = blockIdx.y;
    const float* src = (t < ZL) ? zf + ((long long)bb*ZL + t)*DIM
                                : x  + ((long long)bb*TT + (t - ZL))*DIM;
    __half* y = out + ((long long)bb*NN + t)*DIM;
    int tid = threadIdx.x;
    float v0 = src[tid], v1 = src[tid+256], v2 = src[tid+512];
    __shared__ float sh[256];
    sh[tid] = v0 + v1 + v2;
    __syncthreads();
    for (int o = 128; o > 0; o >>= 1) { if (tid < o) sh[tid] += sh[tid+o]; __syncthreads(); }
    float mean = sh[0] * (1.f/768.f);
    __syncthreads();
    float d0 = v0-mean, d1 = v1-mean, d2 = v2-mean;
    sh[tid] = d0*d0 + d1*d1 + d2*d2;
    __syncthreads();
    for (int o = 128; o > 0; o >>= 1) { if (tid < o) sh[tid] += sh[tid+o]; __syncthreads(); }
    float inv = rsqrtf(sh[0] * (1.f/768.f) + 1e-5f);
    y[tid]     = __float2half_rn(d0*inv*g[tid]     + b[tid]);
    y[tid+256] = __float2half_rn(d1*inv*g[tid+256] + b[tid+256]);
    y[tid+512] = __float2half_rn(d2*inv*g[tid+512] + b[tid+512]);
}

// ---------------- fusion: entropies over ZL axis ----------------------------
__global__ void fusion_kernel(const float* __restrict__ ax, const float* __restrict__ axi,
                              float* __restrict__ alpha_o, float* __restrict__ um_o,
                              float* __restrict__ u_o, float* __restrict__ ui_o)
{
    int b = blockIdx.x, s = threadIdx.x;
    const float* X  = ax  + (long long)b*ZL*SL + s;
    const float* Xi = axi + (long long)b*ZL*SL + s;
    float u, ui;
    {
        float mx = -1e30f;
        for (int t = 0; t < ZL; t++) mx = fmaxf(mx, X[t*SL]);
        float sum = 0.f;
        for (int t = 0; t < ZL; t++) sum += expf(X[t*SL] - mx);
        float inv = 1.f/sum, acc = 0.f;
        for (int t = 0; t < ZL; t++) { float p = expf(X[t*SL]-mx)*inv; acc -= p*logf(p + 1e-8f); }
        u = acc;
    }
    {
        float mx = -1e30f;
        for (int t = 0; t < ZL; t++) mx = fmaxf(mx, Xi[t*SL]);
        float sum = 0.f;
        for (int t = 0; t < ZL; t++) sum += expf(Xi[t*SL] - mx);
        float inv = 1.f/sum, acc = 0.f;
        for (int t = 0; t < ZL; t++) { float p = expf(Xi[t*SL]-mx)*inv; acc -= p*logf(p + 1e-8f); }
        ui = acc;
    }
    int idx = b*SL + s;
    float alpha = 1.f / (1.f + expf(-(ui - u)));
    alpha_o[idx] = alpha;
    um_o[idx] = 0.5f*(u + ui);
    u_o[idx] = u;
    ui_o[idx] = ui;
}

// ---------------- elementwise helpers ----------------------------------------
__global__ void cat_feat_k(const float* __restrict__ x, const float* __restrict__ xi,
                           __half* __restrict__ o)
{
    long long i = (long long)blockIdx.x*blockDim.x + threadIdx.x;
    const long long n = (long long)BATCH*ZL*2*DIM;
    if (i >= n) return;
    int c = (int)(i % (2*DIM));
    long long bt = i / (2*DIM);
    long long b = bt / ZL, t = bt % ZL;
    long long src = (b*TT + t)*DIM;
    float v = (c < DIM) ? x[src + c] : xi[src + c - DIM];
    o[i] = __float2half_rn(v);
}

__global__ void vtrans_k(const float* __restrict__ qkv, __half* __restrict__ vt)
{
    __shared__ float t[32][33];
    int bh = blockIdx.z;
    long long b = bh / HEADS, h = bh % HEADS;
    const float* src = qkv + b*NN*QKV3 + 2*DIM + h*HD;
    int tt0 = blockIdx.x*32;
    int cc0 = blockIdx.y*32;
    int tx = threadIdx.x, ty = threadIdx.y;
    #pragma unroll
    for (int i = 0; i < 32; i += 8)
        t[ty+i][tx] = src[(long long)(tt0+ty+i)*QKV3 + cc0 + tx];
    __syncthreads();
    __half* dst = vt + ((long long)bh*HD)*NN;
    #pragma unroll
    for (int i = 0; i < 32; i += 8)
        dst[(long long)(cc0+ty+i)*NN + tt0 + tx] = __float2half_rn(t[tx][ty+i]);
}

__global__ void make_v_k(const float* __restrict__ ns, const float* __restrict__ nsi,
                         const float* __restrict__ alpha, float* __restrict__ v)
{
    long long i = (long long)blockIdx.x*blockDim.x + threadIdx.x;
    const long long n = (long long)BATCH*SL*DIM;
    if (i >= n) return;
    long long bs = i / DIM;
    float a = alpha[bs];
    v[i] = a*ns[i] + (1.f - a)*nsi[i];
}

__global__ void make_vfc_k(const float* __restrict__ xiattn, const float* __restrict__ vf,
                           float* __restrict__ o)
{
    long long i = (long long)blockIdx.x*blockDim.x + threadIdx.x;
    const long long n = (long long)BATCH*TT*DIM;
    if (i >= n) return;
    int c = (int)(i % DIM);
    long long bt = i / DIM;
    long long b = bt / TT, t = bt % TT;
    o[i] = (t < ZL) ? xiattn[(b*NN + t)*DIM + c]
                    : vf[(b*SL + (t-ZL))*DIM + c];
}

__global__ void make_xnew_k(const float* __restrict__ x, const float* __restrict__ xi,
                            const float* __restrict__ xattn, const float* __restrict__ xiattn,
                            const float* __restrict__ vfc,
                            float* __restrict__ xo, float* __restrict__ xio)
{
    long long i = (long long)blockIdx.x*blockDim.x + threadIdx.x;
    const long long n = (long long)BATCH*TT*DIM;
    if (i >= n) return;
    int c = (int)(i % DIM);
    long long bt = i / DIM;
    long long b = bt / TT, t = bt % TT;
    long long aidx = (b*NN + ZL + t)*DIM + c;
    float vf = vfc[i];
    xo[i]  = x[i]  + xattn[aidx]  + vf;
    xio[i] = xi[i] + xiattn[aidx] + vf;
}

__global__ void i2f_k(const int* __restrict__ in, float* __restrict__ out, int n)
{
    int i = blockIdx.x*blockDim.x + threadIdx.x;
    if (i < n) out[i] = (float)in[i];
}

__global__ void f2h_k(const float* __restrict__ in, __half* __restrict__ out, int n)
{
    int i = blockIdx.x*blockDim.x + threadIdx.x;
    if (i < n) out[i] = __float2half_rn(in[i]);
}

// ---------------- host-side helpers ----------------
template<int TM, int TN, typename TA, typename TB, typename TC>
static inline void mm(const TA* A, const TB* B, const float* bias,
                      const float* r1, const float* r2, TC* C,
                      int M, int N, int K, int lda, int ldb, int ldc,
                      long long sAb, long long sBb, long long sCb,
                      int nb, int nh,
                      long long sAh, long long sBh, long long sCh,
                      float alpha, int act)
{
    constexpr int STAGE_BYTES = (TM*RWH + TN*RWH)*2;
    constexpr int EPI = TM*(TN+4)*4;
    constexpr int DS = (2*STAGE_BYTES > EPI) ? 2*STAGE_BYTES : EPI;
    static bool init = false;
    if (!init) {
        cudaFuncSetAttribute(mm2<TM,TN,TA,TB,TC>, cudaFuncAttributeMaxDynamicSharedMemorySize, DS);
        init = true;
    }
    dim3 g(N/TN, M/TM, nb*nh);
    mm2<TM,TN,TA,TB,TC><<<g, 512, DS>>>(A,B,bias,r1,r2,C,K,lda,ldb,ldc,sAb,sBb,sCb,nh,sAh,sBh,sCh,alpha,act);
}

static inline int cdiv(long long a, int b) { return (int)((a + b - 1) / b); }

extern "C" void kernel_launch(void* const* d_in, const int* in_sizes, int n_in,
                              void* d_out, int out_size)
{
    const float* x      = (const float*)d_in[0];
    const float* xi     = (const float*)d_in[1];
    const int*   git    = (const int*)  d_in[2];
    const int*   giti   = (const int*)  d_in[3];
    const int*   gis    = (const int*)  d_in[4];
    const int*   gisi   = (const int*)  d_in[5];
    const float* w_qkv  = (const float*)d_in[6];
    const float* b_qkv  = (const float*)d_in[7];
    const float* w_proj = (const float*)d_in[8];
    const float* b_proj = (const float*)d_in[9];
    const float* g1     = (const float*)d_in[10];
    const float* bt1    = (const float*)d_in[11];
    const float* g2     = (const float*)d_in[12];
    const float* bt2    = (const float*)d_in[13];
    const float* w_fc1  = (const float*)d_in[14];
    const float* b_fc1  = (const float*)d_in[15];
    const float* w_fc2  = (const float*)d_in[16];
    const float* b_fc2  = (const float*)d_in[17];
    const float* w_al   = (const float*)d_in[18];
    const float* b_al   = (const float*)d_in[19];
    const float* w_al2  = (const float*)d_in[20];
    const float* b_al2  = (const float*)d_in[21];
    const float* w_fus  = (const float*)d_in[22];
    const float* b_fus  = (const float*)d_in[23];
    float* out = (float*)d_out;

    float *p_zf, *p_ns, *p_nsi, *p_attnx, *p_attnxi, *p_qkv,
          *p_xattn, *p_xiattn, *p_v, *p_vf, *p_vfc, *p_xnew, *p_xinew, *p_adap2;
    __half *p_cath, *p_lnh, *p_vth, *p_aoh, *p_hh;
    __half *wqkvh, *wprojh, *wfc1h, *wfc2h, *walh, *wal2h, *wfush;
    cudaGetSymbolAddress((void**)&p_cath,  g_cath);
    cudaGetSymbolAddress((void**)&p_zf,    g_zf);
    cudaGetSymbolAddress((void**)&p_ns,    g_ns);
    cudaGetSymbolAddress((void**)&p_nsi,   g_nsi);
    cudaGetSymbolAddress((void**)&p_attnx, g_attnx);
    cudaGetSymbolAddress((void**)&p_attnxi,g_attnxi);
    cudaGetSymbolAddress((void**)&p_lnh,   g_lnh);
    cudaGetSymbolAddress((void**)&p_qkv,   g_qkv);
    cudaGetSymbolAddress((void**)&p_vth,   g_vth);
    cudaGetSymbolAddress((void**)&p_aoh,   g_aoh);
    cudaGetSymbolAddress((void**)&p_xattn, g_xattn);
    cudaGetSymbolAddress((void**)&p_xiattn,g_xiattn);
    cudaGetSymbolAddress((void**)&p_v,     g_v);
    cudaGetSymbolAddress((void**)&p_vf,    g_vf);
    cudaGetSymbolAddress((void**)&p_vfc,   g_vfc);
    cudaGetSymbolAddress((void**)&p_xnew,  g_xnew);
    cudaGetSymbolAddress((void**)&p_xinew, g_xinew);
    cudaGetSymbolAddress((void**)&p_adap2, g_adap2);
    cudaGetSymbolAddress((void**)&p_hh,    g_hh);
    cudaGetSymbolAddress((void**)&wqkvh,   g_wqkvh);
    cudaGetSymbolAddress((void**)&wprojh,  g_wprojh);
    cudaGetSymbolAddress((void**)&wfc1h,   g_wfc1h);
    cudaGetSymbolAddress((void**)&wfc2h,   g_wfc2h);
    cudaGetSymbolAddress((void**)&walh,    g_walh);
    cudaGetSymbolAddress((void**)&wal2h,   g_wal2h);
    cudaGetSymbolAddress((void**)&wfush,   g_wfush);

    const float scale_dim = 1.f / sqrtf((float)DIM);

    // ---- weight conversions (fp32 -> fp16, once per launch) ----
    f2h_k<<<cdiv(QKV3*DIM,256),256>>>(w_qkv,  wqkvh,  QKV3*DIM);
    f2h_k<<<cdiv(DIM*DIM,256),256>>>(w_proj, wprojh, DIM*DIM);
    f2h_k<<<cdiv(HID*DIM,256),256>>>(w_fc1,  wfc1h,  HID*DIM);
    f2h_k<<<cdiv(DIM*HID,256),256>>>(w_fc2,  wfc2h,  DIM*HID);
    f2h_k<<<cdiv(DIM*2*DIM,256),256>>>(w_al, walh,   DIM*2*DIM);
    f2h_k<<<cdiv(DIM*DIM,256),256>>>(w_al2,  wal2h,  DIM*DIM);
    f2h_k<<<cdiv(DIM*DIM,256),256>>>(w_fus,  wfush,  DIM*DIM);

    // ---- z_f = concat(z,zi) @ w_al^T + b_al ----
    cat_feat_k<<<cdiv((long long)BATCH*ZL*2*DIM, 256), 256>>>(x, xi, p_cath);
    mm<128,128,__half,__half,float>(p_cath, walh, b_al, nullptr, nullptr, p_zf,
        BATCH*ZL, DIM, 2*DIM, 2*DIM, 2*DIM, DIM, 0,0,0, 1,1, 0,0,0, 1.f, 0);

    // ---- ns/nsi (f32: feed fusion + attn_x) ----
    ln_kernel<float><<<dim3(SL, BATCH), 256>>>(x  + (long long)ZL*DIM, p_ns,  g1, bt1,
                                               (long long)TT*DIM, (long long)SL*DIM);
    ln_kernel<float><<<dim3(SL, BATCH), 256>>>(xi + (long long)ZL*DIM, p_nsi, g1, bt1,
                                               (long long)TT*DIM, (long long)SL*DIM);

    // ---- MHA both streams ----
    {
        static bool ainit = false;
        if (!ainit) {
            cudaFuncSetAttribute(attn_score, cudaFuncAttributeMaxDynamicSharedMemorySize,
                                 128*RW2*2 + 384*RW2*2 + 128*4*4);
            ainit = true;
        }
    }
    const float* src[2]    = {x, xi};
    float*       attn_o[2] = {out + O_ATTN, out + O_IATTN};
    float*       proj_o[2] = {p_xattn, p_xiattn};
    for (int side = 0; side < 2; side++) {
        ln_cat_kernel<<<dim3(NN, BATCH), 256>>>(p_zf, src[side], p_lnh, g1, bt1);
        mm<128,128,__half,__half,float>(p_lnh, wqkvh, b_qkv, nullptr, nullptr, p_qkv,
            BATCH*NN, QKV3, DIM, DIM, DIM, QKV3, 0,0,0, 1,1, 0,0,0, 1.f, 0);
        vtrans_k<<<dim3(NN/32, HD/32, BATCH*HEADS), dim3(32,8)>>>(p_qkv, p_vth);
        // fused QK^T + softmax -> P directly into d_out
        attn_score<<<dim3(3, BATCH*HEADS), 512, 128*RW2*2 + 384*RW2*2 + 128*4*4>>>(
            p_qkv, attn_o[side]);
        // out = P @ V
        mm<128,64,float,__half,__half>(attn_o[side], p_vth, nullptr, nullptr, nullptr, p_aoh,
            NN, HD, NN, NN, NN, DIM,
            (long long)HEADS*NN*NN, (long long)HEADS*HD*NN, (long long)NN*DIM,
            BATCH, HEADS, (long long)NN*NN, (long long)HD*NN, HD, 1.f, 0);
        mm<128,128,__half,__half,float>(p_aoh, wprojh, b_proj, nullptr, nullptr, proj_o[side],
            BATCH*NN, DIM, DIM, DIM, DIM, DIM, 0,0,0, 1,1, 0,0,0, 1.f, 0);
    }

    // ---- attn_x / attn_xi ----
    mm<64,128,float,float,float>(p_zf, p_ns, nullptr, nullptr, nullptr, p_attnx,
        ZL, SL, DIM, DIM, DIM, SL,
        (long long)ZL*DIM, (long long)SL*DIM, (long long)ZL*SL,
        BATCH, 1, 0,0,0, scale_dim, 0);
    mm<64,128,float,float,float>(p_zf, p_nsi, nullptr, nullptr, nullptr, p_attnxi,
        ZL, SL, DIM, DIM, DIM, SL,
        (long long)ZL*DIM, (long long)SL*DIM, (long long)ZL*SL,
        BATCH, 1, 0,0,0, scale_dim, 0);

    // ---- fusion ----
    fusion_kernel<<<BATCH, SL>>>(p_attnx, p_attnxi,
                                 out + O_ALPHA, out + O_UM, out + O_U, out + O_UI);
    make_v_k<<<cdiv((long long)BATCH*SL*DIM, 256), 256>>>(p_ns, p_nsi, out + O_ALPHA, p_v);
    mm<128,128,float,__half,float>(p_v, wfush, b_fus, nullptr, nullptr, p_vf,
        BATCH*SL, DIM, DIM, DIM, DIM, DIM, 0,0,0, 1,1, 0,0,0, 1.f, 0);
    make_vfc_k<<<cdiv((long long)BATCH*TT*DIM, 256), 256>>>(p_xiattn, p_vf, p_vfc);

    // ---- residual adds ----
    make_xnew_k<<<cdiv((long long)BATCH*TT*DIM, 256), 256>>>(
        x, xi, p_xattn, p_xiattn, p_vfc, p_xnew, p_xinew);

    // ---- adap2 ----
    ln_kernel<__half><<<dim3(TT, BATCH), 256>>>(p_vfc, p_lnh, g2, bt2,
                                                (long long)TT*DIM, (long long)TT*DIM);
    mm<128,128,__half,__half,float>(p_lnh, wal2h, b_al2, nullptr, nullptr, p_adap2,
        BATCH*TT, DIM, DIM, DIM, DIM, DIM, 0,0,0, 1,1, 0,0,0, 1.f, 0);

    // ---- MLP both streams ----
    float* xn[2] = {p_xnew, p_xinew};
    float* xo[2] = {out + O_XOUT, out + O_XIOUT};
    for (int side = 0; side < 2; side++) {
        ln_kernel<__half><<<dim3(TT, BATCH), 256>>>(xn[side], p_lnh, g2, bt2,
                                                    (long long)TT*DIM, (long long)TT*DIM);
        mm<128,128,__half,__half,__half>(p_lnh, wfc1h, b_fc1, nullptr, nullptr, p_hh,
            BATCH*TT, HID, DIM, DIM, DIM, HID, 0,0,0, 1,1, 0,0,0, 1.f, 1);
        mm<128,128,__half,__half,float>(p_hh, wfc2h, b_fc2, xn[side], p_adap2, xo[side],
            BATCH*TT, DIM, HID, HID, HID, DIM, 0,0,0, 1,1, 0,0,0, 1.f, 0);
    }

    // ---- index passthroughs ----
    i2f_k<<<cdiv(BATCH*ZL, 256), 256>>>(git,  out + O_GIT,  BATCH*ZL);
    i2f_k<<<cdiv(BATCH*SL, 256), 256>>>(gis,  out + O_GIS,  BATCH*SL);
    i2f_k<<<cdiv(BATCH*ZL, 256), 256>>>(giti, out + O_GITI, BATCH*ZL);
    i2f_k<<<cdiv(BATCH*SL, 256), 256>>>(gisi, out + O_GISI, BATCH*SL);
}

// round 7
// speedup vs baseline: 4.5161x; 1.0461x over previous
#include <cuda_runtime.h>
#include <cuda_fp16.h>
#include <math.h>
#include <cstdint>

// ---------------- problem constants ----------------
#define BATCH 32
#define ZL 64
#define SL 256
#define TT 320
#define NN 384
#define DIM 768
#define HEADS 12
#define HD 64
#define HID 3072
#define QKV3 2304

#define O_XOUT   0LL
#define O_GIT    7864320LL
#define O_GIS    7866368LL
#define O_ATTN   7874560LL
#define O_XIOUT  64497664LL
#define O_GITI   72361984LL
#define O_GISI   72364032LL
#define O_IATTN  72372224LL
#define O_ALPHA  128995328LL
#define O_UM     129003520LL
#define O_U      129011712LL
#define O_UI     129019904LL

// ---------------- scratch ----------------
__device__ __half g_cath [BATCH*ZL*2*DIM];
__device__ float  g_zf   [BATCH*ZL*DIM];
__device__ float  g_ns   [BATCH*SL*DIM];
__device__ float  g_nsi  [BATCH*SL*DIM];
__device__ float  g_attnx [BATCH*ZL*SL];
__device__ float  g_attnxi[BATCH*ZL*SL];
__device__ __half g_lnh  [BATCH*NN*DIM];
__device__ float  g_qkv  [BATCH*NN*QKV3];
__device__ __half g_vth  [BATCH*HEADS*HD*NN];
__device__ __half g_aoh  [BATCH*NN*DIM];
__device__ float  g_xattn [BATCH*NN*DIM];
__device__ float  g_xiattn[BATCH*NN*DIM];
__device__ float  g_v    [BATCH*SL*DIM];
__device__ float  g_vf   [BATCH*SL*DIM];
__device__ float  g_vfc  [BATCH*TT*DIM];
__device__ float  g_xnew [BATCH*TT*DIM];
__device__ float  g_xinew[BATCH*TT*DIM];
__device__ float  g_adap2[BATCH*TT*DIM];
__device__ __half g_hh   [BATCH*TT*HID];
// fp16 weight copies
__device__ __half g_wqkvh[QKV3*DIM];
__device__ __half g_wprojh[DIM*DIM];
__device__ __half g_wfc1h[HID*DIM];
__device__ __half g_wfc2h[DIM*HID];
__device__ __half g_walh [DIM*2*DIM];
__device__ __half g_wal2h[DIM*DIM];
__device__ __half g_wfush[DIM*DIM];

// =============== helpers =====================================================
__device__ __forceinline__ uint32_t smem_u32(const void* p) {
    uint32_t a;
    asm("{ .reg .u64 t; cvta.to.shared.u64 t, %1; cvt.u32.u64 %0, t; }" : "=r"(a) : "l"(p));
    return a;
}
__device__ __forceinline__ void mma16816h(float* d, const uint32_t* a, const uint32_t* b) {
    asm volatile("mma.sync.aligned.m16n8k16.row.col.f32.f16.f16.f32 "
        "{%0,%1,%2,%3}, {%4,%5,%6,%7}, {%8,%9}, {%0,%1,%2,%3};"
        : "+f"(d[0]), "+f"(d[1]), "+f"(d[2]), "+f"(d[3])
        : "r"(a[0]), "r"(a[1]), "r"(a[2]), "r"(a[3]), "r"(b[0]), "r"(b[1]));
}
__device__ __forceinline__ void ldsm4(uint32_t& r0, uint32_t& r1, uint32_t& r2, uint32_t& r3,
                                      uint32_t addr) {
    asm volatile("ldmatrix.sync.aligned.m8n8.x4.shared.b16 {%0,%1,%2,%3}, [%4];"
        : "=r"(r0), "=r"(r1), "=r"(r2), "=r"(r3) : "r"(addr));
}
__device__ __forceinline__ uint32_t pack_h2(float x, float y) {
    __half2 p = __float22half2_rn(make_float2(x, y));
    return *(uint32_t*)&p;
}
template<typename T> struct RawVec;
template<> struct RawVec<float>  { using type = float4; };
template<> struct RawVec<__half> { using type = uint2;  };
__device__ __forceinline__ uint2 to_h2(const float4& v) {
    return make_uint2(pack_h2(v.x, v.y), pack_h2(v.z, v.w));
}
__device__ __forceinline__ uint2 to_h2(const uint2& v) { return v; }
__device__ __forceinline__ void st_out4(float* p, float4 v) { *(float4*)p = v; }
__device__ __forceinline__ void st_out4(__half* p, float4 v) {
    *(uint2*)p = make_uint2(pack_h2(v.x, v.y), pack_h2(v.z, v.w));
}
__device__ __forceinline__ void st_s(float* p, float v)  { *p = v; }
__device__ __forceinline__ void st_s(__half* p, float v) { *p = __float2half_rn(v); }

// =============== fp16 mma.sync GEMM, typed A/B/C, occ-2 ======================
#define RWH 40

template<int TM, int TN, typename TA, typename TB, typename TC>
__global__ __launch_bounds__(512, 2)
void mm2(const TA* __restrict__ A, const TB* __restrict__ B,
         const float* __restrict__ bias,
         const float* __restrict__ res1, const float* __restrict__ res2,
         TC* __restrict__ C,
         int K, int lda, int ldb, int ldc,
         long long sAb, long long sBb, long long sCb, int batchH,
         long long sAh, long long sBh, long long sCh,
         float alpha, int act)
{
    extern __shared__ char dsm[];
    constexpr int WTM = TM/4, WTN = TN/4;
    constexpr int MI = WTM/16, NI = WTN/8;
    constexpr int AHL = TM*RWH;
    constexpr int BHL = TN*RWH;
    constexpr int STAGE_BYTES = (AHL + BHL)*2;
    constexpr int PA = TM/64, PB = TN/64;

    const int tid  = threadIdx.x;
    const int lane = tid & 31;
    const int w    = tid >> 5;
    const int wm   = w >> 2;
    const int wn   = w & 3;

    const int bz = blockIdx.z;
    const int b  = bz / batchH;
    const int h  = bz - b*batchH;
    const int m0 = blockIdx.y * TM;
    const int n0 = blockIdx.x * TN;
    const TA* Ab = A + (long long)b*sAb + (long long)h*sAh + (long long)m0*lda;
    const TB* Bb = B + (long long)b*sBb + (long long)h*sBh + (long long)n0*ldb;
    const long long coff = (long long)b*sCb + (long long)h*sCh;

    const int lq = tid & 7;
    const int lr = tid >> 3;

    const uint32_t sb0 = smem_u32(dsm);
    const uint32_t a_l = (uint32_t)(((wm*WTM + (lane & 15))*RWH + ((lane >> 4) << 3)) * 2);
    const uint32_t b_l = (uint32_t)(AHL*2 + ((wn*WTN + (lane & 15))*RWH + ((lane >> 4) << 3)) * 2);

    float acc[MI][NI][4];
    #pragma unroll
    for (int mi = 0; mi < MI; mi++)
        #pragma unroll
        for (int ni = 0; ni < NI; ni++)
            #pragma unroll
            for (int j = 0; j < 4; j++) acc[mi][ni][j] = 0.f;

    const int NC = K >> 5;
    typename RawVec<TA>::type pA[PA];
    typename RawVec<TB>::type pB[PB];

    #pragma unroll
    for (int p = 0; p < PA; p++)
        pA[p] = *(const typename RawVec<TA>::type*)(Ab + (long long)(lr + 64*p)*lda + 4*lq);
    #pragma unroll
    for (int p = 0; p < PB; p++)
        pB[p] = *(const typename RawVec<TB>::type*)(Bb + (long long)(lr + 64*p)*ldb + 4*lq);

    for (int c = 0; c < NC; c++) {
        const int st = c & 1;
        char* sb = dsm + st * STAGE_BYTES;
        __half* Ah = (__half*)sb;
        __half* Bh = Ah + AHL;

        #pragma unroll
        for (int p = 0; p < PA; p++)
            *(uint2*)(Ah + (lr + 64*p)*RWH + 4*lq) = to_h2(pA[p]);
        #pragma unroll
        for (int p = 0; p < PB; p++)
            *(uint2*)(Bh + (lr + 64*p)*RWH + 4*lq) = to_h2(pB[p]);
        __syncthreads();

        if (c + 1 < NC) {
            const int k0 = (c + 1) << 5;
            #pragma unroll
            for (int p = 0; p < PA; p++)
                pA[p] = *(const typename RawVec<TA>::type*)(Ab + (long long)(lr + 64*p)*lda + k0 + 4*lq);
            #pragma unroll
            for (int p = 0; p < PB; p++)
                pB[p] = *(const typename RawVec<TB>::type*)(Bb + (long long)(lr + 64*p)*ldb + k0 + 4*lq);
        }

        const uint32_t stageu = sb0 + st * STAGE_BYTES;
        #pragma unroll
        for (int ks = 0; ks < 2; ks++) {
            const uint32_t kb = ks * 32;
            uint32_t ah[MI][4];
            #pragma unroll
            for (int mi = 0; mi < MI; mi++) {
                uint32_t ad = stageu + a_l + mi*(16*RWH*2) + kb;
                ldsm4(ah[mi][0], ah[mi][1], ah[mi][2], ah[mi][3], ad);
            }
            uint32_t bh[NI][2];
            #pragma unroll
            for (int nj = 0; nj < NI/2; nj++) {
                uint32_t bd = stageu + b_l + nj*(16*RWH*2) + kb;
                uint32_t q0, q1, q2, q3;
                ldsm4(q0, q1, q2, q3, bd);
                bh[2*nj][0] = q0; bh[2*nj][1] = q2;
                bh[2*nj+1][0] = q1; bh[2*nj+1][1] = q3;
            }
            #pragma unroll
            for (int mi = 0; mi < MI; mi++)
                #pragma unroll
                for (int ni = 0; ni < NI; ni++)
                    mma16816h(acc[mi][ni], ah[mi], bh[ni]);
        }
        __syncthreads();
    }

    // ---- epilogue: 32-row passes through SMEM (keeps smem at 2*STAGE) ----
    constexpr int ROWW = TN + 4;
    constexpr int NPASS = TM / 32;
    float* sbuf = (float*)dsm;
    const int g = lane >> 2, t4 = lane & 3;
    const int my_pass = (wm*WTM) >> 5;
    const int my_lb   = (wm*WTM) & 31;

    #pragma unroll
    for (int pass = 0; pass < NPASS; pass++) {
        if (my_pass == pass) {
            #pragma unroll
            for (int mi = 0; mi < MI; mi++)
                #pragma unroll
                for (int ni = 0; ni < NI; ni++)
                    #pragma unroll
                    for (int j = 0; j < 4; j++) {
                        int row = my_lb + mi*16 + g + 8*(j >> 1);
                        int col = wn*WTN + ni*8 + 2*t4 + (j & 1);
                        sbuf[row*ROWW + col] = acc[mi][ni][j];
                    }
        }
        __syncthreads();
        #pragma unroll
        for (int p = 0; p < 32*TN/2048; p++) {
            int i4 = tid + (p << 9);
            int elem = i4 << 2;
            int rr = elem / TN;
            int cc = elem - rr*TN;
            float4 v = *(float4*)(sbuf + rr*ROWW + cc);
            v.x *= alpha; v.y *= alpha; v.z *= alpha; v.w *= alpha;
            if (bias) {
                float4 bb = *(const float4*)(bias + n0 + cc);
                v.x += bb.x; v.y += bb.y; v.z += bb.z; v.w += bb.w;
            }
            long long off = coff + (long long)(m0 + pass*32 + rr)*ldc + (n0 + cc);
            if (res1) {
                float4 a = *(const float4*)(res1 + off);
                v.x += a.x; v.y += a.y; v.z += a.z; v.w += a.w;
            }
            if (res2) {
                float4 a = *(const float4*)(res2 + off);
                v.x += a.x; v.y += a.y; v.z += a.z; v.w += a.w;
            }
            if (act == 1) {
                v.x = 0.5f*v.x*(1.f + erff(v.x*0.70710678118654752f));
                v.y = 0.5f*v.y*(1.f + erff(v.y*0.70710678118654752f));
                v.z = 0.5f*v.z*(1.f + erff(v.z*0.70710678118654752f));
                v.w = 0.5f*v.w*(1.f + erff(v.w*0.70710678118654752f));
            }
            st_out4(C + off, v);
        }
        __syncthreads();
    }
}

// =============== fused QK^T + softmax + P@V =================================
// grid (3, BATCH*HEADS), 512 threads. Phase A: scores + softmax, write P (f32).
// Phase B: bounce e (fp16) through SMEM, MMA with V^T (fp16), write ao (fp16).
#define RW2 72
#define RW3 392
#define PV_SMEM (128*RW3*2 + 64*RW3*2 + 128*4*4 + 128*4)

__global__ __launch_bounds__(512, 1)
void attn_fused(const float* __restrict__ qkv, const __half* __restrict__ vt,
                float* __restrict__ attn, __half* __restrict__ ao)
{
    extern __shared__ char dsm[];
    __half* Ph  = (__half*)dsm;                           // 128 x RW3 (phase B)
    __half* Vs  = (__half*)(dsm + 128*RW3*2);             // 64 x RW3
    float*  red = (float*)(dsm + 128*RW3*2 + 64*RW3*2);   // 128 x 4
    float*  invb= red + 128*4;                            // 128
    __half* Qs  = (__half*)dsm;                           // phase A alias
    __half* Ks  = Qs + 128*RW2;

    const int tid = threadIdx.x;
    const int lane = tid & 31;
    const int w = tid >> 5;
    const int wm = w >> 2, wn = w & 3;
    const int g = lane >> 2, t4 = lane & 3;

    const int m0 = blockIdx.x * 128;
    const int bh = blockIdx.y;
    const int b  = bh / HEADS;
    const int hh = bh - b*HEADS;

    const float* qbase = qkv + (long long)b*NN*QKV3 + hh*HD;

    // ---- phase A: load Q (128x64), K (384x64) fp16 ----
    #pragma unroll
    for (int p = 0; p < 4; p++) {
        int u = tid + (p << 9);
        int r = u >> 4, q4 = u & 15;
        float4 v = *(const float4*)(qbase + (long long)(m0 + r)*QKV3 + 4*q4);
        *(uint2*)(Qs + r*RW2 + 4*q4) = to_h2(v);
    }
    #pragma unroll
    for (int p = 0; p < 12; p++) {
        int u = tid + (p << 9);
        int r = u >> 4, q4 = u & 15;
        float4 v = *(const float4*)(qbase + DIM + (long long)r*QKV3 + 4*q4);
        *(uint2*)(Ks + r*RW2 + 4*q4) = to_h2(v);
    }
    __syncthreads();

    const uint32_t sq = smem_u32(Qs);
    const uint32_t sk = smem_u32(Ks);
    const uint32_t a_l = sq + ((wm*32 + (lane & 15))*RW2 + ((lane >> 4) << 3)) * 2;
    const uint32_t b_l = sk + ((wn*96 + (lane & 15))*RW2 + ((lane >> 4) << 3)) * 2;

    float acc[2][12][4];
    #pragma unroll
    for (int mi = 0; mi < 2; mi++)
        #pragma unroll
        for (int ni = 0; ni < 12; ni++)
            #pragma unroll
            for (int j = 0; j < 4; j++) acc[mi][ni][j] = 0.f;

    #pragma unroll
    for (int ks = 0; ks < 4; ks++) {
        const uint32_t kb = ks * 32;
        uint32_t ah[2][4];
        #pragma unroll
        for (int mi = 0; mi < 2; mi++)
            ldsm4(ah[mi][0], ah[mi][1], ah[mi][2], ah[mi][3],
                  a_l + mi*(16*RW2*2) + kb);
        #pragma unroll
        for (int nj = 0; nj < 6; nj++) {
            uint32_t q0, q1, q2, q3;
            ldsm4(q0, q1, q2, q3, b_l + nj*(16*RW2*2) + kb);
            uint32_t b0[2] = {q0, q2}, b1[2] = {q1, q3};
            #pragma unroll
            for (int mi = 0; mi < 2; mi++) {
                mma16816h(acc[mi][2*nj],   ah[mi], b0);
                mma16816h(acc[mi][2*nj+1], ah[mi], b1);
            }
        }
    }

    #pragma unroll
    for (int mi = 0; mi < 2; mi++)
        #pragma unroll
        for (int ni = 0; ni < 12; ni++)
            #pragma unroll
            for (int j = 0; j < 4; j++) acc[mi][ni][j] *= 0.125f;

    // row max
    float M[2][2];
    #pragma unroll
    for (int mi = 0; mi < 2; mi++)
        #pragma unroll
        for (int h2 = 0; h2 < 2; h2++) {
            float m = -1e30f;
            #pragma unroll
            for (int ni = 0; ni < 12; ni++)
                m = fmaxf(m, fmaxf(acc[mi][ni][2*h2], acc[mi][ni][2*h2+1]));
            m = fmaxf(m, __shfl_xor_sync(0xFFFFFFFFu, m, 1));
            m = fmaxf(m, __shfl_xor_sync(0xFFFFFFFFu, m, 2));
            if (t4 == 0) red[(wm*32 + mi*16 + g + 8*h2)*4 + wn] = m;
        }
    __syncthreads();
    #pragma unroll
    for (int mi = 0; mi < 2; mi++)
        #pragma unroll
        for (int h2 = 0; h2 < 2; h2++) {
            int row = wm*32 + mi*16 + g + 8*h2;
            M[mi][h2] = fmaxf(fmaxf(red[row*4], red[row*4+1]),
                              fmaxf(red[row*4+2], red[row*4+3]));
        }
    __syncthreads();

    // exp + row sum
    float S[2][2];
    #pragma unroll
    for (int mi = 0; mi < 2; mi++)
        #pragma unroll
        for (int h2 = 0; h2 < 2; h2++) {
            float s = 0.f;
            #pragma unroll
            for (int ni = 0; ni < 12; ni++) {
                float e0 = __expf(acc[mi][ni][2*h2]   - M[mi][h2]);
                float e1 = __expf(acc[mi][ni][2*h2+1] - M[mi][h2]);
                acc[mi][ni][2*h2] = e0; acc[mi][ni][2*h2+1] = e1;
                s += e0 + e1;
            }
            s += __shfl_xor_sync(0xFFFFFFFFu, s, 1);
            s += __shfl_xor_sync(0xFFFFFFFFu, s, 2);
            if (t4 == 0) red[(wm*32 + mi*16 + g + 8*h2)*4 + wn] = s;
        }
    __syncthreads();
    #pragma unroll
    for (int mi = 0; mi < 2; mi++)
        #pragma unroll
        for (int h2 = 0; h2 < 2; h2++) {
            int row = wm*32 + mi*16 + g + 8*h2;
            float inv = 1.f / (red[row*4] + red[row*4+1] + red[row*4+2] + red[row*4+3]);
            S[mi][h2] = inv;
            if (wn == 0 && t4 == 0) invb[row] = inv;
        }

    // write P = e*inv (f32, required output)
    float* abase = attn + (long long)bh*NN*NN;
    #pragma unroll
    for (int mi = 0; mi < 2; mi++)
        #pragma unroll
        for (int h2 = 0; h2 < 2; h2++) {
            int row = m0 + wm*32 + mi*16 + g + 8*h2;
            float inv = S[mi][h2];
            float* rp = abase + (long long)row*NN + wn*96 + 2*t4;
            #pragma unroll
            for (int ni = 0; ni < 12; ni++) {
                float2 o;
                o.x = acc[mi][ni][2*h2]   * inv;
                o.y = acc[mi][ni][2*h2+1] * inv;
                *(float2*)(rp + ni*8) = o;
            }
        }

    __syncthreads();   // done reading Qs/Ks/red; Ph/Vs writes may begin

    // ---- phase B: e -> fp16 SMEM, load V^T, P@V ----
    #pragma unroll
    for (int mi = 0; mi < 2; mi++)
        #pragma unroll
        for (int h2 = 0; h2 < 2; h2++) {
            int row = wm*32 + mi*16 + g + 8*h2;
            __half* rp = Ph + row*RW3 + wn*96 + 2*t4;
            #pragma unroll
            for (int ni = 0; ni < 12; ni++)
                *(uint32_t*)(rp + ni*8) = pack_h2(acc[mi][ni][2*h2], acc[mi][ni][2*h2+1]);
        }
    const __half* vbase = vt + (long long)bh*HD*NN;
    #pragma unroll
    for (int p = 0; p < 6; p++) {
        int u = tid + (p << 9);
        int r = u / 48, c = u - r*48;
        *(uint4*)(Vs + r*RW3 + c*8) = *(const uint4*)(vbase + r*NN + c*8);
    }
    __syncthreads();

    const int wm2 = w >> 2, wn2 = w & 3;
    const uint32_t pa = smem_u32(Ph) + ((wm2*32 + (lane & 15))*RW3 + ((lane >> 4) << 3))*2;
    const uint32_t pb = smem_u32(Vs) + ((wn2*16 + (lane & 15))*RW3 + ((lane >> 4) << 3))*2;

    float acc2[2][2][4];
    #pragma unroll
    for (int mi = 0; mi < 2; mi++)
        #pragma unroll
        for (int ni = 0; ni < 2; ni++)
            #pragma unroll
            for (int j = 0; j < 4; j++) acc2[mi][ni][j] = 0.f;

    #pragma unroll
    for (int ks = 0; ks < 24; ks++) {
        const uint32_t kb = ks * 32;
        uint32_t ah0[4], ah1[4], q0, q1, q2, q3;
        ldsm4(ah0[0], ah0[1], ah0[2], ah0[3], pa + kb);
        ldsm4(ah1[0], ah1[1], ah1[2], ah1[3], pa + 16*RW3*2 + kb);
        ldsm4(q0, q1, q2, q3, pb + kb);
        uint32_t b0[2] = {q0, q2}, b1[2] = {q1, q3};
        mma16816h(acc2[0][0], ah0, b0);
        mma16816h(acc2[0][1], ah0, b1);
        mma16816h(acc2[1][0], ah1, b0);
        mma16816h(acc2[1][1], ah1, b1);
    }

    #pragma unroll
    for (int mi = 0; mi < 2; mi++) {
        int r0 = wm2*32 + mi*16 + g;
        float inv0 = invb[r0], inv1 = invb[r0 + 8];
        long long base0 = ((long long)b*NN + m0 + r0)*DIM + hh*HD;
        long long base1 = base0 + 8LL*DIM;
        #pragma unroll
        for (int ni = 0; ni < 2; ni++) {
            int col = wn2*16 + ni*8 + 2*t4;
            *(uint32_t*)(ao + base0 + col) = pack_h2(acc2[mi][ni][0]*inv0, acc2[mi][ni][1]*inv0);
            *(uint32_t*)(ao + base1 + col) = pack_h2(acc2[mi][ni][2]*inv1, acc2[mi][ni][3]*inv1);
        }
    }
}

// ---------------- LayerNorm over 768 features -------------------------------
template<typename TO>
__global__ void ln_kernel(const float* __restrict__ in, TO* __restrict__ out,
                          const float* __restrict__ g, const float* __restrict__ b,
                          long long in_bstride, long long out_bstride)
{
    const float* x = in  + (long long)blockIdx.y*in_bstride  + (long long)blockIdx.x*DIM;
    TO*          y = out + (long long)blockIdx.y*out_bstride + (long long)blockIdx.x*DIM;
    int tid = threadIdx.x;
    float v0 = x[tid], v1 = x[tid+256], v2 = x[tid+512];
    __shared__ float sh[256];
    sh[tid] = v0 + v1 + v2;
    __syncthreads();
    for (int o = 128; o > 0; o >>= 1) { if (tid < o) sh[tid] += sh[tid+o]; __syncthreads(); }
    float mean = sh[0] * (1.f/768.f);
    __syncthreads();
    float d0 = v0-mean, d1 = v1-mean, d2 = v2-mean;
    sh[tid] = d0*d0 + d1*d1 + d2*d2;
    __syncthreads();
    for (int o = 128; o > 0; o >>= 1) { if (tid < o) sh[tid] += sh[tid+o]; __syncthreads(); }
    float inv = rsqrtf(sh[0] * (1.f/768.f) + 1e-5f);
    st_s(y + tid,     d0*inv*g[tid]     + b[tid]);
    st_s(y + tid+256, d1*inv*g[tid+256] + b[tid+256]);
    st_s(y + tid+512, d2*inv*g[tid+512] + b[tid+512]);
}

__global__ void ln_cat_kernel(const float* __restrict__ zf, const float* __restrict__ x,
                              __half* __restrict__ out,
                              const float* __restrict__ g, const float* __restrict__ b)
{
    int t = blockIdx.x, bb = blockIdx.y;
    const float* src = (t < ZL) ? zf + ((long long)bb*ZL + t)*DIM
                                : x  + ((long long)bb*TT + (t - ZL))*DIM;
    __half* y = out + ((long long)bb*NN + t)*DIM;
    int tid = threadIdx.x;
    float v0 = src[tid], v1 = src[tid+256], v2 = src[tid+512];
    __shared__ float sh[256];
    sh[tid] = v0 + v1 + v2;
    __syncthreads();
    for (int o = 128; o > 0; o >>= 1) { if (tid < o) sh[tid] += sh[tid+o]; __syncthreads(); }
    float mean = sh[0] * (1.f/768.f);
    __syncthreads();
    float d0 = v0-mean, d1 = v1-mean, d2 = v2-mean;
    sh[tid] = d0*d0 + d1*d1 + d2*d2;
    __syncthreads();
    for (int o = 128; o > 0; o >>= 1) { if (tid < o) sh[tid] += sh[tid+o]; __syncthreads(); }
    float inv = rsqrtf(sh[0] * (1.f/768.f) + 1e-5f);
    y[tid]     = __float2half_rn(d0*inv*g[tid]     + b[tid]);
    y[tid+256] = __float2half_rn(d1*inv*g[tid+256] + b[tid+256]);
    y[tid+512] = __float2half_rn(d2*inv*g[tid+512] + b[tid+512]);
}

// ---------------- fusion: entropies over ZL axis ----------------------------
__global__ void fusion_kernel(const float* __restrict__ ax, const float* __restrict__ axi,
                              float* __restrict__ alpha_o, float* __restrict__ um_o,
                              float* __restrict__ u_o, float* __restrict__ ui_o)
{
    int b = blockIdx.x, s = threadIdx.x;
    const float* X  = ax  + (long long)b*ZL*SL + s;
    const float* Xi = axi + (long long)b*ZL*SL + s;
    float u, ui;
    {
        float mx = -1e30f;
        for (int t = 0; t < ZL; t++) mx = fmaxf(mx, X[t*SL]);
        float sum = 0.f;
        for (int t = 0; t < ZL; t++) sum += expf(X[t*SL] - mx);
        float inv = 1.f/sum, acc = 0.f;
        for (int t = 0; t < ZL; t++) { float p = expf(X[t*SL]-mx)*inv; acc -= p*logf(p + 1e-8f); }
        u = acc;
    }
    {
        float mx = -1e30f;
        for (int t = 0; t < ZL; t++) mx = fmaxf(mx, Xi[t*SL]);
        float sum = 0.f;
        for (int t = 0; t < ZL; t++) sum += expf(Xi[t*SL] - mx);
        float inv = 1.f/sum, acc = 0.f;
        for (int t = 0; t < ZL; t++) { float p = expf(Xi[t*SL]-mx)*inv; acc -= p*logf(p + 1e-8f); }
        ui = acc;
    }
    int idx = b*SL + s;
    float alpha = 1.f / (1.f + expf(-(ui - u)));
    alpha_o[idx] = alpha;
    um_o[idx] = 0.5f*(u + ui);
    u_o[idx] = u;
    ui_o[idx] = ui;
}

// ---------------- elementwise helpers ----------------------------------------
__global__ void cat_feat_k(const float* __restrict__ x, const float* __restrict__ xi,
                           __half* __restrict__ o)
{
    long long i = (long long)blockIdx.x*blockDim.x + threadIdx.x;
    const long long n = (long long)BATCH*ZL*2*DIM;
    if (i >= n) return;
    int c = (int)(i % (2*DIM));
    long long bt = i / (2*DIM);
    long long b = bt / ZL, t = bt % ZL;
    long long src = (b*TT + t)*DIM;
    float v = (c < DIM) ? x[src + c] : xi[src + c - DIM];
    o[i] = __float2half_rn(v);
}

__global__ void vtrans_k(const float* __restrict__ qkv, __half* __restrict__ vt)
{
    __shared__ float t[32][33];
    int bh = blockIdx.z;
    long long b = bh / HEADS, h = bh % HEADS;
    const float* src = qkv + b*NN*QKV3 + 2*DIM + h*HD;
    int tt0 = blockIdx.x*32;
    int cc0 = blockIdx.y*32;
    int tx = threadIdx.x, ty = threadIdx.y;
    #pragma unroll
    for (int i = 0; i < 32; i += 8)
        t[ty+i][tx] = src[(long long)(tt0+ty+i)*QKV3 + cc0 + tx];
    __syncthreads();
    __half* dst = vt + ((long long)bh*HD)*NN;
    #pragma unroll
    for (int i = 0; i < 32; i += 8)
        dst[(long long)(cc0+ty+i)*NN + tt0 + tx] = __float2half_rn(t[tx][ty+i]);
}

__global__ void make_v_k(const float* __restrict__ ns, const float* __restrict__ nsi,
                         const float* __restrict__ alpha, float* __restrict__ v)
{
    long long i = (long long)blockIdx.x*blockDim.x + threadIdx.x;
    const long long n = (long long)BATCH*SL*DIM;
    if (i >= n) return;
    long long bs = i / DIM;
    float a = alpha[bs];
    v[i] = a*ns[i] + (1.f - a)*nsi[i];
}

__global__ void make_vfc_k(const float* __restrict__ xiattn, const float* __restrict__ vf,
                           float* __restrict__ o)
{
    long long i = (long long)blockIdx.x*blockDim.x + threadIdx.x;
    const long long n = (long long)BATCH*TT*DIM;
    if (i >= n) return;
    int c = (int)(i % DIM);
    long long bt = i / DIM;
    long long b = bt / TT, t = bt % TT;
    o[i] = (t < ZL) ? xiattn[(b*NN + t)*DIM + c]
                    : vf[(b*SL + (t-ZL))*DIM + c];
}

__global__ void make_xnew_k(const float* __restrict__ x, const float* __restrict__ xi,
                            const float* __restrict__ xattn, const float* __restrict__ xiattn,
                            const float* __restrict__ vfc,
                            float* __restrict__ xo, float* __restrict__ xio)
{
    long long i = (long long)blockIdx.x*blockDim.x + threadIdx.x;
    const long long n = (long long)BATCH*TT*DIM;
    if (i >= n) return;
    int c = (int)(i % DIM);
    long long bt = i / DIM;
    long long b = bt / TT, t = bt % TT;
    long long aidx = (b*NN + ZL + t)*DIM + c;
    float vf = vfc[i];
    xo[i]  = x[i]  + xattn[aidx]  + vf;
    xio[i] = xi[i] + xiattn[aidx] + vf;
}

__global__ void i2f_k(const int* __restrict__ in, float* __restrict__ out, int n)
{
    int i = blockIdx.x*blockDim.x + threadIdx.x;
    if (i < n) out[i] = (float)in[i];
}

__global__ void f2h_k(const float* __restrict__ in, __half* __restrict__ out, int n4)
{
    int i = blockIdx.x*blockDim.x + threadIdx.x;
    if (i < n4) {
        float4 v = *(const float4*)(in + 4*i);
        *(uint2*)(out + 4*i) = to_h2(v);
    }
}

// ---------------- host-side helpers ----------------
template<int TM, int TN, typename TA, typename TB, typename TC>
static inline void mm(const TA* A, const TB* B, const float* bias,
                      const float* r1, const float* r2, TC* C,
                      int M, int N, int K, int lda, int ldb, int ldc,
                      long long sAb, long long sBb, long long sCb,
                      int nb, int nh,
                      long long sAh, long long sBh, long long sCh,
                      float alpha, int act)
{
    constexpr int STAGE_BYTES = (TM*RWH + TN*RWH)*2;
    constexpr int EPI = 32*(TN+4)*4;
    constexpr int DS = (2*STAGE_BYTES > EPI) ? 2*STAGE_BYTES : EPI;
    static bool init = false;
    if (!init) {
        cudaFuncSetAttribute(mm2<TM,TN,TA,TB,TC>, cudaFuncAttributeMaxDynamicSharedMemorySize, DS);
        init = true;
    }
    dim3 g(N/TN, M/TM, nb*nh);
    mm2<TM,TN,TA,TB,TC><<<g, 512, DS>>>(A,B,bias,r1,r2,C,K,lda,ldb,ldc,sAb,sBb,sCb,nh,sAh,sBh,sCh,alpha,act);
}

static inline int cdiv(long long a, int b) { return (int)((a + b - 1) / b); }

extern "C" void kernel_launch(void* const* d_in, const int* in_sizes, int n_in,
                              void* d_out, int out_size)
{
    const float* x      = (const float*)d_in[0];
    const float* xi     = (const float*)d_in[1];
    const int*   git    = (const int*)  d_in[2];
    const int*   giti   = (const int*)  d_in[3];
    const int*   gis    = (const int*)  d_in[4];
    const int*   gisi   = (const int*)  d_in[5];
    const float* w_qkv  = (const float*)d_in[6];
    const float* b_qkv  = (const float*)d_in[7];
    const float* w_proj = (const float*)d_in[8];
    const float* b_proj = (const float*)d_in[9];
    const float* g1     = (const float*)d_in[10];
    const float* bt1    = (const float*)d_in[11];
    const float* g2     = (const float*)d_in[12];
    const float* bt2    = (const float*)d_in[13];
    const float* w_fc1  = (const float*)d_in[14];
    const float* b_fc1  = (const float*)d_in[15];
    const float* w_fc2  = (const float*)d_in[16];
    const float* b_fc2  = (const float*)d_in[17];
    const float* w_al   = (const float*)d_in[18];
    const float* b_al   = (const float*)d_in[19];
    const float* w_al2  = (const float*)d_in[20];
    const float* b_al2  = (const float*)d_in[21];
    const float* w_fus  = (const float*)d_in[22];
    const float* b_fus  = (const float*)d_in[23];
    float* out = (float*)d_out;

    float *p_zf, *p_ns, *p_nsi, *p_attnx, *p_attnxi, *p_qkv,
          *p_xattn, *p_xiattn, *p_v, *p_vf, *p_vfc, *p_xnew, *p_xinew, *p_adap2;
    __half *p_cath, *p_lnh, *p_vth, *p_aoh, *p_hh;
    __half *wqkvh, *wprojh, *wfc1h, *wfc2h, *walh, *wal2h, *wfush;
    cudaGetSymbolAddress((void**)&p_cath,  g_cath);
    cudaGetSymbolAddress((void**)&p_zf,    g_zf);
    cudaGetSymbolAddress((void**)&p_ns,    g_ns);
    cudaGetSymbolAddress((void**)&p_nsi,   g_nsi);
    cudaGetSymbolAddress((void**)&p_attnx, g_attnx);
    cudaGetSymbolAddress((void**)&p_attnxi,g_attnxi);
    cudaGetSymbolAddress((void**)&p_lnh,   g_lnh);
    cudaGetSymbolAddress((void**)&p_qkv,   g_qkv);
    cudaGetSymbolAddress((void**)&p_vth,   g_vth);
    cudaGetSymbolAddress((void**)&p_aoh,   g_aoh);
    cudaGetSymbolAddress((void**)&p_xattn, g_xattn);
    cudaGetSymbolAddress((void**)&p_xiattn,g_xiattn);
    cudaGetSymbolAddress((void**)&p_v,     g_v);
    cudaGetSymbolAddress((void**)&p_vf,    g_vf);
    cudaGetSymbolAddress((void**)&p_vfc,   g_vfc);
    cudaGetSymbolAddress((void**)&p_xnew,  g_xnew);
    cudaGetSymbolAddress((void**)&p_xinew, g_xinew);
    cudaGetSymbolAddress((void**)&p_adap2, g_adap2);
    cudaGetSymbolAddress((void**)&p_hh,    g_hh);
    cudaGetSymbolAddress((void**)&wqkvh,   g_wqkvh);
    cudaGetSymbolAddress((void**)&wprojh,  g_wprojh);
    cudaGetSymbolAddress((void**)&wfc1h,   g_wfc1h);
    cudaGetSymbolAddress((void**)&wfc2h,   g_wfc2h);
    cudaGetSymbolAddress((void**)&walh,    g_walh);
    cudaGetSymbolAddress((void**)&wal2h,   g_wal2h);
    cudaGetSymbolAddress((void**)&wfush,   g_wfush);

    const float scale_dim = 1.f / sqrtf((float)DIM);

    // ---- weight conversions ----
    f2h_k<<<cdiv(QKV3*DIM/4,256),256>>>(w_qkv,  wqkvh,  QKV3*DIM/4);
    f2h_k<<<cdiv(DIM*DIM/4,256),256>>>(w_proj, wprojh, DIM*DIM/4);
    f2h_k<<<cdiv(HID*DIM/4,256),256>>>(w_fc1,  wfc1h,  HID*DIM/4);
    f2h_k<<<cdiv(DIM*HID/4,256),256>>>(w_fc2,  wfc2h,  DIM*HID/4);
    f2h_k<<<cdiv(DIM*2*DIM/4,256),256>>>(w_al, walh,   DIM*2*DIM/4);
    f2h_k<<<cdiv(DIM*DIM/4,256),256>>>(w_al2,  wal2h,  DIM*DIM/4);
    f2h_k<<<cdiv(DIM*DIM/4,256),256>>>(w_fus,  wfush,  DIM*DIM/4);

    // ---- z_f ----
    cat_feat_k<<<cdiv((long long)BATCH*ZL*2*DIM, 256), 256>>>(x, xi, p_cath);
    mm<128,128,__half,__half,float>(p_cath, walh, b_al, nullptr, nullptr, p_zf,
        BATCH*ZL, DIM, 2*DIM, 2*DIM, 2*DIM, DIM, 0,0,0, 1,1, 0,0,0, 1.f, 0);

    // ---- ns/nsi ----
    ln_kernel<float><<<dim3(SL, BATCH), 256>>>(x  + (long long)ZL*DIM, p_ns,  g1, bt1,
                                               (long long)TT*DIM, (long long)SL*DIM);
    ln_kernel<float><<<dim3(SL, BATCH), 256>>>(xi + (long long)ZL*DIM, p_nsi, g1, bt1,
                                               (long long)TT*DIM, (long long)SL*DIM);

    // ---- MHA both streams ----
    {
        static bool ainit = false;
        if (!ainit) {
            cudaFuncSetAttribute(attn_fused, cudaFuncAttributeMaxDynamicSharedMemorySize, PV_SMEM);
            ainit = true;
        }
    }
    const float* src[2]    = {x, xi};
    float*       attn_o[2] = {out + O_ATTN, out + O_IATTN};
    float*       proj_o[2] = {p_xattn, p_xiattn};
    for (int side = 0; side < 2; side++) {
        ln_cat_kernel<<<dim3(NN, BATCH), 256>>>(p_zf, src[side], p_lnh, g1, bt1);
        mm<128,128,__half,__half,float>(p_lnh, wqkvh, b_qkv, nullptr, nullptr, p_qkv,
            BATCH*NN, QKV3, DIM, DIM, DIM, QKV3, 0,0,0, 1,1, 0,0,0, 1.f, 0);
        vtrans_k<<<dim3(NN/32, HD/32, BATCH*HEADS), dim3(32,8)>>>(p_qkv, p_vth);
        attn_fused<<<dim3(3, BATCH*HEADS), 512, PV_SMEM>>>(p_qkv, p_vth, attn_o[side], p_aoh);
        mm<128,128,__half,__half,float>(p_aoh, wprojh, b_proj, nullptr, nullptr, proj_o[side],
            BATCH*NN, DIM, DIM, DIM, DIM, DIM, 0,0,0, 1,1, 0,0,0, 1.f, 0);
    }

    // ---- attn_x / attn_xi ----
    mm<64,128,float,float,float>(p_zf, p_ns, nullptr, nullptr, nullptr, p_attnx,
        ZL, SL, DIM, DIM, DIM, SL,
        (long long)ZL*DIM, (long long)SL*DIM, (long long)ZL*SL,
        BATCH, 1, 0,0,0, scale_dim, 0);
    mm<64,128,float,float,float>(p_zf, p_nsi, nullptr, nullptr, nullptr, p_attnxi,
        ZL, SL, DIM, DIM, DIM, SL,
        (long long)ZL*DIM, (long long)SL*DIM, (long long)ZL*SL,
        BATCH, 1, 0,0,0, scale_dim, 0);

    // ---- fusion ----
    fusion_kernel<<<BATCH, SL>>>(p_attnx, p_attnxi,
                                 out + O_ALPHA, out + O_UM, out + O_U, out + O_UI);
    make_v_k<<<cdiv((long long)BATCH*SL*DIM, 256), 256>>>(p_ns, p_nsi, out + O_ALPHA, p_v);
    mm<128,128,float,__half,float>(p_v, wfush, b_fus, nullptr, nullptr, p_vf,
        BATCH*SL, DIM, DIM, DIM, DIM, DIM, 0,0,0, 1,1, 0,0,0, 1.f, 0);
    make_vfc_k<<<cdiv((long long)BATCH*TT*DIM, 256), 256>>>(p_xiattn, p_vf, p_vfc);

    // ---- residual adds ----
    make_xnew_k<<<cdiv((long long)BATCH*TT*DIM, 256), 256>>>(
        x, xi, p_xattn, p_xiattn, p_vfc, p_xnew, p_xinew);

    // ---- adap2 ----
    ln_kernel<__half><<<dim3(TT, BATCH), 256>>>(p_vfc, p_lnh, g2, bt2,
                                                (long long)TT*DIM, (long long)TT*DIM);
    mm<128,128,__half,__half,float>(p_lnh, wal2h, b_al2, nullptr, nullptr, p_adap2,
        BATCH*TT, DIM, DIM, DIM, DIM, DIM, 0,0,0, 1,1, 0,0,0, 1.f, 0);

    // ---- MLP both streams ----
    float* xn[2] = {p_xnew, p_xinew};
    float* xo[2] = {out + O_XOUT, out + O_XIOUT};
    for (int side = 0; side < 2; side++) {
        ln_kernel<__half><<<dim3(TT, BATCH), 256>>>(xn[side], p_lnh, g2, bt2,
                                                    (long long)TT*DIM, (long long)TT*DIM);
        mm<128,128,__half,__half,__half>(p_lnh, wfc1h, b_fc1, nullptr, nullptr, p_hh,
            BATCH*TT, HID, DIM, DIM, DIM, HID, 0,0,0, 1,1, 0,0,0, 1.f, 1);
        mm<128,128,__half,__half,float>(p_hh, wfc2h, b_fc2, xn[side], p_adap2, xo[side],
            BATCH*TT, DIM, HID, HID, HID, DIM, 0,0,0, 1,1, 0,0,0, 1.f, 0);
    }

    // ---- index passthroughs ----
    i2f_k<<<cdiv(BATCH*ZL, 256), 256>>>(git,  out + O_GIT,  BATCH*ZL);
    i2f_k<<<cdiv(BATCH*SL, 256), 256>>>(gis,  out + O_GIS,  BATCH*SL);
    i2f_k<<<cdiv(BATCH*ZL, 256), 256>>>(giti, out + O_GITI, BATCH*ZL);
    i2f_k<<<cdiv(BATCH*SL, 256), 256>>>(gisi, out + O_GISI, BATCH*SL);
}

// round 8
// speedup vs baseline: 5.2122x; 1.1541x over previous
#include <cuda_runtime.h>
#include <cuda_fp16.h>
#include <math.h>
#include <cstdint>
#include <type_traits>

// ---------------- problem constants ----------------
#define BATCH 32
#define ZL 64
#define SL 256
#define TT 320
#define NN 384
#define DIM 768
#define HEADS 12
#define HD 64
#define HID 3072
#define QKV3 2304

#define O_XOUT   0LL
#define O_GIT    7864320LL
#define O_GIS    7866368LL
#define O_ATTN   7874560LL
#define O_XIOUT  64497664LL
#define O_GITI   72361984LL
#define O_GISI   72364032LL
#define O_IATTN  72372224LL
#define O_ALPHA  128995328LL
#define O_UM     129003520LL
#define O_U      129011712LL
#define O_UI     129019904LL

// ---------------- scratch ----------------
__device__ __half g_cath [BATCH*ZL*2*DIM];
__device__ float  g_zf   [BATCH*ZL*DIM];
__device__ float  g_ns   [BATCH*SL*DIM];
__device__ float  g_nsi  [BATCH*SL*DIM];
__device__ float  g_attnx [BATCH*ZL*SL];
__device__ float  g_attnxi[BATCH*ZL*SL];
__device__ __half g_lnh  [BATCH*NN*DIM];
__device__ float  g_qkv  [BATCH*NN*QKV3];
__device__ __half g_vth  [BATCH*HEADS*HD*NN];
__device__ __half g_aoh  [BATCH*NN*DIM];
__device__ float  g_xattn [BATCH*NN*DIM];
__device__ float  g_xiattn[BATCH*NN*DIM];
__device__ __half g_vh   [BATCH*SL*DIM];
__device__ float  g_vf   [BATCH*SL*DIM];
__device__ float  g_vfc  [BATCH*TT*DIM];
__device__ float  g_xnew [BATCH*TT*DIM];
__device__ float  g_xinew[BATCH*TT*DIM];
__device__ float  g_adap2[BATCH*TT*DIM];
__device__ __half g_hh   [BATCH*TT*HID];
__device__ __half g_wqkvh[QKV3*DIM];
__device__ __half g_wprojh[DIM*DIM];
__device__ __half g_wfc1h[HID*DIM];
__device__ __half g_wfc2h[DIM*HID];
__device__ __half g_walh [DIM*2*DIM];
__device__ __half g_wal2h[DIM*DIM];
__device__ __half g_wfush[DIM*DIM];

// =============== helpers =====================================================
__device__ __forceinline__ uint32_t smem_u32(const void* p) {
    uint32_t a;
    asm("{ .reg .u64 t; cvta.to.shared.u64 t, %1; cvt.u32.u64 %0, t; }" : "=r"(a) : "l"(p));
    return a;
}
__device__ __forceinline__ void mma16816h(float* d, const uint32_t* a, const uint32_t* b) {
    asm volatile("mma.sync.aligned.m16n8k16.row.col.f32.f16.f16.f32 "
        "{%0,%1,%2,%3}, {%4,%5,%6,%7}, {%8,%9}, {%0,%1,%2,%3};"
        : "+f"(d[0]), "+f"(d[1]), "+f"(d[2]), "+f"(d[3])
        : "r"(a[0]), "r"(a[1]), "r"(a[2]), "r"(a[3]), "r"(b[0]), "r"(b[1]));
}
__device__ __forceinline__ void ldsm4(uint32_t& r0, uint32_t& r1, uint32_t& r2, uint32_t& r3,
                                      uint32_t addr) {
    asm volatile("ldmatrix.sync.aligned.m8n8.x4.shared.b16 {%0,%1,%2,%3}, [%4];"
        : "=r"(r0), "=r"(r1), "=r"(r2), "=r"(r3) : "r"(addr));
}
__device__ __forceinline__ uint32_t pack_h2(float x, float y) {
    __half2 p = __float22half2_rn(make_float2(x, y));
    return *(uint32_t*)&p;
}
template<typename T> struct RawVec;
template<> struct RawVec<float>  { using type = float4; };
template<> struct RawVec<__half> { using type = uint2;  };
__device__ __forceinline__ uint2 to_h2(const float4& v) {
    return make_uint2(pack_h2(v.x, v.y), pack_h2(v.z, v.w));
}
__device__ __forceinline__ uint2 to_h2(const uint2& v) { return v; }
__device__ __forceinline__ void st_out4(float* p, float4 v) { *(float4*)p = v; }
__device__ __forceinline__ void st_out4(__half* p, float4 v) {
    *(uint2*)p = make_uint2(pack_h2(v.x, v.y), pack_h2(v.z, v.w));
}
__device__ __forceinline__ void st_s(float* p, float v)  { *p = v; }
__device__ __forceinline__ void st_s(__half* p, float v) { *p = __float2half_rn(v); }

#define CP_ASYNC16(dst, src) \
    asm volatile("cp.async.cg.shared.global [%0], [%1], 16;" :: "r"(dst), "l"(src))
#define CP_COMMIT()  asm volatile("cp.async.commit_group;")
#define CP_WAIT1()   asm volatile("cp.async.wait_group 1;")
#define CP_WAIT0()   asm volatile("cp.async.wait_group 0;")

// =============== fp16 mma.sync GEMM, typed A/B/C =============================
#define RWH 40

template<int TM, int TN, typename TA, typename TB, typename TC>
__global__ __launch_bounds__(512, 2)
void mm2(const TA* __restrict__ A, const TB* __restrict__ B,
         const float* __restrict__ bias,
         const float* __restrict__ res1, const float* __restrict__ res2,
         TC* __restrict__ C,
         int K, int lda, int ldb, int ldc,
         long long sAb, long long sBb, long long sCb, int batchH,
         long long sAh, long long sBh, long long sCh,
         float alpha, int act)
{
    extern __shared__ char dsm[];
    constexpr int WTM = TM/4, WTN = TN/4;
    constexpr int MI = WTM/16, NI = WTN/8;
    constexpr int AHL = TM*RWH;
    constexpr int BHL = TN*RWH;
    constexpr int STAGE_BYTES = (AHL + BHL)*2;
    constexpr int PA = TM/64, PB = TN/64;
    constexpr bool ASYNC = (TM == 128) &&
        std::is_same<TA,__half>::value && std::is_same<TB,__half>::value;

    const int tid  = threadIdx.x;
    const int lane = tid & 31;
    const int w    = tid >> 5;
    const int wm   = w >> 2;
    const int wn   = w & 3;

    const int bz = blockIdx.z;
    const int b  = bz / batchH;
    const int h  = bz - b*batchH;
    const int m0 = blockIdx.y * TM;
    const int n0 = blockIdx.x * TN;
    const TA* Ab = A + (long long)b*sAb + (long long)h*sAh + (long long)m0*lda;
    const TB* Bb = B + (long long)b*sBb + (long long)h*sBh + (long long)n0*ldb;
    const long long coff = (long long)b*sCb + (long long)h*sCh;

    const uint32_t sb0 = smem_u32(dsm);
    const uint32_t a_l = (uint32_t)(((wm*WTM + (lane & 15))*RWH + ((lane >> 4) << 3)) * 2);
    const uint32_t b_l = (uint32_t)(AHL*2 + ((wn*WTN + (lane & 15))*RWH + ((lane >> 4) << 3)) * 2);

    float acc[MI][NI][4];
    #pragma unroll
    for (int mi = 0; mi < MI; mi++)
        #pragma unroll
        for (int ni = 0; ni < NI; ni++)
            #pragma unroll
            for (int j = 0; j < 4; j++) acc[mi][ni][j] = 0.f;

    const int NC = K >> 5;

    if constexpr (ASYNC) {
        // 16B/thread cp.async loaders: thread -> (row = tid>>2, chunk = tid&3)
        const int arow = tid >> 2;
        const int c16  = tid & 3;
        const uint32_t adst0 = arow*RWH*2 + c16*16;
        const uint32_t bdst0 = AHL*2 + arow*RWH*2 + c16*16;
        const bool bact = (TN == 128) || (tid < 256);

        // prologue: stage 0
        CP_ASYNC16(sb0 + adst0, (const __half*)Ab + (long long)arow*lda + c16*8);
        if (bact)
            CP_ASYNC16(sb0 + bdst0, (const __half*)Bb + (long long)arow*ldb + c16*8);
        CP_COMMIT();

        for (int c = 0; c < NC; c++) {
            const int st = c & 1;
            if (c + 1 < NC) {
                const int k0 = (c + 1) << 5;
                const uint32_t base = sb0 + ((c + 1) & 1) * STAGE_BYTES;
                CP_ASYNC16(base + adst0, (const __half*)Ab + (long long)arow*lda + k0 + c16*8);
                if (bact)
                    CP_ASYNC16(base + bdst0, (const __half*)Bb + (long long)arow*ldb + k0 + c16*8);
                CP_COMMIT();
                CP_WAIT1();
            } else {
                CP_WAIT0();
            }
            __syncthreads();

            const uint32_t stageu = sb0 + st * STAGE_BYTES;
            #pragma unroll
            for (int ks = 0; ks < 2; ks++) {
                const uint32_t kb = ks * 32;
                uint32_t ah[MI][4];
                #pragma unroll
                for (int mi = 0; mi < MI; mi++) {
                    uint32_t ad = stageu + a_l + mi*(16*RWH*2) + kb;
                    ldsm4(ah[mi][0], ah[mi][1], ah[mi][2], ah[mi][3], ad);
                }
                uint32_t bh[NI][2];
                #pragma unroll
                for (int nj = 0; nj < NI/2; nj++) {
                    uint32_t bd = stageu + b_l + nj*(16*RWH*2) + kb;
                    uint32_t q0, q1, q2, q3;
                    ldsm4(q0, q1, q2, q3, bd);
                    bh[2*nj][0] = q0; bh[2*nj][1] = q2;
                    bh[2*nj+1][0] = q1; bh[2*nj+1][1] = q3;
                }
                #pragma unroll
                for (int mi = 0; mi < MI; mi++)
                    #pragma unroll
                    for (int ni = 0; ni < NI; ni++)
                        mma16816h(acc[mi][ni], ah[mi], bh[ni]);
            }
            __syncthreads();
        }
    } else {
        const int lq = tid & 7;
        const int lr = tid >> 3;
        typename RawVec<TA>::type pA[PA];
        typename RawVec<TB>::type pB[PB];

        #pragma unroll
        for (int p = 0; p < PA; p++)
            pA[p] = *(const typename RawVec<TA>::type*)(Ab + (long long)(lr + 64*p)*lda + 4*lq);
        #pragma unroll
        for (int p = 0; p < PB; p++)
            pB[p] = *(const typename RawVec<TB>::type*)(Bb + (long long)(lr + 64*p)*ldb + 4*lq);

        for (int c = 0; c < NC; c++) {
            const int st = c & 1;
            char* sb = dsm + st * STAGE_BYTES;
            __half* Ah = (__half*)sb;
            __half* Bh = Ah + AHL;

            #pragma unroll
            for (int p = 0; p < PA; p++)
                *(uint2*)(Ah + (lr + 64*p)*RWH + 4*lq) = to_h2(pA[p]);
            #pragma unroll
            for (int p = 0; p < PB; p++)
                *(uint2*)(Bh + (lr + 64*p)*RWH + 4*lq) = to_h2(pB[p]);
            __syncthreads();

            if (c + 1 < NC) {
                const int k0 = (c + 1) << 5;
                #pragma unroll
                for (int p = 0; p < PA; p++)
                    pA[p] = *(const typename RawVec<TA>::type*)(Ab + (long long)(lr + 64*p)*lda + k0 + 4*lq);
                #pragma unroll
                for (int p = 0; p < PB; p++)
                    pB[p] = *(const typename RawVec<TB>::type*)(Bb + (long long)(lr + 64*p)*ldb + k0 + 4*lq);
            }

            const uint32_t stageu = sb0 + st * STAGE_BYTES;
            #pragma unroll
            for (int ks = 0; ks < 2; ks++) {
                const uint32_t kb = ks * 32;
                uint32_t ah[MI][4];
                #pragma unroll
                for (int mi = 0; mi < MI; mi++) {
                    uint32_t ad = stageu + a_l + mi*(16*RWH*2) + kb;
                    ldsm4(ah[mi][0], ah[mi][1], ah[mi][2], ah[mi][3], ad);
                }
                uint32_t bh[NI][2];
                #pragma unroll
                for (int nj = 0; nj < NI/2; nj++) {
                    uint32_t bd = stageu + b_l + nj*(16*RWH*2) + kb;
                    uint32_t q0, q1, q2, q3;
                    ldsm4(q0, q1, q2, q3, bd);
                    bh[2*nj][0] = q0; bh[2*nj][1] = q2;
                    bh[2*nj+1][0] = q1; bh[2*nj+1][1] = q3;
                }
                #pragma unroll
                for (int mi = 0; mi < MI; mi++)
                    #pragma unroll
                    for (int ni = 0; ni < NI; ni++)
                        mma16816h(acc[mi][ni], ah[mi], bh[ni]);
            }
            __syncthreads();
        }
    }

    // ---- epilogue: 32-row passes through SMEM ----
    constexpr int ROWW = TN + 4;
    constexpr int NPASS = TM / 32;
    float* sbuf = (float*)dsm;
    const int g = lane >> 2, t4 = lane & 3;
    const int my_pass = (wm*WTM) >> 5;
    const int my_lb   = (wm*WTM) & 31;

    #pragma unroll
    for (int pass = 0; pass < NPASS; pass++) {
        if (my_pass == pass) {
            #pragma unroll
            for (int mi = 0; mi < MI; mi++)
                #pragma unroll
                for (int ni = 0; ni < NI; ni++)
                    #pragma unroll
                    for (int j = 0; j < 4; j++) {
                        int row = my_lb + mi*16 + g + 8*(j >> 1);
                        int col = wn*WTN + ni*8 + 2*t4 + (j & 1);
                        sbuf[row*ROWW + col] = acc[mi][ni][j];
                    }
        }
        __syncthreads();
        #pragma unroll
        for (int p = 0; p < 32*TN/2048; p++) {
            int i4 = tid + (p << 9);
            int elem = i4 << 2;
            int rr = elem / TN;
            int cc = elem - rr*TN;
            float4 v = *(float4*)(sbuf + rr*ROWW + cc);
            v.x *= alpha; v.y *= alpha; v.z *= alpha; v.w *= alpha;
            if (bias) {
                float4 bb = *(const float4*)(bias + n0 + cc);
                v.x += bb.x; v.y += bb.y; v.z += bb.z; v.w += bb.w;
            }
            long long off = coff + (long long)(m0 + pass*32 + rr)*ldc + (n0 + cc);
            if (res1) {
                float4 a = *(const float4*)(res1 + off);
                v.x += a.x; v.y += a.y; v.z += a.z; v.w += a.w;
            }
            if (res2) {
                float4 a = *(const float4*)(res2 + off);
                v.x += a.x; v.y += a.y; v.z += a.z; v.w += a.w;
            }
            if (act == 1) {
                v.x = 0.5f*v.x*(1.f + erff(v.x*0.70710678118654752f));
                v.y = 0.5f*v.y*(1.f + erff(v.y*0.70710678118654752f));
                v.z = 0.5f*v.z*(1.f + erff(v.z*0.70710678118654752f));
                v.w = 0.5f*v.w*(1.f + erff(v.w*0.70710678118654752f));
            }
            st_out4(C + off, v);
        }
        __syncthreads();
    }
}

// =============== fused QK^T + softmax + P@V =================================
#define RW2 72
#define RW3 392
#define PV_SMEM (128*RW3*2 + 64*RW3*2 + 128*4*4 + 128*4)

__global__ __launch_bounds__(512, 1)
void attn_fused(const float* __restrict__ qkv, const __half* __restrict__ vt,
                float* __restrict__ attn, __half* __restrict__ ao)
{
    extern __shared__ char dsm[];
    __half* Ph  = (__half*)dsm;
    __half* Vs  = (__half*)(dsm + 128*RW3*2);
    float*  red = (float*)(dsm + 128*RW3*2 + 64*RW3*2);
    float*  invb= red + 128*4;
    __half* Qs  = (__half*)dsm;
    __half* Ks  = Qs + 128*RW2;

    const int tid = threadIdx.x;
    const int lane = tid & 31;
    const int w = tid >> 5;
    const int wm = w >> 2, wn = w & 3;
    const int g = lane >> 2, t4 = lane & 3;

    const int m0 = blockIdx.x * 128;
    const int bh = blockIdx.y;
    const int b  = bh / HEADS;
    const int hh = bh - b*HEADS;

    const float* qbase = qkv + (long long)b*NN*QKV3 + hh*HD;

    #pragma unroll
    for (int p = 0; p < 4; p++) {
        int u = tid + (p << 9);
        int r = u >> 4, q4 = u & 15;
        float4 v = *(const float4*)(qbase + (long long)(m0 + r)*QKV3 + 4*q4);
        *(uint2*)(Qs + r*RW2 + 4*q4) = to_h2(v);
    }
    #pragma unroll
    for (int p = 0; p < 12; p++) {
        int u = tid + (p << 9);
        int r = u >> 4, q4 = u & 15;
        float4 v = *(const float4*)(qbase + DIM + (long long)r*QKV3 + 4*q4);
        *(uint2*)(Ks + r*RW2 + 4*q4) = to_h2(v);
    }
    __syncthreads();

    const uint32_t sq = smem_u32(Qs);
    const uint32_t sk = smem_u32(Ks);
    const uint32_t a_l = sq + ((wm*32 + (lane & 15))*RW2 + ((lane >> 4) << 3)) * 2;
    const uint32_t b_l = sk + ((wn*96 + (lane & 15))*RW2 + ((lane >> 4) << 3)) * 2;

    float acc[2][12][4];
    #pragma unroll
    for (int mi = 0; mi < 2; mi++)
        #pragma unroll
        for (int ni = 0; ni < 12; ni++)
            #pragma unroll
            for (int j = 0; j < 4; j++) acc[mi][ni][j] = 0.f;

    #pragma unroll
    for (int ks = 0; ks < 4; ks++) {
        const uint32_t kb = ks * 32;
        uint32_t ah[2][4];
        #pragma unroll
        for (int mi = 0; mi < 2; mi++)
            ldsm4(ah[mi][0], ah[mi][1], ah[mi][2], ah[mi][3],
                  a_l + mi*(16*RW2*2) + kb);
        #pragma unroll
        for (int nj = 0; nj < 6; nj++) {
            uint32_t q0, q1, q2, q3;
            ldsm4(q0, q1, q2, q3, b_l + nj*(16*RW2*2) + kb);
            uint32_t b0[2] = {q0, q2}, b1[2] = {q1, q3};
            #pragma unroll
            for (int mi = 0; mi < 2; mi++) {
                mma16816h(acc[mi][2*nj],   ah[mi], b0);
                mma16816h(acc[mi][2*nj+1], ah[mi], b1);
            }
        }
    }

    #pragma unroll
    for (int mi = 0; mi < 2; mi++)
        #pragma unroll
        for (int ni = 0; ni < 12; ni++)
            #pragma unroll
            for (int j = 0; j < 4; j++) acc[mi][ni][j] *= 0.125f;

    float M[2][2];
    #pragma unroll
    for (int mi = 0; mi < 2; mi++)
        #pragma unroll
        for (int h2 = 0; h2 < 2; h2++) {
            float m = -1e30f;
            #pragma unroll
            for (int ni = 0; ni < 12; ni++)
                m = fmaxf(m, fmaxf(acc[mi][ni][2*h2], acc[mi][ni][2*h2+1]));
            m = fmaxf(m, __shfl_xor_sync(0xFFFFFFFFu, m, 1));
            m = fmaxf(m, __shfl_xor_sync(0xFFFFFFFFu, m, 2));
            if (t4 == 0) red[(wm*32 + mi*16 + g + 8*h2)*4 + wn] = m;
        }
    __syncthreads();
    #pragma unroll
    for (int mi = 0; mi < 2; mi++)
        #pragma unroll
        for (int h2 = 0; h2 < 2; h2++) {
            int row = wm*32 + mi*16 + g + 8*h2;
            M[mi][h2] = fmaxf(fmaxf(red[row*4], red[row*4+1]),
                              fmaxf(red[row*4+2], red[row*4+3]));
        }
    __syncthreads();

    float S[2][2];
    #pragma unroll
    for (int mi = 0; mi < 2; mi++)
        #pragma unroll
        for (int h2 = 0; h2 < 2; h2++) {
            float s = 0.f;
            #pragma unroll
            for (int ni = 0; ni < 12; ni++) {
                float e0 = __expf(acc[mi][ni][2*h2]   - M[mi][h2]);
                float e1 = __expf(acc[mi][ni][2*h2+1] - M[mi][h2]);
                acc[mi][ni][2*h2] = e0; acc[mi][ni][2*h2+1] = e1;
                s += e0 + e1;
            }
            s += __shfl_xor_sync(0xFFFFFFFFu, s, 1);
            s += __shfl_xor_sync(0xFFFFFFFFu, s, 2);
            if (t4 == 0) red[(wm*32 + mi*16 + g + 8*h2)*4 + wn] = s;
        }
    __syncthreads();
    #pragma unroll
    for (int mi = 0; mi < 2; mi++)
        #pragma unroll
        for (int h2 = 0; h2 < 2; h2++) {
            int row = wm*32 + mi*16 + g + 8*h2;
            float inv = 1.f / (red[row*4] + red[row*4+1] + red[row*4+2] + red[row*4+3]);
            S[mi][h2] = inv;
            if (wn == 0 && t4 == 0) invb[row] = inv;
        }

    float* abase = attn + (long long)bh*NN*NN;
    #pragma unroll
    for (int mi = 0; mi < 2; mi++)
        #pragma unroll
        for (int h2 = 0; h2 < 2; h2++) {
            int row = m0 + wm*32 + mi*16 + g + 8*h2;
            float inv = S[mi][h2];
            float* rp = abase + (long long)row*NN + wn*96 + 2*t4;
            #pragma unroll
            for (int ni = 0; ni < 12; ni++) {
                float2 o;
                o.x = acc[mi][ni][2*h2]   * inv;
                o.y = acc[mi][ni][2*h2+1] * inv;
                *(float2*)(rp + ni*8) = o;
            }
        }

    __syncthreads();

    #pragma unroll
    for (int mi = 0; mi < 2; mi++)
        #pragma unroll
        for (int h2 = 0; h2 < 2; h2++) {
            int row = wm*32 + mi*16 + g + 8*h2;
            __half* rp = Ph + row*RW3 + wn*96 + 2*t4;
            #pragma unroll
            for (int ni = 0; ni < 12; ni++)
                *(uint32_t*)(rp + ni*8) = pack_h2(acc[mi][ni][2*h2], acc[mi][ni][2*h2+1]);
        }
    const __half* vbase = vt + (long long)bh*HD*NN;
    #pragma unroll
    for (int p = 0; p < 6; p++) {
        int u = tid + (p << 9);
        int r = u / 48, c = u - r*48;
        *(uint4*)(Vs + r*RW3 + c*8) = *(const uint4*)(vbase + r*NN + c*8);
    }
    __syncthreads();

    const int wm2 = w >> 2, wn2 = w & 3;
    const uint32_t pa = smem_u32(Ph) + ((wm2*32 + (lane & 15))*RW3 + ((lane >> 4) << 3))*2;
    const uint32_t pb = smem_u32(Vs) + ((wn2*16 + (lane & 15))*RW3 + ((lane >> 4) << 3))*2;

    float acc2[2][2][4];
    #pragma unroll
    for (int mi = 0; mi < 2; mi++)
        #pragma unroll
        for (int ni = 0; ni < 2; ni++)
            #pragma unroll
            for (int j = 0; j < 4; j++) acc2[mi][ni][j] = 0.f;

    #pragma unroll
    for (int ks = 0; ks < 24; ks++) {
        const uint32_t kb = ks * 32;
        uint32_t ah0[4], ah1[4], q0, q1, q2, q3;
        ldsm4(ah0[0], ah0[1], ah0[2], ah0[3], pa + kb);
        ldsm4(ah1[0], ah1[1], ah1[2], ah1[3], pa + 16*RW3*2 + kb);
        ldsm4(q0, q1, q2, q3, pb + kb);
        uint32_t b0[2] = {q0, q2}, b1[2] = {q1, q3};
        mma16816h(acc2[0][0], ah0, b0);
        mma16816h(acc2[0][1], ah0, b1);
        mma16816h(acc2[1][0], ah1, b0);
        mma16816h(acc2[1][1], ah1, b1);
    }

    #pragma unroll
    for (int mi = 0; mi < 2; mi++) {
        int r0 = wm2*32 + mi*16 + g;
        float inv0 = invb[r0], inv1 = invb[r0 + 8];
        long long base0 = ((long long)b*NN + m0 + r0)*DIM + hh*HD;
        long long base1 = base0 + 8LL*DIM;
        #pragma unroll
        for (int ni = 0; ni < 2; ni++) {
            int col = wn2*16 + ni*8 + 2*t4;
            *(uint32_t*)(ao + base0 + col) = pack_h2(acc2[mi][ni][0]*inv0, acc2[mi][ni][1]*inv0);
            *(uint32_t*)(ao + base1 + col) = pack_h2(acc2[mi][ni][2]*inv1, acc2[mi][ni][3]*inv1);
        }
    }
}

// ---------------- LayerNorm over 768 features -------------------------------
template<typename TO>
__global__ void ln_kernel(const float* __restrict__ in, TO* __restrict__ out,
                          const float* __restrict__ g, const float* __restrict__ b,
                          long long in_bstride, long long out_bstride)
{
    const float* x = in  + (long long)blockIdx.y*in_bstride  + (long long)blockIdx.x*DIM;
    TO*          y = out + (long long)blockIdx.y*out_bstride + (long long)blockIdx.x*DIM;
    int tid = threadIdx.x;
    float v0 = x[tid], v1 = x[tid+256], v2 = x[tid+512];
    __shared__ float sh[256];
    sh[tid] = v0 + v1 + v2;
    __syncthreads();
    for (int o = 128; o > 0; o >>= 1) { if (tid < o) sh[tid] += sh[tid+o]; __syncthreads(); }
    float mean = sh[0] * (1.f/768.f);
    __syncthreads();
    float d0 = v0-mean, d1 = v1-mean, d2 = v2-mean;
    sh[tid] = d0*d0 + d1*d1 + d2*d2;
    __syncthreads();
    for (int o = 128; o > 0; o >>= 1) { if (tid < o) sh[tid] += sh[tid+o]; __syncthreads(); }
    float inv = rsqrtf(sh[0] * (1.f/768.f) + 1e-5f);
    st_s(y + tid,     d0*inv*g[tid]     + b[tid]);
    st_s(y + tid+256, d1*inv*g[tid+256] + b[tid+256]);
    st_s(y + tid+512, d2*inv*g[tid+512] + b[tid+512]);
}

__global__ void ln_cat_kernel(const float* __restrict__ zf, const float* __restrict__ x,
                              __half* __restrict__ out,
                              const float* __restrict__ g, const float* __restrict__ b)
{
    int t = blockIdx.x, bb = blockIdx.y;
    const float* src = (t < ZL) ? zf + ((long long)bb*ZL + t)*DIM
                                : x  + ((long long)bb*TT + (t - ZL))*DIM;
    __half* y = out + ((long long)bb*NN + t)*DIM;
    int tid = threadIdx.x;
    float v0 = src[tid], v1 = src[tid+256], v2 = src[tid+512];
    __shared__ float sh[256];
    sh[tid] = v0 + v1 + v2;
    __syncthreads();
    for (int o = 128; o > 0; o >>= 1) { if (tid < o) sh[tid] += sh[tid+o]; __syncthreads(); }
    float mean = sh[0] * (1.f/768.f);
    __syncthreads();
    float d0 = v0-mean, d1 = v1-mean, d2 = v2-mean;
    sh[tid] = d0*d0 + d1*d1 + d2*d2;
    __syncthreads();
    for (int o = 128; o > 0; o >>= 1) { if (tid < o) sh[tid] += sh[tid+o]; __syncthreads(); }
    float inv = rsqrtf(sh[0] * (1.f/768.f) + 1e-5f);
    y[tid]     = __float2half_rn(d0*inv*g[tid]     + b[tid]);
    y[tid+256] = __float2half_rn(d1*inv*g[tid+256] + b[tid+256]);
    y[tid+512] = __float2half_rn(d2*inv*g[tid+512] + b[tid+512]);
}

// ---------------- fusion ----------------
__global__ void fusion_kernel(const float* __restrict__ ax, const float* __restrict__ axi,
                              float* __restrict__ alpha_o, float* __restrict__ um_o,
                              float* __restrict__ u_o, float* __restrict__ ui_o)
{
    int b = blockIdx.x, s = threadIdx.x;
    const float* X  = ax  + (long long)b*ZL*SL + s;
    const float* Xi = axi + (long long)b*ZL*SL + s;
    float u, ui;
    {
        float mx = -1e30f;
        for (int t = 0; t < ZL; t++) mx = fmaxf(mx, X[t*SL]);
        float sum = 0.f;
        for (int t = 0; t < ZL; t++) sum += expf(X[t*SL] - mx);
        float inv = 1.f/sum, acc = 0.f;
        for (int t = 0; t < ZL; t++) { float p = expf(X[t*SL]-mx)*inv; acc -= p*logf(p + 1e-8f); }
        u = acc;
    }
    {
        float mx = -1e30f;
        for (int t = 0; t < ZL; t++) mx = fmaxf(mx, Xi[t*SL]);
        float sum = 0.f;
        for (int t = 0; t < ZL; t++) sum += expf(Xi[t*SL] - mx);
        float inv = 1.f/sum, acc = 0.f;
        for (int t = 0; t < ZL; t++) { float p = expf(Xi[t*SL]-mx)*inv; acc -= p*logf(p + 1e-8f); }
        ui = acc;
    }
    int idx = b*SL + s;
    float alpha = 1.f / (1.f + expf(-(ui - u)));
    alpha_o[idx] = alpha;
    um_o[idx] = 0.5f*(u + ui);
    u_o[idx] = u;
    ui_o[idx] = ui;
}

// ---------------- elementwise helpers ----------------
__global__ void cat_feat_k(const float* __restrict__ x, const float* __restrict__ xi,
                           __half* __restrict__ o)
{
    long long i = (long long)blockIdx.x*blockDim.x + threadIdx.x;
    const long long n = (long long)BATCH*ZL*2*DIM;
    if (i >= n) return;
    int c = (int)(i % (2*DIM));
    long long bt = i / (2*DIM);
    long long b = bt / ZL, t = bt % ZL;
    long long src = (b*TT + t)*DIM;
    float v = (c < DIM) ? x[src + c] : xi[src + c - DIM];
    o[i] = __float2half_rn(v);
}

__global__ void vtrans_k(const float* __restrict__ qkv, __half* __restrict__ vt)
{
    __shared__ float t[32][33];
    int bh = blockIdx.z;
    long long b = bh / HEADS, h = bh % HEADS;
    const float* src = qkv + b*NN*QKV3 + 2*DIM + h*HD;
    int tt0 = blockIdx.x*32;
    int cc0 = blockIdx.y*32;
    int tx = threadIdx.x, ty = threadIdx.y;
    #pragma unroll
    for (int i = 0; i < 32; i += 8)
        t[ty+i][tx] = src[(long long)(tt0+ty+i)*QKV3 + cc0 + tx];
    __syncthreads();
    __half* dst = vt + ((long long)bh*HD)*NN;
    #pragma unroll
    for (int i = 0; i < 32; i += 8)
        dst[(long long)(cc0+ty+i)*NN + tt0 + tx] = __float2half_rn(t[tx][ty+i]);
}

__global__ void make_v_k(const float* __restrict__ ns, const float* __restrict__ nsi,
                         const float* __restrict__ alpha, __half* __restrict__ v)
{
    long long i = (long long)blockIdx.x*blockDim.x + threadIdx.x;
    const long long n = (long long)BATCH*SL*DIM;
    if (i >= n) return;
    long long bs = i / DIM;
    float a = alpha[bs];
    v[i] = __float2half_rn(a*ns[i] + (1.f - a)*nsi[i]);
}

__global__ void make_vfc_k(const float* __restrict__ xiattn, const float* __restrict__ vf,
                           float* __restrict__ o)
{
    long long i = (long long)blockIdx.x*blockDim.x + threadIdx.x;
    const long long n = (long long)BATCH*TT*DIM;
    if (i >= n) return;
    int c = (int)(i % DIM);
    long long bt = i / DIM;
    long long b = bt / TT, t = bt % TT;
    o[i] = (t < ZL) ? xiattn[(b*NN + t)*DIM + c]
                    : vf[(b*SL + (t-ZL))*DIM + c];
}

__global__ void make_xnew_k(const float* __restrict__ x, const float* __restrict__ xi,
                            const float* __restrict__ xattn, const float* __restrict__ xiattn,
                            const float* __restrict__ vfc,
                            float* __restrict__ xo, float* __restrict__ xio)
{
    long long i = (long long)blockIdx.x*blockDim.x + threadIdx.x;
    const long long n = (long long)BATCH*TT*DIM;
    if (i >= n) return;
    int c = (int)(i % DIM);
    long long bt = i / DIM;
    long long b = bt / TT, t = bt % TT;
    long long aidx = (b*NN + ZL + t)*DIM + c;
    float vf = vfc[i];
    xo[i]  = x[i]  + xattn[aidx]  + vf;
    xio[i] = xi[i] + xiattn[aidx] + vf;
}

__global__ void i2f_k(const int* __restrict__ in, float* __restrict__ out, int n)
{
    int i = blockIdx.x*blockDim.x + threadIdx.x;
    if (i < n) out[i] = (float)in[i];
}

__global__ void f2h_k(const float* __restrict__ in, __half* __restrict__ out, int n4)
{
    int i = blockIdx.x*blockDim.x + threadIdx.x;
    if (i < n4) {
        float4 v = *(const float4*)(in + 4*i);
        *(uint2*)(out + 4*i) = to_h2(v);
    }
}

// ---------------- host-side helpers ----------------
template<int TM, int TN, typename TA, typename TB, typename TC>
static inline void mm(const TA* A, const TB* B, const float* bias,
                      const float* r1, const float* r2, TC* C,
                      int M, int N, int K, int lda, int ldb, int ldc,
                      long long sAb, long long sBb, long long sCb,
                      int nb, int nh,
                      long long sAh, long long sBh, long long sCh,
                      float alpha, int act)
{
    constexpr int STAGE_BYTES = (TM*RWH + TN*RWH)*2;
    constexpr int EPI = 32*(TN+4)*4;
    constexpr int DS = (2*STAGE_BYTES > EPI) ? 2*STAGE_BYTES : EPI;
    static bool init = false;
    if (!init) {
        cudaFuncSetAttribute(mm2<TM,TN,TA,TB,TC>, cudaFuncAttributeMaxDynamicSharedMemorySize, DS);
        init = true;
    }
    dim3 g(N/TN, M/TM, nb*nh);
    mm2<TM,TN,TA,TB,TC><<<g, 512, DS>>>(A,B,bias,r1,r2,C,K,lda,ldb,ldc,sAb,sBb,sCb,nh,sAh,sBh,sCh,alpha,act);
}

static inline int cdiv(long long a, int b) { return (int)((a + b - 1) / b); }

extern "C" void kernel_launch(void* const* d_in, const int* in_sizes, int n_in,
                              void* d_out, int out_size)
{
    const float* x      = (const float*)d_in[0];
    const float* xi     = (const float*)d_in[1];
    const int*   git    = (const int*)  d_in[2];
    const int*   giti   = (const int*)  d_in[3];
    const int*   gis    = (const int*)  d_in[4];
    const int*   gisi   = (const int*)  d_in[5];
    const float* w_qkv  = (const float*)d_in[6];
    const float* b_qkv  = (const float*)d_in[7];
    const float* w_proj = (const float*)d_in[8];
    const float* b_proj = (const float*)d_in[9];
    const float* g1     = (const float*)d_in[10];
    const float* bt1    = (const float*)d_in[11];
    const float* g2     = (const float*)d_in[12];
    const float* bt2    = (const float*)d_in[13];
    const float* w_fc1  = (const float*)d_in[14];
    const float* b_fc1  = (const float*)d_in[15];
    const float* w_fc2  = (const float*)d_in[16];
    const float* b_fc2  = (const float*)d_in[17];
    const float* w_al   = (const float*)d_in[18];
    const float* b_al   = (const float*)d_in[19];
    const float* w_al2  = (const float*)d_in[20];
    const float* b_al2  = (const float*)d_in[21];
    const float* w_fus  = (const float*)d_in[22];
    const float* b_fus  = (const float*)d_in[23];
    float* out = (float*)d_out;

    float *p_zf, *p_ns, *p_nsi, *p_attnx, *p_attnxi, *p_qkv,
          *p_xattn, *p_xiattn, *p_vf, *p_vfc, *p_xnew, *p_xinew, *p_adap2;
    __half *p_cath, *p_lnh, *p_vth, *p_aoh, *p_hh, *p_vh;
    __half *wqkvh, *wprojh, *wfc1h, *wfc2h, *walh, *wal2h, *wfush;
    cudaGetSymbolAddress((void**)&p_cath,  g_cath);
    cudaGetSymbolAddress((void**)&p_zf,    g_zf);
    cudaGetSymbolAddress((void**)&p_ns,    g_ns);
    cudaGetSymbolAddress((void**)&p_nsi,   g_nsi);
    cudaGetSymbolAddress((void**)&p_attnx, g_attnx);
    cudaGetSymbolAddress((void**)&p_attnxi,g_attnxi);
    cudaGetSymbolAddress((void**)&p_lnh,   g_lnh);
    cudaGetSymbolAddress((void**)&p_qkv,   g_qkv);
    cudaGetSymbolAddress((void**)&p_vth,   g_vth);
    cudaGetSymbolAddress((void**)&p_aoh,   g_aoh);
    cudaGetSymbolAddress((void**)&p_xattn, g_xattn);
    cudaGetSymbolAddress((void**)&p_xiattn,g_xiattn);
    cudaGetSymbolAddress((void**)&p_vh,    g_vh);
    cudaGetSymbolAddress((void**)&p_vf,    g_vf);
    cudaGetSymbolAddress((void**)&p_vfc,   g_vfc);
    cudaGetSymbolAddress((void**)&p_xnew,  g_xnew);
    cudaGetSymbolAddress((void**)&p_xinew, g_xinew);
    cudaGetSymbolAddress((void**)&p_adap2, g_adap2);
    cudaGetSymbolAddress((void**)&p_hh,    g_hh);
    cudaGetSymbolAddress((void**)&wqkvh,   g_wqkvh);
    cudaGetSymbolAddress((void**)&wprojh,  g_wprojh);
    cudaGetSymbolAddress((void**)&wfc1h,   g_wfc1h);
    cudaGetSymbolAddress((void**)&wfc2h,   g_wfc2h);
    cudaGetSymbolAddress((void**)&walh,    g_walh);
    cudaGetSymbolAddress((void**)&wal2h,   g_wal2h);
    cudaGetSymbolAddress((void**)&wfush,   g_wfush);

    const float scale_dim = 1.f / sqrtf((float)DIM);

    // ---- ordered so launch index 5 is a representative mm2 (ncu -s 5 -c 1) ----
    f2h_k<<<cdiv(DIM*2*DIM/4,256),256>>>(w_al, walh,   DIM*2*DIM/4);             // 0
    cat_feat_k<<<cdiv((long long)BATCH*ZL*2*DIM, 256), 256>>>(x, xi, p_cath);    // 1
    f2h_k<<<cdiv(QKV3*DIM/4,256),256>>>(w_qkv,  wqkvh,  QKV3*DIM/4);             // 2
    f2h_k<<<cdiv(HID*DIM/4,256),256>>>(w_fc1,  wfc1h,  HID*DIM/4);               // 3
    f2h_k<<<cdiv(DIM*HID/4,256),256>>>(w_fc2,  wfc2h,  DIM*HID/4);               // 4
    mm<128,128,__half,__half,float>(p_cath, walh, b_al, nullptr, nullptr, p_zf,  // 5 <- profiled
        BATCH*ZL, DIM, 2*DIM, 2*DIM, 2*DIM, DIM, 0,0,0, 1,1, 0,0,0, 1.f, 0);
    f2h_k<<<cdiv(DIM*DIM/4,256),256>>>(w_proj, wprojh, DIM*DIM/4);
    f2h_k<<<cdiv(DIM*DIM/4,256),256>>>(w_al2,  wal2h,  DIM*DIM/4);
    f2h_k<<<cdiv(DIM*DIM/4,256),256>>>(w_fus,  wfush,  DIM*DIM/4);

    // ---- ns/nsi ----
    ln_kernel<float><<<dim3(SL, BATCH), 256>>>(x  + (long long)ZL*DIM, p_ns,  g1, bt1,
                                               (long long)TT*DIM, (long long)SL*DIM);
    ln_kernel<float><<<dim3(SL, BATCH), 256>>>(xi + (long long)ZL*DIM, p_nsi, g1, bt1,
                                               (long long)TT*DIM, (long long)SL*DIM);

    // ---- MHA both streams ----
    {
        static bool ainit = false;
        if (!ainit) {
            cudaFuncSetAttribute(attn_fused, cudaFuncAttributeMaxDynamicSharedMemorySize, PV_SMEM);
            ainit = true;
        }
    }
    const float* src[2]    = {x, xi};
    float*       attn_o[2] = {out + O_ATTN, out + O_IATTN};
    float*       proj_o[2] = {p_xattn, p_xiattn};
    for (int side = 0; side < 2; side++) {
        ln_cat_kernel<<<dim3(NN, BATCH), 256>>>(p_zf, src[side], p_lnh, g1, bt1);
        mm<128,128,__half,__half,float>(p_lnh, wqkvh, b_qkv, nullptr, nullptr, p_qkv,
            BATCH*NN, QKV3, DIM, DIM, DIM, QKV3, 0,0,0, 1,1, 0,0,0, 1.f, 0);
        vtrans_k<<<dim3(NN/32, HD/32, BATCH*HEADS), dim3(32,8)>>>(p_qkv, p_vth);
        attn_fused<<<dim3(3, BATCH*HEADS), 512, PV_SMEM>>>(p_qkv, p_vth, attn_o[side], p_aoh);
        mm<128,128,__half,__half,float>(p_aoh, wprojh, b_proj, nullptr, nullptr, proj_o[side],
            BATCH*NN, DIM, DIM, DIM, DIM, DIM, 0,0,0, 1,1, 0,0,0, 1.f, 0);
    }

    // ---- attn_x / attn_xi (small; float path) ----
    mm<64,128,float,float,float>(p_zf, p_ns, nullptr, nullptr, nullptr, p_attnx,
        ZL, SL, DIM, DIM, DIM, SL,
        (long long)ZL*DIM, (long long)SL*DIM, (long long)ZL*SL,
        BATCH, 1, 0,0,0, scale_dim, 0);
    mm<64,128,float,float,float>(p_zf, p_nsi, nullptr, nullptr, nullptr, p_attnxi,
        ZL, SL, DIM, DIM, DIM, SL,
        (long long)ZL*DIM, (long long)SL*DIM, (long long)ZL*SL,
        BATCH, 1, 0,0,0, scale_dim, 0);

    // ---- fusion ----
    fusion_kernel<<<BATCH, SL>>>(p_attnx, p_attnxi,
                                 out + O_ALPHA, out + O_UM, out + O_U, out + O_UI);
    make_v_k<<<cdiv((long long)BATCH*SL*DIM, 256), 256>>>(p_ns, p_nsi, out + O_ALPHA, p_vh);
    mm<128,128,__half,__half,float>(p_vh, wfush, b_fus, nullptr, nullptr, p_vf,
        BATCH*SL, DIM, DIM, DIM, DIM, DIM, 0,0,0, 1,1, 0,0,0, 1.f, 0);
    make_vfc_k<<<cdiv((long long)BATCH*TT*DIM, 256), 256>>>(p_xiattn, p_vf, p_vfc);

    // ---- residual adds ----
    make_xnew_k<<<cdiv((long long)BATCH*TT*DIM, 256), 256>>>(
        x, xi, p_xattn, p_xiattn, p_vfc, p_xnew, p_xinew);

    // ---- adap2 ----
    ln_kernel<__half><<<dim3(TT, BATCH), 256>>>(p_vfc, p_lnh, g2, bt2,
                                                (long long)TT*DIM, (long long)TT*DIM);
    mm<128,128,__half,__half,float>(p_lnh, wal2h, b_al2, nullptr, nullptr, p_adap2,
        BATCH*TT, DIM, DIM, DIM, DIM, DIM, 0,0,0, 1,1, 0,0,0, 1.f, 0);

    // ---- MLP both streams ----
    float* xn[2] = {p_xnew, p_xinew};
    float* xo[2] = {out + O_XOUT, out + O_XIOUT};
    for (int side = 0; side < 2; side++) {
        ln_kernel<__half><<<dim3(TT, BATCH), 256>>>(xn[side], p_lnh, g2, bt2,
                                                    (long long)TT*DIM, (long long)TT*DIM);
        mm<128,128,__half,__half,__half>(p_lnh, wfc1h, b_fc1, nullptr, nullptr, p_hh,
            BATCH*TT, HID, DIM, DIM, DIM, HID, 0,0,0, 1,1, 0,0,0, 1.f, 1);
        mm<128,128,__half,__half,float>(p_hh, wfc2h, b_fc2, xn[side], p_adap2, xo[side],
            BATCH*TT, DIM, HID, HID, HID, DIM, 0,0,0, 1,1, 0,0,0, 1.f, 0);
    }

    // ---- index passthroughs ----
    i2f_k<<<cdiv(BATCH*ZL, 256), 256>>>(git,  out + O_GIT,  BATCH*ZL);
    i2f_k<<<cdiv(BATCH*SL, 256), 256>>>(gis,  out + O_GIS,  BATCH*SL);
    i2f_k<<<cdiv(BATCH*ZL, 256), 256>>>(giti, out + O_GITI, BATCH*ZL);
    i2f_k<<<cdiv(BATCH*SL, 256), 256>>>(gisi, out + O_GISI, BATCH*SL);
}

// round 9
// speedup vs baseline: 5.9347x; 1.1386x over previous
#include <cuda_runtime.h>
#include <cuda_fp16.h>
#include <math.h>
#include <cstdint>
#include <type_traits>

// ---------------- problem constants ----------------
#define BATCH 32
#define ZL 64
#define SL 256
#define TT 320
#define NN 384
#define DIM 768
#define HEADS 12
#define HD 64
#define HID 3072
#define QKV3 2304

#define O_XOUT   0LL
#define O_GIT    7864320LL
#define O_GIS    7866368LL
#define O_ATTN   7874560LL
#define O_XIOUT  64497664LL
#define O_GITI   72361984LL
#define O_GISI   72364032LL
#define O_IATTN  72372224LL
#define O_ALPHA  128995328LL
#define O_UM     129003520LL
#define O_U      129011712LL
#define O_UI     129019904LL

// ---------------- scratch ----------------
__device__ __half g_cath [BATCH*ZL*2*DIM];
__device__ float  g_zf   [BATCH*ZL*DIM];
__device__ __half g_nsh  [BATCH*SL*DIM];
__device__ __half g_nsih [BATCH*SL*DIM];
__device__ float  g_attnx [BATCH*ZL*SL];
__device__ float  g_attnxi[BATCH*ZL*SL];
__device__ __half g_lnh  [BATCH*NN*DIM];
__device__ __half g_qkvh [BATCH*NN*QKV3];
__device__ __half g_vth  [BATCH*HEADS*HD*NN];
__device__ __half g_aoh  [BATCH*NN*DIM];
__device__ float  g_xattn [BATCH*NN*DIM];
__device__ float  g_xiattn[BATCH*NN*DIM];
__device__ __half g_vh   [BATCH*SL*DIM];
__device__ float  g_vfc  [BATCH*TT*DIM];
__device__ float  g_xnew [BATCH*TT*DIM];
__device__ float  g_xinew[BATCH*TT*DIM];
__device__ float  g_adap2[BATCH*TT*DIM];
__device__ __half g_hh   [BATCH*TT*HID];
__device__ __half g_wqkvh[QKV3*DIM];
__device__ __half g_wprojh[DIM*DIM];
__device__ __half g_wfc1h[HID*DIM];
__device__ __half g_wfc2h[DIM*HID];
__device__ __half g_walh [DIM*2*DIM];
__device__ __half g_wal2h[DIM*DIM];
__device__ __half g_wfush[DIM*DIM];

// =============== helpers =====================================================
__device__ __forceinline__ uint32_t smem_u32(const void* p) {
    uint32_t a;
    asm("{ .reg .u64 t; cvta.to.shared.u64 t, %1; cvt.u32.u64 %0, t; }" : "=r"(a) : "l"(p));
    return a;
}
__device__ __forceinline__ void mma16816h(float* d, const uint32_t* a, const uint32_t* b) {
    asm volatile("mma.sync.aligned.m16n8k16.row.col.f32.f16.f16.f32 "
        "{%0,%1,%2,%3}, {%4,%5,%6,%7}, {%8,%9}, {%0,%1,%2,%3};"
        : "+f"(d[0]), "+f"(d[1]), "+f"(d[2]), "+f"(d[3])
        : "r"(a[0]), "r"(a[1]), "r"(a[2]), "r"(a[3]), "r"(b[0]), "r"(b[1]));
}
__device__ __forceinline__ void ldsm4(uint32_t& r0, uint32_t& r1, uint32_t& r2, uint32_t& r3,
                                      uint32_t addr) {
    asm volatile("ldmatrix.sync.aligned.m8n8.x4.shared.b16 {%0,%1,%2,%3}, [%4];"
        : "=r"(r0), "=r"(r1), "=r"(r2), "=r"(r3) : "r"(addr));
}
__device__ __forceinline__ uint32_t pack_h2(float x, float y) {
    __half2 p = __float22half2_rn(make_float2(x, y));
    return *(uint32_t*)&p;
}
template<typename T> struct RawVec;
template<> struct RawVec<float>  { using type = float4; };
template<> struct RawVec<__half> { using type = uint2;  };
__device__ __forceinline__ uint2 to_h2(const float4& v) {
    return make_uint2(pack_h2(v.x, v.y), pack_h2(v.z, v.w));
}
__device__ __forceinline__ uint2 to_h2(const uint2& v) { return v; }
__device__ __forceinline__ void st_out4(float* p, float4 v) { *(float4*)p = v; }
__device__ __forceinline__ void st_out4(__half* p, float4 v) {
    *(uint2*)p = make_uint2(pack_h2(v.x, v.y), pack_h2(v.z, v.w));
}
__device__ __forceinline__ void st_s(float* p, float v)  { *p = v; }
__device__ __forceinline__ void st_s(__half* p, float v) { *p = __float2half_rn(v); }

#define CP_ASYNC16(dst, src) \
    asm volatile("cp.async.cg.shared.global [%0], [%1], 16;" :: "r"(dst), "l"(src))
#define CP_COMMIT()  asm volatile("cp.async.commit_group;")
#define CP_WAIT1()   asm volatile("cp.async.wait_group 1;")
#define CP_WAIT0()   asm volatile("cp.async.wait_group 0;")

// =============== fp16 mma.sync GEMM, typed A/B/C =============================
#define RWH 40          // sync path: 32-K chunk rows (+8 pad)
#define RWA 72          // async path: 64-K chunk rows (+8 pad)

template<int TM, int TN, typename TA, typename TB, typename TC>
__global__ __launch_bounds__(512, 2)
void mm2(const TA* __restrict__ A, const TB* __restrict__ B,
         const float* __restrict__ bias,
         const float* __restrict__ res1, const float* __restrict__ res2,
         TC* __restrict__ C,
         int K, int lda, int ldb, int ldc,
         long long sAb, long long sBb, long long sCb, int batchH,
         long long sAh, long long sBh, long long sCh,
         float alpha, int act)
{
    extern __shared__ char dsm[];
    constexpr int WTM = TM/4, WTN = TN/4;
    constexpr int MI = WTM/16, NI = WTN/8;
    constexpr bool ASYNC = (TM == 128) &&
        std::is_same<TA,__half>::value && std::is_same<TB,__half>::value;

    const int tid  = threadIdx.x;
    const int lane = tid & 31;
    const int w    = tid >> 5;
    const int wm   = w >> 2;
    const int wn   = w & 3;

    const int bz = blockIdx.z;
    const int b  = bz / batchH;
    const int h  = bz - b*batchH;
    const int m0 = blockIdx.y * TM;
    const int n0 = blockIdx.x * TN;
    const TA* Ab = A + (long long)b*sAb + (long long)h*sAh + (long long)m0*lda;
    const TB* Bb = B + (long long)b*sBb + (long long)h*sBh + (long long)n0*ldb;
    const long long coff = (long long)b*sCb + (long long)h*sCh;

    const uint32_t sb0 = smem_u32(dsm);

    float acc[MI][NI][4];
    #pragma unroll
    for (int mi = 0; mi < MI; mi++)
        #pragma unroll
        for (int ni = 0; ni < NI; ni++)
            #pragma unroll
            for (int j = 0; j < 4; j++) acc[mi][ni][j] = 0.f;

    if constexpr (ASYNC) {
        constexpr int AHL = TM*RWA;                  // halves
        constexpr int STAGE_BYTES = (TM + TN)*RWA*2;
        constexpr int PLA = TM*8/512, PLB = TN*8/512;
        const uint32_t a_l = (uint32_t)(((wm*WTM + (lane & 15))*RWA + ((lane >> 4) << 3)) * 2);
        const uint32_t b_l = (uint32_t)(AHL*2 + ((wn*WTN + (lane & 15))*RWA + ((lane >> 4) << 3)) * 2);
        const __half* Abh = (const __half*)Ab;
        const __half* Bbh = (const __half*)Bb;
        const int NC = K >> 6;

        // prologue: stage 0
        #pragma unroll
        for (int p = 0; p < PLA; p++) {
            int u = tid + (p << 9);
            int r = u >> 3, ch = u & 7;
            CP_ASYNC16(sb0 + (uint32_t)(r*RWA*2 + ch*16),
                       Abh + (long long)r*lda + ch*8);
        }
        #pragma unroll
        for (int p = 0; p < PLB; p++) {
            int u = tid + (p << 9);
            int r = u >> 3, ch = u & 7;
            CP_ASYNC16(sb0 + (uint32_t)(AHL*2 + r*RWA*2 + ch*16),
                       Bbh + (long long)r*ldb + ch*8);
        }
        CP_COMMIT();

        for (int c = 0; c < NC; c++) {
            const int st = c & 1;
            if (c + 1 < NC) {
                const int k0 = (c + 1) << 6;
                const uint32_t base = sb0 + ((c + 1) & 1) * STAGE_BYTES;
                #pragma unroll
                for (int p = 0; p < PLA; p++) {
                    int u = tid + (p << 9);
                    int r = u >> 3, ch = u & 7;
                    CP_ASYNC16(base + (uint32_t)(r*RWA*2 + ch*16),
                               Abh + (long long)r*lda + k0 + ch*8);
                }
                #pragma unroll
                for (int p = 0; p < PLB; p++) {
                    int u = tid + (p << 9);
                    int r = u >> 3, ch = u & 7;
                    CP_ASYNC16(base + (uint32_t)(AHL*2 + r*RWA*2 + ch*16),
                               Bbh + (long long)r*ldb + k0 + ch*8);
                }
                CP_COMMIT();
                CP_WAIT1();
            } else {
                CP_WAIT0();
            }
            __syncthreads();

            const uint32_t stageu = sb0 + st * STAGE_BYTES;
            #pragma unroll
            for (int ks = 0; ks < 4; ks++) {
                const uint32_t kb = ks * 32;
                uint32_t ah[MI][4];
                #pragma unroll
                for (int mi = 0; mi < MI; mi++) {
                    uint32_t ad = stageu + a_l + mi*(16*RWA*2) + kb;
                    ldsm4(ah[mi][0], ah[mi][1], ah[mi][2], ah[mi][3], ad);
                }
                uint32_t bh[NI][2];
                #pragma unroll
                for (int nj = 0; nj < NI/2; nj++) {
                    uint32_t bd = stageu + b_l + nj*(16*RWA*2) + kb;
                    uint32_t q0, q1, q2, q3;
                    ldsm4(q0, q1, q2, q3, bd);
                    bh[2*nj][0] = q0; bh[2*nj][1] = q2;
                    bh[2*nj+1][0] = q1; bh[2*nj+1][1] = q3;
                }
                #pragma unroll
                for (int mi = 0; mi < MI; mi++)
                    #pragma unroll
                    for (int ni = 0; ni < NI; ni++)
                        mma16816h(acc[mi][ni], ah[mi], bh[ni]);
            }
            __syncthreads();
        }
    } else {
        constexpr int AHL = TM*RWH;
        constexpr int STAGE_BYTES = (TM + TN)*RWH*2;
        constexpr int PA = TM/64, PB = TN/64;
        const uint32_t a_l = (uint32_t)(((wm*WTM + (lane & 15))*RWH + ((lane >> 4) << 3)) * 2);
        const uint32_t b_l = (uint32_t)(AHL*2 + ((wn*WTN + (lane & 15))*RWH + ((lane >> 4) << 3)) * 2);
        const int lq = tid & 7;
        const int lr = tid >> 3;
        const int NC = K >> 5;
        typename RawVec<TA>::type pA[PA];
        typename RawVec<TB>::type pB[PB];

        #pragma unroll
        for (int p = 0; p < PA; p++)
            pA[p] = *(const typename RawVec<TA>::type*)(Ab + (long long)(lr + 64*p)*lda + 4*lq);
        #pragma unroll
        for (int p = 0; p < PB; p++)
            pB[p] = *(const typename RawVec<TB>::type*)(Bb + (long long)(lr + 64*p)*ldb + 4*lq);

        for (int c = 0; c < NC; c++) {
            const int st = c & 1;
            char* sb = dsm + st * STAGE_BYTES;
            __half* Ah = (__half*)sb;
            __half* Bh = Ah + AHL;

            #pragma unroll
            for (int p = 0; p < PA; p++)
                *(uint2*)(Ah + (lr + 64*p)*RWH + 4*lq) = to_h2(pA[p]);
            #pragma unroll
            for (int p = 0; p < PB; p++)
                *(uint2*)(Bh + (lr + 64*p)*RWH + 4*lq) = to_h2(pB[p]);
            __syncthreads();

            if (c + 1 < NC) {
                const int k0 = (c + 1) << 5;
                #pragma unroll
                for (int p = 0; p < PA; p++)
                    pA[p] = *(const typename RawVec<TA>::type*)(Ab + (long long)(lr + 64*p)*lda + k0 + 4*lq);
                #pragma unroll
                for (int p = 0; p < PB; p++)
                    pB[p] = *(const typename RawVec<TB>::type*)(Bb + (long long)(lr + 64*p)*ldb + k0 + 4*lq);
            }

            const uint32_t stageu = sb0 + st * STAGE_BYTES;
            #pragma unroll
            for (int ks = 0; ks < 2; ks++) {
                const uint32_t kb = ks * 32;
                uint32_t ah[MI][4];
                #pragma unroll
                for (int mi = 0; mi < MI; mi++) {
                    uint32_t ad = stageu + a_l + mi*(16*RWH*2) + kb;
                    ldsm4(ah[mi][0], ah[mi][1], ah[mi][2], ah[mi][3], ad);
                }
                uint32_t bh[NI][2];
                #pragma unroll
                for (int nj = 0; nj < NI/2; nj++) {
                    uint32_t bd = stageu + b_l + nj*(16*RWH*2) + kb;
                    uint32_t q0, q1, q2, q3;
                    ldsm4(q0, q1, q2, q3, bd);
                    bh[2*nj][0] = q0; bh[2*nj][1] = q2;
                    bh[2*nj+1][0] = q1; bh[2*nj+1][1] = q3;
                }
                #pragma unroll
                for (int mi = 0; mi < MI; mi++)
                    #pragma unroll
                    for (int ni = 0; ni < NI; ni++)
                        mma16816h(acc[mi][ni], ah[mi], bh[ni]);
            }
            __syncthreads();
        }
    }

    // ---- epilogue: 32-row passes through SMEM ----
    constexpr int ROWW = TN + 4;
    constexpr int NPASS = TM / 32;
    float* sbuf = (float*)dsm;
    const int g = lane >> 2, t4 = lane & 3;
    const int my_pass = (wm*WTM) >> 5;
    const int my_lb   = (wm*WTM) & 31;

    #pragma unroll
    for (int pass = 0; pass < NPASS; pass++) {
        if (my_pass == pass) {
            #pragma unroll
            for (int mi = 0; mi < MI; mi++)
                #pragma unroll
                for (int ni = 0; ni < NI; ni++)
                    #pragma unroll
                    for (int j = 0; j < 4; j++) {
                        int row = my_lb + mi*16 + g + 8*(j >> 1);
                        int col = wn*WTN + ni*8 + 2*t4 + (j & 1);
                        sbuf[row*ROWW + col] = acc[mi][ni][j];
                    }
        }
        __syncthreads();
        #pragma unroll
        for (int p = 0; p < 32*TN/2048; p++) {
            int i4 = tid + (p << 9);
            int elem = i4 << 2;
            int rr = elem / TN;
            int cc = elem - rr*TN;
            float4 v = *(float4*)(sbuf + rr*ROWW + cc);
            v.x *= alpha; v.y *= alpha; v.z *= alpha; v.w *= alpha;
            if (bias) {
                float4 bb = *(const float4*)(bias + n0 + cc);
                v.x += bb.x; v.y += bb.y; v.z += bb.z; v.w += bb.w;
            }
            long long off = coff + (long long)(m0 + pass*32 + rr)*ldc + (n0 + cc);
            if (res1) {
                float4 a = *(const float4*)(res1 + off);
                v.x += a.x; v.y += a.y; v.z += a.z; v.w += a.w;
            }
            if (res2) {
                float4 a = *(const float4*)(res2 + off);
                v.x += a.x; v.y += a.y; v.z += a.z; v.w += a.w;
            }
            if (act == 1) {
                v.x = 0.5f*v.x*(1.f + erff(v.x*0.70710678118654752f));
                v.y = 0.5f*v.y*(1.f + erff(v.y*0.70710678118654752f));
                v.z = 0.5f*v.z*(1.f + erff(v.z*0.70710678118654752f));
                v.w = 0.5f*v.w*(1.f + erff(v.w*0.70710678118654752f));
            }
            st_out4(C + off, v);
        }
        __syncthreads();
    }
}

// =============== fused QK^T + softmax + P@V (qkv in fp16) ====================
#define RW2 72
#define RW3 392
#define PV_SMEM (128*RW3*2 + 64*RW3*2 + 128*4*4 + 128*4)

__global__ __launch_bounds__(512, 1)
void attn_fused(const __half* __restrict__ qkv, const __half* __restrict__ vt,
                float* __restrict__ attn, __half* __restrict__ ao)
{
    extern __shared__ char dsm[];
    __half* Ph  = (__half*)dsm;
    __half* Vs  = (__half*)(dsm + 128*RW3*2);
    float*  red = (float*)(dsm + 128*RW3*2 + 64*RW3*2);
    float*  invb= red + 128*4;
    __half* Qs  = (__half*)dsm;
    __half* Ks  = Qs + 128*RW2;

    const int tid = threadIdx.x;
    const int lane = tid & 31;
    const int w = tid >> 5;
    const int wm = w >> 2, wn = w & 3;
    const int g = lane >> 2, t4 = lane & 3;

    const int m0 = blockIdx.x * 128;
    const int bh = blockIdx.y;
    const int b  = bh / HEADS;
    const int hh = bh - b*HEADS;

    const __half* qbase = qkv + (long long)b*NN*QKV3 + hh*HD;

    // Q: 128 rows x 64 halves (8x16B per row)
    #pragma unroll
    for (int p = 0; p < 2; p++) {
        int u = tid + (p << 9);
        int r = u >> 3, ch = u & 7;
        *(uint4*)(Qs + r*RW2 + ch*8) =
            *(const uint4*)(qbase + (long long)(m0 + r)*QKV3 + ch*8);
    }
    // K: 384 rows
    #pragma unroll
    for (int p = 0; p < 6; p++) {
        int u = tid + (p << 9);
        int r = u >> 3, ch = u & 7;
        *(uint4*)(Ks + r*RW2 + ch*8) =
            *(const uint4*)(qbase + DIM + (long long)r*QKV3 + ch*8);
    }
    __syncthreads();

    const uint32_t sq = smem_u32(Qs);
    const uint32_t sk = smem_u32(Ks);
    const uint32_t a_l = sq + ((wm*32 + (lane & 15))*RW2 + ((lane >> 4) << 3)) * 2;
    const uint32_t b_l = sk + ((wn*96 + (lane & 15))*RW2 + ((lane >> 4) << 3)) * 2;

    float acc[2][12][4];
    #pragma unroll
    for (int mi = 0; mi < 2; mi++)
        #pragma unroll
        for (int ni = 0; ni < 12; ni++)
            #pragma unroll
            for (int j = 0; j < 4; j++) acc[mi][ni][j] = 0.f;

    #pragma unroll
    for (int ks = 0; ks < 4; ks++) {
        const uint32_t kb = ks * 32;
        uint32_t ah[2][4];
        #pragma unroll
        for (int mi = 0; mi < 2; mi++)
            ldsm4(ah[mi][0], ah[mi][1], ah[mi][2], ah[mi][3],
                  a_l + mi*(16*RW2*2) + kb);
        #pragma unroll
        for (int nj = 0; nj < 6; nj++) {
            uint32_t q0, q1, q2, q3;
            ldsm4(q0, q1, q2, q3, b_l + nj*(16*RW2*2) + kb);
            uint32_t b0[2] = {q0, q2}, b1[2] = {q1, q3};
            #pragma unroll
            for (int mi = 0; mi < 2; mi++) {
                mma16816h(acc[mi][2*nj],   ah[mi], b0);
                mma16816h(acc[mi][2*nj+1], ah[mi], b1);
            }
        }
    }

    #pragma unroll
    for (int mi = 0; mi < 2; mi++)
        #pragma unroll
        for (int ni = 0; ni < 12; ni++)
            #pragma unroll
            for (int j = 0; j < 4; j++) acc[mi][ni][j] *= 0.125f;

    float M[2][2];
    #pragma unroll
    for (int mi = 0; mi < 2; mi++)
        #pragma unroll
        for (int h2 = 0; h2 < 2; h2++) {
            float m = -1e30f;
            #pragma unroll
            for (int ni = 0; ni < 12; ni++)
                m = fmaxf(m, fmaxf(acc[mi][ni][2*h2], acc[mi][ni][2*h2+1]));
            m = fmaxf(m, __shfl_xor_sync(0xFFFFFFFFu, m, 1));
            m = fmaxf(m, __shfl_xor_sync(0xFFFFFFFFu, m, 2));
            if (t4 == 0) red[(wm*32 + mi*16 + g + 8*h2)*4 + wn] = m;
        }
    __syncthreads();
    #pragma unroll
    for (int mi = 0; mi < 2; mi++)
        #pragma unroll
        for (int h2 = 0; h2 < 2; h2++) {
            int row = wm*32 + mi*16 + g + 8*h2;
            M[mi][h2] = fmaxf(fmaxf(red[row*4], red[row*4+1]),
                              fmaxf(red[row*4+2], red[row*4+3]));
        }
    __syncthreads();

    float S[2][2];
    #pragma unroll
    for (int mi = 0; mi < 2; mi++)
        #pragma unroll
        for (int h2 = 0; h2 < 2; h2++) {
            float s = 0.f;
            #pragma unroll
            for (int ni = 0; ni < 12; ni++) {
                float e0 = __expf(acc[mi][ni][2*h2]   - M[mi][h2]);
                float e1 = __expf(acc[mi][ni][2*h2+1] - M[mi][h2]);
                acc[mi][ni][2*h2] = e0; acc[mi][ni][2*h2+1] = e1;
                s += e0 + e1;
            }
            s += __shfl_xor_sync(0xFFFFFFFFu, s, 1);
            s += __shfl_xor_sync(0xFFFFFFFFu, s, 2);
            if (t4 == 0) red[(wm*32 + mi*16 + g + 8*h2)*4 + wn] = s;
        }
    __syncthreads();
    #pragma unroll
    for (int mi = 0; mi < 2; mi++)
        #pragma unroll
        for (int h2 = 0; h2 < 2; h2++) {
            int row = wm*32 + mi*16 + g + 8*h2;
            float inv = 1.f / (red[row*4] + red[row*4+1] + red[row*4+2] + red[row*4+3]);
            S[mi][h2] = inv;
            if (wn == 0 && t4 == 0) invb[row] = inv;
        }

    float* abase = attn + (long long)bh*NN*NN;
    #pragma unroll
    for (int mi = 0; mi < 2; mi++)
        #pragma unroll
        for (int h2 = 0; h2 < 2; h2++) {
            int row = m0 + wm*32 + mi*16 + g + 8*h2;
            float inv = S[mi][h2];
            float* rp = abase + (long long)row*NN + wn*96 + 2*t4;
            #pragma unroll
            for (int ni = 0; ni < 12; ni++) {
                float2 o;
                o.x = acc[mi][ni][2*h2]   * inv;
                o.y = acc[mi][ni][2*h2+1] * inv;
                *(float2*)(rp + ni*8) = o;
            }
        }

    __syncthreads();

    #pragma unroll
    for (int mi = 0; mi < 2; mi++)
        #pragma unroll
        for (int h2 = 0; h2 < 2; h2++) {
            int row = wm*32 + mi*16 + g + 8*h2;
            __half* rp = Ph + row*RW3 + wn*96 + 2*t4;
            #pragma unroll
            for (int ni = 0; ni < 12; ni++)
                *(uint32_t*)(rp + ni*8) = pack_h2(acc[mi][ni][2*h2], acc[mi][ni][2*h2+1]);
        }
    const __half* vbase = vt + (long long)bh*HD*NN;
    #pragma unroll
    for (int p = 0; p < 6; p++) {
        int u = tid + (p << 9);
        int r = u / 48, c = u - r*48;
        *(uint4*)(Vs + r*RW3 + c*8) = *(const uint4*)(vbase + r*NN + c*8);
    }
    __syncthreads();

    const int wm2 = w >> 2, wn2 = w & 3;
    const uint32_t pa = smem_u32(Ph) + ((wm2*32 + (lane & 15))*RW3 + ((lane >> 4) << 3))*2;
    const uint32_t pb = smem_u32(Vs) + ((wn2*16 + (lane & 15))*RW3 + ((lane >> 4) << 3))*2;

    float acc2[2][2][4];
    #pragma unroll
    for (int mi = 0; mi < 2; mi++)
        #pragma unroll
        for (int ni = 0; ni < 2; ni++)
            #pragma unroll
            for (int j = 0; j < 4; j++) acc2[mi][ni][j] = 0.f;

    #pragma unroll
    for (int ks = 0; ks < 24; ks++) {
        const uint32_t kb = ks * 32;
        uint32_t ah0[4], ah1[4], q0, q1, q2, q3;
        ldsm4(ah0[0], ah0[1], ah0[2], ah0[3], pa + kb);
        ldsm4(ah1[0], ah1[1], ah1[2], ah1[3], pa + 16*RW3*2 + kb);
        ldsm4(q0, q1, q2, q3, pb + kb);
        uint32_t b0[2] = {q0, q2}, b1[2] = {q1, q3};
        mma16816h(acc2[0][0], ah0, b0);
        mma16816h(acc2[0][1], ah0, b1);
        mma16816h(acc2[1][0], ah1, b0);
        mma16816h(acc2[1][1], ah1, b1);
    }

    #pragma unroll
    for (int mi = 0; mi < 2; mi++) {
        int r0 = wm2*32 + mi*16 + g;
        float inv0 = invb[r0], inv1 = invb[r0 + 8];
        long long base0 = ((long long)b*NN + m0 + r0)*DIM + hh*HD;
        long long base1 = base0 + 8LL*DIM;
        #pragma unroll
        for (int ni = 0; ni < 2; ni++) {
            int col = wn2*16 + ni*8 + 2*t4;
            *(uint32_t*)(ao + base0 + col) = pack_h2(acc2[mi][ni][0]*inv0, acc2[mi][ni][1]*inv0);
            *(uint32_t*)(ao + base1 + col) = pack_h2(acc2[mi][ni][2]*inv1, acc2[mi][ni][3]*inv1);
        }
    }
}

// ---------------- LayerNorm over 768 features -------------------------------
template<typename TO>
__global__ void ln_kernel(const float* __restrict__ in, TO* __restrict__ out,
                          const float* __restrict__ g, const float* __restrict__ b,
                          long long in_bstride, long long out_bstride)
{
    const float* x = in  + (long long)blockIdx.y*in_bstride  + (long long)blockIdx.x*DIM;
    TO*          y = out + (long long)blockIdx.y*out_bstride + (long long)blockIdx.x*DIM;
    int tid = threadIdx.x;
    float v0 = x[tid], v1 = x[tid+256], v2 = x[tid+512];
    __shared__ float sh[256];
    sh[tid] = v0 + v1 + v2;
    __syncthreads();
    for (int o = 128; o > 0; o >>= 1) { if (tid < o) sh[tid] += sh[tid+o]; __syncthreads(); }
    float mean = sh[0] * (1.f/768.f);
    __syncthreads();
    float d0 = v0-mean, d1 = v1-mean, d2 = v2-mean;
    sh[tid] = d0*d0 + d1*d1 + d2*d2;
    __syncthreads();
    for (int o = 128; o > 0; o >>= 1) { if (tid < o) sh[tid] += sh[tid+o]; __syncthreads(); }
    float inv = rsqrtf(sh[0] * (1.f/768.f) + 1e-5f);
    st_s(y + tid,     d0*inv*g[tid]     + b[tid]);
    st_s(y + tid+256, d1*inv*g[tid+256] + b[tid+256]);
    st_s(y + tid+512, d2*inv*g[tid+512] + b[tid+512]);
}

__global__ void ln_cat_kernel(const float* __restrict__ zf, const float* __restrict__ x,
                              __half* __restrict__ out,
                              const float* __restrict__ g, const float* __restrict__ b)
{
    int t = blockIdx.x, bb = blockIdx.y;
    const float* src = (t < ZL) ? zf + ((long long)bb*ZL + t)*DIM
                                : x  + ((long long)bb*TT + (t - ZL))*DIM;
    __half* y = out + ((long long)bb*NN + t)*DIM;
    int tid = threadIdx.x;
    float v0 = src[tid], v1 = src[tid+256], v2 = src[tid+512];
    __shared__ float sh[256];
    sh[tid] = v0 + v1 + v2;
    __syncthreads();
    for (int o = 128; o > 0; o >>= 1) { if (tid < o) sh[tid] += sh[tid+o]; __syncthreads(); }
    float mean = sh[0] * (1.f/768.f);
    __syncthreads();
    float d0 = v0-mean, d1 = v1-mean, d2 = v2-mean;
    sh[tid] = d0*d0 + d1*d1 + d2*d2;
    __syncthreads();
    for (int o = 128; o > 0; o >>= 1) { if (tid < o) sh[tid] += sh[tid+o]; __syncthreads(); }
    float inv = rsqrtf(sh[0] * (1.f/768.f) + 1e-5f);
    y[tid]     = __float2half_rn(d0*inv*g[tid]     + b[tid]);
    y[tid+256] = __float2half_rn(d1*inv*g[tid+256] + b[tid+256]);
    y[tid+512] = __float2half_rn(d2*inv*g[tid+512] + b[tid+512]);
}

// ---------------- fusion ----------------
__global__ void fusion_kernel(const float* __restrict__ ax, const float* __restrict__ axi,
                              float* __restrict__ alpha_o, float* __restrict__ um_o,
                              float* __restrict__ u_o, float* __restrict__ ui_o)
{
    int b = blockIdx.x, s = threadIdx.x;
    const float* X  = ax  + (long long)b*ZL*SL + s;
    const float* Xi = axi + (long long)b*ZL*SL + s;
    float u, ui;
    {
        float mx = -1e30f;
        for (int t = 0; t < ZL; t++) mx = fmaxf(mx, X[t*SL]);
        float sum = 0.f;
        for (int t = 0; t < ZL; t++) sum += expf(X[t*SL] - mx);
        float inv = 1.f/sum, acc = 0.f;
        for (int t = 0; t < ZL; t++) { float p = expf(X[t*SL]-mx)*inv; acc -= p*logf(p + 1e-8f); }
        u = acc;
    }
    {
        float mx = -1e30f;
        for (int t = 0; t < ZL; t++) mx = fmaxf(mx, Xi[t*SL]);
        float sum = 0.f;
        for (int t = 0; t < ZL; t++) sum += expf(Xi[t*SL] - mx);
        float inv = 1.f/sum, acc = 0.f;
        for (int t = 0; t < ZL; t++) { float p = expf(Xi[t*SL]-mx)*inv; acc -= p*logf(p + 1e-8f); }
        ui = acc;
    }
    int idx = b*SL + s;
    float alpha = 1.f / (1.f + expf(-(ui - u)));
    alpha_o[idx] = alpha;
    um_o[idx] = 0.5f*(u + ui);
    u_o[idx] = u;
    ui_o[idx] = ui;
}

// ---------------- elementwise helpers ----------------
__global__ void cat_feat_k(const float* __restrict__ x, const float* __restrict__ xi,
                           __half* __restrict__ o)
{
    long long i = (long long)blockIdx.x*blockDim.x + threadIdx.x;
    const long long n = (long long)BATCH*ZL*2*DIM;
    if (i >= n) return;
    int c = (int)(i % (2*DIM));
    long long bt = i / (2*DIM);
    long long b = bt / ZL, t = bt % ZL;
    long long src = (b*TT + t)*DIM;
    float v = (c < DIM) ? x[src + c] : xi[src + c - DIM];
    o[i] = __float2half_rn(v);
}

__global__ void vtrans_k(const __half* __restrict__ qkv, __half* __restrict__ vt)
{
    __shared__ float t[32][33];
    int bh = blockIdx.z;
    long long b = bh / HEADS, h = bh % HEADS;
    const __half* src = qkv + b*NN*QKV3 + 2*DIM + h*HD;
    int tt0 = blockIdx.x*32;
    int cc0 = blockIdx.y*32;
    int tx = threadIdx.x, ty = threadIdx.y;
    #pragma unroll
    for (int i = 0; i < 32; i += 8)
        t[ty+i][tx] = __half2float(src[(long long)(tt0+ty+i)*QKV3 + cc0 + tx]);
    __syncthreads();
    __half* dst = vt + ((long long)bh*HD)*NN;
    #pragma unroll
    for (int i = 0; i < 32; i += 8)
        dst[(long long)(cc0+ty+i)*NN + tt0 + tx] = __float2half_rn(t[tx][ty+i]);
}

__global__ void make_v_k(const __half* __restrict__ ns, const __half* __restrict__ nsi,
                         const float* __restrict__ alpha, __half* __restrict__ v)
{
    long long i = (long long)blockIdx.x*blockDim.x + threadIdx.x;
    const long long n = (long long)BATCH*SL*DIM;
    if (i >= n) return;
    long long bs = i / DIM;
    float a = alpha[bs];
    v[i] = __float2half_rn(a*__half2float(ns[i]) + (1.f - a)*__half2float(nsi[i]));
}

__global__ void copy_zf_vfc_k(const float* __restrict__ xiattn, float* __restrict__ vfc)
{
    long long i = (long long)blockIdx.x*blockDim.x + threadIdx.x;
    const long long n = (long long)BATCH*ZL*DIM;
    if (i >= n) return;
    int c = (int)(i % DIM);
    long long bt = i / DIM;
    long long b = bt / ZL, t = bt % ZL;
    vfc[(b*TT + t)*DIM + c] = xiattn[(b*NN + t)*DIM + c];
}

__global__ void make_xnew_k(const float* __restrict__ x, const float* __restrict__ xi,
                            const float* __restrict__ xattn, const float* __restrict__ xiattn,
                            const float* __restrict__ vfc,
                            float* __restrict__ xo, float* __restrict__ xio)
{
    long long i = (long long)blockIdx.x*blockDim.x + threadIdx.x;
    const long long n = (long long)BATCH*TT*DIM;
    if (i >= n) return;
    int c = (int)(i % DIM);
    long long bt = i / DIM;
    long long b = bt / TT, t = bt % TT;
    long long aidx = (b*NN + ZL + t)*DIM + c;
    float vf = vfc[i];
    xo[i]  = x[i]  + xattn[aidx]  + vf;
    xio[i] = xi[i] + xiattn[aidx] + vf;
}

__global__ void i2f_k(const int* __restrict__ in, float* __restrict__ out, int n)
{
    int i = blockIdx.x*blockDim.x + threadIdx.x;
    if (i < n) out[i] = (float)in[i];
}

__global__ void f2h_k(const float* __restrict__ in, __half* __restrict__ out, int n4)
{
    int i = blockIdx.x*blockDim.x + threadIdx.x;
    if (i < n4) {
        float4 v = *(const float4*)(in + 4*i);
        *(uint2*)(out + 4*i) = to_h2(v);
    }
}

// ---------------- host-side helpers ----------------
template<int TM, int TN, typename TA, typename TB, typename TC>
static inline void mm(const TA* A, const TB* B, const float* bias,
                      const float* r1, const float* r2, TC* C,
                      int M, int N, int K, int lda, int ldb, int ldc,
                      long long sAb, long long sBb, long long sCb,
                      int nb, int nh,
                      long long sAh, long long sBh, long long sCh,
                      float alpha, int act)
{
    constexpr bool ASYNC = (TM == 128) &&
        std::is_same<TA,__half>::value && std::is_same<TB,__half>::value;
    constexpr int STAGE_BYTES = ASYNC ? (TM + TN)*RWA*2 : (TM + TN)*RWH*2;
    constexpr int EPI = 32*(TN+4)*4;
    constexpr int DS = (2*STAGE_BYTES > EPI) ? 2*STAGE_BYTES : EPI;
    static bool init = false;
    if (!init) {
        cudaFuncSetAttribute(mm2<TM,TN,TA,TB,TC>, cudaFuncAttributeMaxDynamicSharedMemorySize, DS);
        init = true;
    }
    dim3 g(N/TN, M/TM, nb*nh);
    mm2<TM,TN,TA,TB,TC><<<g, 512, DS>>>(A,B,bias,r1,r2,C,K,lda,ldb,ldc,sAb,sBb,sCb,nh,sAh,sBh,sCh,alpha,act);
}

static inline int cdiv(long long a, int b) { return (int)((a + b - 1) / b); }

extern "C" void kernel_launch(void* const* d_in, const int* in_sizes, int n_in,
                              void* d_out, int out_size)
{
    const float* x      = (const float*)d_in[0];
    const float* xi     = (const float*)d_in[1];
    const int*   git    = (const int*)  d_in[2];
    const int*   giti   = (const int*)  d_in[3];
    const int*   gis    = (const int*)  d_in[4];
    const int*   gisi   = (const int*)  d_in[5];
    const float* w_qkv  = (const float*)d_in[6];
    const float* b_qkv  = (const float*)d_in[7];
    const float* w_proj = (const float*)d_in[8];
    const float* b_proj = (const float*)d_in[9];
    const float* g1     = (const float*)d_in[10];
    const float* bt1    = (const float*)d_in[11];
    const float* g2     = (const float*)d_in[12];
    const float* bt2    = (const float*)d_in[13];
    const float* w_fc1  = (const float*)d_in[14];
    const float* b_fc1  = (const float*)d_in[15];
    const float* w_fc2  = (const float*)d_in[16];
    const float* b_fc2  = (const float*)d_in[17];
    const float* w_al   = (const float*)d_in[18];
    const float* b_al   = (const float*)d_in[19];
    const float* w_al2  = (const float*)d_in[20];
    const float* b_al2  = (const float*)d_in[21];
    const float* w_fus  = (const float*)d_in[22];
    const float* b_fus  = (const float*)d_in[23];
    float* out = (float*)d_out;

    float *p_zf, *p_attnx, *p_attnxi, *p_xattn, *p_xiattn, *p_vfc,
          *p_xnew, *p_xinew, *p_adap2;
    __half *p_cath, *p_nsh, *p_nsih, *p_lnh, *p_qkvh, *p_vth, *p_aoh, *p_hh, *p_vh;
    __half *wqkvh, *wprojh, *wfc1h, *wfc2h, *walh, *wal2h, *wfush;
    cudaGetSymbolAddress((void**)&p_cath,  g_cath);
    cudaGetSymbolAddress((void**)&p_zf,    g_zf);
    cudaGetSymbolAddress((void**)&p_nsh,   g_nsh);
    cudaGetSymbolAddress((void**)&p_nsih,  g_nsih);
    cudaGetSymbolAddress((void**)&p_attnx, g_attnx);
    cudaGetSymbolAddress((void**)&p_attnxi,g_attnxi);
    cudaGetSymbolAddress((void**)&p_lnh,   g_lnh);
    cudaGetSymbolAddress((void**)&p_qkvh,  g_qkvh);
    cudaGetSymbolAddress((void**)&p_vth,   g_vth);
    cudaGetSymbolAddress((void**)&p_aoh,   g_aoh);
    cudaGetSymbolAddress((void**)&p_xattn, g_xattn);
    cudaGetSymbolAddress((void**)&p_xiattn,g_xiattn);
    cudaGetSymbolAddress((void**)&p_vh,    g_vh);
    cudaGetSymbolAddress((void**)&p_vfc,   g_vfc);
    cudaGetSymbolAddress((void**)&p_xnew,  g_xnew);
    cudaGetSymbolAddress((void**)&p_xinew, g_xinew);
    cudaGetSymbolAddress((void**)&p_adap2, g_adap2);
    cudaGetSymbolAddress((void**)&p_hh,    g_hh);
    cudaGetSymbolAddress((void**)&wqkvh,   g_wqkvh);
    cudaGetSymbolAddress((void**)&wprojh,  g_wprojh);
    cudaGetSymbolAddress((void**)&wfc1h,   g_wfc1h);
    cudaGetSymbolAddress((void**)&wfc2h,   g_wfc2h);
    cudaGetSymbolAddress((void**)&walh,    g_walh);
    cudaGetSymbolAddress((void**)&wal2h,   g_wal2h);
    cudaGetSymbolAddress((void**)&wfush,   g_wfush);

    const float scale_dim = 1.f / sqrtf((float)DIM);

    f2h_k<<<cdiv(DIM*2*DIM/4,256),256>>>(w_al, walh,   DIM*2*DIM/4);
    cat_feat_k<<<cdiv((long long)BATCH*ZL*2*DIM, 256), 256>>>(x, xi, p_cath);
    f2h_k<<<cdiv(QKV3*DIM/4,256),256>>>(w_qkv,  wqkvh,  QKV3*DIM/4);
    f2h_k<<<cdiv(HID*DIM/4,256),256>>>(w_fc1,  wfc1h,  HID*DIM/4);
    f2h_k<<<cdiv(DIM*HID/4,256),256>>>(w_fc2,  wfc2h,  DIM*HID/4);
    mm<128,128,__half,__half,float>(p_cath, walh, b_al, nullptr, nullptr, p_zf,
        BATCH*ZL, DIM, 2*DIM, 2*DIM, 2*DIM, DIM, 0,0,0, 1,1, 0,0,0, 1.f, 0);
    f2h_k<<<cdiv(DIM*DIM/4,256),256>>>(w_proj, wprojh, DIM*DIM/4);
    f2h_k<<<cdiv(DIM*DIM/4,256),256>>>(w_al2,  wal2h,  DIM*DIM/4);
    f2h_k<<<cdiv(DIM*DIM/4,256),256>>>(w_fus,  wfush,  DIM*DIM/4);

    // ---- ns/nsi (fp16) ----
    ln_kernel<__half><<<dim3(SL, BATCH), 256>>>(x  + (long long)ZL*DIM, p_nsh,  g1, bt1,
                                                (long long)TT*DIM, (long long)SL*DIM);
    ln_kernel<__half><<<dim3(SL, BATCH), 256>>>(xi + (long long)ZL*DIM, p_nsih, g1, bt1,
                                                (long long)TT*DIM, (long long)SL*DIM);

    // ---- MHA both streams ----
    {
        static bool ainit = false;
        if (!ainit) {
            cudaFuncSetAttribute(attn_fused, cudaFuncAttributeMaxDynamicSharedMemorySize, PV_SMEM);
            ainit = true;
        }
    }
    const float* src[2]    = {x, xi};
    float*       attn_o[2] = {out + O_ATTN, out + O_IATTN};
    float*       proj_o[2] = {p_xattn, p_xiattn};
    for (int side = 0; side < 2; side++) {
        ln_cat_kernel<<<dim3(NN, BATCH), 256>>>(p_zf, src[side], p_lnh, g1, bt1);
        mm<128,128,__half,__half,__half>(p_lnh, wqkvh, b_qkv, nullptr, nullptr, p_qkvh,
            BATCH*NN, QKV3, DIM, DIM, DIM, QKV3, 0,0,0, 1,1, 0,0,0, 1.f, 0);
        vtrans_k<<<dim3(NN/32, HD/32, BATCH*HEADS), dim3(32,8)>>>(p_qkvh, p_vth);
        attn_fused<<<dim3(3, BATCH*HEADS), 512, PV_SMEM>>>(p_qkvh, p_vth, attn_o[side], p_aoh);
        mm<128,128,__half,__half,float>(p_aoh, wprojh, b_proj, nullptr, nullptr, proj_o[side],
            BATCH*NN, DIM, DIM, DIM, DIM, DIM, 0,0,0, 1,1, 0,0,0, 1.f, 0);
    }

    // ---- attn_x / attn_xi ----
    mm<64,128,float,__half,float>(p_zf, p_nsh, nullptr, nullptr, nullptr, p_attnx,
        ZL, SL, DIM, DIM, DIM, SL,
        (long long)ZL*DIM, (long long)SL*DIM, (long long)ZL*SL,
        BATCH, 1, 0,0,0, scale_dim, 0);
    mm<64,128,float,__half,float>(p_zf, p_nsih, nullptr, nullptr, nullptr, p_attnxi,
        ZL, SL, DIM, DIM, DIM, SL,
        (long long)ZL*DIM, (long long)SL*DIM, (long long)ZL*SL,
        BATCH, 1, 0,0,0, scale_dim, 0);

    // ---- fusion ----
    fusion_kernel<<<BATCH, SL>>>(p_attnx, p_attnxi,
                                 out + O_ALPHA, out + O_UM, out + O_U, out + O_UI);
    make_v_k<<<cdiv((long long)BATCH*SL*DIM, 256), 256>>>(p_nsh, p_nsih, out + O_ALPHA, p_vh);
    // fus GEMM writes directly into vfc rows [ZL, TT)
    mm<128,128,__half,__half,float>(p_vh, wfush, b_fus, nullptr, nullptr,
        p_vfc + (long long)ZL*DIM,
        SL, DIM, DIM, DIM, DIM, DIM,
        (long long)SL*DIM, 0, (long long)TT*DIM,
        BATCH, 1, 0,0,0, 1.f, 0);
    copy_zf_vfc_k<<<cdiv((long long)BATCH*ZL*DIM, 256), 256>>>(p_xiattn, p_vfc);

    // ---- residual adds ----
    make_xnew_k<<<cdiv((long long)BATCH*TT*DIM, 256), 256>>>(
        x, xi, p_xattn, p_xiattn, p_vfc, p_xnew, p_xinew);

    // ---- adap2 ----
    ln_kernel<__half><<<dim3(TT, BATCH), 256>>>(p_vfc, p_lnh, g2, bt2,
                                                (long long)TT*DIM, (long long)TT*DIM);
    mm<128,128,__half,__half,float>(p_lnh, wal2h, b_al2, nullptr, nullptr, p_adap2,
        BATCH*TT, DIM, DIM, DIM, DIM, DIM, 0,0,0, 1,1, 0,0,0, 1.f, 0);

    // ---- MLP both streams ----
    float* xn[2] = {p_xnew, p_xinew};
    float* xo[2] = {out + O_XOUT, out + O_XIOUT};
    for (int side = 0; side < 2; side++) {
        ln_kernel<__half><<<dim3(TT, BATCH), 256>>>(xn[side], p_lnh, g2, bt2,
                                                    (long long)TT*DIM, (long long)TT*DIM);
        mm<128,128,__half,__half,__half>(p_lnh, wfc1h, b_fc1, nullptr, nullptr, p_hh,
            BATCH*TT, HID, DIM, DIM, DIM, HID, 0,0,0, 1,1, 0,0,0, 1.f, 1);
        mm<128,128,__half,__half,float>(p_hh, wfc2h, b_fc2, xn[side], p_adap2, xo[side],
            BATCH*TT, DIM, HID, HID, HID, DIM, 0,0,0, 1,1, 0,0,0, 1.f, 0);
    }

    // ---- index passthroughs ----
    i2f_k<<<cdiv(BATCH*ZL, 256), 256>>>(git,  out + O_GIT,  BATCH*ZL);
    i2f_k<<<cdiv(BATCH*SL, 256), 256>>>(gis,  out + O_GIS,  BATCH*SL);
    i2f_k<<<cdiv(BATCH*ZL, 256), 256>>>(giti, out + O_GITI, BATCH*ZL);
    i2f_k<<<cdiv(BATCH*SL, 256), 256>>>(gisi, out + O_GISI, BATCH*SL);
}

// round 10
// speedup vs baseline: 6.1680x; 1.0393x over previous
#include <cuda_runtime.h>
#include <cuda_fp16.h>
#include <math.h>
#include <cstdint>
#include <type_traits>

// ---------------- problem constants ----------------
#define BATCH 32
#define ZL 64
#define SL 256
#define TT 320
#define NN 384
#define DIM 768
#define HEADS 12
#define HD 64
#define HID 3072
#define QKV3 2304

#define O_XOUT   0LL
#define O_GIT    7864320LL
#define O_GIS    7866368LL
#define O_ATTN   7874560LL
#define O_XIOUT  64497664LL
#define O_GITI   72361984LL
#define O_GISI   72364032LL
#define O_IATTN  72372224LL
#define O_ALPHA  128995328LL
#define O_UM     129003520LL
#define O_U      129011712LL
#define O_UI     129019904LL

// ---------------- scratch ----------------
__device__ __half g_cath [BATCH*ZL*2*DIM];
__device__ __half g_zfh  [BATCH*ZL*DIM];
__device__ __half g_nsh  [BATCH*SL*DIM];
__device__ __half g_nsih [BATCH*SL*DIM];
__device__ float  g_attnx [BATCH*ZL*SL];
__device__ float  g_attnxi[BATCH*ZL*SL];
__device__ __half g_lnh  [BATCH*NN*DIM];
__device__ __half g_qkvh [BATCH*NN*QKV3];
__device__ __half g_vth  [BATCH*HEADS*HD*NN];
__device__ __half g_aoh  [BATCH*NN*DIM];
__device__ float  g_xattn [BATCH*NN*DIM];
__device__ float  g_xiattn[BATCH*NN*DIM];
__device__ __half g_vh   [BATCH*SL*DIM];
__device__ float  g_vf   [BATCH*SL*DIM];
__device__ float  g_xnew [BATCH*TT*DIM];
__device__ float  g_xinew[BATCH*TT*DIM];
__device__ __half g_lnvh [BATCH*TT*DIM];
__device__ __half g_lnxh [BATCH*TT*DIM];
__device__ __half g_lnxih[BATCH*TT*DIM];
__device__ float  g_adap2[BATCH*TT*DIM];
__device__ __half g_hh   [BATCH*TT*HID];
__device__ __half g_wqkvh[QKV3*DIM];
__device__ __half g_wprojh[DIM*DIM];
__device__ __half g_wfc1h[HID*DIM];
__device__ __half g_wfc2h[DIM*HID];
__device__ __half g_walh [DIM*2*DIM];
__device__ __half g_wal2h[DIM*DIM];
__device__ __half g_wfush[DIM*DIM];

// =============== helpers =====================================================
__device__ __forceinline__ uint32_t smem_u32(const void* p) {
    uint32_t a;
    asm("{ .reg .u64 t; cvta.to.shared.u64 t, %1; cvt.u32.u64 %0, t; }" : "=r"(a) : "l"(p));
    return a;
}
__device__ __forceinline__ void mma16816h(float* d, const uint32_t* a, const uint32_t* b) {
    asm volatile("mma.sync.aligned.m16n8k16.row.col.f32.f16.f16.f32 "
        "{%0,%1,%2,%3}, {%4,%5,%6,%7}, {%8,%9}, {%0,%1,%2,%3};"
        : "+f"(d[0]), "+f"(d[1]), "+f"(d[2]), "+f"(d[3])
        : "r"(a[0]), "r"(a[1]), "r"(a[2]), "r"(a[3]), "r"(b[0]), "r"(b[1]));
}
__device__ __forceinline__ void ldsm4(uint32_t& r0, uint32_t& r1, uint32_t& r2, uint32_t& r3,
                                      uint32_t addr) {
    asm volatile("ldmatrix.sync.aligned.m8n8.x4.shared.b16 {%0,%1,%2,%3}, [%4];"
        : "=r"(r0), "=r"(r1), "=r"(r2), "=r"(r3) : "r"(addr));
}
__device__ __forceinline__ uint32_t pack_h2(float x, float y) {
    __half2 p = __float22half2_rn(make_float2(x, y));
    return *(uint32_t*)&p;
}
template<typename T> struct RawVec;
template<> struct RawVec<float>  { using type = float4; };
template<> struct RawVec<__half> { using type = uint2;  };
__device__ __forceinline__ uint2 to_h2(const float4& v) {
    return make_uint2(pack_h2(v.x, v.y), pack_h2(v.z, v.w));
}
__device__ __forceinline__ uint2 to_h2(const uint2& v) { return v; }
__device__ __forceinline__ void st_out4(float* p, float4 v) { *(float4*)p = v; }
__device__ __forceinline__ void st_out4(__half* p, float4 v) {
    *(uint2*)p = make_uint2(pack_h2(v.x, v.y), pack_h2(v.z, v.w));
}
__device__ __forceinline__ void st_s(float* p, float v)  { *p = v; }
__device__ __forceinline__ void st_s(__half* p, float v) { *p = __float2half_rn(v); }

#define CP_ASYNC16(dst, src) \
    asm volatile("cp.async.cg.shared.global [%0], [%1], 16;" :: "r"(dst), "l"(src))
#define CP_COMMIT()  asm volatile("cp.async.commit_group;")
#define CP_WAIT1()   asm volatile("cp.async.wait_group 1;")
#define CP_WAIT0()   asm volatile("cp.async.wait_group 0;")

// =============== fp16 mma.sync GEMM, typed A/B/C =============================
#define RWH 40          // sync path rows (+8 pad)
#define RWA 72          // async path rows (+8 pad)

template<int TM, int TN, typename TA, typename TB, typename TC>
__global__ __launch_bounds__(512, 2)
void mm2(const TA* __restrict__ A, const TB* __restrict__ B,
         const float* __restrict__ bias,
         const float* __restrict__ res1, const float* __restrict__ res2,
         TC* __restrict__ C,
         int K, int lda, int ldb, int ldc,
         long long sAb, long long sBb, long long sCb, int batchH,
         long long sAh, long long sBh, long long sCh,
         float alpha, int act)
{
    extern __shared__ char dsm[];
    constexpr int WTM = TM/4, WTN = TN/4;
    constexpr int MI = WTM/16, NI = WTN/8;
    constexpr bool ASYNC =
        std::is_same<TA,__half>::value && std::is_same<TB,__half>::value;

    const int tid  = threadIdx.x;
    const int lane = tid & 31;
    const int w    = tid >> 5;
    const int wm   = w >> 2;
    const int wn   = w & 3;

    const int bz = blockIdx.z;
    const int b  = bz / batchH;
    const int h  = bz - b*batchH;
    const int m0 = blockIdx.y * TM;
    const int n0 = blockIdx.x * TN;
    const TA* Ab = A + (long long)b*sAb + (long long)h*sAh + (long long)m0*lda;
    const TB* Bb = B + (long long)b*sBb + (long long)h*sBh + (long long)n0*ldb;
    const long long coff = (long long)b*sCb + (long long)h*sCh;

    const uint32_t sb0 = smem_u32(dsm);

    float acc[MI][NI][4];
    #pragma unroll
    for (int mi = 0; mi < MI; mi++)
        #pragma unroll
        for (int ni = 0; ni < NI; ni++)
            #pragma unroll
            for (int j = 0; j < 4; j++) acc[mi][ni][j] = 0.f;

    if constexpr (ASYNC) {
        constexpr int AHL = TM*RWA;
        constexpr int STAGE_BYTES = (TM + TN)*RWA*2;
        constexpr int PLA = TM*8/512, PLB = TN*8/512;
        const uint32_t a_l = (uint32_t)(((wm*WTM + (lane & 15))*RWA + ((lane >> 4) << 3)) * 2);
        const uint32_t b_l = (uint32_t)(AHL*2 + ((wn*WTN + (lane & 15))*RWA + ((lane >> 4) << 3)) * 2);
        const __half* Abh = (const __half*)Ab;
        const __half* Bbh = (const __half*)Bb;
        const int NC = K >> 6;

        #pragma unroll
        for (int p = 0; p < PLA; p++) {
            int u = tid + (p << 9);
            int r = u >> 3, ch = u & 7;
            CP_ASYNC16(sb0 + (uint32_t)(r*RWA*2 + ch*16),
                       Abh + (long long)r*lda + ch*8);
        }
        #pragma unroll
        for (int p = 0; p < PLB; p++) {
            int u = tid + (p << 9);
            int r = u >> 3, ch = u & 7;
            CP_ASYNC16(sb0 + (uint32_t)(AHL*2 + r*RWA*2 + ch*16),
                       Bbh + (long long)r*ldb + ch*8);
        }
        CP_COMMIT();

        for (int c = 0; c < NC; c++) {
            const int st = c & 1;
            if (c + 1 < NC) {
                const int k0 = (c + 1) << 6;
                const uint32_t base = sb0 + ((c + 1) & 1) * STAGE_BYTES;
                #pragma unroll
                for (int p = 0; p < PLA; p++) {
                    int u = tid + (p << 9);
                    int r = u >> 3, ch = u & 7;
                    CP_ASYNC16(base + (uint32_t)(r*RWA*2 + ch*16),
                               Abh + (long long)r*lda + k0 + ch*8);
                }
                #pragma unroll
                for (int p = 0; p < PLB; p++) {
                    int u = tid + (p << 9);
                    int r = u >> 3, ch = u & 7;
                    CP_ASYNC16(base + (uint32_t)(AHL*2 + r*RWA*2 + ch*16),
                               Bbh + (long long)r*ldb + k0 + ch*8);
                }
                CP_COMMIT();
                CP_WAIT1();
            } else {
                CP_WAIT0();
            }
            __syncthreads();

            const uint32_t stageu = sb0 + st * STAGE_BYTES;
            #pragma unroll
            for (int ks = 0; ks < 4; ks++) {
                const uint32_t kb = ks * 32;
                uint32_t ah[MI][4];
                #pragma unroll
                for (int mi = 0; mi < MI; mi++) {
                    uint32_t ad = stageu + a_l + mi*(16*RWA*2) + kb;
                    ldsm4(ah[mi][0], ah[mi][1], ah[mi][2], ah[mi][3], ad);
                }
                uint32_t bh[NI][2];
                #pragma unroll
                for (int nj = 0; nj < NI/2; nj++) {
                    uint32_t bd = stageu + b_l + nj*(16*RWA*2) + kb;
                    uint32_t q0, q1, q2, q3;
                    ldsm4(q0, q1, q2, q3, bd);
                    bh[2*nj][0] = q0; bh[2*nj][1] = q2;
                    bh[2*nj+1][0] = q1; bh[2*nj+1][1] = q3;
                }
                #pragma unroll
                for (int mi = 0; mi < MI; mi++)
                    #pragma unroll
                    for (int ni = 0; ni < NI; ni++)
                        mma16816h(acc[mi][ni], ah[mi], bh[ni]);
            }
            __syncthreads();
        }
    } else {
        constexpr int AHL = TM*RWH;
        constexpr int STAGE_BYTES = (TM + TN)*RWH*2;
        constexpr int PA = TM/64, PB = TN/64;
        const uint32_t a_l = (uint32_t)(((wm*WTM + (lane & 15))*RWH + ((lane >> 4) << 3)) * 2);
        const uint32_t b_l = (uint32_t)(AHL*2 + ((wn*WTN + (lane & 15))*RWH + ((lane >> 4) << 3)) * 2);
        const int lq = tid & 7;
        const int lr = tid >> 3;
        const int NC = K >> 5;
        typename RawVec<TA>::type pA[PA];
        typename RawVec<TB>::type pB[PB];

        #pragma unroll
        for (int p = 0; p < PA; p++)
            pA[p] = *(const typename RawVec<TA>::type*)(Ab + (long long)(lr + 64*p)*lda + 4*lq);
        #pragma unroll
        for (int p = 0; p < PB; p++)
            pB[p] = *(const typename RawVec<TB>::type*)(Bb + (long long)(lr + 64*p)*ldb + 4*lq);

        for (int c = 0; c < NC; c++) {
            const int st = c & 1;
            char* sb = dsm + st * STAGE_BYTES;
            __half* Ah = (__half*)sb;
            __half* Bh = Ah + AHL;

            #pragma unroll
            for (int p = 0; p < PA; p++)
                *(uint2*)(Ah + (lr + 64*p)*RWH + 4*lq) = to_h2(pA[p]);
            #pragma unroll
            for (int p = 0; p < PB; p++)
                *(uint2*)(Bh + (lr + 64*p)*RWH + 4*lq) = to_h2(pB[p]);
            __syncthreads();

            if (c + 1 < NC) {
                const int k0 = (c + 1) << 5;
                #pragma unroll
                for (int p = 0; p < PA; p++)
                    pA[p] = *(const typename RawVec<TA>::type*)(Ab + (long long)(lr + 64*p)*lda + k0 + 4*lq);
                #pragma unroll
                for (int p = 0; p < PB; p++)
                    pB[p] = *(const typename RawVec<TB>::type*)(Bb + (long long)(lr + 64*p)*ldb + k0 + 4*lq);
            }

            const uint32_t stageu = sb0 + st * STAGE_BYTES;
            #pragma unroll
            for (int ks = 0; ks < 2; ks++) {
                const uint32_t kb = ks * 32;
                uint32_t ah[MI][4];
                #pragma unroll
                for (int mi = 0; mi < MI; mi++) {
                    uint32_t ad = stageu + a_l + mi*(16*RWH*2) + kb;
                    ldsm4(ah[mi][0], ah[mi][1], ah[mi][2], ah[mi][3], ad);
                }
                uint32_t bh[NI][2];
                #pragma unroll
                for (int nj = 0; nj < NI/2; nj++) {
                    uint32_t bd = stageu + b_l + nj*(16*RWH*2) + kb;
                    uint32_t q0, q1, q2, q3;
                    ldsm4(q0, q1, q2, q3, bd);
                    bh[2*nj][0] = q0; bh[2*nj][1] = q2;
                    bh[2*nj+1][0] = q1; bh[2*nj+1][1] = q3;
                }
                #pragma unroll
                for (int mi = 0; mi < MI; mi++)
                    #pragma unroll
                    for (int ni = 0; ni < NI; ni++)
                        mma16816h(acc[mi][ni], ah[mi], bh[ni]);
            }
            __syncthreads();
        }
    }

    // ---- epilogue: 32-row passes through SMEM ----
    constexpr int ROWW = TN + 4;
    constexpr int NPASS = TM / 32;
    float* sbuf = (float*)dsm;
    const int g = lane >> 2, t4 = lane & 3;
    const int my_pass = (wm*WTM) >> 5;
    const int my_lb   = (wm*WTM) & 31;

    #pragma unroll
    for (int pass = 0; pass < NPASS; pass++) {
        if (my_pass == pass) {
            #pragma unroll
            for (int mi = 0; mi < MI; mi++)
                #pragma unroll
                for (int ni = 0; ni < NI; ni++)
                    #pragma unroll
                    for (int j = 0; j < 4; j++) {
                        int row = my_lb + mi*16 + g + 8*(j >> 1);
                        int col = wn*WTN + ni*8 + 2*t4 + (j & 1);
                        sbuf[row*ROWW + col] = acc[mi][ni][j];
                    }
        }
        __syncthreads();
        #pragma unroll
        for (int p = 0; p < 32*TN/2048; p++) {
            int i4 = tid + (p << 9);
            int elem = i4 << 2;
            int rr = elem / TN;
            int cc = elem - rr*TN;
            float4 v = *(float4*)(sbuf + rr*ROWW + cc);
            v.x *= alpha; v.y *= alpha; v.z *= alpha; v.w *= alpha;
            if (bias) {
                float4 bb = *(const float4*)(bias + n0 + cc);
                v.x += bb.x; v.y += bb.y; v.z += bb.z; v.w += bb.w;
            }
            long long off = coff + (long long)(m0 + pass*32 + rr)*ldc + (n0 + cc);
            if (res1) {
                float4 a = *(const float4*)(res1 + off);
                v.x += a.x; v.y += a.y; v.z += a.z; v.w += a.w;
            }
            if (res2) {
                float4 a = *(const float4*)(res2 + off);
                v.x += a.x; v.y += a.y; v.z += a.z; v.w += a.w;
            }
            if (act == 1) {
                v.x = 0.5f*v.x*(1.f + erff(v.x*0.70710678118654752f));
                v.y = 0.5f*v.y*(1.f + erff(v.y*0.70710678118654752f));
                v.z = 0.5f*v.z*(1.f + erff(v.z*0.70710678118654752f));
                v.w = 0.5f*v.w*(1.f + erff(v.w*0.70710678118654752f));
            }
            st_out4(C + off, v);
        }
        __syncthreads();
    }
}

// =============== fused QK^T + softmax + P@V (qkv in fp16) ====================
#define RW2 72
#define RW3 392
#define PV_SMEM (128*RW3*2 + 64*RW3*2 + 128*4*4 + 128*4)

__global__ __launch_bounds__(512, 1)
void attn_fused(const __half* __restrict__ qkv, const __half* __restrict__ vt,
                float* __restrict__ attn, __half* __restrict__ ao)
{
    extern __shared__ char dsm[];
    __half* Ph  = (__half*)dsm;
    __half* Vs  = (__half*)(dsm + 128*RW3*2);
    float*  red = (float*)(dsm + 128*RW3*2 + 64*RW3*2);
    float*  invb= red + 128*4;
    __half* Qs  = (__half*)dsm;
    __half* Ks  = Qs + 128*RW2;

    const int tid = threadIdx.x;
    const int lane = tid & 31;
    const int w = tid >> 5;
    const int wm = w >> 2, wn = w & 3;
    const int g = lane >> 2, t4 = lane & 3;

    const int m0 = blockIdx.x * 128;
    const int bh = blockIdx.y;
    const int b  = bh / HEADS;
    const int hh = bh - b*HEADS;

    const __half* qbase = qkv + (long long)b*NN*QKV3 + hh*HD;

    #pragma unroll
    for (int p = 0; p < 2; p++) {
        int u = tid + (p << 9);
        int r = u >> 3, ch = u & 7;
        *(uint4*)(Qs + r*RW2 + ch*8) =
            *(const uint4*)(qbase + (long long)(m0 + r)*QKV3 + ch*8);
    }
    #pragma unroll
    for (int p = 0; p < 6; p++) {
        int u = tid + (p << 9);
        int r = u >> 3, ch = u & 7;
        *(uint4*)(Ks + r*RW2 + ch*8) =
            *(const uint4*)(qbase + DIM + (long long)r*QKV3 + ch*8);
    }
    __syncthreads();

    const uint32_t sq = smem_u32(Qs);
    const uint32_t sk = smem_u32(Ks);
    const uint32_t a_l = sq + ((wm*32 + (lane & 15))*RW2 + ((lane >> 4) << 3)) * 2;
    const uint32_t b_l = sk + ((wn*96 + (lane & 15))*RW2 + ((lane >> 4) << 3)) * 2;

    float acc[2][12][4];
    #pragma unroll
    for (int mi = 0; mi < 2; mi++)
        #pragma unroll
        for (int ni = 0; ni < 12; ni++)
            #pragma unroll
            for (int j = 0; j < 4; j++) acc[mi][ni][j] = 0.f;

    #pragma unroll
    for (int ks = 0; ks < 4; ks++) {
        const uint32_t kb = ks * 32;
        uint32_t ah[2][4];
        #pragma unroll
        for (int mi = 0; mi < 2; mi++)
            ldsm4(ah[mi][0], ah[mi][1], ah[mi][2], ah[mi][3],
                  a_l + mi*(16*RW2*2) + kb);
        #pragma unroll
        for (int nj = 0; nj < 6; nj++) {
            uint32_t q0, q1, q2, q3;
            ldsm4(q0, q1, q2, q3, b_l + nj*(16*RW2*2) + kb);
            uint32_t b0[2] = {q0, q2}, b1[2] = {q1, q3};
            #pragma unroll
            for (int mi = 0; mi < 2; mi++) {
                mma16816h(acc[mi][2*nj],   ah[mi], b0);
                mma16816h(acc[mi][2*nj+1], ah[mi], b1);
            }
        }
    }

    #pragma unroll
    for (int mi = 0; mi < 2; mi++)
        #pragma unroll
        for (int ni = 0; ni < 12; ni++)
            #pragma unroll
            for (int j = 0; j < 4; j++) acc[mi][ni][j] *= 0.125f;

    float M[2][2];
    #pragma unroll
    for (int mi = 0; mi < 2; mi++)
        #pragma unroll
        for (int h2 = 0; h2 < 2; h2++) {
            float m = -1e30f;
            #pragma unroll
            for (int ni = 0; ni < 12; ni++)
                m = fmaxf(m, fmaxf(acc[mi][ni][2*h2], acc[mi][ni][2*h2+1]));
            m = fmaxf(m, __shfl_xor_sync(0xFFFFFFFFu, m, 1));
            m = fmaxf(m, __shfl_xor_sync(0xFFFFFFFFu, m, 2));
            if (t4 == 0) red[(wm*32 + mi*16 + g + 8*h2)*4 + wn] = m;
        }
    __syncthreads();
    #pragma unroll
    for (int mi = 0; mi < 2; mi++)
        #pragma unroll
        for (int h2 = 0; h2 < 2; h2++) {
            int row = wm*32 + mi*16 + g + 8*h2;
            M[mi][h2] = fmaxf(fmaxf(red[row*4], red[row*4+1]),
                              fmaxf(red[row*4+2], red[row*4+3]));
        }
    __syncthreads();

    float S[2][2];
    #pragma unroll
    for (int mi = 0; mi < 2; mi++)
        #pragma unroll
        for (int h2 = 0; h2 < 2; h2++) {
            float s = 0.f;
            #pragma unroll
            for (int ni = 0; ni < 12; ni++) {
                float e0 = __expf(acc[mi][ni][2*h2]   - M[mi][h2]);
                float e1 = __expf(acc[mi][ni][2*h2+1] - M[mi][h2]);
                acc[mi][ni][2*h2] = e0; acc[mi][ni][2*h2+1] = e1;
                s += e0 + e1;
            }
            s += __shfl_xor_sync(0xFFFFFFFFu, s, 1);
            s += __shfl_xor_sync(0xFFFFFFFFu, s, 2);
            if (t4 == 0) red[(wm*32 + mi*16 + g + 8*h2)*4 + wn] = s;
        }
    __syncthreads();
    #pragma unroll
    for (int mi = 0; mi < 2; mi++)
        #pragma unroll
        for (int h2 = 0; h2 < 2; h2++) {
            int row = wm*32 + mi*16 + g + 8*h2;
            float inv = 1.f / (red[row*4] + red[row*4+1] + red[row*4+2] + red[row*4+3]);
            S[mi][h2] = inv;
            if (wn == 0 && t4 == 0) invb[row] = inv;
        }

    float* abase = attn + (long long)bh*NN*NN;
    #pragma unroll
    for (int mi = 0; mi < 2; mi++)
        #pragma unroll
        for (int h2 = 0; h2 < 2; h2++) {
            int row = m0 + wm*32 + mi*16 + g + 8*h2;
            float inv = S[mi][h2];
            float* rp = abase + (long long)row*NN + wn*96 + 2*t4;
            #pragma unroll
            for (int ni = 0; ni < 12; ni++) {
                float2 o;
                o.x = acc[mi][ni][2*h2]   * inv;
                o.y = acc[mi][ni][2*h2+1] * inv;
                *(float2*)(rp + ni*8) = o;
            }
        }

    __syncthreads();

    #pragma unroll
    for (int mi = 0; mi < 2; mi++)
        #pragma unroll
        for (int h2 = 0; h2 < 2; h2++) {
            int row = wm*32 + mi*16 + g + 8*h2;
            __half* rp = Ph + row*RW3 + wn*96 + 2*t4;
            #pragma unroll
            for (int ni = 0; ni < 12; ni++)
                *(uint32_t*)(rp + ni*8) = pack_h2(acc[mi][ni][2*h2], acc[mi][ni][2*h2+1]);
        }
    const __half* vbase = vt + (long long)bh*HD*NN;
    #pragma unroll
    for (int p = 0; p < 6; p++) {
        int u = tid + (p << 9);
        int r = u / 48, c = u - r*48;
        *(uint4*)(Vs + r*RW3 + c*8) = *(const uint4*)(vbase + r*NN + c*8);
    }
    __syncthreads();

    const int wm2 = w >> 2, wn2 = w & 3;
    const uint32_t pa = smem_u32(Ph) + ((wm2*32 + (lane & 15))*RW3 + ((lane >> 4) << 3))*2;
    const uint32_t pb = smem_u32(Vs) + ((wn2*16 + (lane & 15))*RW3 + ((lane >> 4) << 3))*2;

    float acc2[2][2][4];
    #pragma unroll
    for (int mi = 0; mi < 2; mi++)
        #pragma unroll
        for (int ni = 0; ni < 2; ni++)
            #pragma unroll
            for (int j = 0; j < 4; j++) acc2[mi][ni][j] = 0.f;

    #pragma unroll
    for (int ks = 0; ks < 24; ks++) {
        const uint32_t kb = ks * 32;
        uint32_t ah0[4], ah1[4], q0, q1, q2, q3;
        ldsm4(ah0[0], ah0[1], ah0[2], ah0[3], pa + kb);
        ldsm4(ah1[0], ah1[1], ah1[2], ah1[3], pa + 16*RW3*2 + kb);
        ldsm4(q0, q1, q2, q3, pb + kb);
        uint32_t b0[2] = {q0, q2}, b1[2] = {q1, q3};
        mma16816h(acc2[0][0], ah0, b0);
        mma16816h(acc2[0][1], ah0, b1);
        mma16816h(acc2[1][0], ah1, b0);
        mma16816h(acc2[1][1], ah1, b1);
    }

    #pragma unroll
    for (int mi = 0; mi < 2; mi++) {
        int r0 = wm2*32 + mi*16 + g;
        float inv0 = invb[r0], inv1 = invb[r0 + 8];
        long long base0 = ((long long)b*NN + m0 + r0)*DIM + hh*HD;
        long long base1 = base0 + 8LL*DIM;
        #pragma unroll
        for (int ni = 0; ni < 2; ni++) {
            int col = wn2*16 + ni*8 + 2*t4;
            *(uint32_t*)(ao + base0 + col) = pack_h2(acc2[mi][ni][0]*inv0, acc2[mi][ni][1]*inv0);
            *(uint32_t*)(ao + base1 + col) = pack_h2(acc2[mi][ni][2]*inv1, acc2[mi][ni][3]*inv1);
        }
    }
}

// ---------------- LayerNorm over 768 features -------------------------------
template<typename TO>
__global__ void ln_kernel(const float* __restrict__ in, TO* __restrict__ out,
                          const float* __restrict__ g, const float* __restrict__ b,
                          long long in_bstride, long long out_bstride)
{
    const float* x = in  + (long long)blockIdx.y*in_bstride  + (long long)blockIdx.x*DIM;
    TO*          y = out + (long long)blockIdx.y*out_bstride + (long long)blockIdx.x*DIM;
    int tid = threadIdx.x;
    float v0 = x[tid], v1 = x[tid+256], v2 = x[tid+512];
    __shared__ float sh[256];
    sh[tid] = v0 + v1 + v2;
    __syncthreads();
    for (int o = 128; o > 0; o >>= 1) { if (tid < o) sh[tid] += sh[tid+o]; __syncthreads(); }
    float mean = sh[0] * (1.f/768.f);
    __syncthreads();
    float d0 = v0-mean, d1 = v1-mean, d2 = v2-mean;
    sh[tid] = d0*d0 + d1*d1 + d2*d2;
    __syncthreads();
    for (int o = 128; o > 0; o >>= 1) { if (tid < o) sh[tid] += sh[tid+o]; __syncthreads(); }
    float inv = rsqrtf(sh[0] * (1.f/768.f) + 1e-5f);
    st_s(y + tid,     d0*inv*g[tid]     + b[tid]);
    st_s(y + tid+256, d1*inv*g[tid+256] + b[tid+256]);
    st_s(y + tid+512, d2*inv*g[tid+512] + b[tid+512]);
}

// LN over the concat [z_f(fp16), x(fp32)]
__global__ void ln_cat_kernel(const __half* __restrict__ zf, const float* __restrict__ x,
                              __half* __restrict__ out,
                              const float* __restrict__ g, const float* __restrict__ b)
{
    int t = blockIdx.x, bb = blockIdx.y;
    __half* y = out + ((long long)bb*NN + t)*DIM;
    int tid = threadIdx.x;
    float v0, v1, v2;
    if (t < ZL) {
        const __half* src = zf + ((long long)bb*ZL + t)*DIM;
        v0 = __half2float(src[tid]);
        v1 = __half2float(src[tid+256]);
        v2 = __half2float(src[tid+512]);
    } else {
        const float* src = x + ((long long)bb*TT + (t - ZL))*DIM;
        v0 = src[tid]; v1 = src[tid+256]; v2 = src[tid+512];
    }
    __shared__ float sh[256];
    sh[tid] = v0 + v1 + v2;
    __syncthreads();
    for (int o = 128; o > 0; o >>= 1) { if (tid < o) sh[tid] += sh[tid+o]; __syncthreads(); }
    float mean = sh[0] * (1.f/768.f);
    __syncthreads();
    float d0 = v0-mean, d1 = v1-mean, d2 = v2-mean;
    sh[tid] = d0*d0 + d1*d1 + d2*d2;
    __syncthreads();
    for (int o = 128; o > 0; o >>= 1) { if (tid < o) sh[tid] += sh[tid+o]; __syncthreads(); }
    float inv = rsqrtf(sh[0] * (1.f/768.f) + 1e-5f);
    y[tid]     = __float2half_rn(d0*inv*g[tid]     + b[tid]);
    y[tid+256] = __float2half_rn(d1*inv*g[tid+256] + b[tid+256]);
    y[tid+512] = __float2half_rn(d2*inv*g[tid+512] + b[tid+512]);
}

// ---------------- fused residual + 3x LayerNorm ------------------------------
// grid (TT, BATCH), 256 threads. Computes vf (virtual vfc row), xnew/xinew,
// LN(vf)->lnv, LN(xnew)->lnx, LN(xinew)->lnxi (all fp16).
__device__ __forceinline__ float2 ln_stats3(float v0, float v1, float v2,
                                            float2* sh, int tid)
{
    sh[tid] = make_float2(v0+v1+v2, v0*v0+v1*v1+v2*v2);
    __syncthreads();
    for (int o = 128; o > 0; o >>= 1) {
        if (tid < o) { sh[tid].x += sh[tid+o].x; sh[tid].y += sh[tid+o].y; }
        __syncthreads();
    }
    float mean = sh[0].x * (1.f/768.f);
    float var  = sh[0].y * (1.f/768.f) - mean*mean;
    float inv  = rsqrtf(var + 1e-5f);
    __syncthreads();
    return make_float2(mean, inv);
}

__global__ void resid_ln_k(const float* __restrict__ x, const float* __restrict__ xi,
                           const float* __restrict__ xattn, const float* __restrict__ xiattn,
                           const float* __restrict__ vfus,
                           const float* __restrict__ g2, const float* __restrict__ bt2,
                           float* __restrict__ xnew, float* __restrict__ xinew,
                           __half* __restrict__ lnv, __half* __restrict__ lnx,
                           __half* __restrict__ lnxi)
{
    const int t = blockIdx.x, b = blockIdx.y;
    const int tid = threadIdx.x;
    const long long rbase = ((long long)b*TT + t)*DIM;
    const long long abase = ((long long)b*NN + ZL + t)*DIM;
    const float* vsrc = (t < ZL) ? xiattn + ((long long)b*NN + t)*DIM
                                 : vfus   + ((long long)b*SL + (t - ZL))*DIM;

    float vf[3], xo[3], xio[3];
    #pragma unroll
    for (int j = 0; j < 3; j++) {
        int c = tid + j*256;
        float vv = vsrc[c];
        vf[j]  = vv;
        xo[j]  = x[rbase + c]  + xattn[abase + c]  + vv;
        xio[j] = xi[rbase + c] + xiattn[abase + c] + vv;
        xnew[rbase + c]  = xo[j];
        xinew[rbase + c] = xio[j];
    }

    __shared__ float2 sh[256];
    float gg[3], bb[3];
    #pragma unroll
    for (int j = 0; j < 3; j++) {
        gg[j] = g2[tid + j*256];
        bb[j] = bt2[tid + j*256];
    }

    float2 st = ln_stats3(vf[0], vf[1], vf[2], sh, tid);
    #pragma unroll
    for (int j = 0; j < 3; j++)
        lnv[rbase + tid + j*256] = __float2half_rn((vf[j]-st.x)*st.y*gg[j] + bb[j]);

    st = ln_stats3(xo[0], xo[1], xo[2], sh, tid);
    #pragma unroll
    for (int j = 0; j < 3; j++)
        lnx[rbase + tid + j*256] = __float2half_rn((xo[j]-st.x)*st.y*gg[j] + bb[j]);

    st = ln_stats3(xio[0], xio[1], xio[2], sh, tid);
    #pragma unroll
    for (int j = 0; j < 3; j++)
        lnxi[rbase + tid + j*256] = __float2half_rn((xio[j]-st.x)*st.y*gg[j] + bb[j]);
}

// ---------------- fusion ----------------
__global__ void fusion_kernel(const float* __restrict__ ax, const float* __restrict__ axi,
                              float* __restrict__ alpha_o, float* __restrict__ um_o,
                              float* __restrict__ u_o, float* __restrict__ ui_o)
{
    int b = blockIdx.x, s = threadIdx.x;
    const float* X  = ax  + (long long)b*ZL*SL + s;
    const float* Xi = axi + (long long)b*ZL*SL + s;
    float u, ui;
    {
        float mx = -1e30f;
        for (int t = 0; t < ZL; t++) mx = fmaxf(mx, X[t*SL]);
        float sum = 0.f;
        for (int t = 0; t < ZL; t++) sum += expf(X[t*SL] - mx);
        float inv = 1.f/sum, acc = 0.f;
        for (int t = 0; t < ZL; t++) { float p = expf(X[t*SL]-mx)*inv; acc -= p*logf(p + 1e-8f); }
        u = acc;
    }
    {
        float mx = -1e30f;
        for (int t = 0; t < ZL; t++) mx = fmaxf(mx, Xi[t*SL]);
        float sum = 0.f;
        for (int t = 0; t < ZL; t++) sum += expf(Xi[t*SL] - mx);
        float inv = 1.f/sum, acc = 0.f;
        for (int t = 0; t < ZL; t++) { float p = expf(Xi[t*SL]-mx)*inv; acc -= p*logf(p + 1e-8f); }
        ui = acc;
    }
    int idx = b*SL + s;
    float alpha = 1.f / (1.f + expf(-(ui - u)));
    alpha_o[idx] = alpha;
    um_o[idx] = 0.5f*(u + ui);
    u_o[idx] = u;
    ui_o[idx] = ui;
}

// ---------------- elementwise helpers ----------------
__global__ void cat_feat_k(const float* __restrict__ x, const float* __restrict__ xi,
                           __half* __restrict__ o)
{
    long long i = (long long)blockIdx.x*blockDim.x + threadIdx.x;
    const long long n = (long long)BATCH*ZL*2*DIM;
    if (i >= n) return;
    int c = (int)(i % (2*DIM));
    long long bt = i / (2*DIM);
    long long b = bt / ZL, t = bt % ZL;
    long long src = (b*TT + t)*DIM;
    float v = (c < DIM) ? x[src + c] : xi[src + c - DIM];
    o[i] = __float2half_rn(v);
}

__global__ void vtrans_k(const __half* __restrict__ qkv, __half* __restrict__ vt)
{
    __shared__ float t[32][33];
    int bh = blockIdx.z;
    long long b = bh / HEADS, h = bh % HEADS;
    const __half* src = qkv + b*NN*QKV3 + 2*DIM + h*HD;
    int tt0 = blockIdx.x*32;
    int cc0 = blockIdx.y*32;
    int tx = threadIdx.x, ty = threadIdx.y;
    #pragma unroll
    for (int i = 0; i < 32; i += 8)
        t[ty+i][tx] = __half2float(src[(long long)(tt0+ty+i)*QKV3 + cc0 + tx]);
    __syncthreads();
    __half* dst = vt + ((long long)bh*HD)*NN;
    #pragma unroll
    for (int i = 0; i < 32; i += 8)
        dst[(long long)(cc0+ty+i)*NN + tt0 + tx] = __float2half_rn(t[tx][ty+i]);
}

__global__ void make_v_k(const __half* __restrict__ ns, const __half* __restrict__ nsi,
                         const float* __restrict__ alpha, __half* __restrict__ v)
{
    long long i = (long long)blockIdx.x*blockDim.x + threadIdx.x;
    const long long n = (long long)BATCH*SL*DIM;
    if (i >= n) return;
    long long bs = i / DIM;
    float a = alpha[bs];
    v[i] = __float2half_rn(a*__half2float(ns[i]) + (1.f - a)*__half2float(nsi[i]));
}

__global__ void i2f_k(const int* __restrict__ in, float* __restrict__ out, int n)
{
    int i = blockIdx.x*blockDim.x + threadIdx.x;
    if (i < n) out[i] = (float)in[i];
}

__global__ void f2h_k(const float* __restrict__ in, __half* __restrict__ out, int n4)
{
    int i = blockIdx.x*blockDim.x + threadIdx.x;
    if (i < n4) {
        float4 v = *(const float4*)(in + 4*i);
        *(uint2*)(out + 4*i) = to_h2(v);
    }
}

// ---------------- host-side helpers ----------------
template<int TM, int TN, typename TA, typename TB, typename TC>
static inline void mm(const TA* A, const TB* B, const float* bias,
                      const float* r1, const float* r2, TC* C,
                      int M, int N, int K, int lda, int ldb, int ldc,
                      long long sAb, long long sBb, long long sCb,
                      int nb, int nh,
                      long long sAh, long long sBh, long long sCh,
                      float alpha, int act)
{
    constexpr bool ASYNC =
        std::is_same<TA,__half>::value && std::is_same<TB,__half>::value;
    constexpr int STAGE_BYTES = ASYNC ? (TM + TN)*RWA*2 : (TM + TN)*RWH*2;
    constexpr int EPI = 32*(TN+4)*4;
    constexpr int DS = (2*STAGE_BYTES > EPI) ? 2*STAGE_BYTES : EPI;
    static bool init = false;
    if (!init) {
        cudaFuncSetAttribute(mm2<TM,TN,TA,TB,TC>, cudaFuncAttributeMaxDynamicSharedMemorySize, DS);
        init = true;
    }
    dim3 g(N/TN, M/TM, nb*nh);
    mm2<TM,TN,TA,TB,TC><<<g, 512, DS>>>(A,B,bias,r1,r2,C,K,lda,ldb,ldc,sAb,sBb,sCb,nh,sAh,sBh,sCh,alpha,act);
}

static inline int cdiv(long long a, int b) { return (int)((a + b - 1) / b); }

extern "C" void kernel_launch(void* const* d_in, const int* in_sizes, int n_in,
                              void* d_out, int out_size)
{
    const float* x      = (const float*)d_in[0];
    const float* xi     = (const float*)d_in[1];
    const int*   git    = (const int*)  d_in[2];
    const int*   giti   = (const int*)  d_in[3];
    const int*   gis    = (const int*)  d_in[4];
    const int*   gisi   = (const int*)  d_in[5];
    const float* w_qkv  = (const float*)d_in[6];
    const float* b_qkv  = (const float*)d_in[7];
    const float* w_proj = (const float*)d_in[8];
    const float* b_proj = (const float*)d_in[9];
    const float* g1     = (const float*)d_in[10];
    const float* bt1    = (const float*)d_in[11];
    const float* g2     = (const float*)d_in[12];
    const float* bt2    = (const float*)d_in[13];
    const float* w_fc1  = (const float*)d_in[14];
    const float* b_fc1  = (const float*)d_in[15];
    const float* w_fc2  = (const float*)d_in[16];
    const float* b_fc2  = (const float*)d_in[17];
    const float* w_al   = (const float*)d_in[18];
    const float* b_al   = (const float*)d_in[19];
    const float* w_al2  = (const float*)d_in[20];
    const float* b_al2  = (const float*)d_in[21];
    const float* w_fus  = (const float*)d_in[22];
    const float* b_fus  = (const float*)d_in[23];
    float* out = (float*)d_out;

    float *p_attnx, *p_attnxi, *p_xattn, *p_xiattn, *p_vf,
          *p_xnew, *p_xinew, *p_adap2;
    __half *p_cath, *p_zfh, *p_nsh, *p_nsih, *p_lnh, *p_qkvh, *p_vth, *p_aoh,
           *p_hh, *p_vh, *p_lnvh, *p_lnxh, *p_lnxih;
    __half *wqkvh, *wprojh, *wfc1h, *wfc2h, *walh, *wal2h, *wfush;
    cudaGetSymbolAddress((void**)&p_cath,  g_cath);
    cudaGetSymbolAddress((void**)&p_zfh,   g_zfh);
    cudaGetSymbolAddress((void**)&p_nsh,   g_nsh);
    cudaGetSymbolAddress((void**)&p_nsih,  g_nsih);
    cudaGetSymbolAddress((void**)&p_attnx, g_attnx);
    cudaGetSymbolAddress((void**)&p_attnxi,g_attnxi);
    cudaGetSymbolAddress((void**)&p_lnh,   g_lnh);
    cudaGetSymbolAddress((void**)&p_qkvh,  g_qkvh);
    cudaGetSymbolAddress((void**)&p_vth,   g_vth);
    cudaGetSymbolAddress((void**)&p_aoh,   g_aoh);
    cudaGetSymbolAddress((void**)&p_xattn, g_xattn);
    cudaGetSymbolAddress((void**)&p_xiattn,g_xiattn);
    cudaGetSymbolAddress((void**)&p_vh,    g_vh);
    cudaGetSymbolAddress((void**)&p_vf,    g_vf);
    cudaGetSymbolAddress((void**)&p_xnew,  g_xnew);
    cudaGetSymbolAddress((void**)&p_xinew, g_xinew);
    cudaGetSymbolAddress((void**)&p_lnvh,  g_lnvh);
    cudaGetSymbolAddress((void**)&p_lnxh,  g_lnxh);
    cudaGetSymbolAddress((void**)&p_lnxih, g_lnxih);
    cudaGetSymbolAddress((void**)&p_adap2, g_adap2);
    cudaGetSymbolAddress((void**)&p_hh,    g_hh);
    cudaGetSymbolAddress((void**)&wqkvh,   g_wqkvh);
    cudaGetSymbolAddress((void**)&wprojh,  g_wprojh);
    cudaGetSymbolAddress((void**)&wfc1h,   g_wfc1h);
    cudaGetSymbolAddress((void**)&wfc2h,   g_wfc2h);
    cudaGetSymbolAddress((void**)&walh,    g_walh);
    cudaGetSymbolAddress((void**)&wal2h,   g_wal2h);
    cudaGetSymbolAddress((void**)&wfush,   g_wfush);

    const float scale_dim = 1.f / sqrtf((float)DIM);

    f2h_k<<<cdiv(DIM*2*DIM/4,256),256>>>(w_al, walh,   DIM*2*DIM/4);
    cat_feat_k<<<cdiv((long long)BATCH*ZL*2*DIM, 256), 256>>>(x, xi, p_cath);
    f2h_k<<<cdiv(QKV3*DIM/4,256),256>>>(w_qkv,  wqkvh,  QKV3*DIM/4);
    f2h_k<<<cdiv(HID*DIM/4,256),256>>>(w_fc1,  wfc1h,  HID*DIM/4);
    f2h_k<<<cdiv(DIM*HID/4,256),256>>>(w_fc2,  wfc2h,  DIM*HID/4);
    mm<128,128,__half,__half,__half>(p_cath, walh, b_al, nullptr, nullptr, p_zfh,
        BATCH*ZL, DIM, 2*DIM, 2*DIM, 2*DIM, DIM, 0,0,0, 1,1, 0,0,0, 1.f, 0);
    f2h_k<<<cdiv(DIM*DIM/4,256),256>>>(w_proj, wprojh, DIM*DIM/4);
    f2h_k<<<cdiv(DIM*DIM/4,256),256>>>(w_al2,  wal2h,  DIM*DIM/4);
    f2h_k<<<cdiv(DIM*DIM/4,256),256>>>(w_fus,  wfush,  DIM*DIM/4);

    // ---- ns/nsi (fp16) ----
    ln_kernel<__half><<<dim3(SL, BATCH), 256>>>(x  + (long long)ZL*DIM, p_nsh,  g1, bt1,
                                                (long long)TT*DIM, (long long)SL*DIM);
    ln_kernel<__half><<<dim3(SL, BATCH), 256>>>(xi + (long long)ZL*DIM, p_nsih, g1, bt1,
                                                (long long)TT*DIM, (long long)SL*DIM);

    // ---- MHA both streams ----
    {
        static bool ainit = false;
        if (!ainit) {
            cudaFuncSetAttribute(attn_fused, cudaFuncAttributeMaxDynamicSharedMemorySize, PV_SMEM);
            ainit = true;
        }
    }
    const float* src[2]    = {x, xi};
    float*       attn_o[2] = {out + O_ATTN, out + O_IATTN};
    float*       proj_o[2] = {p_xattn, p_xiattn};
    for (int side = 0; side < 2; side++) {
        ln_cat_kernel<<<dim3(NN, BATCH), 256>>>(p_zfh, src[side], p_lnh, g1, bt1);
        mm<128,128,__half,__half,__half>(p_lnh, wqkvh, b_qkv, nullptr, nullptr, p_qkvh,
            BATCH*NN, QKV3, DIM, DIM, DIM, QKV3, 0,0,0, 1,1, 0,0,0, 1.f, 0);
        vtrans_k<<<dim3(NN/32, HD/32, BATCH*HEADS), dim3(32,8)>>>(p_qkvh, p_vth);
        attn_fused<<<dim3(3, BATCH*HEADS), 512, PV_SMEM>>>(p_qkvh, p_vth, attn_o[side], p_aoh);
        mm<128,128,__half,__half,float>(p_aoh, wprojh, b_proj, nullptr, nullptr, proj_o[side],
            BATCH*NN, DIM, DIM, DIM, DIM, DIM, 0,0,0, 1,1, 0,0,0, 1.f, 0);
    }

    // ---- attn_x / attn_xi (now async fp16 path, TM=64) ----
    mm<64,128,__half,__half,float>(p_zfh, p_nsh, nullptr, nullptr, nullptr, p_attnx,
        ZL, SL, DIM, DIM, DIM, SL,
        (long long)ZL*DIM, (long long)SL*DIM, (long long)ZL*SL,
        BATCH, 1, 0,0,0, scale_dim, 0);
    mm<64,128,__half,__half,float>(p_zfh, p_nsih, nullptr, nullptr, nullptr, p_attnxi,
        ZL, SL, DIM, DIM, DIM, SL,
        (long long)ZL*DIM, (long long)SL*DIM, (long long)ZL*SL,
        BATCH, 1, 0,0,0, scale_dim, 0);

    // ---- fusion ----
    fusion_kernel<<<BATCH, SL>>>(p_attnx, p_attnxi,
                                 out + O_ALPHA, out + O_UM, out + O_U, out + O_UI);
    make_v_k<<<cdiv((long long)BATCH*SL*DIM, 256), 256>>>(p_nsh, p_nsih, out + O_ALPHA, p_vh);
    mm<128,128,__half,__half,float>(p_vh, wfush, b_fus, nullptr, nullptr, p_vf,
        BATCH*SL, DIM, DIM, DIM, DIM, DIM, 0,0,0, 1,1, 0,0,0, 1.f, 0);

    // ---- fused residual + 3x LN ----
    resid_ln_k<<<dim3(TT, BATCH), 256>>>(x, xi, p_xattn, p_xiattn, p_vf, g2, bt2,
                                         p_xnew, p_xinew, p_lnvh, p_lnxh, p_lnxih);

    // ---- adap2 ----
    mm<128,128,__half,__half,float>(p_lnvh, wal2h, b_al2, nullptr, nullptr, p_adap2,
        BATCH*TT, DIM, DIM, DIM, DIM, DIM, 0,0,0, 1,1, 0,0,0, 1.f, 0);

    // ---- MLP both streams ----
    __half* lnin[2] = {p_lnxh, p_lnxih};
    float*  xn[2]   = {p_xnew, p_xinew};
    float*  xo[2]   = {out + O_XOUT, out + O_XIOUT};
    for (int side = 0; side < 2; side++) {
        mm<128,128,__half,__half,__half>(lnin[side], wfc1h, b_fc1, nullptr, nullptr, p_hh,
            BATCH*TT, HID, DIM, DIM, DIM, HID, 0,0,0, 1,1, 0,0,0, 1.f, 1);
        mm<128,128,__half,__half,float>(p_hh, wfc2h, b_fc2, xn[side], p_adap2, xo[side],
            BATCH*TT, DIM, HID, HID, HID, DIM, 0,0,0, 1,1, 0,0,0, 1.f, 0);
    }

    // ---- index passthroughs ----
    i2f_k<<<cdiv(BATCH*ZL, 256), 256>>>(git,  out + O_GIT,  BATCH*ZL);
    i2f_k<<<cdiv(BATCH*SL, 256), 256>>>(gis,  out + O_GIS,  BATCH*SL);
    i2f_k<<<cdiv(BATCH*ZL, 256), 256>>>(giti, out + O_GITI, BATCH*ZL);
    i2f_k<<<cdiv(BATCH*SL, 256), 256>>>(gisi, out + O_GISI, BATCH*SL);
}

// round 11
// speedup vs baseline: 6.3271x; 1.0258x over previous
#include <cuda_runtime.h>
#include <cuda_fp16.h>
#include <math.h>
#include <cstdint>
#include <type_traits>

// ---------------- problem constants ----------------
#define BATCH 32
#define ZL 64
#define SL 256
#define TT 320
#define NN 384
#define DIM 768
#define HEADS 12
#define HD 64
#define HID 3072
#define QKV3 2304

#define O_XOUT   0LL
#define O_GIT    7864320LL
#define O_GIS    7866368LL
#define O_ATTN   7874560LL
#define O_XIOUT  64497664LL
#define O_GITI   72361984LL
#define O_GISI   72364032LL
#define O_IATTN  72372224LL
#define O_ALPHA  128995328LL
#define O_UM     129003520LL
#define O_U      129011712LL
#define O_UI     129019904LL

#define SIDE_OUT 64497664LL
#define NND  (BATCH*NN*DIM)      // 9437184
#define TTD  (BATCH*TT*DIM)      // 7864320
#define TTH  (BATCH*TT*HID)      // 31457280
#define NNQ  (BATCH*NN*QKV3)     // 28311552
#define VTN  (BATCH*HEADS*HD*NN) // 9437184
#define SLD  (BATCH*SL*DIM)      // 6291456

// ---------------- scratch ----------------
__device__ __half g_cath [BATCH*ZL*2*DIM];
__device__ __half g_zfh  [BATCH*ZL*DIM];
__device__ __half g_nsh  [SLD];
__device__ __half g_nsih [SLD];
__device__ float  g_attnx [BATCH*ZL*SL];
__device__ float  g_attnxi[BATCH*ZL*SL];
__device__ __half g_lnh2 [2*NND];
__device__ __half g_qkvh2[2*NNQ];
__device__ __half g_vth2 [2*VTN];
__device__ __half g_aoh2 [2*NND];
__device__ float  g_xattn2[2*NND];
__device__ __half g_vh   [SLD];
__device__ float  g_vf   [SLD];
__device__ float  g_xnew2[2*TTD];
__device__ __half g_lnvh [TTD];
__device__ __half g_lnx2 [2*TTD];
__device__ float  g_adap2[TTD];
__device__ __half g_hh2  [2*TTH];
__device__ __half g_wqkvh[QKV3*DIM];
__device__ __half g_wprojh[DIM*DIM];
__device__ __half g_wfc1h[HID*DIM];
__device__ __half g_wfc2h[DIM*HID];
__device__ __half g_walh [DIM*2*DIM];
__device__ __half g_wal2h[DIM*DIM];
__device__ __half g_wfush[DIM*DIM];

// =============== helpers =====================================================
__device__ __forceinline__ uint32_t smem_u32(const void* p) {
    uint32_t a;
    asm("{ .reg .u64 t; cvta.to.shared.u64 t, %1; cvt.u32.u64 %0, t; }" : "=r"(a) : "l"(p));
    return a;
}
__device__ __forceinline__ void mma16816h(float* d, const uint32_t* a, const uint32_t* b) {
    asm volatile("mma.sync.aligned.m16n8k16.row.col.f32.f16.f16.f32 "
        "{%0,%1,%2,%3}, {%4,%5,%6,%7}, {%8,%9}, {%0,%1,%2,%3};"
        : "+f"(d[0]), "+f"(d[1]), "+f"(d[2]), "+f"(d[3])
        : "r"(a[0]), "r"(a[1]), "r"(a[2]), "r"(a[3]), "r"(b[0]), "r"(b[1]));
}
__device__ __forceinline__ void ldsm4(uint32_t& r0, uint32_t& r1, uint32_t& r2, uint32_t& r3,
                                      uint32_t addr) {
    asm volatile("ldmatrix.sync.aligned.m8n8.x4.shared.b16 {%0,%1,%2,%3}, [%4];"
        : "=r"(r0), "=r"(r1), "=r"(r2), "=r"(r3) : "r"(addr));
}
__device__ __forceinline__ uint32_t pack_h2(float x, float y) {
    __half2 p = __float22half2_rn(make_float2(x, y));
    return *(uint32_t*)&p;
}
template<typename T> struct RawVec;
template<> struct RawVec<float>  { using type = float4; };
template<> struct RawVec<__half> { using type = uint2;  };
__device__ __forceinline__ uint2 to_h2(const float4& v) {
    return make_uint2(pack_h2(v.x, v.y), pack_h2(v.z, v.w));
}
__device__ __forceinline__ uint2 to_h2(const uint2& v) { return v; }
__device__ __forceinline__ void st_s(float* p, float v)  { *p = v; }
__device__ __forceinline__ void st_s(__half* p, float v) { *p = __float2half_rn(v); }
__device__ __forceinline__ void st2(float* p, float x, float y) {
    *(float2*)p = make_float2(x, y);
}
__device__ __forceinline__ void st2(__half* p, float x, float y) {
    *(uint32_t*)p = pack_h2(x, y);
}

#define CP_ASYNC16(dst, src) \
    asm volatile("cp.async.cg.shared.global [%0], [%1], 16;" :: "r"(dst), "l"(src))
#define CP_COMMIT()  asm volatile("cp.async.commit_group;")
#define CP_WAIT1()   asm volatile("cp.async.wait_group 1;")
#define CP_WAIT0()   asm volatile("cp.async.wait_group 0;")

// =============== fp16 mma.sync GEMM, typed A/B/C =============================
#define RWH 40
#define RWA 72

template<int TM, int TN, typename TA, typename TB, typename TC>
__global__ __launch_bounds__(512, 2)
void mm2(const TA* __restrict__ A, const TB* __restrict__ B,
         const float* __restrict__ bias,
         const float* __restrict__ res1, const float* __restrict__ res2,
         TC* __restrict__ C,
         int K, int lda, int ldb, int ldc,
         long long sAb, long long sBb, long long sCb, int batchH,
         long long sAh, long long sBh, long long sCh,
         long long sR1b, long long sR2b,
         float alpha, int act)
{
    extern __shared__ char dsm[];
    constexpr int WTM = TM/4, WTN = TN/4;
    constexpr int MI = WTM/16, NI = WTN/8;
    constexpr bool ASYNC =
        std::is_same<TA,__half>::value && std::is_same<TB,__half>::value;

    const int tid  = threadIdx.x;
    const int lane = tid & 31;
    const int w    = tid >> 5;
    const int wm   = w >> 2;
    const int wn   = w & 3;

    const int bz = blockIdx.z;
    const int b  = bz / batchH;
    const int h  = bz - b*batchH;
    const int m0 = blockIdx.y * TM;
    const int n0 = blockIdx.x * TN;
    const TA* Ab = A + (long long)b*sAb + (long long)h*sAh + (long long)m0*lda;
    const TB* Bb = B + (long long)b*sBb + (long long)h*sBh + (long long)n0*ldb;
    const long long coffC  = (long long)b*sCb + (long long)h*sCh;
    const long long coffR1 = (long long)b*sR1b;
    const long long coffR2 = (long long)b*sR2b;

    const uint32_t sb0 = smem_u32(dsm);

    float acc[MI][NI][4];
    #pragma unroll
    for (int mi = 0; mi < MI; mi++)
        #pragma unroll
        for (int ni = 0; ni < NI; ni++)
            #pragma unroll
            for (int j = 0; j < 4; j++) acc[mi][ni][j] = 0.f;

    if constexpr (ASYNC) {
        constexpr int AHL = TM*RWA;
        constexpr int STAGE_BYTES = (TM + TN)*RWA*2;
        constexpr int PLA = TM*8/512, PLB = TN*8/512;
        const uint32_t a_l = (uint32_t)(((wm*WTM + (lane & 15))*RWA + ((lane >> 4) << 3)) * 2);
        const uint32_t b_l = (uint32_t)(AHL*2 + ((wn*WTN + (lane & 15))*RWA + ((lane >> 4) << 3)) * 2);
        const __half* Abh = (const __half*)Ab;
        const __half* Bbh = (const __half*)Bb;
        const int NC = K >> 6;

        #pragma unroll
        for (int p = 0; p < PLA; p++) {
            int u = tid + (p << 9);
            int r = u >> 3, ch = u & 7;
            CP_ASYNC16(sb0 + (uint32_t)(r*RWA*2 + ch*16),
                       Abh + (long long)r*lda + ch*8);
        }
        #pragma unroll
        for (int p = 0; p < PLB; p++) {
            int u = tid + (p << 9);
            int r = u >> 3, ch = u & 7;
            CP_ASYNC16(sb0 + (uint32_t)(AHL*2 + r*RWA*2 + ch*16),
                       Bbh + (long long)r*ldb + ch*8);
        }
        CP_COMMIT();

        for (int c = 0; c < NC; c++) {
            const int st = c & 1;
            if (c + 1 < NC) {
                const int k0 = (c + 1) << 6;
                const uint32_t base = sb0 + ((c + 1) & 1) * STAGE_BYTES;
                #pragma unroll
                for (int p = 0; p < PLA; p++) {
                    int u = tid + (p << 9);
                    int r = u >> 3, ch = u & 7;
                    CP_ASYNC16(base + (uint32_t)(r*RWA*2 + ch*16),
                               Abh + (long long)r*lda + k0 + ch*8);
                }
                #pragma unroll
                for (int p = 0; p < PLB; p++) {
                    int u = tid + (p << 9);
                    int r = u >> 3, ch = u & 7;
                    CP_ASYNC16(base + (uint32_t)(AHL*2 + r*RWA*2 + ch*16),
                               Bbh + (long long)r*ldb + k0 + ch*8);
                }
                CP_COMMIT();
                CP_WAIT1();
            } else {
                CP_WAIT0();
            }
            __syncthreads();

            const uint32_t stageu = sb0 + st * STAGE_BYTES;
            #pragma unroll
            for (int ks = 0; ks < 4; ks++) {
                const uint32_t kb = ks * 32;
                uint32_t ah[MI][4];
                #pragma unroll
                for (int mi = 0; mi < MI; mi++) {
                    uint32_t ad = stageu + a_l + mi*(16*RWA*2) + kb;
                    ldsm4(ah[mi][0], ah[mi][1], ah[mi][2], ah[mi][3], ad);
                }
                uint32_t bh[NI][2];
                #pragma unroll
                for (int nj = 0; nj < NI/2; nj++) {
                    uint32_t bd = stageu + b_l + nj*(16*RWA*2) + kb;
                    uint32_t q0, q1, q2, q3;
                    ldsm4(q0, q1, q2, q3, bd);
                    bh[2*nj][0] = q0; bh[2*nj][1] = q2;
                    bh[2*nj+1][0] = q1; bh[2*nj+1][1] = q3;
                }
                #pragma unroll
                for (int mi = 0; mi < MI; mi++)
                    #pragma unroll
                    for (int ni = 0; ni < NI; ni++)
                        mma16816h(acc[mi][ni], ah[mi], bh[ni]);
            }
            __syncthreads();
        }
    } else {
        constexpr int AHL = TM*RWH;
        constexpr int STAGE_BYTES = (TM + TN)*RWH*2;
        constexpr int PA = TM/64, PB = TN/64;
        const uint32_t a_l = (uint32_t)(((wm*WTM + (lane & 15))*RWH + ((lane >> 4) << 3)) * 2);
        const uint32_t b_l = (uint32_t)(AHL*2 + ((wn*WTN + (lane & 15))*RWH + ((lane >> 4) << 3)) * 2);
        const int lq = tid & 7;
        const int lr = tid >> 3;
        const int NC = K >> 5;
        typename RawVec<TA>::type pA[PA];
        typename RawVec<TB>::type pB[PB];

        #pragma unroll
        for (int p = 0; p < PA; p++)
            pA[p] = *(const typename RawVec<TA>::type*)(Ab + (long long)(lr + 64*p)*lda + 4*lq);
        #pragma unroll
        for (int p = 0; p < PB; p++)
            pB[p] = *(const typename RawVec<TB>::type*)(Bb + (long long)(lr + 64*p)*ldb + 4*lq);

        for (int c = 0; c < NC; c++) {
            const int st = c & 1;
            char* sb = dsm + st * STAGE_BYTES;
            __half* Ah = (__half*)sb;
            __half* Bh = Ah + AHL;

            #pragma unroll
            for (int p = 0; p < PA; p++)
                *(uint2*)(Ah + (lr + 64*p)*RWH + 4*lq) = to_h2(pA[p]);
            #pragma unroll
            for (int p = 0; p < PB; p++)
                *(uint2*)(Bh + (lr + 64*p)*RWH + 4*lq) = to_h2(pB[p]);
            __syncthreads();

            if (c + 1 < NC) {
                const int k0 = (c + 1) << 5;
                #pragma unroll
                for (int p = 0; p < PA; p++)
                    pA[p] = *(const typename RawVec<TA>::type*)(Ab + (long long)(lr + 64*p)*lda + k0 + 4*lq);
                #pragma unroll
                for (int p = 0; p < PB; p++)
                    pB[p] = *(const typename RawVec<TB>::type*)(Bb + (long long)(lr + 64*p)*ldb + k0 + 4*lq);
            }

            const uint32_t stageu = sb0 + st * STAGE_BYTES;
            #pragma unroll
            for (int ks = 0; ks < 2; ks++) {
                const uint32_t kb = ks * 32;
                uint32_t ah[MI][4];
                #pragma unroll
                for (int mi = 0; mi < MI; mi++) {
                    uint32_t ad = stageu + a_l + mi*(16*RWH*2) + kb;
                    ldsm4(ah[mi][0], ah[mi][1], ah[mi][2], ah[mi][3], ad);
                }
                uint32_t bh[NI][2];
                #pragma unroll
                for (int nj = 0; nj < NI/2; nj++) {
                    uint32_t bd = stageu + b_l + nj*(16*RWH*2) + kb;
                    uint32_t q0, q1, q2, q3;
                    ldsm4(q0, q1, q2, q3, bd);
                    bh[2*nj][0] = q0; bh[2*nj][1] = q2;
                    bh[2*nj+1][0] = q1; bh[2*nj+1][1] = q3;
                }
                #pragma unroll
                for (int mi = 0; mi < MI; mi++)
                    #pragma unroll
                    for (int ni = 0; ni < NI; ni++)
                        mma16816h(acc[mi][ni], ah[mi], bh[ni]);
            }
            __syncthreads();
        }
    }

    // ---- epilogue: direct fragment stores (no SMEM bounce, no syncs) ----
    const int g = lane >> 2, t4 = lane & 3;
    float2 bv[NI];
    if (bias) {
        #pragma unroll
        for (int ni = 0; ni < NI; ni++)
            bv[ni] = *(const float2*)(bias + n0 + wn*WTN + ni*8 + 2*t4);
    }
    #pragma unroll
    for (int mi = 0; mi < MI; mi++)
        #pragma unroll
        for (int h2 = 0; h2 < 2; h2++) {
            long long row = m0 + wm*WTM + mi*16 + g + 8*h2;
            long long base = row*(long long)ldc + n0 + wn*WTN + 2*t4;
            #pragma unroll
            for (int ni = 0; ni < NI; ni++) {
                float vx = acc[mi][ni][2*h2]   * alpha;
                float vy = acc[mi][ni][2*h2+1] * alpha;
                if (bias) { vx += bv[ni].x; vy += bv[ni].y; }
                long long off = base + ni*8;
                if (res1) { float2 a = *(const float2*)(res1 + coffR1 + off); vx += a.x; vy += a.y; }
                if (res2) { float2 a = *(const float2*)(res2 + coffR2 + off); vx += a.x; vy += a.y; }
                if (act == 1) {
                    vx = 0.5f*vx*(1.f + erff(vx*0.70710678118654752f));
                    vy = 0.5f*vy*(1.f + erff(vy*0.70710678118654752f));
                }
                st2(C + coffC + off, vx, vy);
            }
        }
}

// =============== fused QK^T + softmax + P@V, dual-stream =====================
#define RW2 72
#define RW3 392
#define PV_SMEM (128*RW3*2 + 64*RW3*2 + 128*4*4 + 128*4)

__global__ __launch_bounds__(512, 1)
void attn_fused(const __half* __restrict__ qkv2, const __half* __restrict__ vt2,
                float* __restrict__ attn_base, __half* __restrict__ ao2)
{
    extern __shared__ char dsm[];
    __half* Ph  = (__half*)dsm;
    __half* Vs  = (__half*)(dsm + 128*RW3*2);
    float*  red = (float*)(dsm + 128*RW3*2 + 64*RW3*2);
    float*  invb= red + 128*4;
    __half* Qs  = (__half*)dsm;
    __half* Ks  = Qs + 128*RW2;

    const int tid = threadIdx.x;
    const int lane = tid & 31;
    const int w = tid >> 5;
    const int wm = w >> 2, wn = w & 3;
    const int g = lane >> 2, t4 = lane & 3;

    const int m0 = blockIdx.x * 128;
    const int sy = blockIdx.y;
    const int side = sy / (BATCH*HEADS);
    const int bh = sy - side*(BATCH*HEADS);
    const int b  = bh / HEADS;
    const int hh = bh - b*HEADS;

    const __half* qkv = qkv2 + (long long)side*NNQ;
    const __half* vt  = vt2  + (long long)side*VTN;
    float* attn = attn_base + (long long)side*SIDE_OUT;
    __half* ao  = ao2 + (long long)side*NND;

    const __half* qbase = qkv + (long long)b*NN*QKV3 + hh*HD;

    #pragma unroll
    for (int p = 0; p < 2; p++) {
        int u = tid + (p << 9);
        int r = u >> 3, ch = u & 7;
        *(uint4*)(Qs + r*RW2 + ch*8) =
            *(const uint4*)(qbase + (long long)(m0 + r)*QKV3 + ch*8);
    }
    #pragma unroll
    for (int p = 0; p < 6; p++) {
        int u = tid + (p << 9);
        int r = u >> 3, ch = u & 7;
        *(uint4*)(Ks + r*RW2 + ch*8) =
            *(const uint4*)(qbase + DIM + (long long)r*QKV3 + ch*8);
    }
    __syncthreads();

    const uint32_t sq = smem_u32(Qs);
    const uint32_t sk = smem_u32(Ks);
    const uint32_t a_l = sq + ((wm*32 + (lane & 15))*RW2 + ((lane >> 4) << 3)) * 2;
    const uint32_t b_l = sk + ((wn*96 + (lane & 15))*RW2 + ((lane >> 4) << 3)) * 2;

    float acc[2][12][4];
    #pragma unroll
    for (int mi = 0; mi < 2; mi++)
        #pragma unroll
        for (int ni = 0; ni < 12; ni++)
            #pragma unroll
            for (int j = 0; j < 4; j++) acc[mi][ni][j] = 0.f;

    #pragma unroll
    for (int ks = 0; ks < 4; ks++) {
        const uint32_t kb = ks * 32;
        uint32_t ah[2][4];
        #pragma unroll
        for (int mi = 0; mi < 2; mi++)
            ldsm4(ah[mi][0], ah[mi][1], ah[mi][2], ah[mi][3],
                  a_l + mi*(16*RW2*2) + kb);
        #pragma unroll
        for (int nj = 0; nj < 6; nj++) {
            uint32_t q0, q1, q2, q3;
            ldsm4(q0, q1, q2, q3, b_l + nj*(16*RW2*2) + kb);
            uint32_t b0[2] = {q0, q2}, b1[2] = {q1, q3};
            #pragma unroll
            for (int mi = 0; mi < 2; mi++) {
                mma16816h(acc[mi][2*nj],   ah[mi], b0);
                mma16816h(acc[mi][2*nj+1], ah[mi], b1);
            }
        }
    }

    #pragma unroll
    for (int mi = 0; mi < 2; mi++)
        #pragma unroll
        for (int ni = 0; ni < 12; ni++)
            #pragma unroll
            for (int j = 0; j < 4; j++) acc[mi][ni][j] *= 0.125f;

    float M[2][2];
    #pragma unroll
    for (int mi = 0; mi < 2; mi++)
        #pragma unroll
        for (int h2 = 0; h2 < 2; h2++) {
            float m = -1e30f;
            #pragma unroll
            for (int ni = 0; ni < 12; ni++)
                m = fmaxf(m, fmaxf(acc[mi][ni][2*h2], acc[mi][ni][2*h2+1]));
            m = fmaxf(m, __shfl_xor_sync(0xFFFFFFFFu, m, 1));
            m = fmaxf(m, __shfl_xor_sync(0xFFFFFFFFu, m, 2));
            if (t4 == 0) red[(wm*32 + mi*16 + g + 8*h2)*4 + wn] = m;
        }
    __syncthreads();
    #pragma unroll
    for (int mi = 0; mi < 2; mi++)
        #pragma unroll
        for (int h2 = 0; h2 < 2; h2++) {
            int row = wm*32 + mi*16 + g + 8*h2;
            M[mi][h2] = fmaxf(fmaxf(red[row*4], red[row*4+1]),
                              fmaxf(red[row*4+2], red[row*4+3]));
        }
    __syncthreads();

    float S[2][2];
    #pragma unroll
    for (int mi = 0; mi < 2; mi++)
        #pragma unroll
        for (int h2 = 0; h2 < 2; h2++) {
            float s = 0.f;
            #pragma unroll
            for (int ni = 0; ni < 12; ni++) {
                float e0 = __expf(acc[mi][ni][2*h2]   - M[mi][h2]);
                float e1 = __expf(acc[mi][ni][2*h2+1] - M[mi][h2]);
                acc[mi][ni][2*h2] = e0; acc[mi][ni][2*h2+1] = e1;
                s += e0 + e1;
            }
            s += __shfl_xor_sync(0xFFFFFFFFu, s, 1);
            s += __shfl_xor_sync(0xFFFFFFFFu, s, 2);
            if (t4 == 0) red[(wm*32 + mi*16 + g + 8*h2)*4 + wn] = s;
        }
    __syncthreads();
    #pragma unroll
    for (int mi = 0; mi < 2; mi++)
        #pragma unroll
        for (int h2 = 0; h2 < 2; h2++) {
            int row = wm*32 + mi*16 + g + 8*h2;
            float inv = 1.f / (red[row*4] + red[row*4+1] + red[row*4+2] + red[row*4+3]);
            S[mi][h2] = inv;
            if (wn == 0 && t4 == 0) invb[row] = inv;
        }

    float* abase = attn + (long long)bh*NN*NN;
    #pragma unroll
    for (int mi = 0; mi < 2; mi++)
        #pragma unroll
        for (int h2 = 0; h2 < 2; h2++) {
            int row = m0 + wm*32 + mi*16 + g + 8*h2;
            float inv = S[mi][h2];
            float* rp = abase + (long long)row*NN + wn*96 + 2*t4;
            #pragma unroll
            for (int ni = 0; ni < 12; ni++) {
                float2 o;
                o.x = acc[mi][ni][2*h2]   * inv;
                o.y = acc[mi][ni][2*h2+1] * inv;
                *(float2*)(rp + ni*8) = o;
            }
        }

    __syncthreads();

    #pragma unroll
    for (int mi = 0; mi < 2; mi++)
        #pragma unroll
        for (int h2 = 0; h2 < 2; h2++) {
            int row = wm*32 + mi*16 + g + 8*h2;
            __half* rp = Ph + row*RW3 + wn*96 + 2*t4;
            #pragma unroll
            for (int ni = 0; ni < 12; ni++)
                *(uint32_t*)(rp + ni*8) = pack_h2(acc[mi][ni][2*h2], acc[mi][ni][2*h2+1]);
        }
    const __half* vbase = vt + (long long)bh*HD*NN;
    #pragma unroll
    for (int p = 0; p < 6; p++) {
        int u = tid + (p << 9);
        int r = u / 48, c = u - r*48;
        *(uint4*)(Vs + r*RW3 + c*8) = *(const uint4*)(vbase + r*NN + c*8);
    }
    __syncthreads();

    const int wm2 = w >> 2, wn2 = w & 3;
    const uint32_t pa = smem_u32(Ph) + ((wm2*32 + (lane & 15))*RW3 + ((lane >> 4) << 3))*2;
    const uint32_t pb = smem_u32(Vs) + ((wn2*16 + (lane & 15))*RW3 + ((lane >> 4) << 3))*2;

    float acc2[2][2][4];
    #pragma unroll
    for (int mi = 0; mi < 2; mi++)
        #pragma unroll
        for (int ni = 0; ni < 2; ni++)
            #pragma unroll
            for (int j = 0; j < 4; j++) acc2[mi][ni][j] = 0.f;

    #pragma unroll
    for (int ks = 0; ks < 24; ks++) {
        const uint32_t kb = ks * 32;
        uint32_t ah0[4], ah1[4], q0, q1, q2, q3;
        ldsm4(ah0[0], ah0[1], ah0[2], ah0[3], pa + kb);
        ldsm4(ah1[0], ah1[1], ah1[2], ah1[3], pa + 16*RW3*2 + kb);
        ldsm4(q0, q1, q2, q3, pb + kb);
        uint32_t b0[2] = {q0, q2}, b1[2] = {q1, q3};
        mma16816h(acc2[0][0], ah0, b0);
        mma16816h(acc2[0][1], ah0, b1);
        mma16816h(acc2[1][0], ah1, b0);
        mma16816h(acc2[1][1], ah1, b1);
    }

    #pragma unroll
    for (int mi = 0; mi < 2; mi++) {
        int r0 = wm2*32 + mi*16 + g;
        float inv0 = invb[r0], inv1 = invb[r0 + 8];
        long long base0 = ((long long)b*NN + m0 + r0)*DIM + hh*HD;
        long long base1 = base0 + 8LL*DIM;
        #pragma unroll
        for (int ni = 0; ni < 2; ni++) {
            int col = wn2*16 + ni*8 + 2*t4;
            *(uint32_t*)(ao + base0 + col) = pack_h2(acc2[mi][ni][0]*inv0, acc2[mi][ni][1]*inv0);
            *(uint32_t*)(ao + base1 + col) = pack_h2(acc2[mi][ni][2]*inv1, acc2[mi][ni][3]*inv1);
        }
    }
}

// ---------------- LayerNorm over 768 features -------------------------------
template<typename TO>
__global__ void ln_kernel(const float* __restrict__ in, TO* __restrict__ out,
                          const float* __restrict__ g, const float* __restrict__ b,
                          long long in_bstride, long long out_bstride)
{
    const float* x = in  + (long long)blockIdx.y*in_bstride  + (long long)blockIdx.x*DIM;
    TO*          y = out + (long long)blockIdx.y*out_bstride + (long long)blockIdx.x*DIM;
    int tid = threadIdx.x;
    float v0 = x[tid], v1 = x[tid+256], v2 = x[tid+512];
    __shared__ float sh[256];
    sh[tid] = v0 + v1 + v2;
    __syncthreads();
    for (int o = 128; o > 0; o >>= 1) { if (tid < o) sh[tid] += sh[tid+o]; __syncthreads(); }
    float mean = sh[0] * (1.f/768.f);
    __syncthreads();
    float d0 = v0-mean, d1 = v1-mean, d2 = v2-mean;
    sh[tid] = d0*d0 + d1*d1 + d2*d2;
    __syncthreads();
    for (int o = 128; o > 0; o >>= 1) { if (tid < o) sh[tid] += sh[tid+o]; __syncthreads(); }
    float inv = rsqrtf(sh[0] * (1.f/768.f) + 1e-5f);
    st_s(y + tid,     d0*inv*g[tid]     + b[tid]);
    st_s(y + tid+256, d1*inv*g[tid+256] + b[tid+256]);
    st_s(y + tid+512, d2*inv*g[tid+512] + b[tid+512]);
}

// LN over concat [z_f(fp16), x/xi(fp32)], both sides in one launch (z axis)
__global__ void ln_cat_kernel(const __half* __restrict__ zf,
                              const float* __restrict__ x, const float* __restrict__ xi,
                              __half* __restrict__ out2,
                              const float* __restrict__ g, const float* __restrict__ b)
{
    int t = blockIdx.x, bb = blockIdx.y, side = blockIdx.z;
    const float* xs = side ? xi : x;
    __half* y = out2 + (long long)side*NND + ((long long)bb*NN + t)*DIM;
    int tid = threadIdx.x;
    float v0, v1, v2;
    if (t < ZL) {
        const __half* src = zf + ((long long)bb*ZL + t)*DIM;
        v0 = __half2float(src[tid]);
        v1 = __half2float(src[tid+256]);
        v2 = __half2float(src[tid+512]);
    } else {
        const float* src = xs + ((long long)bb*TT + (t - ZL))*DIM;
        v0 = src[tid]; v1 = src[tid+256]; v2 = src[tid+512];
    }
    __shared__ float sh[256];
    sh[tid] = v0 + v1 + v2;
    __syncthreads();
    for (int o = 128; o > 0; o >>= 1) { if (tid < o) sh[tid] += sh[tid+o]; __syncthreads(); }
    float mean = sh[0] * (1.f/768.f);
    __syncthreads();
    float d0 = v0-mean, d1 = v1-mean, d2 = v2-mean;
    sh[tid] = d0*d0 + d1*d1 + d2*d2;
    __syncthreads();
    for (int o = 128; o > 0; o >>= 1) { if (tid < o) sh[tid] += sh[tid+o]; __syncthreads(); }
    float inv = rsqrtf(sh[0] * (1.f/768.f) + 1e-5f);
    y[tid]     = __float2half_rn(d0*inv*g[tid]     + b[tid]);
    y[tid+256] = __float2half_rn(d1*inv*g[tid+256] + b[tid+256]);
    y[tid+512] = __float2half_rn(d2*inv*g[tid+512] + b[tid+512]);
}

// ---------------- fused residual + 3x LayerNorm (single combined reduction) --
__global__ void resid_ln_k(const float* __restrict__ x, const float* __restrict__ xi,
                           const float* __restrict__ xattn2,
                           const float* __restrict__ vfus,
                           const float* __restrict__ g2, const float* __restrict__ bt2,
                           float* __restrict__ xnew2,
                           __half* __restrict__ lnv, __half* __restrict__ lnx2)
{
    const int t = blockIdx.x, b = blockIdx.y;
    const int tid = threadIdx.x;
    const long long rbase = ((long long)b*TT + t)*DIM;
    const long long abase = ((long long)b*NN + ZL + t)*DIM;
    const float* xattn  = xattn2;
    const float* xiattn = xattn2 + NND;
    const float* vsrc = (t < ZL) ? xiattn + ((long long)b*NN + t)*DIM
                                 : vfus   + ((long long)b*SL + (t - ZL))*DIM;

    float vf[3], xo[3], xio[3];
    float s[6] = {0,0,0,0,0,0};
    #pragma unroll
    for (int j = 0; j < 3; j++) {
        int c = tid + j*256;
        float vv = vsrc[c];
        float a1 = xattn[abase + c], a2 = xiattn[abase + c];
        float xv = x[rbase + c] + a1 + vv;
        float xiv = xi[rbase + c] + a2 + vv;
        vf[j] = vv; xo[j] = xv; xio[j] = xiv;
        xnew2[rbase + c]       = xv;
        xnew2[TTD + rbase + c] = xiv;
        s[0] += vv;  s[1] += vv*vv;
        s[2] += xv;  s[3] += xv*xv;
        s[4] += xiv; s[5] += xiv*xiv;
    }

    __shared__ float sh[6][256];
    #pragma unroll
    for (int k = 0; k < 6; k++) sh[k][tid] = s[k];
    __syncthreads();
    for (int o = 128; o > 0; o >>= 1) {
        if (tid < o) {
            #pragma unroll
            for (int k = 0; k < 6; k++) sh[k][tid] += sh[k][tid+o];
        }
        __syncthreads();
    }
    float mv = sh[0][0]*(1.f/768.f), iv = rsqrtf(sh[1][0]*(1.f/768.f) - mv*mv + 1e-5f);
    float mx = sh[2][0]*(1.f/768.f), ix = rsqrtf(sh[3][0]*(1.f/768.f) - mx*mx + 1e-5f);
    float mi2 = sh[4][0]*(1.f/768.f), ii = rsqrtf(sh[5][0]*(1.f/768.f) - mi2*mi2 + 1e-5f);

    #pragma unroll
    for (int j = 0; j < 3; j++) {
        int c = tid + j*256;
        float gg = g2[c], bb = bt2[c];
        lnv[rbase + c]        = __float2half_rn((vf[j]-mv)*iv*gg + bb);
        lnx2[rbase + c]       = __float2half_rn((xo[j]-mx)*ix*gg + bb);
        lnx2[TTD + rbase + c] = __float2half_rn((xio[j]-mi2)*ii*gg + bb);
    }
}

// ---------------- fusion ----------------
__global__ void fusion_kernel(const float* __restrict__ ax, const float* __restrict__ axi,
                              float* __restrict__ alpha_o, float* __restrict__ um_o,
                              float* __restrict__ u_o, float* __restrict__ ui_o)
{
    int b = blockIdx.x, s = threadIdx.x;
    const float* X  = ax  + (long long)b*ZL*SL + s;
    const float* Xi = axi + (long long)b*ZL*SL + s;
    float u, ui;
    {
        float mx = -1e30f;
        for (int t = 0; t < ZL; t++) mx = fmaxf(mx, X[t*SL]);
        float sum = 0.f;
        for (int t = 0; t < ZL; t++) sum += expf(X[t*SL] - mx);
        float inv = 1.f/sum, acc = 0.f;
        for (int t = 0; t < ZL; t++) { float p = expf(X[t*SL]-mx)*inv; acc -= p*logf(p + 1e-8f); }
        u = acc;
    }
    {
        float mx = -1e30f;
        for (int t = 0; t < ZL; t++) mx = fmaxf(mx, Xi[t*SL]);
        float sum = 0.f;
        for (int t = 0; t < ZL; t++) sum += expf(Xi[t*SL] - mx);
        float inv = 1.f/sum, acc = 0.f;
        for (int t = 0; t < ZL; t++) { float p = expf(Xi[t*SL]-mx)*inv; acc -= p*logf(p + 1e-8f); }
        ui = acc;
    }
    int idx = b*SL + s;
    float alpha = 1.f / (1.f + expf(-(ui - u)));
    alpha_o[idx] = alpha;
    um_o[idx] = 0.5f*(u + ui);
    u_o[idx] = u;
    ui_o[idx] = ui;
}

// ---------------- elementwise helpers ----------------
__global__ void cat_feat_k(const float* __restrict__ x, const float* __restrict__ xi,
                           __half* __restrict__ o)
{
    long long i = (long long)blockIdx.x*blockDim.x + threadIdx.x;
    const long long n = (long long)BATCH*ZL*2*DIM;
    if (i >= n) return;
    int c = (int)(i % (2*DIM));
    long long bt = i / (2*DIM);
    long long b = bt / ZL, t = bt % ZL;
    long long src = (b*TT + t)*DIM;
    float v = (c < DIM) ? x[src + c] : xi[src + c - DIM];
    o[i] = __float2half_rn(v);
}

// V transpose, both sides in one launch (z axis doubled)
__global__ void vtrans_k(const __half* __restrict__ qkv2, __half* __restrict__ vt2)
{
    __shared__ float t[32][33];
    int z = blockIdx.z;
    int side = z / (BATCH*HEADS);
    int bh = z - side*(BATCH*HEADS);
    long long b = bh / HEADS, h = bh % HEADS;
    const __half* src = qkv2 + (long long)side*NNQ + b*NN*QKV3 + 2*DIM + h*HD;
    int tt0 = blockIdx.x*32;
    int cc0 = blockIdx.y*32;
    int tx = threadIdx.x, ty = threadIdx.y;
    #pragma unroll
    for (int i = 0; i < 32; i += 8)
        t[ty+i][tx] = __half2float(src[(long long)(tt0+ty+i)*QKV3 + cc0 + tx]);
    __syncthreads();
    __half* dst = vt2 + (long long)side*VTN + ((long long)bh*HD)*NN;
    #pragma unroll
    for (int i = 0; i < 32; i += 8)
        dst[(long long)(cc0+ty+i)*NN + tt0 + tx] = __float2half_rn(t[tx][ty+i]);
}

__global__ void make_v_k(const __half* __restrict__ ns, const __half* __restrict__ nsi,
                         const float* __restrict__ alpha, __half* __restrict__ v)
{
    long long i = (long long)blockIdx.x*blockDim.x + threadIdx.x;
    const long long n = (long long)SLD;
    if (i >= n) return;
    long long bs = i / DIM;
    float a = alpha[bs];
    v[i] = __float2half_rn(a*__half2float(ns[i]) + (1.f - a)*__half2float(nsi[i]));
}

__global__ void i2f_k(const int* __restrict__ in, float* __restrict__ out, int n)
{
    int i = blockIdx.x*blockDim.x + threadIdx.x;
    if (i < n) out[i] = (float)in[i];
}

// all 7 weight conversions fused, float4 granular
__global__ void f2h_all(const float* s0, __half* d0, int n0,
                        const float* s1, __half* d1, int n1,
                        const float* s2, __half* d2, int n2,
                        const float* s3, __half* d3, int n3,
                        const float* s4, __half* d4, int n4,
                        const float* s5, __half* d5, int n5,
                        const float* s6, __half* d6, int n6)
{
    int i = blockIdx.x*blockDim.x + threadIdx.x;
    const float* s; __half* d;
    if      (i < n0)                      { s = s0; d = d0; }
    else if ((i -= n0) < n1)              { s = s1; d = d1; }
    else if ((i -= n1) < n2)              { s = s2; d = d2; }
    else if ((i -= n2) < n3)              { s = s3; d = d3; }
    else if ((i -= n3) < n4)              { s = s4; d = d4; }
    else if ((i -= n4) < n5)              { s = s5; d = d5; }
    else if ((i -= n5) < n6)              { s = s6; d = d6; }
    else return;
    float4 v = *(const float4*)(s + 4*i);
    *(uint2*)(d + 4*i) = to_h2(v);
}

// ---------------- host-side helpers ----------------
template<int TM, int TN, typename TA, typename TB, typename TC>
static inline void mm(const TA* A, const TB* B, const float* bias,
                      const float* r1, const float* r2, TC* C,
                      int M, int N, int K, int lda, int ldb, int ldc,
                      long long sAb, long long sBb, long long sCb,
                      int nb, int nh,
                      long long sAh, long long sBh, long long sCh,
                      long long sR1b, long long sR2b,
                      float alpha, int act)
{
    constexpr bool ASYNC =
        std::is_same<TA,__half>::value && std::is_same<TB,__half>::value;
    constexpr int DS = 2 * (ASYNC ? (TM + TN)*RWA*2 : (TM + TN)*RWH*2);
    static bool init = false;
    if (!init) {
        cudaFuncSetAttribute(mm2<TM,TN,TA,TB,TC>, cudaFuncAttributeMaxDynamicSharedMemorySize, DS);
        init = true;
    }
    dim3 g(N/TN, M/TM, nb*nh);
    mm2<TM,TN,TA,TB,TC><<<g, 512, DS>>>(A,B,bias,r1,r2,C,K,lda,ldb,ldc,
        sAb,sBb,sCb,nh,sAh,sBh,sCh,sR1b,sR2b,alpha,act);
}

static inline int cdiv(long long a, int b) { return (int)((a + b - 1) / b); }

extern "C" void kernel_launch(void* const* d_in, const int* in_sizes, int n_in,
                              void* d_out, int out_size)
{
    const float* x      = (const float*)d_in[0];
    const float* xi     = (const float*)d_in[1];
    const int*   git    = (const int*)  d_in[2];
    const int*   giti   = (const int*)  d_in[3];
    const int*   gis    = (const int*)  d_in[4];
    const int*   gisi   = (const int*)  d_in[5];
    const float* w_qkv  = (const float*)d_in[6];
    const float* b_qkv  = (const float*)d_in[7];
    const float* w_proj = (const float*)d_in[8];
    const float* b_proj = (const float*)d_in[9];
    const float* g1     = (const float*)d_in[10];
    const float* bt1    = (const float*)d_in[11];
    const float* g2     = (const float*)d_in[12];
    const float* bt2    = (const float*)d_in[13];
    const float* w_fc1  = (const float*)d_in[14];
    const float* b_fc1  = (const float*)d_in[15];
    const float* w_fc2  = (const float*)d_in[16];
    const float* b_fc2  = (const float*)d_in[17];
    const float* w_al   = (const float*)d_in[18];
    const float* b_al   = (const float*)d_in[19];
    const float* w_al2  = (const float*)d_in[20];
    const float* b_al2  = (const float*)d_in[21];
    const float* w_fus  = (const float*)d_in[22];
    const float* b_fus  = (const float*)d_in[23];
    float* out = (float*)d_out;

    float *p_attnx, *p_attnxi, *p_xattn2, *p_vf, *p_xnew2, *p_adap2;
    __half *p_cath, *p_zfh, *p_nsh, *p_nsih, *p_lnh2, *p_qkvh2, *p_vth2, *p_aoh2,
           *p_hh2, *p_vh, *p_lnvh, *p_lnx2;
    __half *wqkvh, *wprojh, *wfc1h, *wfc2h, *walh, *wal2h, *wfush;
    cudaGetSymbolAddress((void**)&p_cath,   g_cath);
    cudaGetSymbolAddress((void**)&p_zfh,    g_zfh);
    cudaGetSymbolAddress((void**)&p_nsh,    g_nsh);
    cudaGetSymbolAddress((void**)&p_nsih,   g_nsih);
    cudaGetSymbolAddress((void**)&p_attnx,  g_attnx);
    cudaGetSymbolAddress((void**)&p_attnxi, g_attnxi);
    cudaGetSymbolAddress((void**)&p_lnh2,   g_lnh2);
    cudaGetSymbolAddress((void**)&p_qkvh2,  g_qkvh2);
    cudaGetSymbolAddress((void**)&p_vth2,   g_vth2);
    cudaGetSymbolAddress((void**)&p_aoh2,   g_aoh2);
    cudaGetSymbolAddress((void**)&p_xattn2, g_xattn2);
    cudaGetSymbolAddress((void**)&p_vh,     g_vh);
    cudaGetSymbolAddress((void**)&p_vf,     g_vf);
    cudaGetSymbolAddress((void**)&p_xnew2,  g_xnew2);
    cudaGetSymbolAddress((void**)&p_lnvh,   g_lnvh);
    cudaGetSymbolAddress((void**)&p_lnx2,   g_lnx2);
    cudaGetSymbolAddress((void**)&p_adap2,  g_adap2);
    cudaGetSymbolAddress((void**)&p_hh2,    g_hh2);
    cudaGetSymbolAddress((void**)&wqkvh,    g_wqkvh);
    cudaGetSymbolAddress((void**)&wprojh,   g_wprojh);
    cudaGetSymbolAddress((void**)&wfc1h,    g_wfc1h);
    cudaGetSymbolAddress((void**)&wfc2h,    g_wfc2h);
    cudaGetSymbolAddress((void**)&walh,     g_walh);
    cudaGetSymbolAddress((void**)&wal2h,    g_wal2h);
    cudaGetSymbolAddress((void**)&wfush,    g_wfush);

    const float scale_dim = 1.f / sqrtf((float)DIM);

    // ---- all weight conversions in one kernel ----
    {
        const int n0 = QKV3*DIM/4, n1 = DIM*DIM/4, n2 = HID*DIM/4, n3 = DIM*HID/4,
                  n4 = DIM*2*DIM/4, n5 = DIM*DIM/4, n6 = DIM*DIM/4;
        f2h_all<<<cdiv(n0+n1+n2+n3+n4+n5+n6, 256), 256>>>(
            w_qkv, wqkvh, n0,  w_proj, wprojh, n1,  w_fc1, wfc1h, n2,
            w_fc2, wfc2h, n3,  w_al, walh, n4,  w_al2, wal2h, n5,
            w_fus, wfush, n6);
    }
    cat_feat_k<<<cdiv((long long)BATCH*ZL*2*DIM, 256), 256>>>(x, xi, p_cath);
    mm<128,128,__half,__half,__half>(p_cath, walh, b_al, nullptr, nullptr, p_zfh,
        BATCH*ZL, DIM, 2*DIM, 2*DIM, 2*DIM, DIM, 0,0,0, 1,1, 0,0,0, 0,0, 1.f, 0);

    // ---- ns/nsi (fp16) ----
    ln_kernel<__half><<<dim3(SL, BATCH), 256>>>(x  + (long long)ZL*DIM, p_nsh,  g1, bt1,
                                                (long long)TT*DIM, (long long)SL*DIM);
    ln_kernel<__half><<<dim3(SL, BATCH), 256>>>(xi + (long long)ZL*DIM, p_nsih, g1, bt1,
                                                (long long)TT*DIM, (long long)SL*DIM);

    // ---- MHA both streams, batched ----
    {
        static bool ainit = false;
        if (!ainit) {
            cudaFuncSetAttribute(attn_fused, cudaFuncAttributeMaxDynamicSharedMemorySize, PV_SMEM);
            ainit = true;
        }
    }
    ln_cat_kernel<<<dim3(NN, BATCH, 2), 256>>>(p_zfh, x, xi, p_lnh2, g1, bt1);
    mm<128,128,__half,__half,__half>(p_lnh2, wqkvh, b_qkv, nullptr, nullptr, p_qkvh2,
        BATCH*NN, QKV3, DIM, DIM, DIM, QKV3,
        (long long)NND, 0, (long long)NNQ, 2, 1, 0,0,0, 0,0, 1.f, 0);
    vtrans_k<<<dim3(NN/32, HD/32, 2*BATCH*HEADS), dim3(32,8)>>>(p_qkvh2, p_vth2);
    attn_fused<<<dim3(3, 2*BATCH*HEADS), 512, PV_SMEM>>>(
        p_qkvh2, p_vth2, out + O_ATTN, p_aoh2);
    mm<128,128,__half,__half,float>(p_aoh2, wprojh, b_proj, nullptr, nullptr, p_xattn2,
        BATCH*NN, DIM, DIM, DIM, DIM, DIM,
        (long long)NND, 0, (long long)NND, 2, 1, 0,0,0, 0,0, 1.f, 0);

    // ---- attn_x / attn_xi ----
    mm<64,128,__half,__half,float>(p_zfh, p_nsh, nullptr, nullptr, nullptr, p_attnx,
        ZL, SL, DIM, DIM, DIM, SL,
        (long long)ZL*DIM, (long long)SL*DIM, (long long)ZL*SL,
        BATCH, 1, 0,0,0, 0,0, scale_dim, 0);
    mm<64,128,__half,__half,float>(p_zfh, p_nsih, nullptr, nullptr, nullptr, p_attnxi,
        ZL, SL, DIM, DIM, DIM, SL,
        (long long)ZL*DIM, (long long)SL*DIM, (long long)ZL*SL,
        BATCH, 1, 0,0,0, 0,0, scale_dim, 0);

    // ---- fusion ----
    fusion_kernel<<<BATCH, SL>>>(p_attnx, p_attnxi,
                                 out + O_ALPHA, out + O_UM, out + O_U, out + O_UI);
    make_v_k<<<cdiv((long long)SLD, 256), 256>>>(p_nsh, p_nsih, out + O_ALPHA, p_vh);
    mm<128,128,__half,__half,float>(p_vh, wfush, b_fus, nullptr, nullptr, p_vf,
        BATCH*SL, DIM, DIM, DIM, DIM, DIM, 0,0,0, 1,1, 0,0,0, 0,0, 1.f, 0);

    // ---- fused residual + 3x LN ----
    resid_ln_k<<<dim3(TT, BATCH), 256>>>(x, xi, p_xattn2, p_vf, g2, bt2,
                                         p_xnew2, p_lnvh, p_lnx2);

    // ---- adap2 ----
    mm<128,128,__half,__half,float>(p_lnvh, wal2h, b_al2, nullptr, nullptr, p_adap2,
        BATCH*TT, DIM, DIM, DIM, DIM, DIM, 0,0,0, 1,1, 0,0,0, 0,0, 1.f, 0);

    // ---- MLP both streams, batched ----
    mm<128,128,__half,__half,__half>(p_lnx2, wfc1h, b_fc1, nullptr, nullptr, p_hh2,
        BATCH*TT, HID, DIM, DIM, DIM, HID,
        (long long)TTD, 0, (long long)TTH, 2, 1, 0,0,0, 0,0, 1.f, 1);
    mm<128,128,__half,__half,float>(p_hh2, wfc2h, b_fc2, p_xnew2, p_adap2, out + O_XOUT,
        BATCH*TT, DIM, HID, HID, HID, DIM,
        (long long)TTH, 0, SIDE_OUT, 2, 1, 0,0,0,
        (long long)TTD, 0, 1.f, 0);

    // ---- index passthroughs ----
    i2f_k<<<cdiv(BATCH*ZL, 256), 256>>>(git,  out + O_GIT,  BATCH*ZL);
    i2f_k<<<cdiv(BATCH*SL, 256), 256>>>(gis,  out + O_GIS,  BATCH*SL);
    i2f_k<<<cdiv(BATCH*ZL, 256), 256>>>(giti, out + O_GITI, BATCH*ZL);
    i2f_k<<<cdiv(BATCH*SL, 256), 256>>>(gisi, out + O_GISI, BATCH*SL);
}

// round 12
// speedup vs baseline: 6.6668x; 1.0537x over previous
#include <cuda_runtime.h>
#include <cuda_fp16.h>
#include <math.h>
#include <cstdint>
#include <type_traits>

// ---------------- problem constants ----------------
#define BATCH 32
#define ZL 64
#define SL 256
#define TT 320
#define NN 384
#define DIM 768
#define HEADS 12
#define HD 64
#define HID 3072
#define QKV3 2304

#define O_XOUT   0LL
#define O_GIT    7864320LL
#define O_GIS    7866368LL
#define O_ATTN   7874560LL
#define O_XIOUT  64497664LL
#define O_GITI   72361984LL
#define O_GISI   72364032LL
#define O_IATTN  72372224LL
#define O_ALPHA  128995328LL
#define O_UM     129003520LL
#define O_U      129011712LL
#define O_UI     129019904LL

#define SIDE_OUT 64497664LL
#define NND  (BATCH*NN*DIM)
#define TTD  (BATCH*TT*DIM)
#define TTH  (BATCH*TT*HID)
#define NNQ  (BATCH*NN*QKV3)
#define VTN  (BATCH*HEADS*HD*NN)
#define SLD  (BATCH*SL*DIM)

// ---------------- scratch ----------------
__device__ __half g_cath [BATCH*ZL*2*DIM];
__device__ __half g_zfh  [BATCH*ZL*DIM];
__device__ __half g_nsh  [SLD];
__device__ __half g_nsih [SLD];
__device__ float  g_attnx [BATCH*ZL*SL];
__device__ float  g_attnxi[BATCH*ZL*SL];
__device__ __half g_lnh2 [2*NND];
__device__ __half g_qkvh2[2*NNQ];
__device__ __half g_vth2 [2*VTN];
__device__ __half g_aoh2 [2*NND];
__device__ float  g_xattn2[2*NND];
__device__ __half g_vh   [SLD];
__device__ float  g_vf   [SLD];
__device__ float  g_xnew2[2*TTD];
__device__ __half g_lnvh [TTD];
__device__ __half g_lnx2 [2*TTD];
__device__ float  g_adap2[TTD];
__device__ __half g_hh2  [2*TTH];
__device__ __half g_wqkvh[QKV3*DIM];
__device__ __half g_wprojh[DIM*DIM];
__device__ __half g_wfc1h[HID*DIM];
__device__ __half g_wfc2h[DIM*HID];
__device__ __half g_walh [DIM*2*DIM];
__device__ __half g_wal2h[DIM*DIM];
__device__ __half g_wfush[DIM*DIM];

// =============== helpers =====================================================
__device__ __forceinline__ uint32_t smem_u32(const void* p) {
    uint32_t a;
    asm("{ .reg .u64 t; cvta.to.shared.u64 t, %1; cvt.u32.u64 %0, t; }" : "=r"(a) : "l"(p));
    return a;
}
__device__ __forceinline__ void mma16816h(float* d, const uint32_t* a, const uint32_t* b) {
    asm volatile("mma.sync.aligned.m16n8k16.row.col.f32.f16.f16.f32 "
        "{%0,%1,%2,%3}, {%4,%5,%6,%7}, {%8,%9}, {%0,%1,%2,%3};"
        : "+f"(d[0]), "+f"(d[1]), "+f"(d[2]), "+f"(d[3])
        : "r"(a[0]), "r"(a[1]), "r"(a[2]), "r"(a[3]), "r"(b[0]), "r"(b[1]));
}
__device__ __forceinline__ void ldsm4(uint32_t& r0, uint32_t& r1, uint32_t& r2, uint32_t& r3,
                                      uint32_t addr) {
    asm volatile("ldmatrix.sync.aligned.m8n8.x4.shared.b16 {%0,%1,%2,%3}, [%4];"
        : "=r"(r0), "=r"(r1), "=r"(r2), "=r"(r3) : "r"(addr));
}
__device__ __forceinline__ uint32_t pack_h2(float x, float y) {
    __half2 p = __float22half2_rn(make_float2(x, y));
    return *(uint32_t*)&p;
}
template<typename T> struct RawVec;
template<> struct RawVec<float>  { using type = float4; };
template<> struct RawVec<__half> { using type = uint2;  };
__device__ __forceinline__ uint2 to_h2(const float4& v) {
    return make_uint2(pack_h2(v.x, v.y), pack_h2(v.z, v.w));
}
__device__ __forceinline__ uint2 to_h2(const uint2& v) { return v; }
__device__ __forceinline__ void st_s(float* p, float v)  { *p = v; }
__device__ __forceinline__ void st_s(__half* p, float v) { *p = __float2half_rn(v); }
__device__ __forceinline__ void st2(float* p, float x, float y) {
    *(float2*)p = make_float2(x, y);
}
__device__ __forceinline__ void st2(__half* p, float x, float y) {
    *(uint32_t*)p = pack_h2(x, y);
}
__device__ __forceinline__ float wred(float v) {
    v += __shfl_xor_sync(0xFFFFFFFFu, v, 16);
    v += __shfl_xor_sync(0xFFFFFFFFu, v, 8);
    v += __shfl_xor_sync(0xFFFFFFFFu, v, 4);
    v += __shfl_xor_sync(0xFFFFFFFFu, v, 2);
    v += __shfl_xor_sync(0xFFFFFFFFu, v, 1);
    return v;
}

#define CP_ASYNC16(dst, src) \
    asm volatile("cp.async.cg.shared.global [%0], [%1], 16;" :: "r"(dst), "l"(src))
#define CP_COMMIT()  asm volatile("cp.async.commit_group;")
#define CP_WAIT0()   asm volatile("cp.async.wait_group 0;")

// =============== fp16 mma.sync GEMM, typed A/B/C =============================
#define RWH 40
#define RWA 72

template<int TM, int TN, typename TA, typename TB, typename TC>
__global__ __launch_bounds__(512, 2)
void mm2(const TA* __restrict__ A, const TB* __restrict__ B,
         const float* __restrict__ bias,
         const float* __restrict__ res1, const float* __restrict__ res2,
         TC* __restrict__ C,
         int K, int lda, int ldb, int ldc,
         long long sAb, long long sBb, long long sCb, int batchH,
         long long sAh, long long sBh, long long sCh,
         long long sR1b, long long sR2b,
         float alpha, int act)
{
    extern __shared__ char dsm[];
    constexpr int WTM = TM/4, WTN = TN/4;
    constexpr int MI = WTM/16, NI = WTN/8;
    constexpr bool ASYNC =
        std::is_same<TA,__half>::value && std::is_same<TB,__half>::value;

    const int tid  = threadIdx.x;
    const int lane = tid & 31;
    const int w    = tid >> 5;
    const int wm   = w >> 2;
    const int wn   = w & 3;

    const int bz = blockIdx.z;
    const int b  = bz / batchH;
    const int h  = bz - b*batchH;
    const int m0 = blockIdx.y * TM;
    const int n0 = blockIdx.x * TN;
    const TA* Ab = A + (long long)b*sAb + (long long)h*sAh + (long long)m0*lda;
    const TB* Bb = B + (long long)b*sBb + (long long)h*sBh + (long long)n0*ldb;
    const long long coffC  = (long long)b*sCb + (long long)h*sCh;
    const long long coffR1 = (long long)b*sR1b;
    const long long coffR2 = (long long)b*sR2b;

    const uint32_t sb0 = smem_u32(dsm);

    float acc[MI][NI][4];
    #pragma unroll
    for (int mi = 0; mi < MI; mi++)
        #pragma unroll
        for (int ni = 0; ni < NI; ni++)
            #pragma unroll
            for (int j = 0; j < 4; j++) acc[mi][ni][j] = 0.f;

    if constexpr (ASYNC) {
        constexpr int AHL = TM*RWA;
        constexpr int STAGE_BYTES = (TM + TN)*RWA*2;
        constexpr int PLA = TM*8/512, PLB = TN*8/512;
        const uint32_t a_l = (uint32_t)(((wm*WTM + (lane & 15))*RWA + ((lane >> 4) << 3)) * 2);
        const uint32_t b_l = (uint32_t)(AHL*2 + ((wn*WTN + (lane & 15))*RWA + ((lane >> 4) << 3)) * 2);
        const __half* Abh = (const __half*)Ab;
        const __half* Bbh = (const __half*)Bb;
        const int NC = K >> 6;

        // prologue: stage 0
        #pragma unroll
        for (int p = 0; p < PLA; p++) {
            int u = tid + (p << 9);
            int r = u >> 3, ch = u & 7;
            CP_ASYNC16(sb0 + (uint32_t)(r*RWA*2 + ch*16),
                       Abh + (long long)r*lda + ch*8);
        }
        #pragma unroll
        for (int p = 0; p < PLB; p++) {
            int u = tid + (p << 9);
            int r = u >> 3, ch = u & 7;
            CP_ASYNC16(sb0 + (uint32_t)(AHL*2 + r*RWA*2 + ch*16),
                       Bbh + (long long)r*ldb + ch*8);
        }
        CP_COMMIT();

        // one sync per chunk: wait -> sync -> issue next -> compute
        for (int c = 0; c < NC; c++) {
            CP_WAIT0();
            __syncthreads();
            if (c + 1 < NC) {
                const int k0 = (c + 1) << 6;
                const uint32_t base = sb0 + ((c + 1) & 1) * STAGE_BYTES;
                #pragma unroll
                for (int p = 0; p < PLA; p++) {
                    int u = tid + (p << 9);
                    int r = u >> 3, ch = u & 7;
                    CP_ASYNC16(base + (uint32_t)(r*RWA*2 + ch*16),
                               Abh + (long long)r*lda + k0 + ch*8);
                }
                #pragma unroll
                for (int p = 0; p < PLB; p++) {
                    int u = tid + (p << 9);
                    int r = u >> 3, ch = u & 7;
                    CP_ASYNC16(base + (uint32_t)(AHL*2 + r*RWA*2 + ch*16),
                               Bbh + (long long)r*ldb + k0 + ch*8);
                }
                CP_COMMIT();
            }
            const uint32_t stageu = sb0 + (c & 1) * STAGE_BYTES;
            #pragma unroll
            for (int ks = 0; ks < 4; ks++) {
                const uint32_t kb = ks * 32;
                uint32_t ah[MI][4];
                #pragma unroll
                for (int mi = 0; mi < MI; mi++) {
                    uint32_t ad = stageu + a_l + mi*(16*RWA*2) + kb;
                    ldsm4(ah[mi][0], ah[mi][1], ah[mi][2], ah[mi][3], ad);
                }
                uint32_t bh[NI][2];
                #pragma unroll
                for (int nj = 0; nj < NI/2; nj++) {
                    uint32_t bd = stageu + b_l + nj*(16*RWA*2) + kb;
                    uint32_t q0, q1, q2, q3;
                    ldsm4(q0, q1, q2, q3, bd);
                    bh[2*nj][0] = q0; bh[2*nj][1] = q2;
                    bh[2*nj+1][0] = q1; bh[2*nj+1][1] = q3;
                }
                #pragma unroll
                for (int mi = 0; mi < MI; mi++)
                    #pragma unroll
                    for (int ni = 0; ni < NI; ni++)
                        mma16816h(acc[mi][ni], ah[mi], bh[ni]);
            }
        }
    } else {
        constexpr int AHL = TM*RWH;
        constexpr int STAGE_BYTES = (TM + TN)*RWH*2;
        constexpr int PA = TM/64, PB = TN/64;
        const uint32_t a_l = (uint32_t)(((wm*WTM + (lane & 15))*RWH + ((lane >> 4) << 3)) * 2);
        const uint32_t b_l = (uint32_t)(AHL*2 + ((wn*WTN + (lane & 15))*RWH + ((lane >> 4) << 3)) * 2);
        const int lq = tid & 7;
        const int lr = tid >> 3;
        const int NC = K >> 5;
        typename RawVec<TA>::type pA[PA];
        typename RawVec<TB>::type pB[PB];

        #pragma unroll
        for (int p = 0; p < PA; p++)
            pA[p] = *(const typename RawVec<TA>::type*)(Ab + (long long)(lr + 64*p)*lda + 4*lq);
        #pragma unroll
        for (int p = 0; p < PB; p++)
            pB[p] = *(const typename RawVec<TB>::type*)(Bb + (long long)(lr + 64*p)*ldb + 4*lq);

        for (int c = 0; c < NC; c++) {
            const int st = c & 1;
            char* sb = dsm + st * STAGE_BYTES;
            __half* Ah = (__half*)sb;
            __half* Bh = Ah + AHL;

            #pragma unroll
            for (int p = 0; p < PA; p++)
                *(uint2*)(Ah + (lr + 64*p)*RWH + 4*lq) = to_h2(pA[p]);
            #pragma unroll
            for (int p = 0; p < PB; p++)
                *(uint2*)(Bh + (lr + 64*p)*RWH + 4*lq) = to_h2(pB[p]);
            __syncthreads();

            if (c + 1 < NC) {
                const int k0 = (c + 1) << 5;
                #pragma unroll
                for (int p = 0; p < PA; p++)
                    pA[p] = *(const typename RawVec<TA>::type*)(Ab + (long long)(lr + 64*p)*lda + k0 + 4*lq);
                #pragma unroll
                for (int p = 0; p < PB; p++)
                    pB[p] = *(const typename RawVec<TB>::type*)(Bb + (long long)(lr + 64*p)*ldb + k0 + 4*lq);
            }

            const uint32_t stageu = sb0 + st * STAGE_BYTES;
            #pragma unroll
            for (int ks = 0; ks < 2; ks++) {
                const uint32_t kb = ks * 32;
                uint32_t ah[MI][4];
                #pragma unroll
                for (int mi = 0; mi < MI; mi++) {
                    uint32_t ad = stageu + a_l + mi*(16*RWH*2) + kb;
                    ldsm4(ah[mi][0], ah[mi][1], ah[mi][2], ah[mi][3], ad);
                }
                uint32_t bh[NI][2];
                #pragma unroll
                for (int nj = 0; nj < NI/2; nj++) {
                    uint32_t bd = stageu + b_l + nj*(16*RWH*2) + kb;
                    uint32_t q0, q1, q2, q3;
                    ldsm4(q0, q1, q2, q3, bd);
                    bh[2*nj][0] = q0; bh[2*nj][1] = q2;
                    bh[2*nj+1][0] = q1; bh[2*nj+1][1] = q3;
                }
                #pragma unroll
                for (int mi = 0; mi < MI; mi++)
                    #pragma unroll
                    for (int ni = 0; ni < NI; ni++)
                        mma16816h(acc[mi][ni], ah[mi], bh[ni]);
            }
            __syncthreads();
        }
    }

    // ---- epilogue: direct fragment stores ----
    const int g = lane >> 2, t4 = lane & 3;
    float2 bv[NI];
    if (bias) {
        #pragma unroll
        for (int ni = 0; ni < NI; ni++)
            bv[ni] = *(const float2*)(bias + n0 + wn*WTN + ni*8 + 2*t4);
    }
    #pragma unroll
    for (int mi = 0; mi < MI; mi++)
        #pragma unroll
        for (int h2 = 0; h2 < 2; h2++) {
            long long row = m0 + wm*WTM + mi*16 + g + 8*h2;
            long long base = row*(long long)ldc + n0 + wn*WTN + 2*t4;
            #pragma unroll
            for (int ni = 0; ni < NI; ni++) {
                float vx = acc[mi][ni][2*h2]   * alpha;
                float vy = acc[mi][ni][2*h2+1] * alpha;
                if (bias) { vx += bv[ni].x; vy += bv[ni].y; }
                long long off = base + ni*8;
                if (res1) { float2 a = *(const float2*)(res1 + coffR1 + off); vx += a.x; vy += a.y; }
                if (res2) { float2 a = *(const float2*)(res2 + coffR2 + off); vx += a.x; vy += a.y; }
                if (act == 1) {
                    vx = 0.5f*vx*(1.f + erff(vx*0.70710678118654752f));
                    vy = 0.5f*vy*(1.f + erff(vy*0.70710678118654752f));
                }
                st2(C + coffC + off, vx, vy);
            }
        }
}

// =============== fused QK^T + softmax + P@V, dual-stream =====================
#define RW2 72
#define RW3 392
#define PV_SMEM (128*RW3*2 + 64*RW3*2 + 128*4*4 + 128*4)

__global__ __launch_bounds__(512, 1)
void attn_fused(const __half* __restrict__ qkv2, const __half* __restrict__ vt2,
                float* __restrict__ attn_base, __half* __restrict__ ao2)
{
    extern __shared__ char dsm[];
    __half* Ph  = (__half*)dsm;
    __half* Vs  = (__half*)(dsm + 128*RW3*2);
    float*  red = (float*)(dsm + 128*RW3*2 + 64*RW3*2);
    float*  invb= red + 128*4;
    __half* Qs  = (__half*)dsm;
    __half* Ks  = Qs + 128*RW2;

    const int tid = threadIdx.x;
    const int lane = tid & 31;
    const int w = tid >> 5;
    const int wm = w >> 2, wn = w & 3;
    const int g = lane >> 2, t4 = lane & 3;

    const int m0 = blockIdx.x * 128;
    const int sy = blockIdx.y;
    const int side = sy / (BATCH*HEADS);
    const int bh = sy - side*(BATCH*HEADS);
    const int b  = bh / HEADS;
    const int hh = bh - b*HEADS;

    const __half* qkv = qkv2 + (long long)side*NNQ;
    const __half* vt  = vt2  + (long long)side*VTN;
    float* attn = attn_base + (long long)side*SIDE_OUT;
    __half* ao  = ao2 + (long long)side*NND;

    const __half* qbase = qkv + (long long)b*NN*QKV3 + hh*HD;

    #pragma unroll
    for (int p = 0; p < 2; p++) {
        int u = tid + (p << 9);
        int r = u >> 3, ch = u & 7;
        *(uint4*)(Qs + r*RW2 + ch*8) =
            *(const uint4*)(qbase + (long long)(m0 + r)*QKV3 + ch*8);
    }
    #pragma unroll
    for (int p = 0; p < 6; p++) {
        int u = tid + (p << 9);
        int r = u >> 3, ch = u & 7;
        *(uint4*)(Ks + r*RW2 + ch*8) =
            *(const uint4*)(qbase + DIM + (long long)r*QKV3 + ch*8);
    }
    __syncthreads();

    const uint32_t sq = smem_u32(Qs);
    const uint32_t sk = smem_u32(Ks);
    const uint32_t a_l = sq + ((wm*32 + (lane & 15))*RW2 + ((lane >> 4) << 3)) * 2;
    const uint32_t b_l = sk + ((wn*96 + (lane & 15))*RW2 + ((lane >> 4) << 3)) * 2;

    float acc[2][12][4];
    #pragma unroll
    for (int mi = 0; mi < 2; mi++)
        #pragma unroll
        for (int ni = 0; ni < 12; ni++)
            #pragma unroll
            for (int j = 0; j < 4; j++) acc[mi][ni][j] = 0.f;

    #pragma unroll
    for (int ks = 0; ks < 4; ks++) {
        const uint32_t kb = ks * 32;
        uint32_t ah[2][4];
        #pragma unroll
        for (int mi = 0; mi < 2; mi++)
            ldsm4(ah[mi][0], ah[mi][1], ah[mi][2], ah[mi][3],
                  a_l + mi*(16*RW2*2) + kb);
        #pragma unroll
        for (int nj = 0; nj < 6; nj++) {
            uint32_t q0, q1, q2, q3;
            ldsm4(q0, q1, q2, q3, b_l + nj*(16*RW2*2) + kb);
            uint32_t b0[2] = {q0, q2}, b1[2] = {q1, q3};
            #pragma unroll
            for (int mi = 0; mi < 2; mi++) {
                mma16816h(acc[mi][2*nj],   ah[mi], b0);
                mma16816h(acc[mi][2*nj+1], ah[mi], b1);
            }
        }
    }

    #pragma unroll
    for (int mi = 0; mi < 2; mi++)
        #pragma unroll
        for (int ni = 0; ni < 12; ni++)
            #pragma unroll
            for (int j = 0; j < 4; j++) acc[mi][ni][j] *= 0.125f;

    float M[2][2];
    #pragma unroll
    for (int mi = 0; mi < 2; mi++)
        #pragma unroll
        for (int h2 = 0; h2 < 2; h2++) {
            float m = -1e30f;
            #pragma unroll
            for (int ni = 0; ni < 12; ni++)
                m = fmaxf(m, fmaxf(acc[mi][ni][2*h2], acc[mi][ni][2*h2+1]));
            m = fmaxf(m, __shfl_xor_sync(0xFFFFFFFFu, m, 1));
            m = fmaxf(m, __shfl_xor_sync(0xFFFFFFFFu, m, 2));
            if (t4 == 0) red[(wm*32 + mi*16 + g + 8*h2)*4 + wn] = m;
        }
    __syncthreads();
    #pragma unroll
    for (int mi = 0; mi < 2; mi++)
        #pragma unroll
        for (int h2 = 0; h2 < 2; h2++) {
            int row = wm*32 + mi*16 + g + 8*h2;
            M[mi][h2] = fmaxf(fmaxf(red[row*4], red[row*4+1]),
                              fmaxf(red[row*4+2], red[row*4+3]));
        }
    __syncthreads();

    float S[2][2];
    #pragma unroll
    for (int mi = 0; mi < 2; mi++)
        #pragma unroll
        for (int h2 = 0; h2 < 2; h2++) {
            float s = 0.f;
            #pragma unroll
            for (int ni = 0; ni < 12; ni++) {
                float e0 = __expf(acc[mi][ni][2*h2]   - M[mi][h2]);
                float e1 = __expf(acc[mi][ni][2*h2+1] - M[mi][h2]);
                acc[mi][ni][2*h2] = e0; acc[mi][ni][2*h2+1] = e1;
                s += e0 + e1;
            }
            s += __shfl_xor_sync(0xFFFFFFFFu, s, 1);
            s += __shfl_xor_sync(0xFFFFFFFFu, s, 2);
            if (t4 == 0) red[(wm*32 + mi*16 + g + 8*h2)*4 + wn] = s;
        }
    __syncthreads();
    #pragma unroll
    for (int mi = 0; mi < 2; mi++)
        #pragma unroll
        for (int h2 = 0; h2 < 2; h2++) {
            int row = wm*32 + mi*16 + g + 8*h2;
            float inv = 1.f / (red[row*4] + red[row*4+1] + red[row*4+2] + red[row*4+3]);
            S[mi][h2] = inv;
            if (wn == 0 && t4 == 0) invb[row] = inv;
        }

    float* abase = attn + (long long)bh*NN*NN;
    #pragma unroll
    for (int mi = 0; mi < 2; mi++)
        #pragma unroll
        for (int h2 = 0; h2 < 2; h2++) {
            int row = m0 + wm*32 + mi*16 + g + 8*h2;
            float inv = S[mi][h2];
            float* rp = abase + (long long)row*NN + wn*96 + 2*t4;
            #pragma unroll
            for (int ni = 0; ni < 12; ni++) {
                float2 o;
                o.x = acc[mi][ni][2*h2]   * inv;
                o.y = acc[mi][ni][2*h2+1] * inv;
                *(float2*)(rp + ni*8) = o;
            }
        }

    __syncthreads();

    #pragma unroll
    for (int mi = 0; mi < 2; mi++)
        #pragma unroll
        for (int h2 = 0; h2 < 2; h2++) {
            int row = wm*32 + mi*16 + g + 8*h2;
            __half* rp = Ph + row*RW3 + wn*96 + 2*t4;
            #pragma unroll
            for (int ni = 0; ni < 12; ni++)
                *(uint32_t*)(rp + ni*8) = pack_h2(acc[mi][ni][2*h2], acc[mi][ni][2*h2+1]);
        }
    const __half* vbase = vt + (long long)bh*HD*NN;
    #pragma unroll
    for (int p = 0; p < 6; p++) {
        int u = tid + (p << 9);
        int r = u / 48, c = u - r*48;
        *(uint4*)(Vs + r*RW3 + c*8) = *(const uint4*)(vbase + r*NN + c*8);
    }
    __syncthreads();

    const int wm2 = w >> 2, wn2 = w & 3;
    const uint32_t pa = smem_u32(Ph) + ((wm2*32 + (lane & 15))*RW3 + ((lane >> 4) << 3))*2;
    const uint32_t pb = smem_u32(Vs) + ((wn2*16 + (lane & 15))*RW3 + ((lane >> 4) << 3))*2;

    float acc2[2][2][4];
    #pragma unroll
    for (int mi = 0; mi < 2; mi++)
        #pragma unroll
        for (int ni = 0; ni < 2; ni++)
            #pragma unroll
            for (int j = 0; j < 4; j++) acc2[mi][ni][j] = 0.f;

    #pragma unroll
    for (int ks = 0; ks < 24; ks++) {
        const uint32_t kb = ks * 32;
        uint32_t ah0[4], ah1[4], q0, q1, q2, q3;
        ldsm4(ah0[0], ah0[1], ah0[2], ah0[3], pa + kb);
        ldsm4(ah1[0], ah1[1], ah1[2], ah1[3], pa + 16*RW3*2 + kb);
        ldsm4(q0, q1, q2, q3, pb + kb);
        uint32_t b0[2] = {q0, q2}, b1[2] = {q1, q3};
        mma16816h(acc2[0][0], ah0, b0);
        mma16816h(acc2[0][1], ah0, b1);
        mma16816h(acc2[1][0], ah1, b0);
        mma16816h(acc2[1][1], ah1, b1);
    }

    #pragma unroll
    for (int mi = 0; mi < 2; mi++) {
        int r0 = wm2*32 + mi*16 + g;
        float inv0 = invb[r0], inv1 = invb[r0 + 8];
        long long base0 = ((long long)b*NN + m0 + r0)*DIM + hh*HD;
        long long base1 = base0 + 8LL*DIM;
        #pragma unroll
        for (int ni = 0; ni < 2; ni++) {
            int col = wn2*16 + ni*8 + 2*t4;
            *(uint32_t*)(ao + base0 + col) = pack_h2(acc2[mi][ni][0]*inv0, acc2[mi][ni][1]*inv0);
            *(uint32_t*)(ao + base1 + col) = pack_h2(acc2[mi][ni][2]*inv1, acc2[mi][ni][3]*inv1);
        }
    }
}

// ---------------- LayerNorm (warp-shuffle reduction) -------------------------
template<typename TO>
__global__ void ln_kernel(const float* __restrict__ in, TO* __restrict__ out,
                          const float* __restrict__ g, const float* __restrict__ b,
                          long long in_bstride, long long out_bstride)
{
    const float* x = in  + (long long)blockIdx.y*in_bstride  + (long long)blockIdx.x*DIM;
    TO*          y = out + (long long)blockIdx.y*out_bstride + (long long)blockIdx.x*DIM;
    int tid = threadIdx.x;
    int wid = tid >> 5, lane = tid & 31;
    float v0 = x[tid], v1 = x[tid+256], v2 = x[tid+512];
    float s = wred(v0 + v1 + v2);
    float q = wred(v0*v0 + v1*v1 + v2*v2);
    __shared__ float ws[8], wq[8];
    if (lane == 0) { ws[wid] = s; wq[wid] = q; }
    __syncthreads();
    float S = 0.f, Q = 0.f;
    #pragma unroll
    for (int k = 0; k < 8; k++) { S += ws[k]; Q += wq[k]; }
    float mean = S * (1.f/768.f);
    float inv = rsqrtf(Q * (1.f/768.f) - mean*mean + 1e-5f);
    st_s(y + tid,     (v0-mean)*inv*g[tid]     + b[tid]);
    st_s(y + tid+256, (v1-mean)*inv*g[tid+256] + b[tid+256]);
    st_s(y + tid+512, (v2-mean)*inv*g[tid+512] + b[tid+512]);
}

// LN over concat [z_f(fp16), x/xi(fp32)], both sides in one launch
__global__ void ln_cat_kernel(const __half* __restrict__ zf,
                              const float* __restrict__ x, const float* __restrict__ xi,
                              __half* __restrict__ out2,
                              const float* __restrict__ g, const float* __restrict__ b)
{
    int t = blockIdx.x, bb = blockIdx.y, side = blockIdx.z;
    const float* xs = side ? xi : x;
    __half* y = out2 + (long long)side*NND + ((long long)bb*NN + t)*DIM;
    int tid = threadIdx.x;
    int wid = tid >> 5, lane = tid & 31;
    float v0, v1, v2;
    if (t < ZL) {
        const __half* src = zf + ((long long)bb*ZL + t)*DIM;
        v0 = __half2float(src[tid]);
        v1 = __half2float(src[tid+256]);
        v2 = __half2float(src[tid+512]);
    } else {
        const float* src = xs + ((long long)bb*TT + (t - ZL))*DIM;
        v0 = src[tid]; v1 = src[tid+256]; v2 = src[tid+512];
    }
    float s = wred(v0 + v1 + v2);
    float q = wred(v0*v0 + v1*v1 + v2*v2);
    __shared__ float ws[8], wq[8];
    if (lane == 0) { ws[wid] = s; wq[wid] = q; }
    __syncthreads();
    float S = 0.f, Q = 0.f;
    #pragma unroll
    for (int k = 0; k < 8; k++) { S += ws[k]; Q += wq[k]; }
    float mean = S * (1.f/768.f);
    float inv = rsqrtf(Q * (1.f/768.f) - mean*mean + 1e-5f);
    y[tid]     = __float2half_rn((v0-mean)*inv*g[tid]     + b[tid]);
    y[tid+256] = __float2half_rn((v1-mean)*inv*g[tid+256] + b[tid+256]);
    y[tid+512] = __float2half_rn((v2-mean)*inv*g[tid+512] + b[tid+512]);
}

// ---------------- fused residual + 3x LayerNorm ------------------------------
__global__ void resid_ln_k(const float* __restrict__ x, const float* __restrict__ xi,
                           const float* __restrict__ xattn2,
                           const float* __restrict__ vfus,
                           const float* __restrict__ g2, const float* __restrict__ bt2,
                           float* __restrict__ xnew2,
                           __half* __restrict__ lnv, __half* __restrict__ lnx2)
{
    const int t = blockIdx.x, b = blockIdx.y;
    const int tid = threadIdx.x;
    const int wid = tid >> 5, lane = tid & 31;
    const long long rbase = ((long long)b*TT + t)*DIM;
    const long long abase = ((long long)b*NN + ZL + t)*DIM;
    const float* xattn  = xattn2;
    const float* xiattn = xattn2 + NND;
    const float* vsrc = (t < ZL) ? xiattn + ((long long)b*NN + t)*DIM
                                 : vfus   + ((long long)b*SL + (t - ZL))*DIM;

    float vf[3], xo[3], xio[3];
    float s[6] = {0,0,0,0,0,0};
    #pragma unroll
    for (int j = 0; j < 3; j++) {
        int c = tid + j*256;
        float vv = vsrc[c];
        float a1 = xattn[abase + c], a2 = xiattn[abase + c];
        float xv = x[rbase + c] + a1 + vv;
        float xiv = xi[rbase + c] + a2 + vv;
        vf[j] = vv; xo[j] = xv; xio[j] = xiv;
        xnew2[rbase + c]       = xv;
        xnew2[TTD + rbase + c] = xiv;
        s[0] += vv;  s[1] += vv*vv;
        s[2] += xv;  s[3] += xv*xv;
        s[4] += xiv; s[5] += xiv*xiv;
    }

    #pragma unroll
    for (int k = 0; k < 6; k++) s[k] = wred(s[k]);
    __shared__ float sh[6][8];
    if (lane == 0) {
        #pragma unroll
        for (int k = 0; k < 6; k++) sh[k][wid] = s[k];
    }
    __syncthreads();
    float tot[6];
    #pragma unroll
    for (int k = 0; k < 6; k++) {
        float acc = 0.f;
        #pragma unroll
        for (int p = 0; p < 8; p++) acc += sh[k][p];
        tot[k] = acc;
    }
    float mv = tot[0]*(1.f/768.f), iv = rsqrtf(tot[1]*(1.f/768.f) - mv*mv + 1e-5f);
    float mx = tot[2]*(1.f/768.f), ix = rsqrtf(tot[3]*(1.f/768.f) - mx*mx + 1e-5f);
    float mi2 = tot[4]*(1.f/768.f), ii = rsqrtf(tot[5]*(1.f/768.f) - mi2*mi2 + 1e-5f);

    #pragma unroll
    for (int j = 0; j < 3; j++) {
        int c = tid + j*256;
        float gg = g2[c], bb = bt2[c];
        lnv[rbase + c]        = __float2half_rn((vf[j]-mv)*iv*gg + bb);
        lnx2[rbase + c]       = __float2half_rn((xo[j]-mx)*ix*gg + bb);
        lnx2[TTD + rbase + c] = __float2half_rn((xio[j]-mi2)*ii*gg + bb);
    }
}

// ---------------- fusion ----------------
__global__ void fusion_kernel(const float* __restrict__ ax, const float* __restrict__ axi,
                              float* __restrict__ alpha_o, float* __restrict__ um_o,
                              float* __restrict__ u_o, float* __restrict__ ui_o)
{
    int b = blockIdx.x, s = threadIdx.x;
    const float* X  = ax  + (long long)b*ZL*SL + s;
    const float* Xi = axi + (long long)b*ZL*SL + s;
    float u, ui;
    {
        float mx = -1e30f;
        for (int t = 0; t < ZL; t++) mx = fmaxf(mx, X[t*SL]);
        float sum = 0.f;
        for (int t = 0; t < ZL; t++) sum += expf(X[t*SL] - mx);
        float inv = 1.f/sum, acc = 0.f;
        for (int t = 0; t < ZL; t++) { float p = expf(X[t*SL]-mx)*inv; acc -= p*logf(p + 1e-8f); }
        u = acc;
    }
    {
        float mx = -1e30f;
        for (int t = 0; t < ZL; t++) mx = fmaxf(mx, Xi[t*SL]);
        float sum = 0.f;
        for (int t = 0; t < ZL; t++) sum += expf(Xi[t*SL] - mx);
        float inv = 1.f/sum, acc = 0.f;
        for (int t = 0; t < ZL; t++) { float p = expf(Xi[t*SL]-mx)*inv; acc -= p*logf(p + 1e-8f); }
        ui = acc;
    }
    int idx = b*SL + s;
    float alpha = 1.f / (1.f + expf(-(ui - u)));
    alpha_o[idx] = alpha;
    um_o[idx] = 0.5f*(u + ui);
    u_o[idx] = u;
    ui_o[idx] = ui;
}

// ---------------- elementwise helpers ----------------
__global__ void cat_feat_k(const float* __restrict__ x, const float* __restrict__ xi,
                           __half* __restrict__ o)
{
    long long i = (long long)blockIdx.x*blockDim.x + threadIdx.x;
    const long long n = (long long)BATCH*ZL*2*DIM;
    if (i >= n) return;
    int c = (int)(i % (2*DIM));
    long long bt = i / (2*DIM);
    long long b = bt / ZL, t = bt % ZL;
    long long src = (b*TT + t)*DIM;
    float v = (c < DIM) ? x[src + c] : xi[src + c - DIM];
    o[i] = __float2half_rn(v);
}

__global__ void vtrans_k(const __half* __restrict__ qkv2, __half* __restrict__ vt2)
{
    __shared__ float t[32][33];
    int z = blockIdx.z;
    int side = z / (BATCH*HEADS);
    int bh = z - side*(BATCH*HEADS);
    long long b = bh / HEADS, h = bh % HEADS;
    const __half* src = qkv2 + (long long)side*NNQ + b*NN*QKV3 + 2*DIM + h*HD;
    int tt0 = blockIdx.x*32;
    int cc0 = blockIdx.y*32;
    int tx = threadIdx.x, ty = threadIdx.y;
    #pragma unroll
    for (int i = 0; i < 32; i += 8)
        t[ty+i][tx] = __half2float(src[(long long)(tt0+ty+i)*QKV3 + cc0 + tx]);
    __syncthreads();
    __half* dst = vt2 + (long long)side*VTN + ((long long)bh*HD)*NN;
    #pragma unroll
    for (int i = 0; i < 32; i += 8)
        dst[(long long)(cc0+ty+i)*NN + tt0 + tx] = __float2half_rn(t[tx][ty+i]);
}

__global__ void make_v_k(const __half* __restrict__ ns, const __half* __restrict__ nsi,
                         const float* __restrict__ alpha, __half* __restrict__ v)
{
    long long i = (long long)blockIdx.x*blockDim.x + threadIdx.x;
    const long long n = (long long)SLD;
    if (i >= n) return;
    long long bs = i / DIM;
    float a = alpha[bs];
    v[i] = __float2half_rn(a*__half2float(ns[i]) + (1.f - a)*__half2float(nsi[i]));
}

// all 4 index passthroughs in one launch
__global__ void i2f_all(const int* a0, float* o0, int n0,
                        const int* a1, float* o1, int n1,
                        const int* a2, float* o2, int n2,
                        const int* a3, float* o3, int n3)
{
    int i = blockIdx.x*blockDim.x + threadIdx.x;
    if      (i < n0)          o0[i] = (float)a0[i];
    else if ((i -= n0) < n1)  o1[i] = (float)a1[i];
    else if ((i -= n1) < n2)  o2[i] = (float)a2[i];
    else if ((i -= n2) < n3)  o3[i] = (float)a3[i];
}

// all 7 weight conversions fused
__global__ void f2h_all(const float* s0, __half* d0, int n0,
                        const float* s1, __half* d1, int n1,
                        const float* s2, __half* d2, int n2,
                        const float* s3, __half* d3, int n3,
                        const float* s4, __half* d4, int n4,
                        const float* s5, __half* d5, int n5,
                        const float* s6, __half* d6, int n6)
{
    int i = blockIdx.x*blockDim.x + threadIdx.x;
    const float* s; __half* d;
    if      (i < n0)                      { s = s0; d = d0; }
    else if ((i -= n0) < n1)              { s = s1; d = d1; }
    else if ((i -= n1) < n2)              { s = s2; d = d2; }
    else if ((i -= n2) < n3)              { s = s3; d = d3; }
    else if ((i -= n3) < n4)              { s = s4; d = d4; }
    else if ((i -= n4) < n5)              { s = s5; d = d5; }
    else if ((i -= n5) < n6)              { s = s6; d = d6; }
    else return;
    float4 v = *(const float4*)(s + 4*i);
    *(uint2*)(d + 4*i) = to_h2(v);
}

// ---------------- host-side helpers ----------------
template<int TM, int TN, typename TA, typename TB, typename TC>
static inline void mm(const TA* A, const TB* B, const float* bias,
                      const float* r1, const float* r2, TC* C,
                      int M, int N, int K, int lda, int ldb, int ldc,
                      long long sAb, long long sBb, long long sCb,
                      int nb, int nh,
                      long long sAh, long long sBh, long long sCh,
                      long long sR1b, long long sR2b,
                      float alpha, int act)
{
    constexpr bool ASYNC =
        std::is_same<TA,__half>::value && std::is_same<TB,__half>::value;
    constexpr int DS = 2 * (ASYNC ? (TM + TN)*RWA*2 : (TM + TN)*RWH*2);
    static bool init = false;
    if (!init) {
        cudaFuncSetAttribute(mm2<TM,TN,TA,TB,TC>, cudaFuncAttributeMaxDynamicSharedMemorySize, DS);
        init = true;
    }
    dim3 g(N/TN, M/TM, nb*nh);
    mm2<TM,TN,TA,TB,TC><<<g, 512, DS>>>(A,B,bias,r1,r2,C,K,lda,ldb,ldc,
        sAb,sBb,sCb,nh,sAh,sBh,sCh,sR1b,sR2b,alpha,act);
}

static inline int cdiv(long long a, int b) { return (int)((a + b - 1) / b); }

extern "C" void kernel_launch(void* const* d_in, const int* in_sizes, int n_in,
                              void* d_out, int out_size)
{
    const float* x      = (const float*)d_in[0];
    const float* xi     = (const float*)d_in[1];
    const int*   git    = (const int*)  d_in[2];
    const int*   giti   = (const int*)  d_in[3];
    const int*   gis    = (const int*)  d_in[4];
    const int*   gisi   = (const int*)  d_in[5];
    const float* w_qkv  = (const float*)d_in[6];
    const float* b_qkv  = (const float*)d_in[7];
    const float* w_proj = (const float*)d_in[8];
    const float* b_proj = (const float*)d_in[9];
    const float* g1     = (const float*)d_in[10];
    const float* bt1    = (const float*)d_in[11];
    const float* g2     = (const float*)d_in[12];
    const float* bt2    = (const float*)d_in[13];
    const float* w_fc1  = (const float*)d_in[14];
    const float* b_fc1  = (const float*)d_in[15];
    const float* w_fc2  = (const float*)d_in[16];
    const float* b_fc2  = (const float*)d_in[17];
    const float* w_al   = (const float*)d_in[18];
    const float* b_al   = (const float*)d_in[19];
    const float* w_al2  = (const float*)d_in[20];
    const float* b_al2  = (const float*)d_in[21];
    const float* w_fus  = (const float*)d_in[22];
    const float* b_fus  = (const float*)d_in[23];
    float* out = (float*)d_out;

    float *p_attnx, *p_attnxi, *p_xattn2, *p_vf, *p_xnew2, *p_adap2;
    __half *p_cath, *p_zfh, *p_nsh, *p_nsih, *p_lnh2, *p_qkvh2, *p_vth2, *p_aoh2,
           *p_hh2, *p_vh, *p_lnvh, *p_lnx2;
    __half *wqkvh, *wprojh, *wfc1h, *wfc2h, *walh, *wal2h, *wfush;
    cudaGetSymbolAddress((void**)&p_cath,   g_cath);
    cudaGetSymbolAddress((void**)&p_zfh,    g_zfh);
    cudaGetSymbolAddress((void**)&p_nsh,    g_nsh);
    cudaGetSymbolAddress((void**)&p_nsih,   g_nsih);
    cudaGetSymbolAddress((void**)&p_attnx,  g_attnx);
    cudaGetSymbolAddress((void**)&p_attnxi, g_attnxi);
    cudaGetSymbolAddress((void**)&p_lnh2,   g_lnh2);
    cudaGetSymbolAddress((void**)&p_qkvh2,  g_qkvh2);
    cudaGetSymbolAddress((void**)&p_vth2,   g_vth2);
    cudaGetSymbolAddress((void**)&p_aoh2,   g_aoh2);
    cudaGetSymbolAddress((void**)&p_xattn2, g_xattn2);
    cudaGetSymbolAddress((void**)&p_vh,     g_vh);
    cudaGetSymbolAddress((void**)&p_vf,     g_vf);
    cudaGetSymbolAddress((void**)&p_xnew2,  g_xnew2);
    cudaGetSymbolAddress((void**)&p_lnvh,   g_lnvh);
    cudaGetSymbolAddress((void**)&p_lnx2,   g_lnx2);
    cudaGetSymbolAddress((void**)&p_adap2,  g_adap2);
    cudaGetSymbolAddress((void**)&p_hh2,    g_hh2);
    cudaGetSymbolAddress((void**)&wqkvh,    g_wqkvh);
    cudaGetSymbolAddress((void**)&wprojh,   g_wprojh);
    cudaGetSymbolAddress((void**)&wfc1h,    g_wfc1h);
    cudaGetSymbolAddress((void**)&wfc2h,    g_wfc2h);
    cudaGetSymbolAddress((void**)&walh,     g_walh);
    cudaGetSymbolAddress((void**)&wal2h,    g_wal2h);
    cudaGetSymbolAddress((void**)&wfush,    g_wfush);

    const float scale_dim = 1.f / sqrtf((float)DIM);

    {
        const int n0 = QKV3*DIM/4, n1 = DIM*DIM/4, n2 = HID*DIM/4, n3 = DIM*HID/4,
                  n4 = DIM*2*DIM/4, n5 = DIM*DIM/4, n6 = DIM*DIM/4;
        f2h_all<<<cdiv(n0+n1+n2+n3+n4+n5+n6, 256), 256>>>(
            w_qkv, wqkvh, n0,  w_proj, wprojh, n1,  w_fc1, wfc1h, n2,
            w_fc2, wfc2h, n3,  w_al, walh, n4,  w_al2, wal2h, n5,
            w_fus, wfush, n6);
    }
    cat_feat_k<<<cdiv((long long)BATCH*ZL*2*DIM, 256), 256>>>(x, xi, p_cath);
    mm<128,128,__half,__half,__half>(p_cath, walh, b_al, nullptr, nullptr, p_zfh,
        BATCH*ZL, DIM, 2*DIM, 2*DIM, 2*DIM, DIM, 0,0,0, 1,1, 0,0,0, 0,0, 1.f, 0);

    // ---- ns/nsi (fp16) ----
    ln_kernel<__half><<<dim3(SL, BATCH), 256>>>(x  + (long long)ZL*DIM, p_nsh,  g1, bt1,
                                                (long long)TT*DIM, (long long)SL*DIM);
    ln_kernel<__half><<<dim3(SL, BATCH), 256>>>(xi + (long long)ZL*DIM, p_nsih, g1, bt1,
                                                (long long)TT*DIM, (long long)SL*DIM);

    // ---- MHA both streams, batched ----
    {
        static bool ainit = false;
        if (!ainit) {
            cudaFuncSetAttribute(attn_fused, cudaFuncAttributeMaxDynamicSharedMemorySize, PV_SMEM);
            ainit = true;
        }
    }
    ln_cat_kernel<<<dim3(NN, BATCH, 2), 256>>>(p_zfh, x, xi, p_lnh2, g1, bt1);
    mm<128,128,__half,__half,__half>(p_lnh2, wqkvh, b_qkv, nullptr, nullptr, p_qkvh2,
        BATCH*NN, QKV3, DIM, DIM, DIM, QKV3,
        (long long)NND, 0, (long long)NNQ, 2, 1, 0,0,0, 0,0, 1.f, 0);
    vtrans_k<<<dim3(NN/32, HD/32, 2*BATCH*HEADS), dim3(32,8)>>>(p_qkvh2, p_vth2);
    attn_fused<<<dim3(3, 2*BATCH*HEADS), 512, PV_SMEM>>>(
        p_qkvh2, p_vth2, out + O_ATTN, p_aoh2);
    mm<128,128,__half,__half,float>(p_aoh2, wprojh, b_proj, nullptr, nullptr, p_xattn2,
        BATCH*NN, DIM, DIM, DIM, DIM, DIM,
        (long long)NND, 0, (long long)NND, 2, 1, 0,0,0, 0,0, 1.f, 0);

    // ---- attn_x / attn_xi ----
    mm<64,128,__half,__half,float>(p_zfh, p_nsh, nullptr, nullptr, nullptr, p_attnx,
        ZL, SL, DIM, DIM, DIM, SL,
        (long long)ZL*DIM, (long long)SL*DIM, (long long)ZL*SL,
        BATCH, 1, 0,0,0, 0,0, scale_dim, 0);
    mm<64,128,__half,__half,float>(p_zfh, p_nsih, nullptr, nullptr, nullptr, p_attnxi,
        ZL, SL, DIM, DIM, DIM, SL,
        (long long)ZL*DIM, (long long)SL*DIM, (long long)ZL*SL,
        BATCH, 1, 0,0,0, 0,0, scale_dim, 0);

    // ---- fusion ----
    fusion_kernel<<<BATCH, SL>>>(p_attnx, p_attnxi,
                                 out + O_ALPHA, out + O_UM, out + O_U, out + O_UI);
    make_v_k<<<cdiv((long long)SLD, 256), 256>>>(p_nsh, p_nsih, out + O_ALPHA, p_vh);
    mm<128,128,__half,__half,float>(p_vh, wfush, b_fus, nullptr, nullptr, p_vf,
        BATCH*SL, DIM, DIM, DIM, DIM, DIM, 0,0,0, 1,1, 0,0,0, 0,0, 1.f, 0);

    // ---- fused residual + 3x LN ----
    resid_ln_k<<<dim3(TT, BATCH), 256>>>(x, xi, p_xattn2, p_vf, g2, bt2,
                                         p_xnew2, p_lnvh, p_lnx2);

    // ---- adap2 ----
    mm<128,128,__half,__half,float>(p_lnvh, wal2h, b_al2, nullptr, nullptr, p_adap2,
        BATCH*TT, DIM, DIM, DIM, DIM, DIM, 0,0,0, 1,1, 0,0,0, 0,0, 1.f, 0);

    // ---- MLP both streams, batched ----
    mm<128,128,__half,__half,__half>(p_lnx2, wfc1h, b_fc1, nullptr, nullptr, p_hh2,
        BATCH*TT, HID, DIM, DIM, DIM, HID,
        (long long)TTD, 0, (long long)TTH, 2, 1, 0,0,0, 0,0, 1.f, 1);
    mm<128,128,__half,__half,float>(p_hh2, wfc2h, b_fc2, p_xnew2, p_adap2, out + O_XOUT,
        BATCH*TT, DIM, HID, HID, HID, DIM,
        (long long)TTH, 0, SIDE_OUT, 2, 1, 0,0,0,
        (long long)TTD, 0, 1.f, 0);

    // ---- index passthroughs (single launch) ----
    i2f_all<<<cdiv(2*(BATCH*ZL + BATCH*SL), 256), 256>>>(
        git,  out + O_GIT,  BATCH*ZL,
        gis,  out + O_GIS,  BATCH*SL,
        giti, out + O_GITI, BATCH*ZL,
        gisi, out + O_GISI, BATCH*SL);
}

// round 13
// speedup vs baseline: 6.9424x; 1.0413x over previous
#include <cuda_runtime.h>
#include <cuda_fp16.h>
#include <math.h>
#include <cstdint>
#include <type_traits>

// ---------------- problem constants ----------------
#define BATCH 32
#define ZL 64
#define SL 256
#define TT 320
#define NN 384
#define DIM 768
#define HEADS 12
#define HD 64
#define HID 3072
#define QKV3 2304

#define O_XOUT   0LL
#define O_GIT    7864320LL
#define O_GIS    7866368LL
#define O_ATTN   7874560LL
#define O_XIOUT  64497664LL
#define O_GITI   72361984LL
#define O_GISI   72364032LL
#define O_IATTN  72372224LL
#define O_ALPHA  128995328LL
#define O_UM     129003520LL
#define O_U      129011712LL
#define O_UI     129019904LL

#define SIDE_OUT 64497664LL
#define NND  (BATCH*NN*DIM)
#define TTD  (BATCH*TT*DIM)
#define TTH  (BATCH*TT*HID)
#define NNQ  (BATCH*NN*QKV3)
#define SLD  (BATCH*SL*DIM)

// ---------------- scratch ----------------
__device__ __half g_cath [BATCH*ZL*2*DIM];
__device__ __half g_zfh  [BATCH*ZL*DIM];
__device__ __half g_nsh  [SLD];
__device__ __half g_nsih [SLD];
__device__ float  g_attnx [BATCH*ZL*SL];
__device__ float  g_attnxi[BATCH*ZL*SL];
__device__ __half g_lnh2 [2*NND];
__device__ __half g_qkvh2[2*NNQ];
__device__ __half g_aoh2 [2*NND];
__device__ float  g_xattn2[2*NND];
__device__ __half g_vh   [SLD];
__device__ float  g_vf   [SLD];
__device__ float  g_xnew2[2*TTD];
__device__ __half g_lnvh [TTD];
__device__ __half g_lnx2 [2*TTD];
__device__ float  g_adap2[TTD];
__device__ __half g_hh2  [2*TTH];
__device__ __half g_wqkvh[QKV3*DIM];
__device__ __half g_wprojh[DIM*DIM];
__device__ __half g_wfc1h[HID*DIM];
__device__ __half g_wfc2h[DIM*HID];
__device__ __half g_walh [DIM*2*DIM];
__device__ __half g_wal2h[DIM*DIM];
__device__ __half g_wfush[DIM*DIM];

// =============== helpers =====================================================
__device__ __forceinline__ uint32_t smem_u32(const void* p) {
    uint32_t a;
    asm("{ .reg .u64 t; cvta.to.shared.u64 t, %1; cvt.u32.u64 %0, t; }" : "=r"(a) : "l"(p));
    return a;
}
__device__ __forceinline__ void mma16816h(float* d, const uint32_t* a, const uint32_t* b) {
    asm volatile("mma.sync.aligned.m16n8k16.row.col.f32.f16.f16.f32 "
        "{%0,%1,%2,%3}, {%4,%5,%6,%7}, {%8,%9}, {%0,%1,%2,%3};"
        : "+f"(d[0]), "+f"(d[1]), "+f"(d[2]), "+f"(d[3])
        : "r"(a[0]), "r"(a[1]), "r"(a[2]), "r"(a[3]), "r"(b[0]), "r"(b[1]));
}
__device__ __forceinline__ void ldsm4(uint32_t& r0, uint32_t& r1, uint32_t& r2, uint32_t& r3,
                                      uint32_t addr) {
    asm volatile("ldmatrix.sync.aligned.m8n8.x4.shared.b16 {%0,%1,%2,%3}, [%4];"
        : "=r"(r0), "=r"(r1), "=r"(r2), "=r"(r3) : "r"(addr));
}
__device__ __forceinline__ void ldsm4t(uint32_t& r0, uint32_t& r1, uint32_t& r2, uint32_t& r3,
                                       uint32_t addr) {
    asm volatile("ldmatrix.sync.aligned.m8n8.x4.trans.shared.b16 {%0,%1,%2,%3}, [%4];"
        : "=r"(r0), "=r"(r1), "=r"(r2), "=r"(r3) : "r"(addr));
}
__device__ __forceinline__ uint32_t pack_h2(float x, float y) {
    __half2 p = __float22half2_rn(make_float2(x, y));
    return *(uint32_t*)&p;
}
template<typename T> struct RawVec;
template<> struct RawVec<float>  { using type = float4; };
template<> struct RawVec<__half> { using type = uint2;  };
__device__ __forceinline__ uint2 to_h2(const float4& v) {
    return make_uint2(pack_h2(v.x, v.y), pack_h2(v.z, v.w));
}
__device__ __forceinline__ uint2 to_h2(const uint2& v) { return v; }
__device__ __forceinline__ void st_s(float* p, float v)  { *p = v; }
__device__ __forceinline__ void st_s(__half* p, float v) { *p = __float2half_rn(v); }
__device__ __forceinline__ void st2(float* p, float x, float y) {
    *(float2*)p = make_float2(x, y);
}
__device__ __forceinline__ void st2(__half* p, float x, float y) {
    *(uint32_t*)p = pack_h2(x, y);
}
__device__ __forceinline__ float wred(float v) {
    v += __shfl_xor_sync(0xFFFFFFFFu, v, 16);
    v += __shfl_xor_sync(0xFFFFFFFFu, v, 8);
    v += __shfl_xor_sync(0xFFFFFFFFu, v, 4);
    v += __shfl_xor_sync(0xFFFFFFFFu, v, 2);
    v += __shfl_xor_sync(0xFFFFFFFFu, v, 1);
    return v;
}

#define CP_ASYNC16(dst, src) \
    asm volatile("cp.async.cg.shared.global [%0], [%1], 16;" :: "r"(dst), "l"(src))
#define CP_COMMIT()  asm volatile("cp.async.commit_group;")
#define CP_WAIT0()   asm volatile("cp.async.wait_group 0;")

// =============== fp16 mma.sync GEMM, typed A/B/C =============================
#define RWH 40
#define RWA 72

template<int TM, int TN, typename TA, typename TB, typename TC>
__global__ __launch_bounds__(512, 2)
void mm2(const TA* __restrict__ A, const TB* __restrict__ B,
         const float* __restrict__ bias,
         const float* __restrict__ res1, const float* __restrict__ res2,
         TC* __restrict__ C,
         int K, int lda, int ldb, int ldc,
         long long sAb, long long sBb, long long sCb, int batchH,
         long long sAh, long long sBh, long long sCh,
         long long sR1b, long long sR2b,
         float alpha, int act)
{
    extern __shared__ char dsm[];
    constexpr int WTM = TM/4, WTN = TN/4;
    constexpr int MI = WTM/16, NI = WTN/8;
    constexpr bool ASYNC =
        std::is_same<TA,__half>::value && std::is_same<TB,__half>::value;

    const int tid  = threadIdx.x;
    const int lane = tid & 31;
    const int w    = tid >> 5;
    const int wm   = w >> 2;
    const int wn   = w & 3;

    const int bz = blockIdx.z;
    const int b  = bz / batchH;
    const int h  = bz - b*batchH;
    const int m0 = blockIdx.y * TM;
    const int n0 = blockIdx.x * TN;
    const TA* Ab = A + (long long)b*sAb + (long long)h*sAh + (long long)m0*lda;
    const TB* Bb = B + (long long)b*sBb + (long long)h*sBh + (long long)n0*ldb;
    const long long coffC  = (long long)b*sCb + (long long)h*sCh;
    const long long coffR1 = (long long)b*sR1b;
    const long long coffR2 = (long long)b*sR2b;

    const uint32_t sb0 = smem_u32(dsm);

    float acc[MI][NI][4];
    #pragma unroll
    for (int mi = 0; mi < MI; mi++)
        #pragma unroll
        for (int ni = 0; ni < NI; ni++)
            #pragma unroll
            for (int j = 0; j < 4; j++) acc[mi][ni][j] = 0.f;

    if constexpr (ASYNC) {
        constexpr int AHL = TM*RWA;
        constexpr int STAGE_BYTES = (TM + TN)*RWA*2;
        constexpr int PLA = TM*8/512, PLB = TN*8/512;
        const uint32_t a_l = (uint32_t)(((wm*WTM + (lane & 15))*RWA + ((lane >> 4) << 3)) * 2);
        const uint32_t b_l = (uint32_t)(AHL*2 + ((wn*WTN + (lane & 15))*RWA + ((lane >> 4) << 3)) * 2);
        const __half* Abh = (const __half*)Ab;
        const __half* Bbh = (const __half*)Bb;
        const int NC = K >> 6;

        #pragma unroll
        for (int p = 0; p < PLA; p++) {
            int u = tid + (p << 9);
            int r = u >> 3, ch = u & 7;
            CP_ASYNC16(sb0 + (uint32_t)(r*RWA*2 + ch*16),
                       Abh + (long long)r*lda + ch*8);
        }
        #pragma unroll
        for (int p = 0; p < PLB; p++) {
            int u = tid + (p << 9);
            int r = u >> 3, ch = u & 7;
            CP_ASYNC16(sb0 + (uint32_t)(AHL*2 + r*RWA*2 + ch*16),
                       Bbh + (long long)r*ldb + ch*8);
        }
        CP_COMMIT();

        for (int c = 0; c < NC; c++) {
            CP_WAIT0();
            __syncthreads();
            if (c + 1 < NC) {
                const int k0 = (c + 1) << 6;
                const uint32_t base = sb0 + ((c + 1) & 1) * STAGE_BYTES;
                #pragma unroll
                for (int p = 0; p < PLA; p++) {
                    int u = tid + (p << 9);
                    int r = u >> 3, ch = u & 7;
                    CP_ASYNC16(base + (uint32_t)(r*RWA*2 + ch*16),
                               Abh + (long long)r*lda + k0 + ch*8);
                }
                #pragma unroll
                for (int p = 0; p < PLB; p++) {
                    int u = tid + (p << 9);
                    int r = u >> 3, ch = u & 7;
                    CP_ASYNC16(base + (uint32_t)(AHL*2 + r*RWA*2 + ch*16),
                               Bbh + (long long)r*ldb + k0 + ch*8);
                }
                CP_COMMIT();
            }
            const uint32_t stageu = sb0 + (c & 1) * STAGE_BYTES;
            #pragma unroll
            for (int ks = 0; ks < 4; ks++) {
                const uint32_t kb = ks * 32;
                uint32_t ah[MI][4];
                #pragma unroll
                for (int mi = 0; mi < MI; mi++) {
                    uint32_t ad = stageu + a_l + mi*(16*RWA*2) + kb;
                    ldsm4(ah[mi][0], ah[mi][1], ah[mi][2], ah[mi][3], ad);
                }
                uint32_t bh[NI][2];
                #pragma unroll
                for (int nj = 0; nj < NI/2; nj++) {
                    uint32_t bd = stageu + b_l + nj*(16*RWA*2) + kb;
                    uint32_t q0, q1, q2, q3;
                    ldsm4(q0, q1, q2, q3, bd);
                    bh[2*nj][0] = q0; bh[2*nj][1] = q2;
                    bh[2*nj+1][0] = q1; bh[2*nj+1][1] = q3;
                }
                #pragma unroll
                for (int mi = 0; mi < MI; mi++)
                    #pragma unroll
                    for (int ni = 0; ni < NI; ni++)
                        mma16816h(acc[mi][ni], ah[mi], bh[ni]);
            }
        }
    } else {
        constexpr int AHL = TM*RWH;
        constexpr int STAGE_BYTES = (TM + TN)*RWH*2;
        constexpr int PA = TM/64, PB = TN/64;
        const uint32_t a_l = (uint32_t)(((wm*WTM + (lane & 15))*RWH + ((lane >> 4) << 3)) * 2);
        const uint32_t b_l = (uint32_t)(AHL*2 + ((wn*WTN + (lane & 15))*RWH + ((lane >> 4) << 3)) * 2);
        const int lq = tid & 7;
        const int lr = tid >> 3;
        const int NC = K >> 5;
        typename RawVec<TA>::type pA[PA];
        typename RawVec<TB>::type pB[PB];

        #pragma unroll
        for (int p = 0; p < PA; p++)
            pA[p] = *(const typename RawVec<TA>::type*)(Ab + (long long)(lr + 64*p)*lda + 4*lq);
        #pragma unroll
        for (int p = 0; p < PB; p++)
            pB[p] = *(const typename RawVec<TB>::type*)(Bb + (long long)(lr + 64*p)*ldb + 4*lq);

        for (int c = 0; c < NC; c++) {
            const int st = c & 1;
            char* sb = dsm + st * STAGE_BYTES;
            __half* Ah = (__half*)sb;
            __half* Bh = Ah + AHL;

            #pragma unroll
            for (int p = 0; p < PA; p++)
                *(uint2*)(Ah + (lr + 64*p)*RWH + 4*lq) = to_h2(pA[p]);
            #pragma unroll
            for (int p = 0; p < PB; p++)
                *(uint2*)(Bh + (lr + 64*p)*RWH + 4*lq) = to_h2(pB[p]);
            __syncthreads();

            if (c + 1 < NC) {
                const int k0 = (c + 1) << 5;
                #pragma unroll
                for (int p = 0; p < PA; p++)
                    pA[p] = *(const typename RawVec<TA>::type*)(Ab + (long long)(lr + 64*p)*lda + k0 + 4*lq);
                #pragma unroll
                for (int p = 0; p < PB; p++)
                    pB[p] = *(const typename RawVec<TB>::type*)(Bb + (long long)(lr + 64*p)*ldb + k0 + 4*lq);
            }

            const uint32_t stageu = sb0 + st * STAGE_BYTES;
            #pragma unroll
            for (int ks = 0; ks < 2; ks++) {
                const uint32_t kb = ks * 32;
                uint32_t ah[MI][4];
                #pragma unroll
                for (int mi = 0; mi < MI; mi++) {
                    uint32_t ad = stageu + a_l + mi*(16*RWH*2) + kb;
                    ldsm4(ah[mi][0], ah[mi][1], ah[mi][2], ah[mi][3], ad);
                }
                uint32_t bh[NI][2];
                #pragma unroll
                for (int nj = 0; nj < NI/2; nj++) {
                    uint32_t bd = stageu + b_l + nj*(16*RWH*2) + kb;
                    uint32_t q0, q1, q2, q3;
                    ldsm4(q0, q1, q2, q3, bd);
                    bh[2*nj][0] = q0; bh[2*nj][1] = q2;
                    bh[2*nj+1][0] = q1; bh[2*nj+1][1] = q3;
                }
                #pragma unroll
                for (int mi = 0; mi < MI; mi++)
                    #pragma unroll
                    for (int ni = 0; ni < NI; ni++)
                        mma16816h(acc[mi][ni], ah[mi], bh[ni]);
            }
            __syncthreads();
        }
    }

    // ---- epilogue: direct fragment stores ----
    const int g = lane >> 2, t4 = lane & 3;
    float2 bv[NI];
    if (bias) {
        #pragma unroll
        for (int ni = 0; ni < NI; ni++)
            bv[ni] = *(const float2*)(bias + n0 + wn*WTN + ni*8 + 2*t4);
    }
    #pragma unroll
    for (int mi = 0; mi < MI; mi++)
        #pragma unroll
        for (int h2 = 0; h2 < 2; h2++) {
            long long row = m0 + wm*WTM + mi*16 + g + 8*h2;
            long long base = row*(long long)ldc + n0 + wn*WTN + 2*t4;
            #pragma unroll
            for (int ni = 0; ni < NI; ni++) {
                float vx = acc[mi][ni][2*h2]   * alpha;
                float vy = acc[mi][ni][2*h2+1] * alpha;
                if (bias) { vx += bv[ni].x; vy += bv[ni].y; }
                long long off = base + ni*8;
                if (res1) { float2 a = *(const float2*)(res1 + coffR1 + off); vx += a.x; vy += a.y; }
                if (res2) { float2 a = *(const float2*)(res2 + coffR2 + off); vx += a.x; vy += a.y; }
                if (act == 1) {
                    vx = 0.5f*vx*(1.f + erff(vx*0.70710678118654752f));
                    vy = 0.5f*vy*(1.f + erff(vy*0.70710678118654752f));
                }
                st2(C + coffC + off, vx, vy);
            }
        }
}

// =============== fused QK^T + softmax + P@V, dual-stream, direct V ===========
#define RW2 72
#define RW3 392
#define RWV 72
#define PV_SMEM (128*RW3*2 + 384*RWV*2 + 128*4*4 + 128*4)

__global__ __launch_bounds__(512, 1)
void attn_fused(const __half* __restrict__ qkv2,
                float* __restrict__ attn_base, __half* __restrict__ ao2)
{
    extern __shared__ char dsm[];
    __half* Ph  = (__half*)dsm;                         // 128 x RW3 (phase B A)
    __half* Vs  = (__half*)(dsm + 128*RW3*2);           // 384 x RWV (V natural)
    float*  red = (float*)(dsm + 128*RW3*2 + 384*RWV*2);
    float*  invb= red + 128*4;
    __half* Qs  = (__half*)dsm;                         // phase A alias (within Ph)
    __half* Ks  = Qs + 128*RW2;

    const int tid = threadIdx.x;
    const int lane = tid & 31;
    const int w = tid >> 5;
    const int wm = w >> 2, wn = w & 3;
    const int g = lane >> 2, t4 = lane & 3;

    const int m0 = blockIdx.x * 128;
    const int sy = blockIdx.y;
    const int side = sy / (BATCH*HEADS);
    const int bh = sy - side*(BATCH*HEADS);
    const int b  = bh / HEADS;
    const int hh = bh - b*HEADS;

    const __half* qkv = qkv2 + (long long)side*NNQ;
    float* attn = attn_base + (long long)side*SIDE_OUT;
    __half* ao  = ao2 + (long long)side*NND;

    const __half* qbase = qkv + (long long)b*NN*QKV3 + hh*HD;

    // load Q (128x64), K (384x64), V (384x64, natural) -- V region disjoint
    #pragma unroll
    for (int p = 0; p < 2; p++) {
        int u = tid + (p << 9);
        int r = u >> 3, ch = u & 7;
        *(uint4*)(Qs + r*RW2 + ch*8) =
            *(const uint4*)(qbase + (long long)(m0 + r)*QKV3 + ch*8);
    }
    #pragma unroll
    for (int p = 0; p < 6; p++) {
        int u = tid + (p << 9);
        int r = u >> 3, ch = u & 7;
        *(uint4*)(Ks + r*RW2 + ch*8) =
            *(const uint4*)(qbase + DIM + (long long)r*QKV3 + ch*8);
    }
    #pragma unroll
    for (int p = 0; p < 6; p++) {
        int u = tid + (p << 9);
        int r = u >> 3, ch = u & 7;
        *(uint4*)(Vs + r*RWV + ch*8) =
            *(const uint4*)(qbase + 2*DIM + (long long)r*QKV3 + ch*8);
    }
    __syncthreads();

    const uint32_t sq = smem_u32(Qs);
    const uint32_t sk = smem_u32(Ks);
    const uint32_t a_l = sq + ((wm*32 + (lane & 15))*RW2 + ((lane >> 4) << 3)) * 2;
    const uint32_t b_l = sk + ((wn*96 + (lane & 15))*RW2 + ((lane >> 4) << 3)) * 2;

    float acc[2][12][4];
    #pragma unroll
    for (int mi = 0; mi < 2; mi++)
        #pragma unroll
        for (int ni = 0; ni < 12; ni++)
            #pragma unroll
            for (int j = 0; j < 4; j++) acc[mi][ni][j] = 0.f;

    #pragma unroll
    for (int ks = 0; ks < 4; ks++) {
        const uint32_t kb = ks * 32;
        uint32_t ah[2][4];
        #pragma unroll
        for (int mi = 0; mi < 2; mi++)
            ldsm4(ah[mi][0], ah[mi][1], ah[mi][2], ah[mi][3],
                  a_l + mi*(16*RW2*2) + kb);
        #pragma unroll
        for (int nj = 0; nj < 6; nj++) {
            uint32_t q0, q1, q2, q3;
            ldsm4(q0, q1, q2, q3, b_l + nj*(16*RW2*2) + kb);
            uint32_t b0[2] = {q0, q2}, b1[2] = {q1, q3};
            #pragma unroll
            for (int mi = 0; mi < 2; mi++) {
                mma16816h(acc[mi][2*nj],   ah[mi], b0);
                mma16816h(acc[mi][2*nj+1], ah[mi], b1);
            }
        }
    }

    #pragma unroll
    for (int mi = 0; mi < 2; mi++)
        #pragma unroll
        for (int ni = 0; ni < 12; ni++)
            #pragma unroll
            for (int j = 0; j < 4; j++) acc[mi][ni][j] *= 0.125f;

    float M[2][2];
    #pragma unroll
    for (int mi = 0; mi < 2; mi++)
        #pragma unroll
        for (int h2 = 0; h2 < 2; h2++) {
            float m = -1e30f;
            #pragma unroll
            for (int ni = 0; ni < 12; ni++)
                m = fmaxf(m, fmaxf(acc[mi][ni][2*h2], acc[mi][ni][2*h2+1]));
            m = fmaxf(m, __shfl_xor_sync(0xFFFFFFFFu, m, 1));
            m = fmaxf(m, __shfl_xor_sync(0xFFFFFFFFu, m, 2));
            if (t4 == 0) red[(wm*32 + mi*16 + g + 8*h2)*4 + wn] = m;
        }
    __syncthreads();
    #pragma unroll
    for (int mi = 0; mi < 2; mi++)
        #pragma unroll
        for (int h2 = 0; h2 < 2; h2++) {
            int row = wm*32 + mi*16 + g + 8*h2;
            M[mi][h2] = fmaxf(fmaxf(red[row*4], red[row*4+1]),
                              fmaxf(red[row*4+2], red[row*4+3]));
        }
    __syncthreads();

    float S[2][2];
    #pragma unroll
    for (int mi = 0; mi < 2; mi++)
        #pragma unroll
        for (int h2 = 0; h2 < 2; h2++) {
            float s = 0.f;
            #pragma unroll
            for (int ni = 0; ni < 12; ni++) {
                float e0 = __expf(acc[mi][ni][2*h2]   - M[mi][h2]);
                float e1 = __expf(acc[mi][ni][2*h2+1] - M[mi][h2]);
                acc[mi][ni][2*h2] = e0; acc[mi][ni][2*h2+1] = e1;
                s += e0 + e1;
            }
            s += __shfl_xor_sync(0xFFFFFFFFu, s, 1);
            s += __shfl_xor_sync(0xFFFFFFFFu, s, 2);
            if (t4 == 0) red[(wm*32 + mi*16 + g + 8*h2)*4 + wn] = s;
        }
    __syncthreads();
    #pragma unroll
    for (int mi = 0; mi < 2; mi++)
        #pragma unroll
        for (int h2 = 0; h2 < 2; h2++) {
            int row = wm*32 + mi*16 + g + 8*h2;
            float inv = 1.f / (red[row*4] + red[row*4+1] + red[row*4+2] + red[row*4+3]);
            S[mi][h2] = inv;
            if (wn == 0 && t4 == 0) invb[row] = inv;
        }

    float* abase = attn + (long long)bh*NN*NN;
    #pragma unroll
    for (int mi = 0; mi < 2; mi++)
        #pragma unroll
        for (int h2 = 0; h2 < 2; h2++) {
            int row = m0 + wm*32 + mi*16 + g + 8*h2;
            float inv = S[mi][h2];
            float* rp = abase + (long long)row*NN + wn*96 + 2*t4;
            #pragma unroll
            for (int ni = 0; ni < 12; ni++) {
                float2 o;
                o.x = acc[mi][ni][2*h2]   * inv;
                o.y = acc[mi][ni][2*h2+1] * inv;
                *(float2*)(rp + ni*8) = o;
            }
        }

    __syncthreads();   // done reading Qs/Ks; Ph writes may begin (Vs untouched)

    #pragma unroll
    for (int mi = 0; mi < 2; mi++)
        #pragma unroll
        for (int h2 = 0; h2 < 2; h2++) {
            int row = wm*32 + mi*16 + g + 8*h2;
            __half* rp = Ph + row*RW3 + wn*96 + 2*t4;
            #pragma unroll
            for (int ni = 0; ni < 12; ni++)
                *(uint32_t*)(rp + ni*8) = pack_h2(acc[mi][ni][2*h2], acc[mi][ni][2*h2+1]);
        }
    __syncthreads();

    // phase B: P@V with V natural + ldmatrix.trans B fragments
    const int wm2 = w >> 2, wn2 = w & 3;
    const uint32_t pa = smem_u32(Ph) + ((wm2*32 + (lane & 15))*RW3 + ((lane >> 4) << 3))*2;
    const int grp = lane >> 3, rr8 = lane & 7;
    const uint32_t v_l = smem_u32(Vs) +
        (uint32_t)(((((grp & 1) * 8) + rr8)*RWV + ((grp >> 1) * 8) + wn2*16) * 2);

    float acc2[2][2][4];
    #pragma unroll
    for (int mi = 0; mi < 2; mi++)
        #pragma unroll
        for (int ni = 0; ni < 2; ni++)
            #pragma unroll
            for (int j = 0; j < 4; j++) acc2[mi][ni][j] = 0.f;

    #pragma unroll
    for (int ks = 0; ks < 24; ks++) {
        uint32_t ah0[4], ah1[4], q0, q1, q2, q3;
        ldsm4(ah0[0], ah0[1], ah0[2], ah0[3], pa + ks*32);
        ldsm4(ah1[0], ah1[1], ah1[2], ah1[3], pa + 16*RW3*2 + ks*32);
        ldsm4t(q0, q1, q2, q3, v_l + (uint32_t)(ks*16*RWV*2));
        uint32_t b0[2] = {q0, q1}, b1[2] = {q2, q3};
        mma16816h(acc2[0][0], ah0, b0);
        mma16816h(acc2[0][1], ah0, b1);
        mma16816h(acc2[1][0], ah1, b0);
        mma16816h(acc2[1][1], ah1, b1);
    }

    #pragma unroll
    for (int mi = 0; mi < 2; mi++) {
        int r0 = wm2*32 + mi*16 + g;
        float inv0 = invb[r0], inv1 = invb[r0 + 8];
        long long base0 = ((long long)b*NN + m0 + r0)*DIM + hh*HD;
        long long base1 = base0 + 8LL*DIM;
        #pragma unroll
        for (int ni = 0; ni < 2; ni++) {
            int col = wn2*16 + ni*8 + 2*t4;
            *(uint32_t*)(ao + base0 + col) = pack_h2(acc2[mi][ni][0]*inv0, acc2[mi][ni][1]*inv0);
            *(uint32_t*)(ao + base1 + col) = pack_h2(acc2[mi][ni][2]*inv1, acc2[mi][ni][3]*inv1);
        }
    }
}

// ---------------- LayerNorm over ns/nsi, both sides in one launch ------------
__global__ void ln_ns_k(const float* __restrict__ x, const float* __restrict__ xi,
                        __half* __restrict__ nsh, __half* __restrict__ nsih,
                        const float* __restrict__ g, const float* __restrict__ b)
{
    int t = blockIdx.x, bb = blockIdx.y, side = blockIdx.z;
    const float* src = (side ? xi : x) + (long long)ZL*DIM + ((long long)bb*TT + t)*DIM;
    __half* y = (side ? nsih : nsh) + ((long long)bb*SL + t)*DIM;
    int tid = threadIdx.x;
    int wid = tid >> 5, lane = tid & 31;
    float v0 = src[tid], v1 = src[tid+256], v2 = src[tid+512];
    float s = wred(v0 + v1 + v2);
    float q = wred(v0*v0 + v1*v1 + v2*v2);
    __shared__ float ws[8], wq[8];
    if (lane == 0) { ws[wid] = s; wq[wid] = q; }
    __syncthreads();
    float S = 0.f, Q = 0.f;
    #pragma unroll
    for (int k = 0; k < 8; k++) { S += ws[k]; Q += wq[k]; }
    float mean = S * (1.f/768.f);
    float inv = rsqrtf(Q * (1.f/768.f) - mean*mean + 1e-5f);
    y[tid]     = __float2half_rn((v0-mean)*inv*g[tid]     + b[tid]);
    y[tid+256] = __float2half_rn((v1-mean)*inv*g[tid+256] + b[tid+256]);
    y[tid+512] = __float2half_rn((v2-mean)*inv*g[tid+512] + b[tid+512]);
}

// LN over concat [z_f(fp16), x/xi(fp32)], both sides in one launch
__global__ void ln_cat_kernel(const __half* __restrict__ zf,
                              const float* __restrict__ x, const float* __restrict__ xi,
                              __half* __restrict__ out2,
                              const float* __restrict__ g, const float* __restrict__ b)
{
    int t = blockIdx.x, bb = blockIdx.y, side = blockIdx.z;
    const float* xs = side ? xi : x;
    __half* y = out2 + (long long)side*NND + ((long long)bb*NN + t)*DIM;
    int tid = threadIdx.x;
    int wid = tid >> 5, lane = tid & 31;
    float v0, v1, v2;
    if (t < ZL) {
        const __half* src = zf + ((long long)bb*ZL + t)*DIM;
        v0 = __half2float(src[tid]);
        v1 = __half2float(src[tid+256]);
        v2 = __half2float(src[tid+512]);
    } else {
        const float* src = xs + ((long long)bb*TT + (t - ZL))*DIM;
        v0 = src[tid]; v1 = src[tid+256]; v2 = src[tid+512];
    }
    float s = wred(v0 + v1 + v2);
    float q = wred(v0*v0 + v1*v1 + v2*v2);
    __shared__ float ws[8], wq[8];
    if (lane == 0) { ws[wid] = s; wq[wid] = q; }
    __syncthreads();
    float S = 0.f, Q = 0.f;
    #pragma unroll
    for (int k = 0; k < 8; k++) { S += ws[k]; Q += wq[k]; }
    float mean = S * (1.f/768.f);
    float inv = rsqrtf(Q * (1.f/768.f) - mean*mean + 1e-5f);
    y[tid]     = __float2half_rn((v0-mean)*inv*g[tid]     + b[tid]);
    y[tid+256] = __float2half_rn((v1-mean)*inv*g[tid+256] + b[tid+256]);
    y[tid+512] = __float2half_rn((v2-mean)*inv*g[tid+512] + b[tid+512]);
}

// ---------------- fused residual + 3x LayerNorm ------------------------------
__global__ void resid_ln_k(const float* __restrict__ x, const float* __restrict__ xi,
                           const float* __restrict__ xattn2,
                           const float* __restrict__ vfus,
                           const float* __restrict__ g2, const float* __restrict__ bt2,
                           float* __restrict__ xnew2,
                           __half* __restrict__ lnv, __half* __restrict__ lnx2)
{
    const int t = blockIdx.x, b = blockIdx.y;
    const int tid = threadIdx.x;
    const int wid = tid >> 5, lane = tid & 31;
    const long long rbase = ((long long)b*TT + t)*DIM;
    const long long abase = ((long long)b*NN + ZL + t)*DIM;
    const float* xattn  = xattn2;
    const float* xiattn = xattn2 + NND;
    const float* vsrc = (t < ZL) ? xiattn + ((long long)b*NN + t)*DIM
                                 : vfus   + ((long long)b*SL + (t - ZL))*DIM;

    float vf[3], xo[3], xio[3];
    float s[6] = {0,0,0,0,0,0};
    #pragma unroll
    for (int j = 0; j < 3; j++) {
        int c = tid + j*256;
        float vv = vsrc[c];
        float a1 = xattn[abase + c], a2 = xiattn[abase + c];
        float xv = x[rbase + c] + a1 + vv;
        float xiv = xi[rbase + c] + a2 + vv;
        vf[j] = vv; xo[j] = xv; xio[j] = xiv;
        xnew2[rbase + c]       = xv;
        xnew2[TTD + rbase + c] = xiv;
        s[0] += vv;  s[1] += vv*vv;
        s[2] += xv;  s[3] += xv*xv;
        s[4] += xiv; s[5] += xiv*xiv;
    }

    #pragma unroll
    for (int k = 0; k < 6; k++) s[k] = wred(s[k]);
    __shared__ float sh[6][8];
    if (lane == 0) {
        #pragma unroll
        for (int k = 0; k < 6; k++) sh[k][wid] = s[k];
    }
    __syncthreads();
    float tot[6];
    #pragma unroll
    for (int k = 0; k < 6; k++) {
        float acc = 0.f;
        #pragma unroll
        for (int p = 0; p < 8; p++) acc += sh[k][p];
        tot[k] = acc;
    }
    float mv = tot[0]*(1.f/768.f), iv = rsqrtf(tot[1]*(1.f/768.f) - mv*mv + 1e-5f);
    float mx = tot[2]*(1.f/768.f), ix = rsqrtf(tot[3]*(1.f/768.f) - mx*mx + 1e-5f);
    float mi2 = tot[4]*(1.f/768.f), ii = rsqrtf(tot[5]*(1.f/768.f) - mi2*mi2 + 1e-5f);

    #pragma unroll
    for (int j = 0; j < 3; j++) {
        int c = tid + j*256;
        float gg = g2[c], bb = bt2[c];
        lnv[rbase + c]        = __float2half_rn((vf[j]-mv)*iv*gg + bb);
        lnx2[rbase + c]       = __float2half_rn((xo[j]-mx)*ix*gg + bb);
        lnx2[TTD + rbase + c] = __float2half_rn((xio[j]-mi2)*ii*gg + bb);
    }
}

// ---------------- fusion ----------------
__global__ void fusion_kernel(const float* __restrict__ ax, const float* __restrict__ axi,
                              float* __restrict__ alpha_o, float* __restrict__ um_o,
                              float* __restrict__ u_o, float* __restrict__ ui_o)
{
    int b = blockIdx.x, s = threadIdx.x;
    const float* X  = ax  + (long long)b*ZL*SL + s;
    const float* Xi = axi + (long long)b*ZL*SL + s;
    float u, ui;
    {
        float mx = -1e30f;
        for (int t = 0; t < ZL; t++) mx = fmaxf(mx, X[t*SL]);
        float sum = 0.f;
        for (int t = 0; t < ZL; t++) sum += expf(X[t*SL] - mx);
        float inv = 1.f/sum, acc = 0.f;
        for (int t = 0; t < ZL; t++) { float p = expf(X[t*SL]-mx)*inv; acc -= p*logf(p + 1e-8f); }
        u = acc;
    }
    {
        float mx = -1e30f;
        for (int t = 0; t < ZL; t++) mx = fmaxf(mx, Xi[t*SL]);
        float sum = 0.f;
        for (int t = 0; t < ZL; t++) sum += expf(Xi[t*SL] - mx);
        float inv = 1.f/sum, acc = 0.f;
        for (int t = 0; t < ZL; t++) { float p = expf(Xi[t*SL]-mx)*inv; acc -= p*logf(p + 1e-8f); }
        ui = acc;
    }
    int idx = b*SL + s;
    float alpha = 1.f / (1.f + expf(-(ui - u)));
    alpha_o[idx] = alpha;
    um_o[idx] = 0.5f*(u + ui);
    u_o[idx] = u;
    ui_o[idx] = ui;
}

// ---------------- elementwise helpers ----------------
__global__ void cat_feat_k(const float* __restrict__ x, const float* __restrict__ xi,
                           __half* __restrict__ o)
{
    long long i = (long long)blockIdx.x*blockDim.x + threadIdx.x;
    const long long n = (long long)BATCH*ZL*2*DIM;
    if (i >= n) return;
    int c = (int)(i % (2*DIM));
    long long bt = i / (2*DIM);
    long long b = bt / ZL, t = bt % ZL;
    long long src = (b*TT + t)*DIM;
    float v = (c < DIM) ? x[src + c] : xi[src + c - DIM];
    o[i] = __float2half_rn(v);
}

__global__ void make_v_k(const __half* __restrict__ ns, const __half* __restrict__ nsi,
                         const float* __restrict__ alpha, __half* __restrict__ v)
{
    long long i = (long long)blockIdx.x*blockDim.x + threadIdx.x;
    const long long n = (long long)SLD;
    if (i >= n) return;
    long long bs = i / DIM;
    float a = alpha[bs];
    v[i] = __float2half_rn(a*__half2float(ns[i]) + (1.f - a)*__half2float(nsi[i]));
}

__global__ void i2f_all(const int* a0, float* o0, int n0,
                        const int* a1, float* o1, int n1,
                        const int* a2, float* o2, int n2,
                        const int* a3, float* o3, int n3)
{
    int i = blockIdx.x*blockDim.x + threadIdx.x;
    if      (i < n0)          o0[i] = (float)a0[i];
    else if ((i -= n0) < n1)  o1[i] = (float)a1[i];
    else if ((i -= n1) < n2)  o2[i] = (float)a2[i];
    else if ((i -= n2) < n3)  o3[i] = (float)a3[i];
}

__global__ void f2h_all(const float* s0, __half* d0, int n0,
                        const float* s1, __half* d1, int n1,
                        const float* s2, __half* d2, int n2,
                        const float* s3, __half* d3, int n3,
                        const float* s4, __half* d4, int n4,
                        const float* s5, __half* d5, int n5,
                        const float* s6, __half* d6, int n6)
{
    int i = blockIdx.x*blockDim.x + threadIdx.x;
    const float* s; __half* d;
    if      (i < n0)                      { s = s0; d = d0; }
    else if ((i -= n0) < n1)              { s = s1; d = d1; }
    else if ((i -= n1) < n2)              { s = s2; d = d2; }
    else if ((i -= n2) < n3)              { s = s3; d = d3; }
    else if ((i -= n3) < n4)              { s = s4; d = d4; }
    else if ((i -= n4) < n5)              { s = s5; d = d5; }
    else if ((i -= n5) < n6)              { s = s6; d = d6; }
    else return;
    float4 v = *(const float4*)(s + 4*i);
    *(uint2*)(d + 4*i) = to_h2(v);
}

// ---------------- host-side helpers ----------------
template<int TM, int TN, typename TA, typename TB, typename TC>
static inline void mm(cudaStream_t st,
                      const TA* A, const TB* B, const float* bias,
                      const float* r1, const float* r2, TC* C,
                      int M, int N, int K, int lda, int ldb, int ldc,
                      long long sAb, long long sBb, long long sCb,
                      int nb, int nh,
                      long long sAh, long long sBh, long long sCh,
                      long long sR1b, long long sR2b,
                      float alpha, int act)
{
    constexpr bool ASYNC =
        std::is_same<TA,__half>::value && std::is_same<TB,__half>::value;
    constexpr int DS = 2 * (ASYNC ? (TM + TN)*RWA*2 : (TM + TN)*RWH*2);
    static bool init = false;
    if (!init) {
        cudaFuncSetAttribute(mm2<TM,TN,TA,TB,TC>, cudaFuncAttributeMaxDynamicSharedMemorySize, DS);
        init = true;
    }
    dim3 g(N/TN, M/TM, nb*nh);
    mm2<TM,TN,TA,TB,TC><<<g, 512, DS, st>>>(A,B,bias,r1,r2,C,K,lda,ldb,ldc,
        sAb,sBb,sCb,nh,sAh,sBh,sCh,sR1b,sR2b,alpha,act);
}

static inline int cdiv(long long a, int b) { return (int)((a + b - 1) / b); }

extern "C" void kernel_launch(void* const* d_in, const int* in_sizes, int n_in,
                              void* d_out, int out_size)
{
    const float* x      = (const float*)d_in[0];
    const float* xi     = (const float*)d_in[1];
    const int*   git    = (const int*)  d_in[2];
    const int*   giti   = (const int*)  d_in[3];
    const int*   gis    = (const int*)  d_in[4];
    const int*   gisi   = (const int*)  d_in[5];
    const float* w_qkv  = (const float*)d_in[6];
    const float* b_qkv  = (const float*)d_in[7];
    const float* w_proj = (const float*)d_in[8];
    const float* b_proj = (const float*)d_in[9];
    const float* g1     = (const float*)d_in[10];
    const float* bt1    = (const float*)d_in[11];
    const float* g2     = (const float*)d_in[12];
    const float* bt2    = (const float*)d_in[13];
    const float* w_fc1  = (const float*)d_in[14];
    const float* b_fc1  = (const float*)d_in[15];
    const float* w_fc2  = (const float*)d_in[16];
    const float* b_fc2  = (const float*)d_in[17];
    const float* w_al   = (const float*)d_in[18];
    const float* b_al   = (const float*)d_in[19];
    const float* w_al2  = (const float*)d_in[20];
    const float* b_al2  = (const float*)d_in[21];
    const float* w_fus  = (const float*)d_in[22];
    const float* b_fus  = (const float*)d_in[23];
    float* out = (float*)d_out;

    float *p_attnx, *p_attnxi, *p_xattn2, *p_vf, *p_xnew2, *p_adap2;
    __half *p_cath, *p_zfh, *p_nsh, *p_nsih, *p_lnh2, *p_qkvh2, *p_aoh2,
           *p_hh2, *p_vh, *p_lnvh, *p_lnx2;
    __half *wqkvh, *wprojh, *wfc1h, *wfc2h, *walh, *wal2h, *wfush;
    cudaGetSymbolAddress((void**)&p_cath,   g_cath);
    cudaGetSymbolAddress((void**)&p_zfh,    g_zfh);
    cudaGetSymbolAddress((void**)&p_nsh,    g_nsh);
    cudaGetSymbolAddress((void**)&p_nsih,   g_nsih);
    cudaGetSymbolAddress((void**)&p_attnx,  g_attnx);
    cudaGetSymbolAddress((void**)&p_attnxi, g_attnxi);
    cudaGetSymbolAddress((void**)&p_lnh2,   g_lnh2);
    cudaGetSymbolAddress((void**)&p_qkvh2,  g_qkvh2);
    cudaGetSymbolAddress((void**)&p_aoh2,   g_aoh2);
    cudaGetSymbolAddress((void**)&p_xattn2, g_xattn2);
    cudaGetSymbolAddress((void**)&p_vh,     g_vh);
    cudaGetSymbolAddress((void**)&p_vf,     g_vf);
    cudaGetSymbolAddress((void**)&p_xnew2,  g_xnew2);
    cudaGetSymbolAddress((void**)&p_lnvh,   g_lnvh);
    cudaGetSymbolAddress((void**)&p_lnx2,   g_lnx2);
    cudaGetSymbolAddress((void**)&p_adap2,  g_adap2);
    cudaGetSymbolAddress((void**)&p_hh2,    g_hh2);
    cudaGetSymbolAddress((void**)&wqkvh,    g_wqkvh);
    cudaGetSymbolAddress((void**)&wprojh,   g_wprojh);
    cudaGetSymbolAddress((void**)&wfc1h,    g_wfc1h);
    cudaGetSymbolAddress((void**)&wfc2h,    g_wfc2h);
    cudaGetSymbolAddress((void**)&walh,     g_walh);
    cudaGetSymbolAddress((void**)&wal2h,    g_wal2h);
    cudaGetSymbolAddress((void**)&wfush,    g_wfush);

    // side stream + events (created once; reused across calls and capture)
    static cudaStream_t s2 = nullptr;
    static cudaEvent_t evFork = nullptr, evJoin = nullptr;
    if (!s2) {
        cudaStreamCreateWithFlags(&s2, cudaStreamNonBlocking);
        cudaEventCreateWithFlags(&evFork, cudaEventDisableTiming);
        cudaEventCreateWithFlags(&evJoin, cudaEventDisableTiming);
    }

    const float scale_dim = 1.f / sqrtf((float)DIM);

    {
        const int n0 = QKV3*DIM/4, n1 = DIM*DIM/4, n2 = HID*DIM/4, n3 = DIM*HID/4,
                  n4 = DIM*2*DIM/4, n5 = DIM*DIM/4, n6 = DIM*DIM/4;
        f2h_all<<<cdiv(n0+n1+n2+n3+n4+n5+n6, 256), 256>>>(
            w_qkv, wqkvh, n0,  w_proj, wprojh, n1,  w_fc1, wfc1h, n2,
            w_fc2, wfc2h, n3,  w_al, walh, n4,  w_al2, wal2h, n5,
            w_fus, wfush, n6);
    }
    cat_feat_k<<<cdiv((long long)BATCH*ZL*2*DIM, 256), 256>>>(x, xi, p_cath);
    mm<128,128,__half,__half,__half>(0, p_cath, walh, b_al, nullptr, nullptr, p_zfh,
        BATCH*ZL, DIM, 2*DIM, 2*DIM, 2*DIM, DIM, 0,0,0, 1,1, 0,0,0, 0,0, 1.f, 0);

    // ---- ns/nsi (one launch, both sides) ----
    ln_ns_k<<<dim3(SL, BATCH, 2), 256>>>(x, xi, p_nsh, p_nsih, g1, bt1);

    // ======= FORK: fusion branch on s2 (needs zfh, nsh, nsih) =======
    cudaEventRecord(evFork, 0);
    cudaStreamWaitEvent(s2, evFork, 0);
    i2f_all<<<cdiv(2*(BATCH*ZL + BATCH*SL), 256), 256, 0, s2>>>(
        git,  out + O_GIT,  BATCH*ZL,
        gis,  out + O_GIS,  BATCH*SL,
        giti, out + O_GITI, BATCH*ZL,
        gisi, out + O_GISI, BATCH*SL);
    mm<64,128,__half,__half,float>(s2, p_zfh, p_nsh, nullptr, nullptr, nullptr, p_attnx,
        ZL, SL, DIM, DIM, DIM, SL,
        (long long)ZL*DIM, (long long)SL*DIM, (long long)ZL*SL,
        BATCH, 1, 0,0,0, 0,0, scale_dim, 0);
    mm<64,128,__half,__half,float>(s2, p_zfh, p_nsih, nullptr, nullptr, nullptr, p_attnxi,
        ZL, SL, DIM, DIM, DIM, SL,
        (long long)ZL*DIM, (long long)SL*DIM, (long long)ZL*SL,
        BATCH, 1, 0,0,0, 0,0, scale_dim, 0);
    fusion_kernel<<<BATCH, SL, 0, s2>>>(p_attnx, p_attnxi,
        out + O_ALPHA, out + O_UM, out + O_U, out + O_UI);
    make_v_k<<<cdiv((long long)SLD, 256), 256, 0, s2>>>(p_nsh, p_nsih, out + O_ALPHA, p_vh);
    mm<128,128,__half,__half,float>(s2, p_vh, wfush, b_fus, nullptr, nullptr, p_vf,
        BATCH*SL, DIM, DIM, DIM, DIM, DIM, 0,0,0, 1,1, 0,0,0, 0,0, 1.f, 0);
    cudaEventRecord(evJoin, s2);

    // ======= main chain: MHA =======
    {
        static bool ainit = false;
        if (!ainit) {
            cudaFuncSetAttribute(attn_fused, cudaFuncAttributeMaxDynamicSharedMemorySize, PV_SMEM);
            ainit = true;
        }
    }
    ln_cat_kernel<<<dim3(NN, BATCH, 2), 256>>>(p_zfh, x, xi, p_lnh2, g1, bt1);
    mm<128,128,__half,__half,__half>(0, p_lnh2, wqkvh, b_qkv, nullptr, nullptr, p_qkvh2,
        BATCH*NN, QKV3, DIM, DIM, DIM, QKV3,
        (long long)NND, 0, (long long)NNQ, 2, 1, 0,0,0, 0,0, 1.f, 0);
    attn_fused<<<dim3(3, 2*BATCH*HEADS), 512, PV_SMEM>>>(
        p_qkvh2, out + O_ATTN, p_aoh2);
    mm<128,128,__half,__half,float>(0, p_aoh2, wprojh, b_proj, nullptr, nullptr, p_xattn2,
        BATCH*NN, DIM, DIM, DIM, DIM, DIM,
        (long long)NND, 0, (long long)NND, 2, 1, 0,0,0, 0,0, 1.f, 0);

    // ======= JOIN: need p_vf =======
    cudaStreamWaitEvent(0, evJoin, 0);

    // ---- fused residual + 3x LN ----
    resid_ln_k<<<dim3(TT, BATCH), 256>>>(x, xi, p_xattn2, p_vf, g2, bt2,
                                         p_xnew2, p_lnvh, p_lnx2);

    // ---- adap2 ----
    mm<128,128,__half,__half,float>(0, p_lnvh, wal2h, b_al2, nullptr, nullptr, p_adap2,
        BATCH*TT, DIM, DIM, DIM, DIM, DIM, 0,0,0, 1,1, 0,0,0, 0,0, 1.f, 0);

    // ---- MLP both streams, batched ----
    mm<128,128,__half,__half,__half>(0, p_lnx2, wfc1h, b_fc1, nullptr, nullptr, p_hh2,
        BATCH*TT, HID, DIM, DIM, DIM, HID,
        (long long)TTD, 0, (long long)TTH, 2, 1, 0,0,0, 0,0, 1.f, 1);
    mm<128,128,__half,__half,float>(0, p_hh2, wfc2h, b_fc2, p_xnew2, p_adap2, out + O_XOUT,
        BATCH*TT, DIM, HID, HID, HID, DIM,
        (long long)TTH, 0, SIDE_OUT, 2, 1, 0,0,0,
        (long long)TTD, 0, 1.f, 0);
}